// round 2
// baseline (speedup 1.0000x reference)
#include <cuda_runtime.h>
#include <math.h>

#define B_ 2
#define C_ 256
#define HH 48
#define WW 48
#define NN 2304          // 48*48
#define NHEAD 8
#define DH 32
#define BHN 16           // B_*NHEAD
#define KTOP 576
#define HID 1024
#define GG 32            // C/8 gate channels
#define QSCALE 0.17677669529663687f   // 1/sqrt(32)

// ---------------- scratch (static device arrays; no allocation) ----------------
__device__ float g_xa  [B_*NN*C_];
__device__ float g_qkv [B_*NN*3*C_];
__device__ float g_q   [BHN*NN*DH];
__device__ float g_k   [BHN*NN*DH];
__device__ float g_v   [BHN*NN*DH];
__device__ float g_sums[BHN*3*DH];        // [bh][qsum,ksum,vsum][d]
__device__ float g_rs  [BHN*NN];
__device__ float g_cs  [BHN*NN];
__device__ int   g_rowlist[BHN*KTOP];
__device__ int   g_collist[BHN*KTOP];
__device__ float g_vunk[BHN*DH];
__device__ float g_o   [B_*NN*C_];
__device__ float g_xattn[B_*NN*C_];
__device__ float g_xdw [B_*NN*C_];
__device__ float g_xc  [B_*NN*C_];
__device__ float g_xs  [B_*NN*C_];
__device__ float g_t1  [B_*NN*GG];
__device__ float g_sg  [B_*NN];
__device__ float g_cgpart[B_*16*C_];
__device__ float g_cg  [B_*C_];
__device__ float g_x2  [B_*NN*C_];
__device__ float g_ln2 [B_*NN*C_];
__device__ float g_h   [B_*NN*HID];
__device__ float g_ff  [B_*NN*C_];

// ---------------- LayerNorm ----------------
__global__ void ln_from_nchw_k(const float* __restrict__ x,
                               const float* __restrict__ g,
                               const float* __restrict__ b) {
    int row = blockIdx.x;            // b*NN + n
    int bb = row / NN, n = row % NN;
    int c = threadIdx.x;             // 256
    float v = x[(bb*C_ + c)*NN + n];
    __shared__ float s1[256], s2[256];
    s1[c] = v; s2[c] = v*v;
    __syncthreads();
    for (int st = 128; st > 0; st >>= 1) {
        if (c < st) { s1[c] += s1[c+st]; s2[c] += s2[c+st]; }
        __syncthreads();
    }
    float mu = s1[0] * (1.0f/C_);
    float var = s2[0] * (1.0f/C_) - mu*mu;
    float r = rsqrtf(var + 1e-6f);
    g_xa[row*C_ + c] = (v - mu)*r*g[c] + b[c];
}

__global__ void ln_from_bnc_k(const float* __restrict__ g,
                              const float* __restrict__ b) {
    int row = blockIdx.x;
    int c = threadIdx.x;
    float v = g_x2[row*C_ + c];
    __shared__ float s1[256], s2[256];
    s1[c] = v; s2[c] = v*v;
    __syncthreads();
    for (int st = 128; st > 0; st >>= 1) {
        if (c < st) { s1[c] += s1[c+st]; s2[c] += s2[c+st]; }
        __syncthreads();
    }
    float mu = s1[0] * (1.0f/C_);
    float var = s2[0] * (1.0f/C_) - mu*mu;
    float r = rsqrtf(var + 1e-6f);
    g_ln2[row*C_ + c] = (v - mu)*r*g[c] + b[c];
}

// ---------------- generic fp32 SGEMM: C[M,N] = A[M,K] @ B ----------------
// TRANSB=false: B is [K,N] row-major. TRANSB=true: B is [N,K] row-major.
// M%128==0, N%64==0, K%16==0 assumed.
template<bool TRANSB>
__global__ __launch_bounds__(256) void gemm_k(const float* __restrict__ A,
                                              const float* __restrict__ B,
                                              float* __restrict__ C,
                                              int M, int N, int K) {
    const int BM = 128, BN = 64, BK = 16;
    __shared__ float As[BK][BM];
    __shared__ float Bs[BK][BN];
    int bm = blockIdx.y * BM, bn = blockIdx.x * BN;
    int tid = threadIdx.x;
    int ty = tid >> 4, tx = tid & 15;      // 16x16 thread grid
    float acc[8][4];
    #pragma unroll
    for (int i = 0; i < 8; i++)
        #pragma unroll
        for (int j = 0; j < 4; j++) acc[i][j] = 0.f;

    int arow = tid >> 1;                 // 0..127
    int acol = (tid & 1) * 8;            // 0 or 8
    int brow = tid >> 4;                 // K index for normal B
    int bcol = (tid & 15) * 4;
    int tbrow = tid >> 2;                // N index for transposed B
    int tbcol = (tid & 3) * 4;           // K offset

    for (int k0 = 0; k0 < K; k0 += BK) {
        float4 a0 = *(const float4*)&A[(bm+arow)*K + k0 + acol];
        float4 a1 = *(const float4*)&A[(bm+arow)*K + k0 + acol + 4];
        As[acol+0][arow]=a0.x; As[acol+1][arow]=a0.y; As[acol+2][arow]=a0.z; As[acol+3][arow]=a0.w;
        As[acol+4][arow]=a1.x; As[acol+5][arow]=a1.y; As[acol+6][arow]=a1.z; As[acol+7][arow]=a1.w;
        if (!TRANSB) {
            float4 b0 = *(const float4*)&B[(k0+brow)*N + bn + bcol];
            *(float4*)&Bs[brow][bcol] = b0;
        } else {
            float4 b0 = *(const float4*)&B[(bn+tbrow)*K + k0 + tbcol];
            Bs[tbcol+0][tbrow]=b0.x; Bs[tbcol+1][tbrow]=b0.y;
            Bs[tbcol+2][tbrow]=b0.z; Bs[tbcol+3][tbrow]=b0.w;
        }
        __syncthreads();
        #pragma unroll
        for (int kk = 0; kk < BK; kk++) {
            float ra[8], rb[4];
            *(float4*)&ra[0] = *(const float4*)&As[kk][ty*8];
            *(float4*)&ra[4] = *(const float4*)&As[kk][ty*8+4];
            *(float4*)&rb[0] = *(const float4*)&Bs[kk][tx*4];
            #pragma unroll
            for (int i = 0; i < 8; i++)
                #pragma unroll
                for (int j = 0; j < 4; j++)
                    acc[i][j] += ra[i]*rb[j];
        }
        __syncthreads();
    }
    #pragma unroll
    for (int i = 0; i < 8; i++)
        #pragma unroll
        for (int j = 0; j < 4; j++)
            C[(bm + ty*8 + i)*N + bn + tx*4 + j] = acc[i][j];
}

// ---------------- qkv scatter (+ q scale) ----------------
__global__ void scatter_qkv_k() {
    int gid = blockIdx.x*256 + threadIdx.x;
    if (gid >= B_*NN*3*C_) return;
    int col = gid % (3*C_);
    int row = gid / (3*C_);
    int b = row / NN, n = row % NN;
    float v = g_qkv[gid];
    int part = col >> 8;
    int c = col & 255;
    int h = c >> 5, d = c & 31;
    int dst = ((b*NHEAD + h)*NN + n)*DH + d;
    if (part == 0)      g_q[dst] = v * QSCALE;
    else if (part == 1) g_k[dst] = v;
    else                g_v[dst] = v;
}

// ---------------- per-(b,h) sums of q,k,v ----------------
__global__ void bh_sums_k() {
    int bh = blockIdx.x;
    int t = threadIdx.x;              // 256
    int d = t & 31, part = t >> 5;    // 8 parts
    float sq = 0, sk = 0, sv = 0;
    for (int n = part; n < NN; n += 8) {
        int idx = (bh*NN + n)*DH + d;
        sq += g_q[idx]; sk += g_k[idx]; sv += g_v[idx];
    }
    __shared__ float sh[3][8][32];
    sh[0][part][d]=sq; sh[1][part][d]=sk; sh[2][part][d]=sv;
    __syncthreads();
    if (t < 96) {
        int which = t >> 5, dd = t & 31;
        float s = 0;
        #pragma unroll
        for (int p = 0; p < 8; p++) s += sh[which][p][dd];
        g_sums[(bh*3 + which)*DH + dd] = s;
    }
}

// ---------------- row/col pruning scores ----------------
__global__ void scores_k() {
    int gid = blockIdx.x*256 + threadIdx.x;    // bh*NN
    int bh = gid / NN;
    __shared__ float qs[DH], ks[DH];
    if (threadIdx.x < DH)        qs[threadIdx.x]     = g_sums[(bh*3+0)*DH + threadIdx.x];
    else if (threadIdx.x < 2*DH) ks[threadIdx.x-DH]  = g_sums[(bh*3+1)*DH + threadIdx.x-DH];
    __syncthreads();
    float r = 0, c = 0;
    const float* qp = &g_q[gid*DH];
    const float* kp = &g_k[gid*DH];
    #pragma unroll
    for (int d = 0; d < DH; d++) { r += qp[d]*ks[d]; c += qs[d]*kp[d]; }
    g_rs[gid] = r; g_cs[gid] = c;
}

// ---------------- exact top-k selection (radix select + stable compaction) ----------------
__device__ __forceinline__ unsigned f2key(float f) {
    unsigned u = __float_as_uint(f);
    return (u & 0x80000000u) ? ~u : (u | 0x80000000u);
}

__global__ void select_k() {
    int blk = blockIdx.x;          // 0..31
    int type = blk >> 4, bh = blk & 15;
    const float* s = (type == 0 ? g_rs : g_cs) + bh*NN;
    int* list = (type == 0 ? g_rowlist : g_collist) + bh*KTOP;
    __shared__ unsigned keys[NN];
    __shared__ int hist[256];
    __shared__ int scan[256];
    __shared__ unsigned sh_T;
    __shared__ int sh_take;
    int t = threadIdx.x;           // 256
    for (int i = t; i < NN; i += 256) keys[i] = f2key(s[i]);
    __syncthreads();

    unsigned prefix = 0, pmask = 0;
    int kneed = KTOP;
    for (int pass = 0; pass < 4; pass++) {
        int shift = 24 - 8*pass;
        hist[t] = 0;
        __syncthreads();
        for (int i = t; i < NN; i += 256) {
            unsigned u = keys[i];
            if ((u & pmask) == prefix) atomicAdd(&hist[(u >> shift) & 255], 1);
        }
        __syncthreads();
        if (t == 0) {
            int run = 0, b = 255;
            for (; b >= 0; b--) {
                int h = hist[b];
                if (run + h >= kneed) break;
                run += h;
            }
            sh_T = prefix | ((unsigned)b << shift);
            sh_take = kneed - run;
        }
        __syncthreads();
        prefix = sh_T;
        kneed = sh_take;
        pmask |= (0xffu << shift);
        __syncthreads();
    }
    unsigned T = prefix;
    int take = kneed;

    // stable compaction: thread t owns indices [t*9, t*9+9)
    unsigned myk[9];
    int eqc = 0;
    #pragma unroll
    for (int j = 0; j < 9; j++) {
        myk[j] = keys[t*9 + j];
        eqc += (myk[j] == T);
    }
    // exclusive scan of eq counts (Hillis-Steele)
    scan[t] = eqc; __syncthreads();
    for (int st = 1; st < 256; st <<= 1) {
        int tmp = (t >= st) ? scan[t-st] : 0;
        __syncthreads();
        scan[t] += tmp;
        __syncthreads();
    }
    int eqbase = scan[t] - eqc;
    __syncthreads();

    bool kept[9];
    int keptc = 0, eqseen = 0;
    #pragma unroll
    for (int j = 0; j < 9; j++) {
        unsigned u = myk[j];
        bool gt = (u > T), eq = (u == T);
        bool kp = gt || (eq && (eqbase + eqseen) < take);
        if (eq) eqseen++;
        kept[j] = kp; keptc += kp;
    }
    scan[t] = keptc; __syncthreads();
    for (int st = 1; st < 256; st <<= 1) {
        int tmp = (t >= st) ? scan[t-st] : 0;
        __syncthreads();
        scan[t] += tmp;
        __syncthreads();
    }
    int wbase = scan[t] - keptc;
    #pragma unroll
    for (int j = 0; j < 9; j++)
        if (kept[j]) list[wbase++] = t*9 + j;
}

// ---------------- v_unkept = vsum - sum over kept cols ----------------
__global__ void vunkept_k() {
    int bh = blockIdx.x;
    int t = threadIdx.x;
    int d = t & 31, part = t >> 5;
    float sv = 0;
    for (int jj = part; jj < KTOP; jj += 8) {
        int j = g_collist[bh*KTOP + jj];
        sv += g_v[(bh*NN + j)*DH + d];
    }
    __shared__ float sh[8][32];
    sh[part][d] = sv;
    __syncthreads();
    if (t < 32) {
        float s = 0;
        #pragma unroll
        for (int p = 0; p < 8; p++) s += sh[p][t];
        g_vunk[bh*DH + t] = g_sums[(bh*3+2)*DH + t] - s;
    }
}

// ---------------- pruned rows: uniform softmax -> mean(v) ----------------
__global__ void fill_o_k() {
    int gid = blockIdx.x*256 + threadIdx.x;
    if (gid >= BHN*NN*DH) return;
    int bh = gid / (NN*DH);
    int r = gid % (NN*DH);
    int n = r / DH, d = r & 31;
    int b = bh >> 3, h = bh & 7;
    g_o[(b*NN + n)*C_ + h*DH + d] = g_sums[(bh*3+2)*DH + d] * (1.0f/NN);
}

// ---------------- kept-row attention with zero-column correction ----------------
__global__ __launch_bounds__(64) void attn_k() {
    int bh = blockIdx.x;
    int t = threadIdx.x;                      // 64
    int slot = blockIdx.y*64 + t;             // 0..575
    int i = g_rowlist[bh*KTOP + slot];

    float qr[DH];
    const float4* qp = (const float4*)&g_q[(bh*NN + i)*DH];
    #pragma unroll
    for (int w = 0; w < 8; w++) {
        float4 f = qp[w];
        qr[4*w]=f.x; qr[4*w+1]=f.y; qr[4*w+2]=f.z; qr[4*w+3]=f.w;
    }

    float m = 0.f, Z = 0.f;                   // m starts at 0: the 1728 implicit zeros
    float acc[DH];
    #pragma unroll
    for (int d = 0; d < DH; d++) acc[d] = 0.f;

    __shared__ int cj[96];
    __shared__ float Kc[96][DH];
    __shared__ float Vc[96][DH];

    for (int c0 = 0; c0 < KTOP; c0 += 96) {
        __syncthreads();
        for (int jj = t; jj < 96; jj += 64) cj[jj] = g_collist[bh*KTOP + c0 + jj];
        __syncthreads();
        for (int idx = t; idx < 96*DH; idx += 64) {
            int jj = idx >> 5, d = idx & 31;
            int base = (bh*NN + cj[jj])*DH + d;
            Kc[jj][d] = g_k[base];
            Vc[jj][d] = g_v[base];
        }
        __syncthreads();
        #pragma unroll 2
        for (int jj = 0; jj < 96; jj++) {
            float s0=0,s1=0,s2=0,s3=0;
            #pragma unroll
            for (int d = 0; d < DH; d += 4) {
                s0 += qr[d+0]*Kc[jj][d+0];
                s1 += qr[d+1]*Kc[jj][d+1];
                s2 += qr[d+2]*Kc[jj][d+2];
                s3 += qr[d+3]*Kc[jj][d+3];
            }
            float s = (s0+s1) + (s2+s3);
            if (s > m) {
                float cf = __expf(m - s);
                Z = Z*cf + 1.f;
                #pragma unroll
                for (int d = 0; d < DH; d++) acc[d] = acc[d]*cf + Vc[jj][d];
                m = s;
            } else {
                float e = __expf(s - m);
                Z += e;
                #pragma unroll
                for (int d = 0; d < DH; d++) acc[d] += e*Vc[jj][d];
            }
        }
    }
    float einv = __expf(-m);
    Z += (float)(NN - KTOP) * einv;
    float invZ = 1.f / Z;
    int b = bh >> 3, h = bh & 7;
    float* op = &g_o[(b*NN + i)*C_ + h*DH];
    #pragma unroll
    for (int d = 0; d < DH; d++)
        op[d] = (acc[d] + einv*g_vunk[bh*DH + d]) * invZ;
}

// ---------------- depthwise 3x3 conv (writes [B,N,C]) ----------------
__global__ void dw_k(const float* __restrict__ x,
                     const float* __restrict__ w,
                     const float* __restrict__ bias) {
    int gid = blockIdx.x*256 + threadIdx.x;
    if (gid >= B_*C_*NN) return;
    int n = gid % NN;
    int bc = gid / NN;
    int c = bc % C_, b = bc / C_;
    int y = n / WW, x0 = n % WW;
    float acc = bias[c];
    const float* xp = &x[(b*C_ + c)*NN];
    const float* wp = &w[c*9];
    #pragma unroll
    for (int dy = 0; dy < 3; dy++) {
        int yy = y + dy - 1;
        if (yy < 0 || yy >= HH) continue;
        #pragma unroll
        for (int dx = 0; dx < 3; dx++) {
            int xx = x0 + dx - 1;
            if (xx < 0 || xx >= WW) continue;
            acc += xp[yy*WW + xx] * wp[dy*3 + dx];
        }
    }
    g_xdw[(b*NN + n)*C_ + c] = acc;
}

// ---------------- xs = attn_branch + conv_branch + pw bias ----------------
__global__ void xs_k(const float* __restrict__ pw_b) {
    int gid = blockIdx.x*256 + threadIdx.x;
    if (gid >= B_*NN*C_) return;
    int c = gid & 255;
    g_xs[gid] = g_xattn[gid] + g_xc[gid] + pw_b[c];
}

// ---------------- spatial gate stage 1: 1x1 conv C->32 + silu ----------------
__global__ void sg1_k(const float* __restrict__ w, const float* __restrict__ bias) {
    int bn = blockIdx.x;              // b*NN+n
    int go = threadIdx.x;             // 32
    __shared__ float row[C_];
    for (int i = go; i < C_; i += 32) row[i] = g_xs[bn*C_ + i];
    __syncthreads();
    float acc = bias[go];
    const float* wp = &w[go*C_];
    #pragma unroll 4
    for (int ci = 0; ci < C_; ci++) acc += row[ci]*wp[ci];
    g_t1[bn*GG + go] = acc / (1.f + expf(-acc));
}

// ---------------- spatial gate stage 2: 7x7 conv 32->1 + sigmoid ----------------
__global__ void sg2_k(const float* __restrict__ w, const float* __restrict__ bias) {
    int gid = blockIdx.x*256 + threadIdx.x;
    if (gid >= B_*NN) return;
    int b = gid / NN, n = gid % NN;
    int y = n / WW, x0 = n % WW;
    float acc = bias[0];
    for (int ky = 0; ky < 7; ky++) {
        int yy = y + ky - 3;
        if (yy < 0 || yy >= HH) continue;
        for (int kx = 0; kx < 7; kx++) {
            int xx = x0 + kx - 3;
            if (xx < 0 || xx >= WW) continue;
            const float* tp = &g_t1[(b*NN + yy*WW + xx)*GG];
            int widx = ky*7 + kx;
            float a0=0,a1=0;
            #pragma unroll
            for (int gi = 0; gi < GG; gi += 2) {
                a0 += tp[gi]   * w[gi*49 + widx];
                a1 += tp[gi+1] * w[(gi+1)*49 + widx];
            }
            acc += a0 + a1;
        }
    }
    g_sg[gid] = 1.f / (1.f + expf(-acc));
}

// ---------------- channel gate: pool partials ----------------
__global__ void cgpool_k() {
    int blk = blockIdx.x;            // b*16 + part
    int b = blk / 16, part = blk % 16;
    int c = threadIdx.x;             // 256
    float s = 0;
    int n0 = part*144;
    for (int n = n0; n < n0 + 144; n++) s += g_xs[(b*NN + n)*C_ + c];
    g_cgpart[blk*C_ + c] = s;
}

// ---------------- channel gate: combine + silu + sigmoid ----------------
__global__ void cggate_k(const float* __restrict__ w1, const float* __restrict__ b1,
                         const float* __restrict__ w2, const float* __restrict__ b2) {
    int b = blockIdx.x;
    int c = threadIdx.x;
    __shared__ float cgm[C_];
    __shared__ float t2[GG];
    float s = 0;
    for (int p = 0; p < 16; p++) s += g_cgpart[(b*16 + p)*C_ + c];
    cgm[c] = s * (1.0f/NN);
    __syncthreads();
    if (c < GG) {
        float a = b1[c];
        const float* wp = &w1[c*C_];
        for (int ci = 0; ci < C_; ci++) a += cgm[ci]*wp[ci];
        t2[c] = a / (1.f + expf(-a));
    }
    __syncthreads();
    float a2 = b2[c];
    const float* wp2 = &w2[c*GG];
    #pragma unroll
    for (int g = 0; g < GG; g++) a2 += t2[g]*wp2[g];
    g_cg[b*C_ + c] = 1.f / (1.f + expf(-a2));
}

// ---------------- x2 = x + gamma1 * xs*sg*cg ----------------
__global__ void x2_k(const float* __restrict__ x, const float* __restrict__ gamma1) {
    int gid = blockIdx.x*256 + threadIdx.x;
    if (gid >= B_*NN*C_) return;
    int c = gid & 255;
    int row = gid >> 8;              // b*NN+n
    int b = row / NN, n = row % NN;
    float xv = x[(b*C_ + c)*NN + n];
    g_x2[gid] = xv + gamma1[0] * g_xs[gid] * g_sg[row] * g_cg[b*C_ + c];
}

// ---------------- ffn1 epilogue: bias + exact gelu ----------------
__global__ void ff1_epi_k(const float* __restrict__ bias) {
    int gid = blockIdx.x*256 + threadIdx.x;
    if (gid >= B_*NN*HID) return;
    float v = g_h[gid] + bias[gid % HID];
    g_h[gid] = 0.5f*v*(1.0f + erff(v*0.70710678118654752f));
}

// ---------------- final: out = x2 + gamma2*(ff + b2), write NCHW ----------------
__global__ void out_k(const float* __restrict__ gamma2,
                      const float* __restrict__ b2,
                      float* __restrict__ out) {
    int gid = blockIdx.x*256 + threadIdx.x;
    if (gid >= B_*NN*C_) return;
    int c = gid & 255;
    int row = gid >> 8;
    int b = row / NN, n = row % NN;
    float v = g_x2[gid] + gamma2[0]*(g_ff[gid] + b2[c]);
    out[(b*C_ + c)*NN + n] = v;
}

// ---------------- host ----------------
#define GETSYM(p, s) do { void* _t; cudaGetSymbolAddress(&_t, s); p = (float*)_t; } while (0)

extern "C" void kernel_launch(void* const* d_in, const int* in_sizes, int n_in,
                              void* d_out, int out_size) {
    const float* x     = (const float*)d_in[0];
    const float* qkv_w = (const float*)d_in[1];
    const float* out_w = (const float*)d_in[2];
    const float* ln1_g = (const float*)d_in[3];
    const float* ln1_b = (const float*)d_in[4];
    const float* ln2_g = (const float*)d_in[5];
    const float* ln2_b = (const float*)d_in[6];
    const float* dw_w  = (const float*)d_in[7];
    const float* dw_b  = (const float*)d_in[8];
    const float* pw_w  = (const float*)d_in[9];
    const float* pw_b  = (const float*)d_in[10];
    const float* sg1_w = (const float*)d_in[11];
    const float* sg1_b = (const float*)d_in[12];
    const float* sg2_w = (const float*)d_in[13];
    const float* sg2_b = (const float*)d_in[14];
    const float* cg1_w = (const float*)d_in[15];
    const float* cg1_b = (const float*)d_in[16];
    const float* cg2_w = (const float*)d_in[17];
    const float* cg2_b = (const float*)d_in[18];
    const float* ff_w1 = (const float*)d_in[19];
    const float* ff_b1 = (const float*)d_in[20];
    const float* ff_w2 = (const float*)d_in[21];
    const float* ff_b2 = (const float*)d_in[22];
    const float* gamma1= (const float*)d_in[23];
    const float* gamma2= (const float*)d_in[24];
    float* out = (float*)d_out;
    (void)in_sizes; (void)n_in; (void)out_size;

    float *p_xa, *p_qkv, *p_o, *p_xattn, *p_xdw, *p_xc, *p_ln2, *p_h, *p_ff;
    GETSYM(p_xa, g_xa); GETSYM(p_qkv, g_qkv); GETSYM(p_o, g_o);
    GETSYM(p_xattn, g_xattn); GETSYM(p_xdw, g_xdw); GETSYM(p_xc, g_xc);
    GETSYM(p_ln2, g_ln2); GETSYM(p_h, g_h); GETSYM(p_ff, g_ff);

    const int M = B_*NN;   // 4608

    // attention branch
    ln_from_nchw_k<<<M, 256>>>(x, ln1_g, ln1_b);
    gemm_k<false><<<dim3(3*C_/64, M/128), 256>>>(p_xa, qkv_w, p_qkv, M, 3*C_, C_);
    scatter_qkv_k<<<(B_*NN*3*C_)/256, 256>>>();
    bh_sums_k<<<BHN, 256>>>();
    scores_k<<<(BHN*NN)/256, 256>>>();
    select_k<<<32, 256>>>();
    vunkept_k<<<BHN, 256>>>();
    fill_o_k<<<(BHN*NN*DH)/256, 256>>>();
    attn_k<<<dim3(BHN, 9), 64>>>();
    gemm_k<false><<<dim3(C_/64, M/128), 256>>>(p_o, out_w, p_xattn, M, C_, C_);

    // conv branch
    dw_k<<<(B_*C_*NN)/256, 256>>>(x, dw_w, dw_b);
    gemm_k<true><<<dim3(C_/64, M/128), 256>>>(p_xdw, pw_w, p_xc, M, C_, C_);
    xs_k<<<(B_*NN*C_)/256, 256>>>(pw_b);

    // gates
    sg1_k<<<B_*NN, 32>>>(sg1_w, sg1_b);
    sg2_k<<<(B_*NN + 255)/256, 256>>>(sg2_w, sg2_b);
    cgpool_k<<<B_*16, 256>>>();
    cggate_k<<<B_, 256>>>(cg1_w, cg1_b, cg2_w, cg2_b);
    x2_k<<<(B_*NN*C_)/256, 256>>>(x, gamma1);

    // FFN
    ln_from_bnc_k<<<M, 256>>>(ln2_g, ln2_b);
    gemm_k<false><<<dim3(HID/64, M/128), 256>>>(p_ln2, ff_w1, p_h, M, HID, C_);
    ff1_epi_k<<<(B_*NN*HID)/256, 256>>>(ff_b1);
    gemm_k<false><<<dim3(C_/64, M/128), 256>>>(p_h, ff_w2, p_ff, M, C_, HID);
    out_k<<<(B_*NN*C_)/256, 256>>>(gamma2, ff_b2, out);
}

// round 3
// speedup vs baseline: 1.3338x; 1.3338x over previous
#include <cuda_runtime.h>
#include <math.h>

#define B_ 2
#define C_ 256
#define HH 48
#define WW 48
#define NN 2304          // 48*48
#define NHEAD 8
#define DH 32
#define BHN 16           // B_*NHEAD
#define KTOP 576
#define HID 1024
#define GG 32            // C/8 gate channels
#define QSCALE 0.17677669529663687f   // 1/sqrt(32)
#define NSPLIT 3         // attention column-split
#define CHUNK 192        // KTOP / NSPLIT

// ---------------- scratch (static device arrays; no allocation) ----------------
__device__ float g_xa  [B_*NN*C_];
__device__ float g_qkv [B_*NN*3*C_];
__device__ float g_q   [BHN*NN*DH];
__device__ float g_k   [BHN*NN*DH];
__device__ float g_v   [BHN*NN*DH];
__device__ float g_spart[BHN*12*3*DH];
__device__ float g_sums[BHN*3*DH];        // [bh][qsum,ksum,vsum][d]
__device__ float g_rs  [BHN*NN];
__device__ float g_cs  [BHN*NN];
__device__ int   g_rowlist[BHN*KTOP];
__device__ int   g_collist[BHN*KTOP];
__device__ float g_vunk[BHN*DH];
__device__ float g_pm  [BHN*KTOP*NSPLIT];
__device__ float g_pz  [BHN*KTOP*NSPLIT];
__device__ float g_pacc[BHN*KTOP*NSPLIT*DH];
__device__ float g_o   [B_*NN*C_];
__device__ float g_xattn[B_*NN*C_];
__device__ float g_xdw [C_*B_*NN];        // [c][b*NN+n]  (K-major for TRANSA gemm)
__device__ float g_xc  [B_*NN*C_];
__device__ float g_xs  [B_*NN*C_];
__device__ float g_t1  [B_*NN*GG];
__device__ float g_sg  [B_*NN];
__device__ float g_cgpart[B_*16*C_];
__device__ float g_cg  [B_*C_];
__device__ float g_x2  [B_*NN*C_];
__device__ float g_ln2 [B_*NN*C_];
__device__ float g_h   [B_*NN*HID];
__device__ float g_ff  [B_*NN*C_];

// ---------------- LayerNorm ----------------
__global__ void ln_from_nchw_k(const float* __restrict__ x,
                               const float* __restrict__ g,
                               const float* __restrict__ b) {
    int row = blockIdx.x;            // b*NN + n
    int bb = row / NN, n = row % NN;
    int c = threadIdx.x;             // 256
    float v = x[(bb*C_ + c)*NN + n];
    __shared__ float s1[256], s2[256];
    s1[c] = v; s2[c] = v*v;
    __syncthreads();
    for (int st = 128; st > 0; st >>= 1) {
        if (c < st) { s1[c] += s1[c+st]; s2[c] += s2[c+st]; }
        __syncthreads();
    }
    float mu = s1[0] * (1.0f/C_);
    float var = s2[0] * (1.0f/C_) - mu*mu;
    float r = rsqrtf(var + 1e-6f);
    g_xa[row*C_ + c] = (v - mu)*r*g[c] + b[c];
}

__global__ void ln_from_bnc_k(const float* __restrict__ g,
                              const float* __restrict__ b) {
    int row = blockIdx.x;
    int c = threadIdx.x;
    float v = g_x2[row*C_ + c];
    __shared__ float s1[256], s2[256];
    s1[c] = v; s2[c] = v*v;
    __syncthreads();
    for (int st = 128; st > 0; st >>= 1) {
        if (c < st) { s1[c] += s1[c+st]; s2[c] += s2[c+st]; }
        __syncthreads();
    }
    float mu = s1[0] * (1.0f/C_);
    float var = s2[0] * (1.0f/C_) - mu*mu;
    float r = rsqrtf(var + 1e-6f);
    g_ln2[row*C_ + c] = (v - mu)*r*g[c] + b[c];
}

// ---------------- tf32 tensor-core GEMM ----------------
// C[M,N] = A @ B (+optional bias, gelu).
// TRANSA=false: A is [M,K] row-major.  TRANSA=true: A is [K,M] row-major.
// TRANSB=false: B is [K,N] row-major.  TRANSB=true: B is [N,K] row-major.
// M%128==0, N%64==0, K%16==0.
__device__ __forceinline__ unsigned f2tf32(float f) {
    unsigned r; asm("cvt.rna.tf32.f32 %0, %1;" : "=r"(r) : "f"(f)); return r;
}
__device__ __forceinline__ void mma_tf32(float* d, const unsigned* a,
                                         const unsigned* b, const float* c) {
    asm volatile("mma.sync.aligned.m16n8k8.row.col.f32.tf32.tf32.f32 "
        "{%0,%1,%2,%3}, {%4,%5,%6,%7}, {%8,%9}, {%10,%11,%12,%13};"
        : "=f"(d[0]),"=f"(d[1]),"=f"(d[2]),"=f"(d[3])
        : "r"(a[0]),"r"(a[1]),"r"(a[2]),"r"(a[3]),
          "r"(b[0]),"r"(b[1]),
          "f"(c[0]),"f"(c[1]),"f"(c[2]),"f"(c[3]));
}

template<bool TRANSA, bool TRANSB, bool GELU_BIAS>
__global__ __launch_bounds__(256) void gemm_tc(const float* __restrict__ A,
                                               const float* __restrict__ B,
                                               float* __restrict__ C,
                                               const float* __restrict__ bias,
                                               int M, int N, int K) {
    const int BM = 128, BN = 64, BK = 16;
    __shared__ unsigned As[BK][136];   // [k][m], 136%32==8 -> conflict-free frags
    __shared__ unsigned Bs[BK][72];    // [k][n], 72%32==8
    int bm = blockIdx.y*BM, bn = blockIdx.x*BN;
    int tid = threadIdx.x;
    int lane = tid & 31, wid = tid >> 5;
    int wm = wid >> 1, wn = wid & 1;          // 4x2 warp grid -> warp tile 32x32
    int g = lane >> 2, tig = lane & 3;
    float acc[2][4][4];
    #pragma unroll
    for (int i = 0; i < 2; i++)
        #pragma unroll
        for (int j = 0; j < 4; j++)
            #pragma unroll
            for (int l = 0; l < 4; l++) acc[i][j][l] = 0.f;

    for (int k0 = 0; k0 < K; k0 += BK) {
        if (!TRANSA) {
            int arow = tid >> 1, acol = (tid & 1)*8;
            float4 a0 = *(const float4*)&A[(bm+arow)*K + k0 + acol];
            float4 a1 = *(const float4*)&A[(bm+arow)*K + k0 + acol + 4];
            As[acol+0][arow]=f2tf32(a0.x); As[acol+1][arow]=f2tf32(a0.y);
            As[acol+2][arow]=f2tf32(a0.z); As[acol+3][arow]=f2tf32(a0.w);
            As[acol+4][arow]=f2tf32(a1.x); As[acol+5][arow]=f2tf32(a1.y);
            As[acol+6][arow]=f2tf32(a1.z); As[acol+7][arow]=f2tf32(a1.w);
        } else {
            int krow = tid >> 4, mcol = (tid & 15)*8;
            float4 a0 = *(const float4*)&A[(k0+krow)*M + bm + mcol];
            float4 a1 = *(const float4*)&A[(k0+krow)*M + bm + mcol + 4];
            As[krow][mcol+0]=f2tf32(a0.x); As[krow][mcol+1]=f2tf32(a0.y);
            As[krow][mcol+2]=f2tf32(a0.z); As[krow][mcol+3]=f2tf32(a0.w);
            As[krow][mcol+4]=f2tf32(a1.x); As[krow][mcol+5]=f2tf32(a1.y);
            As[krow][mcol+6]=f2tf32(a1.z); As[krow][mcol+7]=f2tf32(a1.w);
        }
        if (!TRANSB) {
            int brow = tid >> 4, bcol = (tid & 15)*4;
            float4 b0 = *(const float4*)&B[(k0+brow)*N + bn + bcol];
            Bs[brow][bcol+0]=f2tf32(b0.x); Bs[brow][bcol+1]=f2tf32(b0.y);
            Bs[brow][bcol+2]=f2tf32(b0.z); Bs[brow][bcol+3]=f2tf32(b0.w);
        } else {
            int tbn = tid >> 2, tbk = (tid & 3)*4;
            float4 b0 = *(const float4*)&B[(bn+tbn)*K + k0 + tbk];
            Bs[tbk+0][tbn]=f2tf32(b0.x); Bs[tbk+1][tbn]=f2tf32(b0.y);
            Bs[tbk+2][tbn]=f2tf32(b0.z); Bs[tbk+3][tbn]=f2tf32(b0.w);
        }
        __syncthreads();
        #pragma unroll
        for (int ks = 0; ks < BK; ks += 8) {
            unsigned afr[2][4];
            #pragma unroll
            for (int mt = 0; mt < 2; mt++) {
                int r0 = wm*32 + mt*16 + g;
                afr[mt][0] = As[ks+tig][r0];
                afr[mt][1] = As[ks+tig][r0+8];
                afr[mt][2] = As[ks+tig+4][r0];
                afr[mt][3] = As[ks+tig+4][r0+8];
            }
            unsigned bfr[4][2];
            #pragma unroll
            for (int nt = 0; nt < 4; nt++) {
                int c0 = wn*32 + nt*8 + g;
                bfr[nt][0] = Bs[ks+tig][c0];
                bfr[nt][1] = Bs[ks+tig+4][c0];
            }
            #pragma unroll
            for (int mt = 0; mt < 2; mt++)
                #pragma unroll
                for (int nt = 0; nt < 4; nt++)
                    mma_tf32(acc[mt][nt], afr[mt], bfr[nt], acc[mt][nt]);
        }
        __syncthreads();
    }
    #pragma unroll
    for (int mt = 0; mt < 2; mt++) {
        int row = bm + wm*32 + mt*16 + g;
        #pragma unroll
        for (int nt = 0; nt < 4; nt++) {
            int col = bn + wn*32 + nt*8 + tig*2;
            float v0 = acc[mt][nt][0], v1 = acc[mt][nt][1];
            float v2 = acc[mt][nt][2], v3 = acc[mt][nt][3];
            if (GELU_BIAS) {
                float bb0 = bias[col], bb1 = bias[col+1];
                v0 += bb0; v1 += bb1; v2 += bb0; v3 += bb1;
                v0 = 0.5f*v0*(1.0f + erff(v0*0.70710678118654752f));
                v1 = 0.5f*v1*(1.0f + erff(v1*0.70710678118654752f));
                v2 = 0.5f*v2*(1.0f + erff(v2*0.70710678118654752f));
                v3 = 0.5f*v3*(1.0f + erff(v3*0.70710678118654752f));
            }
            *(float2*)&C[row*N + col] = make_float2(v0, v1);
            *(float2*)&C[(row+8)*N + col] = make_float2(v2, v3);
        }
    }
}

// ---------------- qkv scatter (+ q scale) ----------------
__global__ void scatter_qkv_k() {
    int gid = blockIdx.x*256 + threadIdx.x;
    if (gid >= B_*NN*3*C_) return;
    int col = gid % (3*C_);
    int row = gid / (3*C_);
    int b = row / NN, n = row % NN;
    float v = g_qkv[gid];
    int part = col >> 8;
    int c = col & 255;
    int h = c >> 5, d = c & 31;
    int dst = ((b*NHEAD + h)*NN + n)*DH + d;
    if (part == 0)      g_q[dst] = v * QSCALE;
    else if (part == 1) g_k[dst] = v;
    else                g_v[dst] = v;
}

// ---------------- per-(b,h) sums of q,k,v (two-stage) ----------------
__global__ void bh_sums1_k() {
    int bh = blockIdx.x, yy = blockIdx.y;     // 16 x 12
    int t = threadIdx.x;                      // 256
    int d = t & 31, part = t >> 5;            // 8 parts x 24 rows
    float sq = 0, sk = 0, sv = 0;
    int n0 = yy*192 + part*24;
    for (int j = 0; j < 24; j++) {
        int idx = (bh*NN + n0 + j)*DH + d;
        sq += g_q[idx]; sk += g_k[idx]; sv += g_v[idx];
    }
    __shared__ float sh[3][8][32];
    sh[0][part][d]=sq; sh[1][part][d]=sk; sh[2][part][d]=sv;
    __syncthreads();
    if (t < 96) {
        int which = t >> 5, dd = t & 31;
        float s = 0;
        #pragma unroll
        for (int p = 0; p < 8; p++) s += sh[which][p][dd];
        g_spart[((bh*12 + yy)*3 + which)*DH + dd] = s;
    }
}

__global__ void bh_sums2_k() {
    int bh = blockIdx.x;
    int t = threadIdx.x;            // 96
    int which = t >> 5, d = t & 31;
    float s = 0;
    #pragma unroll
    for (int y = 0; y < 12; y++) s += g_spart[((bh*12 + y)*3 + which)*DH + d];
    g_sums[(bh*3 + which)*DH + d] = s;
}

// ---------------- row/col pruning scores ----------------
__global__ void scores_k() {
    int gid = blockIdx.x*256 + threadIdx.x;    // bh*NN
    int bh = gid / NN;
    __shared__ float qs[DH], ks[DH];
    if (threadIdx.x < DH)        qs[threadIdx.x]     = g_sums[(bh*3+0)*DH + threadIdx.x];
    else if (threadIdx.x < 2*DH) ks[threadIdx.x-DH]  = g_sums[(bh*3+1)*DH + threadIdx.x-DH];
    __syncthreads();
    float r = 0, c = 0;
    const float* qp = &g_q[gid*DH];
    const float* kp = &g_k[gid*DH];
    #pragma unroll
    for (int d = 0; d < DH; d++) { r += qp[d]*ks[d]; c += qs[d]*kp[d]; }
    g_rs[gid] = r; g_cs[gid] = c;
}

// ---------------- exact top-k selection (radix select + stable compaction) ----------------
__device__ __forceinline__ unsigned f2key(float f) {
    unsigned u = __float_as_uint(f);
    return (u & 0x80000000u) ? ~u : (u | 0x80000000u);
}

__global__ void select_k() {
    int blk = blockIdx.x;          // 0..31
    int type = blk >> 4, bh = blk & 15;
    const float* s = (type == 0 ? g_rs : g_cs) + bh*NN;
    int* list = (type == 0 ? g_rowlist : g_collist) + bh*KTOP;
    __shared__ unsigned keys[NN];
    __shared__ int hist[256];
    __shared__ int scan[256];
    __shared__ unsigned sh_T;
    __shared__ int sh_take;
    int t = threadIdx.x;           // 256
    for (int i = t; i < NN; i += 256) keys[i] = f2key(s[i]);
    __syncthreads();

    unsigned prefix = 0, pmask = 0;
    int kneed = KTOP;
    for (int pass = 0; pass < 4; pass++) {
        int shift = 24 - 8*pass;
        hist[t] = 0;
        __syncthreads();
        for (int i = t; i < NN; i += 256) {
            unsigned u = keys[i];
            if ((u & pmask) == prefix) atomicAdd(&hist[(u >> shift) & 255], 1);
        }
        __syncthreads();
        if (t == 0) {
            int run = 0, b = 255;
            for (; b >= 0; b--) {
                int h = hist[b];
                if (run + h >= kneed) break;
                run += h;
            }
            sh_T = prefix | ((unsigned)b << shift);
            sh_take = kneed - run;
        }
        __syncthreads();
        prefix = sh_T;
        kneed = sh_take;
        pmask |= (0xffu << shift);
        __syncthreads();
    }
    unsigned T = prefix;
    int take = kneed;

    unsigned myk[9];
    int eqc = 0;
    #pragma unroll
    for (int j = 0; j < 9; j++) {
        myk[j] = keys[t*9 + j];
        eqc += (myk[j] == T);
    }
    scan[t] = eqc; __syncthreads();
    for (int st = 1; st < 256; st <<= 1) {
        int tmp = (t >= st) ? scan[t-st] : 0;
        __syncthreads();
        scan[t] += tmp;
        __syncthreads();
    }
    int eqbase = scan[t] - eqc;
    __syncthreads();

    bool kept[9];
    int keptc = 0, eqseen = 0;
    #pragma unroll
    for (int j = 0; j < 9; j++) {
        unsigned u = myk[j];
        bool gt = (u > T), eq = (u == T);
        bool kp = gt || (eq && (eqbase + eqseen) < take);
        if (eq) eqseen++;
        kept[j] = kp; keptc += kp;
    }
    scan[t] = keptc; __syncthreads();
    for (int st = 1; st < 256; st <<= 1) {
        int tmp = (t >= st) ? scan[t-st] : 0;
        __syncthreads();
        scan[t] += tmp;
        __syncthreads();
    }
    int wbase = scan[t] - keptc;
    #pragma unroll
    for (int j = 0; j < 9; j++)
        if (kept[j]) list[wbase++] = t*9 + j;
}

// ---------------- v_unkept = vsum - sum over kept cols ----------------
__global__ void vunkept_k() {
    int bh = blockIdx.x;
    int t = threadIdx.x;
    int d = t & 31, part = t >> 5;
    float sv = 0;
    for (int jj = part; jj < KTOP; jj += 8) {
        int j = g_collist[bh*KTOP + jj];
        sv += g_v[(bh*NN + j)*DH + d];
    }
    __shared__ float sh[8][32];
    sh[part][d] = sv;
    __syncthreads();
    if (t < 32) {
        float s = 0;
        #pragma unroll
        for (int p = 0; p < 8; p++) s += sh[p][t];
        g_vunk[bh*DH + t] = g_sums[(bh*3+2)*DH + t] - s;
    }
}

// ---------------- pruned rows: uniform softmax -> mean(v) ----------------
__global__ void fill_o_k() {
    int gid = blockIdx.x*256 + threadIdx.x;
    if (gid >= BHN*NN*DH) return;
    int bh = gid / (NN*DH);
    int r = gid % (NN*DH);
    int n = r / DH, d = r & 31;
    int b = bh >> 3, h = bh & 7;
    g_o[(b*NN + n)*C_ + h*DH + d] = g_sums[(bh*3+2)*DH + d] * (1.0f/NN);
}

// ---------------- kept-row attention partials over a column chunk ----------------
__global__ __launch_bounds__(64) void attn_part_k() {
    int bh = blockIdx.x;
    int t = threadIdx.x;                      // 64
    int slot = blockIdx.y*64 + t;             // 0..575
    int chunk = blockIdx.z;                   // 0..2
    int i = g_rowlist[bh*KTOP + slot];

    float qr[DH];
    const float4* qp = (const float4*)&g_q[(bh*NN + i)*DH];
    #pragma unroll
    for (int w = 0; w < 8; w++) {
        float4 f = qp[w];
        qr[4*w]=f.x; qr[4*w+1]=f.y; qr[4*w+2]=f.z; qr[4*w+3]=f.w;
    }

    float m = -3.0e38f, Z = 0.f;
    float acc[DH];
    #pragma unroll
    for (int d = 0; d < DH; d++) acc[d] = 0.f;

    __shared__ int cj[96];
    __shared__ float Kc[96][DH];
    __shared__ float Vc[96][DH];

    for (int c0 = chunk*CHUNK; c0 < chunk*CHUNK + CHUNK; c0 += 96) {
        __syncthreads();
        for (int jj = t; jj < 96; jj += 64) cj[jj] = g_collist[bh*KTOP + c0 + jj];
        __syncthreads();
        for (int idx = t; idx < 96*DH; idx += 64) {
            int jj = idx >> 5, d = idx & 31;
            int base = (bh*NN + cj[jj])*DH + d;
            Kc[jj][d] = g_k[base];
            Vc[jj][d] = g_v[base];
        }
        __syncthreads();
        #pragma unroll 2
        for (int jj = 0; jj < 96; jj++) {
            float s0=0,s1=0,s2=0,s3=0;
            #pragma unroll
            for (int d = 0; d < DH; d += 4) {
                s0 += qr[d+0]*Kc[jj][d+0];
                s1 += qr[d+1]*Kc[jj][d+1];
                s2 += qr[d+2]*Kc[jj][d+2];
                s3 += qr[d+3]*Kc[jj][d+3];
            }
            float s = (s0+s1) + (s2+s3);
            if (s > m) {
                float cf = __expf(m - s);
                Z = Z*cf + 1.f;
                #pragma unroll
                for (int d = 0; d < DH; d++) acc[d] = acc[d]*cf + Vc[jj][d];
                m = s;
            } else {
                float e = __expf(s - m);
                Z += e;
                #pragma unroll
                for (int d = 0; d < DH; d++) acc[d] += e*Vc[jj][d];
            }
        }
    }
    int pidx = (bh*KTOP + slot)*NSPLIT + chunk;
    g_pm[pidx] = m;
    g_pz[pidx] = Z;
    float* pa = &g_pacc[pidx*DH];
    #pragma unroll
    for (int d = 0; d < DH; d++) pa[d] = acc[d];
}

// ---------------- combine partials + zero-column correction ----------------
__global__ void attn_comb_k() {
    int gid = blockIdx.x*128 + threadIdx.x;
    if (gid >= BHN*KTOP) return;
    int bh = gid / KTOP, slot = gid % KTOP;
    int i = g_rowlist[bh*KTOP + slot];
    int p0 = gid*NSPLIT;
    float m0 = g_pm[p0], m1 = g_pm[p0+1], m2 = g_pm[p0+2];
    float mstar = fmaxf(0.f, fmaxf(m0, fmaxf(m1, m2)));
    float e0 = __expf(m0 - mstar), e1 = __expf(m1 - mstar), e2 = __expf(m2 - mstar);
    float ez = __expf(-mstar);
    float Z = g_pz[p0]*e0 + g_pz[p0+1]*e1 + g_pz[p0+2]*e2 + (float)(NN - KTOP)*ez;
    float invZ = 1.f / Z;
    const float* a0 = &g_pacc[p0*DH];
    const float* a1 = &g_pacc[(p0+1)*DH];
    const float* a2 = &g_pacc[(p0+2)*DH];
    const float* vu = &g_vunk[bh*DH];
    int b = bh >> 3, h = bh & 7;
    float* op = &g_o[(b*NN + i)*C_ + h*DH];
    #pragma unroll
    for (int d = 0; d < DH; d++)
        op[d] = (a0[d]*e0 + a1[d]*e1 + a2[d]*e2 + ez*vu[d]) * invZ;
}

// ---------------- depthwise 3x3 conv (writes [C][B*NN], coalesced) ----------------
__global__ void dw_k(const float* __restrict__ x,
                     const float* __restrict__ w,
                     const float* __restrict__ bias) {
    int gid = blockIdx.x*256 + threadIdx.x;
    if (gid >= B_*C_*NN) return;
    int n = gid % NN;
    int bc = gid / NN;
    int c = bc % C_, b = bc / C_;
    int y = n / WW, x0 = n % WW;
    float acc = bias[c];
    const float* xp = &x[(b*C_ + c)*NN];
    const float* wp = &w[c*9];
    #pragma unroll
    for (int dy = 0; dy < 3; dy++) {
        int yy = y + dy - 1;
        if (yy < 0 || yy >= HH) continue;
        #pragma unroll
        for (int dx = 0; dx < 3; dx++) {
            int xx = x0 + dx - 1;
            if (xx < 0 || xx >= WW) continue;
            acc += xp[yy*WW + xx] * wp[dy*3 + dx];
        }
    }
    g_xdw[c*(B_*NN) + b*NN + n] = acc;
}

// ---------------- xs = attn_branch + conv_branch + pw bias ----------------
__global__ void xs_k(const float* __restrict__ pw_b) {
    int gid = blockIdx.x*256 + threadIdx.x;
    if (gid >= B_*NN*C_) return;
    int c = gid & 255;
    g_xs[gid] = g_xattn[gid] + g_xc[gid] + pw_b[c];
}

// ---------------- spatial gate stage 1: 1x1 conv C->32 + silu ----------------
__global__ void sg1_k(const float* __restrict__ w, const float* __restrict__ bias) {
    int bn = blockIdx.x;              // b*NN+n
    int go = threadIdx.x;             // 32
    __shared__ float row[C_];
    for (int i = go; i < C_; i += 32) row[i] = g_xs[bn*C_ + i];
    __syncthreads();
    float acc = bias[go];
    const float* wp = &w[go*C_];
    #pragma unroll 4
    for (int ci = 0; ci < C_; ci++) acc += row[ci]*wp[ci];
    g_t1[bn*GG + go] = acc / (1.f + expf(-acc));
}

// ---------------- spatial gate stage 2: 7x7 conv 32->1 + sigmoid ----------------
__global__ void sg2_k(const float* __restrict__ w, const float* __restrict__ bias) {
    int gid = blockIdx.x*256 + threadIdx.x;
    if (gid >= B_*NN) return;
    int b = gid / NN, n = gid % NN;
    int y = n / WW, x0 = n % WW;
    float acc = bias[0];
    for (int ky = 0; ky < 7; ky++) {
        int yy = y + ky - 3;
        if (yy < 0 || yy >= HH) continue;
        for (int kx = 0; kx < 7; kx++) {
            int xx = x0 + kx - 3;
            if (xx < 0 || xx >= WW) continue;
            const float* tp = &g_t1[(b*NN + yy*WW + xx)*GG];
            int widx = ky*7 + kx;
            float a0=0,a1=0;
            #pragma unroll
            for (int gi = 0; gi < GG; gi += 2) {
                a0 += tp[gi]   * w[gi*49 + widx];
                a1 += tp[gi+1] * w[(gi+1)*49 + widx];
            }
            acc += a0 + a1;
        }
    }
    g_sg[gid] = 1.f / (1.f + expf(-acc));
}

// ---------------- channel gate: pool partials ----------------
__global__ void cgpool_k() {
    int blk = blockIdx.x;            // b*16 + part
    int b = blk / 16, part = blk % 16;
    int c = threadIdx.x;             // 256
    float s = 0;
    int n0 = part*144;
    for (int n = n0; n < n0 + 144; n++) s += g_xs[(b*NN + n)*C_ + c];
    g_cgpart[blk*C_ + c] = s;
}

// ---------------- channel gate: combine + silu + sigmoid ----------------
__global__ void cggate_k(const float* __restrict__ w1, const float* __restrict__ b1,
                         const float* __restrict__ w2, const float* __restrict__ b2) {
    int b = blockIdx.x;
    int c = threadIdx.x;
    __shared__ float cgm[C_];
    __shared__ float t2[GG];
    float s = 0;
    for (int p = 0; p < 16; p++) s += g_cgpart[(b*16 + p)*C_ + c];
    cgm[c] = s * (1.0f/NN);
    __syncthreads();
    if (c < GG) {
        float a = b1[c];
        const float* wp = &w1[c*C_];
        for (int ci = 0; ci < C_; ci++) a += cgm[ci]*wp[ci];
        t2[c] = a / (1.f + expf(-a));
    }
    __syncthreads();
    float a2 = b2[c];
    const float* wp2 = &w2[c*GG];
    #pragma unroll
    for (int g = 0; g < GG; g++) a2 += t2[g]*wp2[g];
    g_cg[b*C_ + c] = 1.f / (1.f + expf(-a2));
}

// ---------------- x2 = x + gamma1 * xs*sg*cg ----------------
__global__ void x2_k(const float* __restrict__ x, const float* __restrict__ gamma1) {
    int gid = blockIdx.x*256 + threadIdx.x;
    if (gid >= B_*NN*C_) return;
    int c = gid & 255;
    int row = gid >> 8;              // b*NN+n
    int b = row / NN, n = row % NN;
    float xv = x[(b*C_ + c)*NN + n];
    g_x2[gid] = xv + gamma1[0] * g_xs[gid] * g_sg[row] * g_cg[b*C_ + c];
}

// ---------------- final: out = x2 + gamma2*(ff + b2), write NCHW ----------------
__global__ void out_k(const float* __restrict__ gamma2,
                      const float* __restrict__ b2,
                      float* __restrict__ out) {
    int gid = blockIdx.x*256 + threadIdx.x;
    if (gid >= B_*NN*C_) return;
    int c = gid & 255;
    int row = gid >> 8;
    int b = row / NN, n = row % NN;
    float v = g_x2[gid] + gamma2[0]*(g_ff[gid] + b2[c]);
    out[(b*C_ + c)*NN + n] = v;
}

// ---------------- host ----------------
#define GETSYM(p, s) do { void* _t; cudaGetSymbolAddress(&_t, s); p = (float*)_t; } while (0)

extern "C" void kernel_launch(void* const* d_in, const int* in_sizes, int n_in,
                              void* d_out, int out_size) {
    const float* x     = (const float*)d_in[0];
    const float* qkv_w = (const float*)d_in[1];
    const float* out_w = (const float*)d_in[2];
    const float* ln1_g = (const float*)d_in[3];
    const float* ln1_b = (const float*)d_in[4];
    const float* ln2_g = (const float*)d_in[5];
    const float* ln2_b = (const float*)d_in[6];
    const float* dw_w  = (const float*)d_in[7];
    const float* dw_b  = (const float*)d_in[8];
    const float* pw_w  = (const float*)d_in[9];
    const float* pw_b  = (const float*)d_in[10];
    const float* sg1_w = (const float*)d_in[11];
    const float* sg1_b = (const float*)d_in[12];
    const float* sg2_w = (const float*)d_in[13];
    const float* sg2_b = (const float*)d_in[14];
    const float* cg1_w = (const float*)d_in[15];
    const float* cg1_b = (const float*)d_in[16];
    const float* cg2_w = (const float*)d_in[17];
    const float* cg2_b = (const float*)d_in[18];
    const float* ff_w1 = (const float*)d_in[19];
    const float* ff_b1 = (const float*)d_in[20];
    const float* ff_w2 = (const float*)d_in[21];
    const float* ff_b2 = (const float*)d_in[22];
    const float* gamma1= (const float*)d_in[23];
    const float* gamma2= (const float*)d_in[24];
    float* out = (float*)d_out;
    (void)in_sizes; (void)n_in; (void)out_size;

    float *p_xa, *p_qkv, *p_o, *p_xattn, *p_xdw, *p_xc, *p_ln2, *p_h, *p_ff;
    GETSYM(p_xa, g_xa); GETSYM(p_qkv, g_qkv); GETSYM(p_o, g_o);
    GETSYM(p_xattn, g_xattn); GETSYM(p_xdw, g_xdw); GETSYM(p_xc, g_xc);
    GETSYM(p_ln2, g_ln2); GETSYM(p_h, g_h); GETSYM(p_ff, g_ff);

    const int M = B_*NN;   // 4608

    // attention branch
    ln_from_nchw_k<<<M, 256>>>(x, ln1_g, ln1_b);
    gemm_tc<false,false,false><<<dim3(3*C_/64, M/128), 256>>>(p_xa, qkv_w, p_qkv, nullptr, M, 3*C_, C_);
    scatter_qkv_k<<<(B_*NN*3*C_)/256, 256>>>();
    bh_sums1_k<<<dim3(BHN, 12), 256>>>();
    bh_sums2_k<<<BHN, 96>>>();
    scores_k<<<(BHN*NN)/256, 256>>>();
    select_k<<<32, 256>>>();
    vunkept_k<<<BHN, 256>>>();
    fill_o_k<<<(BHN*NN*DH)/256, 256>>>();
    attn_part_k<<<dim3(BHN, 9, NSPLIT), 64>>>();
    attn_comb_k<<<(BHN*KTOP + 127)/128, 128>>>();
    gemm_tc<false,false,false><<<dim3(C_/64, M/128), 256>>>(p_o, out_w, p_xattn, nullptr, M, C_, C_);

    // conv branch
    dw_k<<<(B_*C_*NN)/256, 256>>>(x, dw_w, dw_b);
    gemm_tc<true,true,false><<<dim3(C_/64, M/128), 256>>>(p_xdw, pw_w, p_xc, nullptr, M, C_, C_);
    xs_k<<<(B_*NN*C_)/256, 256>>>(pw_b);

    // gates
    sg1_k<<<B_*NN, 32>>>(sg1_w, sg1_b);
    sg2_k<<<(B_*NN + 255)/256, 256>>>(sg2_w, sg2_b);
    cgpool_k<<<B_*16, 256>>>();
    cggate_k<<<B_, 256>>>(cg1_w, cg1_b, cg2_w, cg2_b);
    x2_k<<<(B_*NN*C_)/256, 256>>>(x, gamma1);

    // FFN
    ln_from_bnc_k<<<M, 256>>>(ln2_g, ln2_b);
    gemm_tc<false,false,true><<<dim3(HID/64, M/128), 256>>>(p_ln2, ff_w1, p_h, ff_b1, M, HID, C_);
    gemm_tc<false,false,false><<<dim3(C_/64, M/128), 256>>>(p_h, ff_w2, p_ff, nullptr, M, C_, HID);
    out_k<<<(B_*NN*C_)/256, 256>>>(gamma2, ff_b2, out);
}

// round 4
// speedup vs baseline: 1.5112x; 1.1330x over previous
#include <cuda_runtime.h>
#include <math.h>

#define B_ 2
#define C_ 256
#define HH 48
#define WW 48
#define NN 2304          // 48*48
#define NHEAD 8
#define DH 32
#define BHN 16           // B_*NHEAD
#define KTOP 576
#define HID 1024
#define GG 32            // C/8 gate channels
#define QSCALE 0.17677669529663687f   // 1/sqrt(32)
#define NSPLIT 3         // attention column-split
#define CHUNK 192        // KTOP / NSPLIT

// ---------------- scratch (static device arrays; no allocation) ----------------
__device__ float g_xa  [B_*NN*C_];
__device__ float g_q   [BHN*NN*DH];
__device__ float g_k   [BHN*NN*DH];
__device__ float g_v   [BHN*NN*DH];
__device__ float g_spart[BHN*12*3*DH];
__device__ float g_sums[BHN*3*DH];        // [bh][qsum,ksum,vsum][d]
__device__ float g_rs  [BHN*NN];
__device__ float g_cs  [BHN*NN];
__device__ int   g_rowlist[BHN*KTOP];
__device__ int   g_collist[BHN*KTOP];
__device__ float g_vunk[BHN*DH];
__device__ float g_pm  [BHN*KTOP*NSPLIT];
__device__ float g_pz  [BHN*KTOP*NSPLIT];
__device__ float g_pacc[BHN*KTOP*NSPLIT*DH];
__device__ float g_o   [B_*NN*C_];
__device__ float g_xattn[B_*NN*C_];
__device__ float g_xdw [C_*B_*NN];        // [c][b*NN+n]  (K-major => TRANSA gemm)
__device__ float g_xs  [B_*NN*C_];
__device__ float g_t1  [B_*NN*GG];
__device__ float g_sg  [B_*NN];
__device__ float g_cgpart[B_*16*C_];
__device__ float g_cg  [B_*C_];
__device__ float g_x2  [B_*NN*C_];
__device__ float g_ln2 [B_*NN*C_];
__device__ float g_h   [B_*NN*HID];

// ---------------- cp.async helpers ----------------
__device__ __forceinline__ void cp16(void* sptr, const void* gptr) {
    unsigned saddr = (unsigned)__cvta_generic_to_shared(sptr);
    asm volatile("cp.async.cg.shared.global [%0], [%1], 16;" :: "r"(saddr), "l"(gptr));
}
__device__ __forceinline__ void cp_commit() { asm volatile("cp.async.commit_group;"); }
__device__ __forceinline__ void cp_wait0()  { asm volatile("cp.async.wait_group 0;" ::: "memory"); }

__device__ __forceinline__ void mma_tf32(float* d, const unsigned* a,
                                         const unsigned* b, const float* c) {
    asm volatile("mma.sync.aligned.m16n8k8.row.col.f32.tf32.tf32.f32 "
        "{%0,%1,%2,%3}, {%4,%5,%6,%7}, {%8,%9}, {%10,%11,%12,%13};"
        : "=f"(d[0]),"=f"(d[1]),"=f"(d[2]),"=f"(d[3])
        : "r"(a[0]),"r"(a[1]),"r"(a[2]),"r"(a[3]),
          "r"(b[0]),"r"(b[1]),
          "f"(c[0]),"f"(c[1]),"f"(c[2]),"f"(c[3]));
}
__device__ __forceinline__ unsigned fbits(float f) { return __float_as_uint(f); }

// ---------------- tf32 tensor-core GEMM, cp.async double-buffered ----------------
// TA=false: A [M,K] row-major. TA=true: A [K,M] row-major.
// TB=false: B [K,N] row-major. TB=true: B [N,K] row-major.
// EPI: 0=plain 1=bias+gelu 2=qkv-scatter 3=xs(add xattn+bias) 4=final out
template<int BM, int BN, int WARPS_M, int WARPS_N, bool TA, bool TB, int EPI>
__global__ __launch_bounds__(WARPS_M*WARPS_N*32)
void gemm_tc(const float* __restrict__ A, const float* __restrict__ B,
             float* __restrict__ C, const float* __restrict__ bias,
             const float* __restrict__ aux, int M, int N, int K) {
    constexpr int BK = 16;
    constexpr int THREADS = WARPS_M*WARPS_N*32;
    constexpr int WM = BM/WARPS_M, WN = BN/WARPS_N;
    constexpr int MT = WM/16, NT = WN/8;
    constexpr int AW = TA ? (BM+8) : 20;
    constexpr int ASZ = TA ? BK*(BM+8) : BM*20;
    constexpr int BW = TB ? 20 : (BN+8);
    constexpr int BSZ = TB ? BN*20 : BK*(BN+8);

    __shared__ __align__(16) float As[2][ASZ];
    __shared__ __align__(16) float Bs[2][BSZ];

    const int bm = blockIdx.y*BM, bn = blockIdx.x*BN;
    const int tid = threadIdx.x;
    const int lane = tid & 31, wid = tid >> 5;
    const int wm = wid / WARPS_N, wn = wid % WARPS_N;
    const int g = lane >> 2, tig = lane & 3;

    float acc[MT][NT][4];
    #pragma unroll
    for (int i = 0; i < MT; i++)
        #pragma unroll
        for (int j = 0; j < NT; j++)
            #pragma unroll
            for (int l = 0; l < 4; l++) acc[i][j][l] = 0.f;

    // copy: BM*4 (A) and BN*4 (B) 16B-chunks per tile
    auto copy_tile = [&](int st, int k0) {
        constexpr int CHA = BM*4, PTA = CHA/THREADS;
        #pragma unroll
        for (int i = 0; i < PTA; i++) {
            int ch = tid + i*THREADS;
            if (!TA) {
                int row = ch >> 2, c4 = (ch & 3)*4;
                cp16(&As[st][row*20 + c4], &A[(size_t)(bm+row)*K + k0 + c4]);
            } else {
                constexpr int MC = BM/4;
                int kr = ch / MC, mc = (ch % MC)*4;
                cp16(&As[st][kr*(BM+8) + mc], &A[(size_t)(k0+kr)*M + bm + mc]);
            }
        }
        constexpr int CHB = BN*4, PTB = CHB/THREADS;
        #pragma unroll
        for (int i = 0; i < PTB; i++) {
            int ch = tid + i*THREADS;
            if (!TB) {
                constexpr int NC = BN/4;
                int kr = ch / NC, nc = (ch % NC)*4;
                cp16(&Bs[st][kr*(BN+8) + nc], &B[(size_t)(k0+kr)*N + bn + nc]);
            } else {
                int row = ch >> 2, c4 = (ch & 3)*4;
                cp16(&Bs[st][row*20 + c4], &B[(size_t)(bn+row)*K + k0 + c4]);
            }
        }
    };

    copy_tile(0, 0);
    cp_commit();
    int stage = 0;
    for (int k0 = 0; k0 < K; k0 += BK) {
        cp_wait0();
        __syncthreads();
        if (k0 + BK < K) { copy_tile(stage^1, k0+BK); cp_commit(); }
        const float* as = As[stage];
        const float* bs = Bs[stage];
        #pragma unroll
        for (int ks = 0; ks < BK; ks += 8) {
            int kk = ks + tig;
            unsigned afr[MT][4];
            #pragma unroll
            for (int mt = 0; mt < MT; mt++) {
                int r0 = wm*WM + mt*16 + g;
                if (!TA) {
                    afr[mt][0] = fbits(as[(r0  )*20 + kk  ]);
                    afr[mt][1] = fbits(as[(r0+8)*20 + kk  ]);
                    afr[mt][2] = fbits(as[(r0  )*20 + kk+4]);
                    afr[mt][3] = fbits(as[(r0+8)*20 + kk+4]);
                } else {
                    afr[mt][0] = fbits(as[(kk  )*(BM+8) + r0  ]);
                    afr[mt][1] = fbits(as[(kk  )*(BM+8) + r0+8]);
                    afr[mt][2] = fbits(as[(kk+4)*(BM+8) + r0  ]);
                    afr[mt][3] = fbits(as[(kk+4)*(BM+8) + r0+8]);
                }
            }
            unsigned bfr[NT][2];
            #pragma unroll
            for (int nt = 0; nt < NT; nt++) {
                int c0 = wn*WN + nt*8 + g;
                if (!TB) {
                    bfr[nt][0] = fbits(bs[(kk  )*(BN+8) + c0]);
                    bfr[nt][1] = fbits(bs[(kk+4)*(BN+8) + c0]);
                } else {
                    bfr[nt][0] = fbits(bs[c0*20 + kk  ]);
                    bfr[nt][1] = fbits(bs[c0*20 + kk+4]);
                }
            }
            #pragma unroll
            for (int mt = 0; mt < MT; mt++)
                #pragma unroll
                for (int nt = 0; nt < NT; nt++)
                    mma_tf32(acc[mt][nt], afr[mt], bfr[nt], acc[mt][nt]);
        }
        stage ^= 1;
    }

    // epilogue
    #pragma unroll
    for (int mt = 0; mt < MT; mt++) {
        int row0 = bm + wm*WM + mt*16 + g;
        #pragma unroll
        for (int nt = 0; nt < NT; nt++) {
            int col = bn + wn*WN + nt*8 + tig*2;
            #pragma unroll
            for (int half = 0; half < 2; half++) {
                int row = row0 + half*8;
                float v0 = acc[mt][nt][half*2], v1 = acc[mt][nt][half*2+1];
                if (EPI == 0) {
                    *(float2*)&C[(size_t)row*N + col] = make_float2(v0, v1);
                } else if (EPI == 1) {
                    v0 += bias[col]; v1 += bias[col+1];
                    v0 = 0.5f*v0*(1.0f + erff(v0*0.70710678118654752f));
                    v1 = 0.5f*v1*(1.0f + erff(v1*0.70710678118654752f));
                    *(float2*)&C[(size_t)row*N + col] = make_float2(v0, v1);
                } else if (EPI == 2) {
                    int b = row / NN, n = row - b*NN;
                    int part = col >> 8, cc = col & 255;
                    int h = cc >> 5, d = cc & 31;
                    size_t dst = ((size_t)(b*NHEAD + h)*NN + n)*DH + d;
                    if (part == 0)
                        *(float2*)&g_q[dst] = make_float2(v0*QSCALE, v1*QSCALE);
                    else if (part == 1)
                        *(float2*)&g_k[dst] = make_float2(v0, v1);
                    else
                        *(float2*)&g_v[dst] = make_float2(v0, v1);
                } else if (EPI == 3) {
                    v0 += g_xattn[(size_t)row*C_ + col]   + bias[col];
                    v1 += g_xattn[(size_t)row*C_ + col+1] + bias[col+1];
                    *(float2*)&C[(size_t)row*N + col] = make_float2(v0, v1);
                } else { // EPI == 4
                    int b = row / NN, n = row - b*NN;
                    float gm = aux[0];
                    float o0 = g_x2[(size_t)row*C_ + col]   + gm*(v0 + bias[col]);
                    float o1 = g_x2[(size_t)row*C_ + col+1] + gm*(v1 + bias[col+1]);
                    C[(size_t)(b*C_ + col  )*NN + n] = o0;
                    C[(size_t)(b*C_ + col+1)*NN + n] = o1;
                }
            }
        }
    }
}

// ---------------- LN1: NCHW -> normalized [B*N, C], tiled transpose ----------------
__global__ __launch_bounds__(256) void ln1_k(const float* __restrict__ x,
                                             const float* __restrict__ gg,
                                             const float* __restrict__ bb) {
    __shared__ float tile[C_*33];
    __shared__ float smu[32], sr[32];
    int blk = blockIdx.x;                  // B_*NN/32 = 144
    int b = blk / (NN/32);
    int n0 = (blk % (NN/32)) * 32;
    int tid = threadIdx.x;
    #pragma unroll
    for (int i = 0; i < 32; i++) {
        int idx = i*256 + tid;
        int c = idx >> 5, n = idx & 31;
        tile[c*33 + n] = x[(size_t)(b*C_ + c)*NN + n0 + n];
    }
    __syncthreads();
    int wid = tid >> 5, lane = tid & 31;
    #pragma unroll
    for (int j = 0; j < 4; j++) {
        int n = wid*4 + j;
        float s1 = 0, s2 = 0;
        #pragma unroll
        for (int i = 0; i < 8; i++) {
            float v = tile[(lane + i*32)*33 + n];
            s1 += v; s2 += v*v;
        }
        #pragma unroll
        for (int o = 16; o; o >>= 1) {
            s1 += __shfl_xor_sync(~0u, s1, o);
            s2 += __shfl_xor_sync(~0u, s2, o);
        }
        if (lane == 0) {
            float mu = s1*(1.0f/C_);
            float var = s2*(1.0f/C_) - mu*mu;
            smu[n] = mu; sr[n] = rsqrtf(var + 1e-6f);
        }
    }
    __syncthreads();
    #pragma unroll
    for (int i = 0; i < 32; i++) {
        int idx = i*256 + tid;
        int n = idx >> 8, c = idx & 255;
        float v = tile[c*33 + n];
        g_xa[(size_t)(b*NN + n0 + n)*C_ + c] = (v - smu[n])*sr[n]*gg[c] + bb[c];
    }
}

// ---------------- LN2: warp per row over g_x2 ----------------
__global__ void ln2_k(const float* __restrict__ gg, const float* __restrict__ bb) {
    int row = (blockIdx.x*256 + threadIdx.x) >> 5;
    int lane = threadIdx.x & 31;
    const float* p = &g_x2[(size_t)row*C_];
    float v[8]; float s1 = 0, s2 = 0;
    #pragma unroll
    for (int i = 0; i < 8; i++) { v[i] = p[lane + i*32]; s1 += v[i]; s2 += v[i]*v[i]; }
    #pragma unroll
    for (int o = 16; o; o >>= 1) {
        s1 += __shfl_xor_sync(~0u, s1, o);
        s2 += __shfl_xor_sync(~0u, s2, o);
    }
    float mu = s1*(1.0f/C_);
    float var = s2*(1.0f/C_) - mu*mu;
    float r = rsqrtf(var + 1e-6f);
    #pragma unroll
    for (int i = 0; i < 8; i++) {
        int c = lane + i*32;
        g_ln2[(size_t)row*C_ + c] = (v[i]-mu)*r*gg[c] + bb[c];
    }
}

// ---------------- per-(b,h) sums of q,k,v (two-stage) ----------------
__global__ void bh_sums1_k() {
    int bh = blockIdx.x, yy = blockIdx.y;     // 16 x 12
    int t = threadIdx.x;                      // 256
    int d = t & 31, part = t >> 5;            // 8 parts x 24 rows
    float sq = 0, sk = 0, sv = 0;
    int n0 = yy*192 + part*24;
    for (int j = 0; j < 24; j++) {
        int idx = (bh*NN + n0 + j)*DH + d;
        sq += g_q[idx]; sk += g_k[idx]; sv += g_v[idx];
    }
    __shared__ float sh[3][8][32];
    sh[0][part][d]=sq; sh[1][part][d]=sk; sh[2][part][d]=sv;
    __syncthreads();
    if (t < 96) {
        int which = t >> 5, dd = t & 31;
        float s = 0;
        #pragma unroll
        for (int p = 0; p < 8; p++) s += sh[which][p][dd];
        g_spart[((bh*12 + yy)*3 + which)*DH + dd] = s;
    }
}

__global__ void bh_sums2_k() {
    int bh = blockIdx.x;
    int t = threadIdx.x;            // 96
    int which = t >> 5, d = t & 31;
    float s = 0;
    #pragma unroll
    for (int y = 0; y < 12; y++) s += g_spart[((bh*12 + y)*3 + which)*DH + d];
    g_sums[(bh*3 + which)*DH + d] = s;
}

// ---------------- row/col pruning scores ----------------
__global__ void scores_k() {
    int gid = blockIdx.x*256 + threadIdx.x;    // bh*NN
    int bh = gid / NN;
    __shared__ float qs[DH], ks[DH];
    if (threadIdx.x < DH)        qs[threadIdx.x]     = g_sums[(bh*3+0)*DH + threadIdx.x];
    else if (threadIdx.x < 2*DH) ks[threadIdx.x-DH]  = g_sums[(bh*3+1)*DH + threadIdx.x-DH];
    __syncthreads();
    float r = 0, c = 0;
    const float4* qp = (const float4*)&g_q[(size_t)gid*DH];
    const float4* kp = (const float4*)&g_k[(size_t)gid*DH];
    #pragma unroll
    for (int w = 0; w < 8; w++) {
        float4 qf = qp[w], kf = kp[w];
        r += qf.x*ks[4*w] + qf.y*ks[4*w+1] + qf.z*ks[4*w+2] + qf.w*ks[4*w+3];
        c += qs[4*w]*kf.x + qs[4*w+1]*kf.y + qs[4*w+2]*kf.z + qs[4*w+3]*kf.w;
    }
    g_rs[gid] = r; g_cs[gid] = c;
}

// ---------------- exact top-k selection (radix select + stable compaction) ----------------
__device__ __forceinline__ unsigned f2key(float f) {
    unsigned u = __float_as_uint(f);
    return (u & 0x80000000u) ? ~u : (u | 0x80000000u);
}

__global__ void select_k() {
    int blk = blockIdx.x;          // 0..31
    int type = blk >> 4, bh = blk & 15;
    const float* s = (type == 0 ? g_rs : g_cs) + bh*NN;
    int* list = (type == 0 ? g_rowlist : g_collist) + bh*KTOP;
    __shared__ unsigned keys[NN];
    __shared__ int hist[256];
    __shared__ int scan[256];
    __shared__ unsigned sh_T;
    __shared__ int sh_take;
    int t = threadIdx.x;           // 256
    for (int i = t; i < NN; i += 256) keys[i] = f2key(s[i]);
    __syncthreads();

    unsigned prefix = 0, pmask = 0;
    int kneed = KTOP;
    for (int pass = 0; pass < 4; pass++) {
        int shift = 24 - 8*pass;
        hist[t] = 0;
        __syncthreads();
        for (int i = t; i < NN; i += 256) {
            unsigned u = keys[i];
            if ((u & pmask) == prefix) atomicAdd(&hist[(u >> shift) & 255], 1);
        }
        __syncthreads();
        if (t == 0) {
            int run = 0, b = 255;
            for (; b >= 0; b--) {
                int h = hist[b];
                if (run + h >= kneed) break;
                run += h;
            }
            sh_T = prefix | ((unsigned)b << shift);
            sh_take = kneed - run;
        }
        __syncthreads();
        prefix = sh_T;
        kneed = sh_take;
        pmask |= (0xffu << shift);
        __syncthreads();
    }
    unsigned T = prefix;
    int take = kneed;

    unsigned myk[9];
    int eqc = 0;
    #pragma unroll
    for (int j = 0; j < 9; j++) {
        myk[j] = keys[t*9 + j];
        eqc += (myk[j] == T);
    }
    scan[t] = eqc; __syncthreads();
    for (int st = 1; st < 256; st <<= 1) {
        int tmp = (t >= st) ? scan[t-st] : 0;
        __syncthreads();
        scan[t] += tmp;
        __syncthreads();
    }
    int eqbase = scan[t] - eqc;
    __syncthreads();

    bool kept[9];
    int keptc = 0, eqseen = 0;
    #pragma unroll
    for (int j = 0; j < 9; j++) {
        unsigned u = myk[j];
        bool gt = (u > T), eq = (u == T);
        bool kp = gt || (eq && (eqbase + eqseen) < take);
        if (eq) eqseen++;
        kept[j] = kp; keptc += kp;
    }
    scan[t] = keptc; __syncthreads();
    for (int st = 1; st < 256; st <<= 1) {
        int tmp = (t >= st) ? scan[t-st] : 0;
        __syncthreads();
        scan[t] += tmp;
        __syncthreads();
    }
    int wbase = scan[t] - keptc;
    #pragma unroll
    for (int j = 0; j < 9; j++)
        if (kept[j]) list[wbase++] = t*9 + j;
}

// ---------------- v_unkept = vsum - sum over kept cols ----------------
__global__ void vunkept_k() {
    int bh = blockIdx.x;
    int t = threadIdx.x;
    int d = t & 31, part = t >> 5;
    float sv = 0;
    for (int jj = part; jj < KTOP; jj += 8) {
        int j = g_collist[bh*KTOP + jj];
        sv += g_v[(bh*NN + j)*DH + d];
    }
    __shared__ float sh[8][32];
    sh[part][d] = sv;
    __syncthreads();
    if (t < 32) {
        float s = 0;
        #pragma unroll
        for (int p = 0; p < 8; p++) s += sh[p][t];
        g_vunk[bh*DH + t] = g_sums[(bh*3+2)*DH + t] - s;
    }
}

// ---------------- pruned rows: uniform softmax -> mean(v) ----------------
__global__ void fill_o_k() {
    int gid = blockIdx.x*256 + threadIdx.x;
    if (gid >= BHN*NN*DH) return;
    int bh = gid / (NN*DH);
    int r = gid % (NN*DH);
    int n = r / DH, d = r & 31;
    int b = bh >> 3, h = bh & 7;
    g_o[(size_t)(b*NN + n)*C_ + h*DH + d] = g_sums[(bh*3+2)*DH + d] * (1.0f/NN);
}

// ---------------- kept-row attention partials over a column chunk ----------------
__global__ __launch_bounds__(64) void attn_part_k() {
    int bh = blockIdx.x;
    int t = threadIdx.x;                      // 64
    int slot = blockIdx.y*64 + t;             // 0..575
    int chunk = blockIdx.z;                   // 0..2
    int i = g_rowlist[bh*KTOP + slot];

    float qr[DH];
    const float4* qp = (const float4*)&g_q[(size_t)(bh*NN + i)*DH];
    #pragma unroll
    for (int w = 0; w < 8; w++) {
        float4 f = qp[w];
        qr[4*w]=f.x; qr[4*w+1]=f.y; qr[4*w+2]=f.z; qr[4*w+3]=f.w;
    }

    float m = -3.0e38f, Z = 0.f;
    float acc[DH];
    #pragma unroll
    for (int d = 0; d < DH; d++) acc[d] = 0.f;

    __shared__ int cj[96];
    __shared__ float Kc[96][DH];
    __shared__ float Vc[96][DH];

    for (int c0 = chunk*CHUNK; c0 < chunk*CHUNK + CHUNK; c0 += 96) {
        __syncthreads();
        for (int jj = t; jj < 96; jj += 64) cj[jj] = g_collist[bh*KTOP + c0 + jj];
        __syncthreads();
        for (int idx = t; idx < 96*DH; idx += 64) {
            int jj = idx >> 5, d = idx & 31;
            int base = (bh*NN + cj[jj])*DH + d;
            Kc[jj][d] = g_k[base];
            Vc[jj][d] = g_v[base];
        }
        __syncthreads();
        #pragma unroll 2
        for (int jj = 0; jj < 96; jj++) {
            float s0=0,s1=0,s2=0,s3=0;
            #pragma unroll
            for (int d = 0; d < DH; d += 4) {
                s0 += qr[d+0]*Kc[jj][d+0];
                s1 += qr[d+1]*Kc[jj][d+1];
                s2 += qr[d+2]*Kc[jj][d+2];
                s3 += qr[d+3]*Kc[jj][d+3];
            }
            float s = (s0+s1) + (s2+s3);
            if (s > m) {
                float cf = __expf(m - s);
                Z = Z*cf + 1.f;
                #pragma unroll
                for (int d = 0; d < DH; d++) acc[d] = acc[d]*cf + Vc[jj][d];
                m = s;
            } else {
                float e = __expf(s - m);
                Z += e;
                #pragma unroll
                for (int d = 0; d < DH; d++) acc[d] += e*Vc[jj][d];
            }
        }
    }
    int pidx = (bh*KTOP + slot)*NSPLIT + chunk;
    g_pm[pidx] = m;
    g_pz[pidx] = Z;
    float* pa = &g_pacc[(size_t)pidx*DH];
    #pragma unroll
    for (int d = 0; d < DH; d++) pa[d] = acc[d];
}

// ---------------- combine partials + zero-column correction ----------------
__global__ void attn_comb_k() {
    int gid = blockIdx.x*128 + threadIdx.x;
    if (gid >= BHN*KTOP) return;
    int bh = gid / KTOP, slot = gid % KTOP;
    int i = g_rowlist[bh*KTOP + slot];
    int p0 = gid*NSPLIT;
    float m0 = g_pm[p0], m1 = g_pm[p0+1], m2 = g_pm[p0+2];
    float mstar = fmaxf(0.f, fmaxf(m0, fmaxf(m1, m2)));
    float e0 = __expf(m0 - mstar), e1 = __expf(m1 - mstar), e2 = __expf(m2 - mstar);
    float ez = __expf(-mstar);
    float Z = g_pz[p0]*e0 + g_pz[p0+1]*e1 + g_pz[p0+2]*e2 + (float)(NN - KTOP)*ez;
    float invZ = 1.f / Z;
    const float* a0 = &g_pacc[(size_t)p0*DH];
    const float* a1 = &g_pacc[(size_t)(p0+1)*DH];
    const float* a2 = &g_pacc[(size_t)(p0+2)*DH];
    const float* vu = &g_vunk[bh*DH];
    int b = bh >> 3, h = bh & 7;
    float* op = &g_o[(size_t)(b*NN + i)*C_ + h*DH];
    #pragma unroll
    for (int d = 0; d < DH; d++)
        op[d] = (a0[d]*e0 + a1[d]*e1 + a2[d]*e2 + ez*vu[d]) * invZ;
}

// ---------------- depthwise 3x3 conv (writes [C][B*NN], coalesced) ----------------
__global__ void dw_k(const float* __restrict__ x,
                     const float* __restrict__ w,
                     const float* __restrict__ bias) {
    int gid = blockIdx.x*256 + threadIdx.x;
    if (gid >= B_*C_*NN) return;
    int n = gid % NN;
    int bc = gid / NN;
    int c = bc % C_, b = bc / C_;
    int y = n / WW, x0 = n % WW;
    float acc = bias[c];
    const float* xp = &x[(size_t)(b*C_ + c)*NN];
    const float* wp = &w[c*9];
    #pragma unroll
    for (int dy = 0; dy < 3; dy++) {
        int yy = y + dy - 1;
        if (yy < 0 || yy >= HH) continue;
        #pragma unroll
        for (int dx = 0; dx < 3; dx++) {
            int xx = x0 + dx - 1;
            if (xx < 0 || xx >= WW) continue;
            acc += xp[yy*WW + xx] * wp[dy*3 + dx];
        }
    }
    g_xdw[(size_t)c*(B_*NN) + b*NN + n] = acc;
}

// ---------------- spatial gate stage 1: 1x1 conv C->32 + silu ----------------
__global__ void sg1_k(const float* __restrict__ w, const float* __restrict__ bias) {
    int bn = blockIdx.x;              // b*NN+n
    int go = threadIdx.x;             // 32
    __shared__ float row[C_];
    for (int i = go; i < C_; i += 32) row[i] = g_xs[(size_t)bn*C_ + i];
    __syncthreads();
    float acc = bias[go];
    const float* wp = &w[go*C_];
    #pragma unroll 4
    for (int ci = 0; ci < C_; ci++) acc += row[ci]*wp[ci];
    g_t1[bn*GG + go] = acc / (1.f + expf(-acc));
}

// ---------------- spatial gate stage 2: 7x7 conv 32->1 + sigmoid ----------------
__global__ void sg2_k(const float* __restrict__ w, const float* __restrict__ bias) {
    int gid = blockIdx.x*256 + threadIdx.x;
    if (gid >= B_*NN) return;
    int b = gid / NN, n = gid % NN;
    int y = n / WW, x0 = n % WW;
    float acc = bias[0];
    for (int ky = 0; ky < 7; ky++) {
        int yy = y + ky - 3;
        if (yy < 0 || yy >= HH) continue;
        for (int kx = 0; kx < 7; kx++) {
            int xx = x0 + kx - 3;
            if (xx < 0 || xx >= WW) continue;
            const float* tp = &g_t1[(b*NN + yy*WW + xx)*GG];
            int widx = ky*7 + kx;
            float a0=0,a1=0;
            #pragma unroll
            for (int gi = 0; gi < GG; gi += 2) {
                a0 += tp[gi]   * w[gi*49 + widx];
                a1 += tp[gi+1] * w[(gi+1)*49 + widx];
            }
            acc += a0 + a1;
        }
    }
    g_sg[gid] = 1.f / (1.f + expf(-acc));
}

// ---------------- channel gate: pool partials ----------------
__global__ void cgpool_k() {
    int blk = blockIdx.x;            // b*16 + part
    int b = blk / 16, part = blk % 16;
    int c = threadIdx.x;             // 256
    float s = 0;
    int n0 = part*144;
    for (int n = n0; n < n0 + 144; n++) s += g_xs[(size_t)(b*NN + n)*C_ + c];
    g_cgpart[blk*C_ + c] = s;
}

// ---------------- channel gate: combine + silu + sigmoid ----------------
__global__ void cggate_k(const float* __restrict__ w1, const float* __restrict__ b1,
                         const float* __restrict__ w2, const float* __restrict__ b2) {
    int b = blockIdx.x;
    int c = threadIdx.x;
    __shared__ float cgm[C_];
    __shared__ float t2[GG];
    float s = 0;
    for (int p = 0; p < 16; p++) s += g_cgpart[(b*16 + p)*C_ + c];
    cgm[c] = s * (1.0f/NN);
    __syncthreads();
    if (c < GG) {
        float a = b1[c];
        const float* wp = &w1[c*C_];
        for (int ci = 0; ci < C_; ci++) a += cgm[ci]*wp[ci];
        t2[c] = a / (1.f + expf(-a));
    }
    __syncthreads();
    float a2 = b2[c];
    const float* wp2 = &w2[c*GG];
    #pragma unroll
    for (int g = 0; g < GG; g++) a2 += t2[g]*wp2[g];
    g_cg[b*C_ + c] = 1.f / (1.f + expf(-a2));
}

// ---------------- x2 = x + gamma1*xs*sg*cg, tiled transpose ----------------
__global__ __launch_bounds__(256) void x2_k(const float* __restrict__ x,
                                            const float* __restrict__ gamma1) {
    __shared__ float tile[C_*33];
    int blk = blockIdx.x;               // 144
    int b = blk / (NN/32);
    int n0 = (blk % (NN/32)) * 32;
    int tid = threadIdx.x;
    #pragma unroll
    for (int i = 0; i < 32; i++) {
        int idx = i*256 + tid;
        int c = idx >> 5, n = idx & 31;
        tile[c*33 + n] = x[(size_t)(b*C_ + c)*NN + n0 + n];
    }
    __syncthreads();
    float gm = gamma1[0];
    #pragma unroll
    for (int i = 0; i < 32; i++) {
        int idx = i*256 + tid;
        int n = idx >> 8, c = idx & 255;
        int row = b*NN + n0 + n;
        g_x2[(size_t)row*C_ + c] =
            tile[c*33 + n] + gm * g_xs[(size_t)row*C_ + c] * g_sg[row] * g_cg[b*C_ + c];
    }
}

// ---------------- host ----------------
#define GETSYM(p, s) do { void* _t; cudaGetSymbolAddress(&_t, s); p = (float*)_t; } while (0)

extern "C" void kernel_launch(void* const* d_in, const int* in_sizes, int n_in,
                              void* d_out, int out_size) {
    const float* x     = (const float*)d_in[0];
    const float* qkv_w = (const float*)d_in[1];
    const float* out_w = (const float*)d_in[2];
    const float* ln1_g = (const float*)d_in[3];
    const float* ln1_b = (const float*)d_in[4];
    const float* ln2_g = (const float*)d_in[5];
    const float* ln2_b = (const float*)d_in[6];
    const float* dw_w  = (const float*)d_in[7];
    const float* dw_b  = (const float*)d_in[8];
    const float* pw_w  = (const float*)d_in[9];
    const float* pw_b  = (const float*)d_in[10];
    const float* sg1_w = (const float*)d_in[11];
    const float* sg1_b = (const float*)d_in[12];
    const float* sg2_w = (const float*)d_in[13];
    const float* sg2_b = (const float*)d_in[14];
    const float* cg1_w = (const float*)d_in[15];
    const float* cg1_b = (const float*)d_in[16];
    const float* cg2_w = (const float*)d_in[17];
    const float* cg2_b = (const float*)d_in[18];
    const float* ff_w1 = (const float*)d_in[19];
    const float* ff_b1 = (const float*)d_in[20];
    const float* ff_w2 = (const float*)d_in[21];
    const float* ff_b2 = (const float*)d_in[22];
    const float* gamma1= (const float*)d_in[23];
    const float* gamma2= (const float*)d_in[24];
    float* out = (float*)d_out;
    (void)in_sizes; (void)n_in; (void)out_size;

    float *p_xa, *p_o, *p_xattn, *p_xdw, *p_xs, *p_ln2, *p_h;
    GETSYM(p_xa, g_xa); GETSYM(p_o, g_o); GETSYM(p_xattn, g_xattn);
    GETSYM(p_xdw, g_xdw); GETSYM(p_xs, g_xs);
    GETSYM(p_ln2, g_ln2); GETSYM(p_h, g_h);

    const int M = B_*NN;   // 4608

    // attention branch
    ln1_k<<<B_*NN/32, 256>>>(x, ln1_g, ln1_b);
    // QKV: [M,768] = xa @ qkv_w, epilogue scatters into g_q/g_k/g_v
    gemm_tc<128,128,2,4,false,false,2><<<dim3(768/128, M/128), 256>>>(
        p_xa, qkv_w, nullptr, nullptr, nullptr, M, 3*C_, C_);
    bh_sums1_k<<<dim3(BHN, 12), 256>>>();
    bh_sums2_k<<<BHN, 96>>>();
    scores_k<<<(BHN*NN)/256, 256>>>();
    select_k<<<32, 256>>>();
    vunkept_k<<<BHN, 256>>>();
    fill_o_k<<<(BHN*NN*DH)/256, 256>>>();
    attn_part_k<<<dim3(BHN, 9, NSPLIT), 64>>>();
    attn_comb_k<<<(BHN*KTOP + 127)/128, 128>>>();
    // out-proj: xattn = o @ out_w
    gemm_tc<64,64,2,2,false,false,0><<<dim3(C_/64, M/64), 128>>>(
        p_o, out_w, p_xattn, nullptr, nullptr, M, C_, C_);

    // conv branch (dw independent; pw epilogue adds xattn + pw_bias -> xs)
    dw_k<<<(B_*C_*NN)/256, 256>>>(x, dw_w, dw_b);
    gemm_tc<64,64,2,2,true,true,3><<<dim3(C_/64, M/64), 128>>>(
        p_xdw, pw_w, p_xs, pw_b, nullptr, M, C_, C_);

    // gates
    sg1_k<<<B_*NN, 32>>>(sg1_w, sg1_b);
    sg2_k<<<(B_*NN + 255)/256, 256>>>(sg2_w, sg2_b);
    cgpool_k<<<B_*16, 256>>>();
    cggate_k<<<B_, 256>>>(cg1_w, cg1_b, cg2_w, cg2_b);
    x2_k<<<B_*NN/32, 256>>>(x, gamma1);

    // FFN
    ln2_k<<<M/8, 256>>>(ln2_g, ln2_b);
    gemm_tc<128,128,2,4,false,false,1><<<dim3(HID/128, M/128), 256>>>(
        p_ln2, ff_w1, p_h, ff_b1, nullptr, M, HID, C_);
    // FFN2 epilogue: out = x2 + gamma2*(ff + b2), NCHW store
    gemm_tc<64,64,2,2,false,false,4><<<dim3(C_/64, M/64), 128>>>(
        p_h, ff_w2, out, ff_b2, gamma2, M, C_, HID);
}

// round 7
// speedup vs baseline: 2.2212x; 1.4698x over previous
#include <cuda_runtime.h>
#include <cuda_bf16.h>
#include <math.h>

#define B_ 2
#define C_ 256
#define HH 48
#define WW 48
#define NN 2304          // 48*48
#define NHEAD 8
#define DH 32
#define BHN 16           // B_*NHEAD
#define KTOP 576
#define HID 1024
#define GG 32            // C/8 gate channels
#define QSCALE 0.17677669529663687f   // 1/sqrt(32)
#define NSPLIT 3         // attention column-split
#define CHUNK 192        // KTOP / NSPLIT

// ---------------- scratch (static device arrays; no allocation) ----------------
__device__ float g_xa  [B_*NN*C_];
__device__ float g_q   [BHN*NN*DH];
__device__ float g_k   [BHN*NN*DH];
__device__ float g_v   [BHN*NN*DH];
__device__ float g_spart[BHN*12*3*DH];
__device__ float g_sums[BHN*3*DH];        // [bh][qsum,ksum,vsum][d]
__device__ float g_rs  [BHN*NN];
__device__ float g_cs  [BHN*NN];
__device__ int   g_rowlist[BHN*KTOP];
__device__ int   g_collist[BHN*KTOP];
__device__ float g_vunk[BHN*DH];
__device__ float g_pm  [BHN*KTOP*NSPLIT];
__device__ float g_pz  [BHN*KTOP*NSPLIT];
__device__ float g_pacc[BHN*KTOP*NSPLIT*DH];
__device__ float g_o   [B_*NN*C_];
__device__ float g_xdw [C_*B_*NN];        // [c][b*NN+n]  (K-major => TRANSA gemm)
__device__ float g_xc  [B_*NN*C_];
__device__ float g_xs  [B_*NN*C_];
__device__ float g_t1  [B_*NN*GG];
__device__ float g_sg  [B_*NN];
__device__ float g_cgpart[B_*16*C_];
__device__ float g_cg  [B_*C_];
__device__ float g_x2  [B_*NN*C_];
__device__ __nv_bfloat16 g_ln2b[B_*NN*C_];
__device__ __nv_bfloat16 g_hb  [B_*NN*HID];
__device__ __nv_bfloat16 g_w1t [HID*C_];    // [N=1024][K=256]
__device__ __nv_bfloat16 g_w2t [C_*HID];    // [N=256][K=1024]

// ---------------- cp.async helpers ----------------
__device__ __forceinline__ void cp16(void* sptr, const void* gptr) {
    unsigned saddr = (unsigned)__cvta_generic_to_shared(sptr);
    asm volatile("cp.async.cg.shared.global [%0], [%1], 16;" :: "r"(saddr), "l"(gptr));
}
__device__ __forceinline__ void cp_commit() { asm volatile("cp.async.commit_group;"); }
__device__ __forceinline__ void cp_wait0()  { asm volatile("cp.async.wait_group 0;" ::: "memory"); }

__device__ __forceinline__ void mma_tf32(float* d, const unsigned* a,
                                         const unsigned* b, const float* c) {
    asm volatile("mma.sync.aligned.m16n8k8.row.col.f32.tf32.tf32.f32 "
        "{%0,%1,%2,%3}, {%4,%5,%6,%7}, {%8,%9}, {%10,%11,%12,%13};"
        : "=f"(d[0]),"=f"(d[1]),"=f"(d[2]),"=f"(d[3])
        : "r"(a[0]),"r"(a[1]),"r"(a[2]),"r"(a[3]),
          "r"(b[0]),"r"(b[1]),
          "f"(c[0]),"f"(c[1]),"f"(c[2]),"f"(c[3]));
}
__device__ __forceinline__ void mma_bf16(float* d, const unsigned* a,
                                         const unsigned* b, const float* c) {
    asm volatile("mma.sync.aligned.m16n8k16.row.col.f32.bf16.bf16.f32 "
        "{%0,%1,%2,%3}, {%4,%5,%6,%7}, {%8,%9}, {%10,%11,%12,%13};"
        : "=f"(d[0]),"=f"(d[1]),"=f"(d[2]),"=f"(d[3])
        : "r"(a[0]),"r"(a[1]),"r"(a[2]),"r"(a[3]),
          "r"(b[0]),"r"(b[1]),
          "f"(c[0]),"f"(c[1]),"f"(c[2]),"f"(c[3]));
}
__device__ __forceinline__ unsigned fbits(float f) { return __float_as_uint(f); }

// ---------------- tf32 tensor-core GEMM, cp.async double-buffered ----------------
// TA=false: A [M,K] row-major. TA=true: A [K,M] row-major.
// TB=false: B [K,N] row-major. TB=true: B [N,K] row-major.
// EPI: 0=plain 2=qkv-scatter 3=xs(add g_xc + bias -> C)
template<int BM, int BN, int WARPS_M, int WARPS_N, bool TA, bool TB, int EPI>
__global__ __launch_bounds__(WARPS_M*WARPS_N*32)
void gemm_tc(const float* __restrict__ A, const float* __restrict__ B,
             float* __restrict__ C, const float* __restrict__ bias,
             int M, int N, int K) {
    constexpr int BK = 16;
    constexpr int THREADS = WARPS_M*WARPS_N*32;
    constexpr int WM = BM/WARPS_M, WN = BN/WARPS_N;
    constexpr int MT = WM/16, NT = WN/8;
    constexpr int ASZ = TA ? BK*(BM+8) : BM*20;
    constexpr int BSZ = TB ? BN*20 : BK*(BN+8);

    __shared__ __align__(16) float As[2][ASZ];
    __shared__ __align__(16) float Bs[2][BSZ];

    const int bm = blockIdx.y*BM, bn = blockIdx.x*BN;
    const int tid = threadIdx.x;
    const int lane = tid & 31, wid = tid >> 5;
    const int wm = wid / WARPS_N, wn = wid % WARPS_N;
    const int g = lane >> 2, tig = lane & 3;

    float acc[MT][NT][4];
    #pragma unroll
    for (int i = 0; i < MT; i++)
        #pragma unroll
        for (int j = 0; j < NT; j++)
            #pragma unroll
            for (int l = 0; l < 4; l++) acc[i][j][l] = 0.f;

    auto copy_tile = [&](int st, int k0) {
        constexpr int PTA = (BM*4)/THREADS;
        #pragma unroll
        for (int i = 0; i < PTA; i++) {
            int ch = tid + i*THREADS;
            if (!TA) {
                int row = ch >> 2, c4 = (ch & 3)*4;
                cp16(&As[st][row*20 + c4], &A[(size_t)(bm+row)*K + k0 + c4]);
            } else {
                constexpr int MC = BM/4;
                int kr = ch / MC, mc = (ch % MC)*4;
                cp16(&As[st][kr*(BM+8) + mc], &A[(size_t)(k0+kr)*M + bm + mc]);
            }
        }
        constexpr int PTB = (BN*4)/THREADS;
        #pragma unroll
        for (int i = 0; i < PTB; i++) {
            int ch = tid + i*THREADS;
            if (!TB) {
                constexpr int NC = BN/4;
                int kr = ch / NC, nc = (ch % NC)*4;
                cp16(&Bs[st][kr*(BN+8) + nc], &B[(size_t)(k0+kr)*N + bn + nc]);
            } else {
                int row = ch >> 2, c4 = (ch & 3)*4;
                cp16(&Bs[st][row*20 + c4], &B[(size_t)(bn+row)*K + k0 + c4]);
            }
        }
    };

    copy_tile(0, 0);
    cp_commit();
    int stage = 0;
    for (int k0 = 0; k0 < K; k0 += BK) {
        cp_wait0();
        __syncthreads();
        if (k0 + BK < K) { copy_tile(stage^1, k0+BK); cp_commit(); }
        const float* as = As[stage];
        const float* bs = Bs[stage];
        #pragma unroll
        for (int ks = 0; ks < BK; ks += 8) {
            int kk = ks + tig;
            unsigned afr[MT][4];
            #pragma unroll
            for (int mt = 0; mt < MT; mt++) {
                int r0 = wm*WM + mt*16 + g;
                if (!TA) {
                    afr[mt][0] = fbits(as[(r0  )*20 + kk  ]);
                    afr[mt][1] = fbits(as[(r0+8)*20 + kk  ]);
                    afr[mt][2] = fbits(as[(r0  )*20 + kk+4]);
                    afr[mt][3] = fbits(as[(r0+8)*20 + kk+4]);
                } else {
                    afr[mt][0] = fbits(as[(kk  )*(BM+8) + r0  ]);
                    afr[mt][1] = fbits(as[(kk  )*(BM+8) + r0+8]);
                    afr[mt][2] = fbits(as[(kk+4)*(BM+8) + r0  ]);
                    afr[mt][3] = fbits(as[(kk+4)*(BM+8) + r0+8]);
                }
            }
            unsigned bfr[NT][2];
            #pragma unroll
            for (int nt = 0; nt < NT; nt++) {
                int c0 = wn*WN + nt*8 + g;
                if (!TB) {
                    bfr[nt][0] = fbits(bs[(kk  )*(BN+8) + c0]);
                    bfr[nt][1] = fbits(bs[(kk+4)*(BN+8) + c0]);
                } else {
                    bfr[nt][0] = fbits(bs[c0*20 + kk  ]);
                    bfr[nt][1] = fbits(bs[c0*20 + kk+4]);
                }
            }
            #pragma unroll
            for (int mt = 0; mt < MT; mt++)
                #pragma unroll
                for (int nt = 0; nt < NT; nt++)
                    mma_tf32(acc[mt][nt], afr[mt], bfr[nt], acc[mt][nt]);
        }
        stage ^= 1;
    }

    #pragma unroll
    for (int mt = 0; mt < MT; mt++) {
        int row0 = bm + wm*WM + mt*16 + g;
        #pragma unroll
        for (int nt = 0; nt < NT; nt++) {
            int col = bn + wn*WN + nt*8 + tig*2;
            #pragma unroll
            for (int half = 0; half < 2; half++) {
                int row = row0 + half*8;
                float v0 = acc[mt][nt][half*2], v1 = acc[mt][nt][half*2+1];
                if (EPI == 0) {
                    *(float2*)&C[(size_t)row*N + col] = make_float2(v0, v1);
                } else if (EPI == 2) {
                    int b = row / NN, n = row - b*NN;
                    int part = col >> 8, cc = col & 255;
                    int h = cc >> 5, d = cc & 31;
                    size_t dst = ((size_t)(b*NHEAD + h)*NN + n)*DH + d;
                    if (part == 0)
                        *(float2*)&g_q[dst] = make_float2(v0*QSCALE, v1*QSCALE);
                    else if (part == 1)
                        *(float2*)&g_k[dst] = make_float2(v0, v1);
                    else
                        *(float2*)&g_v[dst] = make_float2(v0, v1);
                } else { // EPI == 3
                    v0 += g_xc[(size_t)row*C_ + col]   + bias[col];
                    v1 += g_xc[(size_t)row*C_ + col+1] + bias[col+1];
                    *(float2*)&C[(size_t)row*N + col] = make_float2(v0, v1);
                }
            }
        }
    }
}

// ---------------- bf16 tensor-core GEMM (A [M,K] bf16, B [N,K] bf16) ----------------
// EPI: 1 = bias + gelu -> bf16 C.  4 = final: out = x2 + gamma2*(v + bias), NCHW f32.
template<int BM, int BN, int WARPS_M, int WARPS_N, int EPI>
__global__ __launch_bounds__(WARPS_M*WARPS_N*32)
void gemm_bf(const __nv_bfloat16* __restrict__ A, const __nv_bfloat16* __restrict__ B,
             void* __restrict__ Cout, const float* __restrict__ bias,
             const float* __restrict__ aux, int M, int N, int K) {
    constexpr int BK = 32;
    constexpr int THREADS = WARPS_M*WARPS_N*32;
    constexpr int WM = BM/WARPS_M, WN = BN/WARPS_N;
    constexpr int MT = WM/16, NT = WN/8;

    __shared__ __align__(16) __nv_bfloat16 As[2][BM*40];
    __shared__ __align__(16) __nv_bfloat16 Bs[2][BN*40];

    const int bm = blockIdx.y*BM, bn = blockIdx.x*BN;
    const int tid = threadIdx.x;
    const int lane = tid & 31, wid = tid >> 5;
    const int wm = wid / WARPS_N, wn = wid % WARPS_N;
    const int g = lane >> 2, tig = lane & 3;

    float acc[MT][NT][4];
    #pragma unroll
    for (int i = 0; i < MT; i++)
        #pragma unroll
        for (int j = 0; j < NT; j++)
            #pragma unroll
            for (int l = 0; l < 4; l++) acc[i][j][l] = 0.f;

    auto copy_tile = [&](int st, int k0) {
        constexpr int PTA = (BM*4)/THREADS;
        #pragma unroll
        for (int i = 0; i < PTA; i++) {
            int ch = tid + i*THREADS;
            int row = ch >> 2, c8 = (ch & 3)*8;
            cp16(&As[st][row*40 + c8], &A[(size_t)(bm+row)*K + k0 + c8]);
        }
        constexpr int PTB = (BN*4)/THREADS;
        #pragma unroll
        for (int i = 0; i < PTB; i++) {
            int ch = tid + i*THREADS;
            int row = ch >> 2, c8 = (ch & 3)*8;
            cp16(&Bs[st][row*40 + c8], &B[(size_t)(bn+row)*K + k0 + c8]);
        }
    };

    copy_tile(0, 0);
    cp_commit();
    int stage = 0;
    for (int k0 = 0; k0 < K; k0 += BK) {
        cp_wait0();
        __syncthreads();
        if (k0 + BK < K) { copy_tile(stage^1, k0+BK); cp_commit(); }
        const __nv_bfloat16* as = As[stage];
        const __nv_bfloat16* bs = Bs[stage];
        #pragma unroll
        for (int ks = 0; ks < BK; ks += 16) {
            int kk = ks + 2*tig;
            unsigned afr[MT][4];
            #pragma unroll
            for (int mt = 0; mt < MT; mt++) {
                int r0 = wm*WM + mt*16 + g;
                afr[mt][0] = *(const unsigned*)&as[(r0  )*40 + kk  ];
                afr[mt][1] = *(const unsigned*)&as[(r0+8)*40 + kk  ];
                afr[mt][2] = *(const unsigned*)&as[(r0  )*40 + kk+8];
                afr[mt][3] = *(const unsigned*)&as[(r0+8)*40 + kk+8];
            }
            unsigned bfr[NT][2];
            #pragma unroll
            for (int nt = 0; nt < NT; nt++) {
                int c0 = wn*WN + nt*8 + g;
                bfr[nt][0] = *(const unsigned*)&bs[c0*40 + kk  ];
                bfr[nt][1] = *(const unsigned*)&bs[c0*40 + kk+8];
            }
            #pragma unroll
            for (int mt = 0; mt < MT; mt++)
                #pragma unroll
                for (int nt = 0; nt < NT; nt++)
                    mma_bf16(acc[mt][nt], afr[mt], bfr[nt], acc[mt][nt]);
        }
        stage ^= 1;
    }

    #pragma unroll
    for (int mt = 0; mt < MT; mt++) {
        int row0 = bm + wm*WM + mt*16 + g;
        #pragma unroll
        for (int nt = 0; nt < NT; nt++) {
            int col = bn + wn*WN + nt*8 + tig*2;
            #pragma unroll
            for (int half = 0; half < 2; half++) {
                int row = row0 + half*8;
                float v0 = acc[mt][nt][half*2], v1 = acc[mt][nt][half*2+1];
                if (EPI == 1) {
                    v0 += bias[col]; v1 += bias[col+1];
                    v0 = 0.5f*v0*(1.0f + erff(v0*0.70710678118654752f));
                    v1 = 0.5f*v1*(1.0f + erff(v1*0.70710678118654752f));
                    __nv_bfloat162 p;
                    p.x = __float2bfloat16(v0); p.y = __float2bfloat16(v1);
                    *(__nv_bfloat162*)&((__nv_bfloat16*)Cout)[(size_t)row*N + col] = p;
                } else { // EPI == 4
                    int b = row / NN, n = row - b*NN;
                    float gm = aux[0];
                    float o0 = g_x2[(size_t)row*C_ + col]   + gm*(v0 + bias[col]);
                    float o1 = g_x2[(size_t)row*C_ + col+1] + gm*(v1 + bias[col+1]);
                    float* C = (float*)Cout;
                    C[(size_t)(b*C_ + col  )*NN + n] = o0;
                    C[(size_t)(b*C_ + col+1)*NN + n] = o1;
                }
            }
        }
    }
}

// ---------------- transpose + f32->bf16 convert: in [K][N] -> out [N][K] ----------------
__global__ __launch_bounds__(256) void tconv_k(const float* __restrict__ in,
                                               __nv_bfloat16* __restrict__ out,
                                               int K, int N) {
    __shared__ float tile[32][33];
    int nb = blockIdx.x*32, kb = blockIdx.y*32;
    int tx = threadIdx.x & 31, ty = threadIdx.x >> 5;
    #pragma unroll
    for (int i = 0; i < 32; i += 8)
        tile[ty+i][tx] = in[(size_t)(kb+ty+i)*N + nb+tx];
    __syncthreads();
    #pragma unroll
    for (int i = 0; i < 32; i += 8)
        out[(size_t)(nb+ty+i)*K + kb+tx] = __float2bfloat16(tile[tx][ty+i]);
}

// ---------------- LN1: NCHW -> normalized [B*N, C], tiled transpose ----------------
__global__ __launch_bounds__(256) void ln1_k(const float* __restrict__ x,
                                             const float* __restrict__ gg,
                                             const float* __restrict__ bb) {
    __shared__ float tile[C_*33];
    __shared__ float smu[32], sr[32];
    int blk = blockIdx.x;                  // B_*NN/32 = 144
    int b = blk / (NN/32);
    int n0 = (blk % (NN/32)) * 32;
    int tid = threadIdx.x;
    #pragma unroll
    for (int i = 0; i < 32; i++) {
        int idx = i*256 + tid;
        int c = idx >> 5, n = idx & 31;
        tile[c*33 + n] = x[(size_t)(b*C_ + c)*NN + n0 + n];
    }
    __syncthreads();
    int wid = tid >> 5, lane = tid & 31;
    #pragma unroll
    for (int j = 0; j < 4; j++) {
        int n = wid*4 + j;
        float s1 = 0, s2 = 0;
        #pragma unroll
        for (int i = 0; i < 8; i++) {
            float v = tile[(lane + i*32)*33 + n];
            s1 += v; s2 += v*v;
        }
        #pragma unroll
        for (int o = 16; o; o >>= 1) {
            s1 += __shfl_xor_sync(~0u, s1, o);
            s2 += __shfl_xor_sync(~0u, s2, o);
        }
        if (lane == 0) {
            float mu = s1*(1.0f/C_);
            float var = s2*(1.0f/C_) - mu*mu;
            smu[n] = mu; sr[n] = rsqrtf(var + 1e-6f);
        }
    }
    __syncthreads();
    #pragma unroll
    for (int i = 0; i < 32; i++) {
        int idx = i*256 + tid;
        int n = idx >> 8, c = idx & 255;
        float v = tile[c*33 + n];
        g_xa[(size_t)(b*NN + n0 + n)*C_ + c] = (v - smu[n])*sr[n]*gg[c] + bb[c];
    }
}

// ---------------- LN2: warp per row over g_x2 -> bf16 ----------------
__global__ void ln2_k(const float* __restrict__ gg, const float* __restrict__ bb) {
    int row = (blockIdx.x*256 + threadIdx.x) >> 5;
    int lane = threadIdx.x & 31;
    const float* p = &g_x2[(size_t)row*C_];
    float v[8]; float s1 = 0, s2 = 0;
    #pragma unroll
    for (int i = 0; i < 8; i++) { v[i] = p[lane + i*32]; s1 += v[i]; s2 += v[i]*v[i]; }
    #pragma unroll
    for (int o = 16; o; o >>= 1) {
        s1 += __shfl_xor_sync(~0u, s1, o);
        s2 += __shfl_xor_sync(~0u, s2, o);
    }
    float mu = s1*(1.0f/C_);
    float var = s2*(1.0f/C_) - mu*mu;
    float r = rsqrtf(var + 1e-6f);
    #pragma unroll
    for (int i = 0; i < 8; i++) {
        int c = lane + i*32;
        g_ln2b[(size_t)row*C_ + c] = __float2bfloat16((v[i]-mu)*r*gg[c] + bb[c]);
    }
}

// ---------------- per-(b,h) partial sums of q,k,v ----------------
__global__ void bh_sums1_k() {
    int bh = blockIdx.x, yy = blockIdx.y;     // 16 x 12
    int t = threadIdx.x;                      // 256
    int d = t & 31, part = t >> 5;            // 8 parts x 24 rows
    float sq = 0, sk = 0, sv = 0;
    int n0 = yy*192 + part*24;
    for (int j = 0; j < 24; j++) {
        int idx = (bh*NN + n0 + j)*DH + d;
        sq += g_q[idx]; sk += g_k[idx]; sv += g_v[idx];
    }
    __shared__ float sh[3][8][32];
    sh[0][part][d]=sq; sh[1][part][d]=sk; sh[2][part][d]=sv;
    __syncthreads();
    if (t < 96) {
        int which = t >> 5, dd = t & 31;
        float s = 0;
        #pragma unroll
        for (int p = 0; p < 8; p++) s += sh[which][p][dd];
        g_spart[((bh*12 + yy)*3 + which)*DH + dd] = s;
    }
}

// ---------------- reduce partials + row/col pruning scores (merged) ----------------
__global__ void scores_k() {
    int bh = blockIdx.x, yy = blockIdx.y;      // 16 x 9
    int t = threadIdx.x;                       // 256
    __shared__ float qs[DH], ks[DH];
    if (t < 96) {
        int which = t >> 5, d = t & 31;
        float s = 0;
        #pragma unroll
        for (int y = 0; y < 12; y++) s += g_spart[((bh*12 + y)*3 + which)*DH + d];
        if (which == 0) qs[d] = s;
        else if (which == 1) ks[d] = s;
        if (yy == 0) g_sums[(bh*3 + which)*DH + d] = s;
    }
    __syncthreads();
    int gid = bh*NN + yy*256 + t;
    float r = 0, c = 0;
    const float4* qp = (const float4*)&g_q[(size_t)gid*DH];
    const float4* kp = (const float4*)&g_k[(size_t)gid*DH];
    #pragma unroll
    for (int w = 0; w < 8; w++) {
        float4 qf = qp[w], kf = kp[w];
        r += qf.x*ks[4*w] + qf.y*ks[4*w+1] + qf.z*ks[4*w+2] + qf.w*ks[4*w+3];
        c += qs[4*w]*kf.x + qs[4*w+1]*kf.y + qs[4*w+2]*kf.z + qs[4*w+3]*kf.w;
    }
    g_rs[gid] = r; g_cs[gid] = c;
}

// ---------------- exact top-k selection (radix select + stable compaction) ----------------
__device__ __forceinline__ unsigned f2key(float f) {
    unsigned u = __float_as_uint(f);
    return (u & 0x80000000u) ? ~u : (u | 0x80000000u);
}

__global__ void select_k() {
    int blk = blockIdx.x;          // 0..31
    int type = blk >> 4, bh = blk & 15;
    const float* s = (type == 0 ? g_rs : g_cs) + bh*NN;
    int* list = (type == 0 ? g_rowlist : g_collist) + bh*KTOP;
    __shared__ unsigned keys[NN];
    __shared__ int hist[256];
    __shared__ int scan[256];
    __shared__ unsigned sh_T;
    __shared__ int sh_take;
    int t = threadIdx.x;           // 256
    for (int i = t; i < NN; i += 256) keys[i] = f2key(s[i]);
    __syncthreads();

    unsigned prefix = 0, pmask = 0;
    int kneed = KTOP;
    for (int pass = 0; pass < 4; pass++) {
        int shift = 24 - 8*pass;
        hist[t] = 0;
        __syncthreads();
        for (int i = t; i < NN; i += 256) {
            unsigned u = keys[i];
            if ((u & pmask) == prefix) atomicAdd(&hist[(u >> shift) & 255], 1);
        }
        __syncthreads();
        if (t == 0) {
            int run = 0, b = 255;
            for (; b >= 0; b--) {
                int h = hist[b];
                if (run + h >= kneed) break;
                run += h;
            }
            sh_T = prefix | ((unsigned)b << shift);
            sh_take = kneed - run;
        }
        __syncthreads();
        prefix = sh_T;
        kneed = sh_take;
        pmask |= (0xffu << shift);
        __syncthreads();
    }
    unsigned T = prefix;
    int take = kneed;

    unsigned myk[9];
    int eqc = 0;
    #pragma unroll
    for (int j = 0; j < 9; j++) {
        myk[j] = keys[t*9 + j];
        eqc += (myk[j] == T);
    }
    scan[t] = eqc; __syncthreads();
    for (int st = 1; st < 256; st <<= 1) {
        int tmp = (t >= st) ? scan[t-st] : 0;
        __syncthreads();
        scan[t] += tmp;
        __syncthreads();
    }
    int eqbase = scan[t] - eqc;
    __syncthreads();

    bool kept[9];
    int keptc = 0, eqseen = 0;
    #pragma unroll
    for (int j = 0; j < 9; j++) {
        unsigned u = myk[j];
        bool gt = (u > T), eq = (u == T);
        bool kp = gt || (eq && (eqbase + eqseen) < take);
        if (eq) eqseen++;
        kept[j] = kp; keptc += kp;
    }
    scan[t] = keptc; __syncthreads();
    for (int st = 1; st < 256; st <<= 1) {
        int tmp = (t >= st) ? scan[t-st] : 0;
        __syncthreads();
        scan[t] += tmp;
        __syncthreads();
    }
    int wbase = scan[t] - keptc;
    #pragma unroll
    for (int j = 0; j < 9; j++)
        if (kept[j]) list[wbase++] = t*9 + j;
}

// ---------------- v_unkept = vsum - sum over kept cols ----------------
__global__ void vunkept_k() {
    int bh = blockIdx.x;
    int t = threadIdx.x;
    int d = t & 31, part = t >> 5;
    float sv = 0;
    for (int jj = part; jj < KTOP; jj += 8) {
        int j = g_collist[bh*KTOP + jj];
        sv += g_v[(bh*NN + j)*DH + d];
    }
    __shared__ float sh[8][32];
    sh[part][d] = sv;
    __syncthreads();
    if (t < 32) {
        float s = 0;
        #pragma unroll
        for (int p = 0; p < 8; p++) s += sh[p][t];
        g_vunk[bh*DH + t] = g_sums[(bh*3+2)*DH + t] - s;
    }
}

// ---------------- pruned rows: uniform softmax -> mean(v) ----------------
__global__ void fill_o_k() {
    int gid = blockIdx.x*256 + threadIdx.x;
    if (gid >= BHN*NN*DH) return;
    int bh = gid / (NN*DH);
    int r = gid % (NN*DH);
    int n = r / DH, d = r & 31;
    int b = bh >> 3, h = bh & 7;
    g_o[(size_t)(b*NN + n)*C_ + h*DH + d] = g_sums[(bh*3+2)*DH + d] * (1.0f/NN);
}

// ---------------- kept-row attention partials over a column chunk ----------------
__global__ __launch_bounds__(64) void attn_part_k() {
    int bh = blockIdx.x;
    int t = threadIdx.x;                      // 64
    int slot = blockIdx.y*64 + t;             // 0..575
    int chunk = blockIdx.z;                   // 0..2
    int i = g_rowlist[bh*KTOP + slot];

    float qr[DH];
    const float4* qp = (const float4*)&g_q[(size_t)(bh*NN + i)*DH];
    #pragma unroll
    for (int w = 0; w < 8; w++) {
        float4 f = qp[w];
        qr[4*w]=f.x; qr[4*w+1]=f.y; qr[4*w+2]=f.z; qr[4*w+3]=f.w;
    }

    float m = -3.0e38f, Z = 0.f;
    float acc[DH];
    #pragma unroll
    for (int d = 0; d < DH; d++) acc[d] = 0.f;

    __shared__ int cj[96];
    __shared__ float Kc[96][DH];
    __shared__ float Vc[96][DH];

    for (int c0 = chunk*CHUNK; c0 < chunk*CHUNK + CHUNK; c0 += 96) {
        __syncthreads();
        for (int jj = t; jj < 96; jj += 64) cj[jj] = g_collist[bh*KTOP + c0 + jj];
        __syncthreads();
        for (int idx = t; idx < 96*DH; idx += 64) {
            int jj = idx >> 5, d = idx & 31;
            int base = (bh*NN + cj[jj])*DH + d;
            Kc[jj][d] = g_k[base];
            Vc[jj][d] = g_v[base];
        }
        __syncthreads();
        #pragma unroll 2
        for (int jj = 0; jj < 96; jj++) {
            float s0=0,s1=0,s2=0,s3=0;
            #pragma unroll
            for (int d = 0; d < DH; d += 4) {
                s0 += qr[d+0]*Kc[jj][d+0];
                s1 += qr[d+1]*Kc[jj][d+1];
                s2 += qr[d+2]*Kc[jj][d+2];
                s3 += qr[d+3]*Kc[jj][d+3];
            }
            float s = (s0+s1) + (s2+s3);
            if (s > m) {
                float cf = __expf(m - s);
                Z = Z*cf + 1.f;
                #pragma unroll
                for (int d = 0; d < DH; d++) acc[d] = acc[d]*cf + Vc[jj][d];
                m = s;
            } else {
                float e = __expf(s - m);
                Z += e;
                #pragma unroll
                for (int d = 0; d < DH; d++) acc[d] += e*Vc[jj][d];
            }
        }
    }
    int pidx = (bh*KTOP + slot)*NSPLIT + chunk;
    g_pm[pidx] = m;
    g_pz[pidx] = Z;
    float* pa = &g_pacc[(size_t)pidx*DH];
    #pragma unroll
    for (int d = 0; d < DH; d++) pa[d] = acc[d];
}

// ---------------- combine partials + zero-column correction ----------------
__global__ void attn_comb_k() {
    int gid = blockIdx.x*128 + threadIdx.x;
    if (gid >= BHN*KTOP) return;
    int bh = gid / KTOP, slot = gid % KTOP;
    int i = g_rowlist[bh*KTOP + slot];
    int p0 = gid*NSPLIT;
    float m0 = g_pm[p0], m1 = g_pm[p0+1], m2 = g_pm[p0+2];
    float mstar = fmaxf(0.f, fmaxf(m0, fmaxf(m1, m2)));
    float e0 = __expf(m0 - mstar), e1 = __expf(m1 - mstar), e2 = __expf(m2 - mstar);
    float ez = __expf(-mstar);
    float Z = g_pz[p0]*e0 + g_pz[p0+1]*e1 + g_pz[p0+2]*e2 + (float)(NN - KTOP)*ez;
    float invZ = 1.f / Z;
    const float* a0 = &g_pacc[(size_t)p0*DH];
    const float* a1 = &g_pacc[(size_t)(p0+1)*DH];
    const float* a2 = &g_pacc[(size_t)(p0+2)*DH];
    const float* vu = &g_vunk[bh*DH];
    int b = bh >> 3, h = bh & 7;
    float* op = &g_o[(size_t)(b*NN + i)*C_ + h*DH];
    #pragma unroll
    for (int d = 0; d < DH; d++)
        op[d] = (a0[d]*e0 + a1[d]*e1 + a2[d]*e2 + ez*vu[d]) * invZ;
}

// ---------------- depthwise 3x3 conv (writes [C][B*NN]) ----------------
__global__ void dw_k(const float* __restrict__ x,
                     const float* __restrict__ w,
                     const float* __restrict__ bias) {
    int gid = blockIdx.x*256 + threadIdx.x;
    if (gid >= B_*C_*NN) return;
    int n = gid % NN;
    int bc = gid / NN;
    int c = bc % C_, b = bc / C_;
    int y = n / WW, x0 = n % WW;
    float acc = bias[c];
    const float* xp = &x[(size_t)(b*C_ + c)*NN];
    const float* wp = &w[c*9];
    #pragma unroll
    for (int dy = 0; dy < 3; dy++) {
        int yy = y + dy - 1;
        if (yy < 0 || yy >= HH) continue;
        #pragma unroll
        for (int dx = 0; dx < 3; dx++) {
            int xx = x0 + dx - 1;
            if (xx < 0 || xx >= WW) continue;
            acc += xp[yy*WW + xx] * wp[dy*3 + dx];
        }
    }
    g_xdw[(size_t)c*(B_*NN) + b*NN + n] = acc;
}

// ---------------- spatial gate stage 1: 1x1 conv C->32 + silu ----------------
__global__ __launch_bounds__(256) void sg1_k(const float* __restrict__ w,
                                             const float* __restrict__ bias) {
    __shared__ float ws[C_*33];        // [ci][go] padded to 33 -> conflict-free
    __shared__ float rows[8][C_];
    int tid = threadIdx.x;
    for (int i = tid; i < GG*C_; i += 256) {
        int go = i >> 8, ci = i & 255;
        ws[ci*33 + go] = w[go*C_ + ci];
    }
    int bn0 = blockIdx.x * 8;          // 8 pixels per block
    for (int i = tid; i < 8*C_; i += 256)
        rows[i >> 8][i & 255] = g_xs[(size_t)(bn0 + (i >> 8))*C_ + (i & 255)];
    __syncthreads();
    int px = tid >> 5, go = tid & 31;
    float acc = bias[go];
    #pragma unroll 4
    for (int ci = 0; ci < C_; ci++)
        acc += rows[px][ci] * ws[ci*33 + go];
    g_t1[(bn0 + px)*GG + go] = acc / (1.f + expf(-acc));
}

// ---------------- spatial gate stage 2: 7x7 conv 32->1 + sigmoid (warp/pixel) ----------------
__global__ __launch_bounds__(256) void sg2_k(const float* __restrict__ w,
                                             const float* __restrict__ bias) {
    __shared__ float ws[GG*49];
    int tid = threadIdx.x;
    for (int i = tid; i < GG*49; i += 256) ws[i] = w[i];
    __syncthreads();
    int p = blockIdx.x*8 + (tid >> 5);     // pixel index
    int lane = tid & 31;
    int b = p / NN, n = p % NN;
    int y = n / WW, x0 = n % WW;
    float acc = 0.f;
    for (int ky = 0; ky < 7; ky++) {
        int yy = y + ky - 3;
        if (yy < 0 || yy >= HH) continue;
        #pragma unroll
        for (int kx = 0; kx < 7; kx++) {
            int xx = x0 + kx - 3;
            if (xx < 0 || xx >= WW) continue;
            acc += g_t1[(b*NN + yy*WW + xx)*GG + lane] * ws[lane*49 + ky*7 + kx];
        }
    }
    #pragma unroll
    for (int o = 16; o; o >>= 1) acc += __shfl_xor_sync(~0u, acc, o);
    if (lane == 0) g_sg[p] = 1.f / (1.f + expf(-(acc + bias[0])));
}

// ---------------- channel gate: pool partials ----------------
__global__ void cgpool_k() {
    int blk = blockIdx.x;            // b*16 + part
    int b = blk / 16, part = blk % 16;
    int c = threadIdx.x;             // 256
    float s = 0;
    int n0 = part*144;
    for (int n = n0; n < n0 + 144; n++) s += g_xs[(size_t)(b*NN + n)*C_ + c];
    g_cgpart[blk*C_ + c] = s;
}

// ---------------- channel gate: combine + silu + sigmoid ----------------
__global__ void cggate_k(const float* __restrict__ w1, const float* __restrict__ b1,
                         const float* __restrict__ w2, const float* __restrict__ b2) {
    int b = blockIdx.x;
    int c = threadIdx.x;
    __shared__ float cgm[C_];
    __shared__ float t2[GG];
    float s = 0;
    for (int p = 0; p < 16; p++) s += g_cgpart[(b*16 + p)*C_ + c];
    cgm[c] = s * (1.0f/NN);
    __syncthreads();
    if (c < GG) {
        float a = b1[c];
        const float* wp = &w1[c*C_];
        for (int ci = 0; ci < C_; ci++) a += cgm[ci]*wp[ci];
        t2[c] = a / (1.f + expf(-a));
    }
    __syncthreads();
    float a2 = b2[c];
    const float* wp2 = &w2[c*GG];
    #pragma unroll
    for (int g = 0; g < GG; g++) a2 += t2[g]*wp2[g];
    g_cg[b*C_ + c] = 1.f / (1.f + expf(-a2));
}

// ---------------- x2 = x + gamma1*xs*sg*cg, tiled transpose ----------------
__global__ __launch_bounds__(256) void x2_k(const float* __restrict__ x,
                                            const float* __restrict__ gamma1) {
    __shared__ float tile[C_*33];
    int blk = blockIdx.x;               // 144
    int b = blk / (NN/32);
    int n0 = (blk % (NN/32)) * 32;
    int tid = threadIdx.x;
    #pragma unroll
    for (int i = 0; i < 32; i++) {
        int idx = i*256 + tid;
        int c = idx >> 5, n = idx & 31;
        tile[c*33 + n] = x[(size_t)(b*C_ + c)*NN + n0 + n];
    }
    __syncthreads();
    float gm = gamma1[0];
    #pragma unroll
    for (int i = 0; i < 32; i++) {
        int idx = i*256 + tid;
        int n = idx >> 8, c = idx & 255;
        int row = b*NN + n0 + n;
        g_x2[(size_t)row*C_ + c] =
            tile[c*33 + n] + gm * g_xs[(size_t)row*C_ + c] * g_sg[row] * g_cg[b*C_ + c];
    }
}

// ---------------- host ----------------
#define GETSYM(p, s, T) do { void* _t; cudaGetSymbolAddress(&_t, s); p = (T*)_t; } while (0)

extern "C" void kernel_launch(void* const* d_in, const int* in_sizes, int n_in,
                              void* d_out, int out_size) {
    const float* x     = (const float*)d_in[0];
    const float* qkv_w = (const float*)d_in[1];
    const float* out_w = (const float*)d_in[2];
    const float* ln1_g = (const float*)d_in[3];
    const float* ln1_b = (const float*)d_in[4];
    const float* ln2_g = (const float*)d_in[5];
    const float* ln2_b = (const float*)d_in[6];
    const float* dw_w  = (const float*)d_in[7];
    const float* dw_b  = (const float*)d_in[8];
    const float* pw_w  = (const float*)d_in[9];
    const float* pw_b  = (const float*)d_in[10];
    const float* sg1_w = (const float*)d_in[11];
    const float* sg1_b = (const float*)d_in[12];
    const float* sg2_w = (const float*)d_in[13];
    const float* sg2_b = (const float*)d_in[14];
    const float* cg1_w = (const float*)d_in[15];
    const float* cg1_b = (const float*)d_in[16];
    const float* cg2_w = (const float*)d_in[17];
    const float* cg2_b = (const float*)d_in[18];
    const float* ff_w1 = (const float*)d_in[19];
    const float* ff_b1 = (const float*)d_in[20];
    const float* ff_w2 = (const float*)d_in[21];
    const float* ff_b2 = (const float*)d_in[22];
    const float* gamma1= (const float*)d_in[23];
    const float* gamma2= (const float*)d_in[24];
    float* out = (float*)d_out;
    (void)in_sizes; (void)n_in; (void)out_size;

    float *p_xa, *p_o, *p_xdw, *p_xc, *p_xs;
    __nv_bfloat16 *p_ln2b, *p_hb, *p_w1t, *p_w2t;
    GETSYM(p_xa, g_xa, float); GETSYM(p_o, g_o, float);
    GETSYM(p_xdw, g_xdw, float); GETSYM(p_xc, g_xc, float); GETSYM(p_xs, g_xs, float);
    GETSYM(p_ln2b, g_ln2b, __nv_bfloat16); GETSYM(p_hb, g_hb, __nv_bfloat16);
    GETSYM(p_w1t, g_w1t, __nv_bfloat16); GETSYM(p_w2t, g_w2t, __nv_bfloat16);

    const int M = B_*NN;   // 4608

    // 0-2: independent prep (conv branch first so QKV gemm lands at profiled idx 3)
    ln1_k<<<B_*NN/32, 256>>>(x, ln1_g, ln1_b);
    dw_k<<<(B_*C_*NN)/256, 256>>>(x, dw_w, dw_b);
    gemm_tc<128,64,2,2,true,true,0><<<dim3(C_/64, M/128), 128>>>(
        p_xdw, pw_w, p_xc, nullptr, M, C_, C_);
    // 3: QKV gemm  <-- ncu profiles this launch
    gemm_tc<128,128,2,4,false,false,2><<<dim3(768/128, M/128), 256>>>(
        p_xa, qkv_w, nullptr, nullptr, M, 3*C_, C_);
    // attention stats + selection
    bh_sums1_k<<<dim3(BHN, 12), 256>>>();
    scores_k<<<dim3(BHN, 9), 256>>>();
    select_k<<<32, 256>>>();
    vunkept_k<<<BHN, 256>>>();
    fill_o_k<<<(BHN*NN*DH)/256, 256>>>();
    attn_part_k<<<dim3(BHN, 9, NSPLIT), 64>>>();
    attn_comb_k<<<(BHN*KTOP + 127)/128, 128>>>();
    // out-proj epilogue: xs = o@out_w + xc + pw_b
    gemm_tc<128,64,2,2,false,false,3><<<dim3(C_/64, M/128), 128>>>(
        p_o, out_w, p_xs, pw_b, M, C_, C_);

    // gates
    sg1_k<<<B_*NN/8, 256>>>(sg1_w, sg1_b);
    sg2_k<<<B_*NN/8, 256>>>(sg2_w, sg2_b);
    cgpool_k<<<B_*16, 256>>>();
    cggate_k<<<B_, 256>>>(cg1_w, cg1_b, cg2_w, cg2_b);
    x2_k<<<B_*NN/32, 256>>>(x, gamma1);

    // FFN (bf16)
    ln2_k<<<M/8, 256>>>(ln2_g, ln2_b);
    tconv_k<<<dim3(HID/32, C_/32), 256>>>(ff_w1, p_w1t, C_, HID);   // [256][1024]->[1024][256]
    tconv_k<<<dim3(C_/32, HID/32), 256>>>(ff_w2, p_w2t, HID, C_);   // [1024][256]->[256][1024]
    gemm_bf<128,128,2,4,1><<<dim3(HID/128, M/128), 256>>>(
        p_ln2b, p_w1t, p_hb, ff_b1, nullptr, M, HID, C_);
    gemm_bf<128,64,2,2,4><<<dim3(C_/64, M/128), 128>>>(
        p_hb, p_w2t, out, ff_b2, gamma2, M, C_, HID);
}

// round 10
// speedup vs baseline: 3.1759x; 1.4299x over previous
#include <cuda_runtime.h>
#include <cuda_bf16.h>
#include <math.h>

#define B_ 2
#define C_ 256
#define HH 48
#define WW 48
#define NN 2304          // 48*48
#define NHEAD 8
#define DH 32
#define BHN 16           // B_*NHEAD
#define KTOP 576
#define HID 1024
#define GG 32            // C/8 gate channels
#define QSCALE 0.17677669529663687f   // 1/sqrt(32)
#define NSPLIT 3         // attention column-split
#define CHUNK 192        // KTOP / NSPLIT

// ---------------- scratch (static device arrays; no allocation) ----------------
__device__ float g_xa  [B_*NN*C_];
__device__ float g_q   [BHN*NN*DH];
__device__ float g_k   [BHN*NN*DH];
__device__ float g_v   [BHN*NN*DH];
__device__ float g_spart[BHN*12*3*DH];
__device__ float g_sums[BHN*3*DH];        // [bh][qsum,ksum,vsum][d]
__device__ float g_rs  [BHN*NN];
__device__ float g_cs  [BHN*NN];
__device__ int   g_rowlist[BHN*KTOP];
__device__ int   g_collist[BHN*KTOP];
__device__ float g_vunk[BHN*DH];
__device__ float g_pm  [BHN*KTOP*NSPLIT];
__device__ float g_pz  [BHN*KTOP*NSPLIT];
__device__ float g_pacc[BHN*KTOP*NSPLIT*DH];
__device__ float g_o   [B_*NN*C_];
__device__ float g_xdw [C_*B_*NN];        // [c][b*NN+n]  (K-major => TRANSA gemm)
__device__ float g_xc  [B_*NN*C_];
__device__ float g_xs  [B_*NN*C_];
__device__ float g_t1  [B_*NN*GG];
__device__ float g_sg  [B_*NN];
__device__ float g_cgpart[B_*16*C_];
__device__ float g_cg  [B_*C_];
__device__ float g_x2  [B_*NN*C_];
__device__ __nv_bfloat16 g_ln2b[B_*NN*C_];
__device__ __nv_bfloat16 g_hb  [B_*NN*HID];
__device__ __nv_bfloat16 g_w1t [HID*C_];    // [N=1024][K=256]
__device__ __nv_bfloat16 g_w2t [C_*HID];    // [N=256][K=1024]

// ---------------- cp.async helpers ----------------
__device__ __forceinline__ void cp16(void* sptr, const void* gptr) {
    unsigned saddr = (unsigned)__cvta_generic_to_shared(sptr);
    asm volatile("cp.async.cg.shared.global [%0], [%1], 16;" :: "r"(saddr), "l"(gptr));
}
__device__ __forceinline__ void cp_commit() { asm volatile("cp.async.commit_group;"); }
__device__ __forceinline__ void cp_wait0()  { asm volatile("cp.async.wait_group 0;" ::: "memory"); }

__device__ __forceinline__ void mma_tf32(float* d, const unsigned* a,
                                         const unsigned* b, const float* c) {
    asm volatile("mma.sync.aligned.m16n8k8.row.col.f32.tf32.tf32.f32 "
        "{%0,%1,%2,%3}, {%4,%5,%6,%7}, {%8,%9}, {%10,%11,%12,%13};"
        : "=f"(d[0]),"=f"(d[1]),"=f"(d[2]),"=f"(d[3])
        : "r"(a[0]),"r"(a[1]),"r"(a[2]),"r"(a[3]),
          "r"(b[0]),"r"(b[1]),
          "f"(c[0]),"f"(c[1]),"f"(c[2]),"f"(c[3]));
}
__device__ __forceinline__ void mma_bf16(float* d, const unsigned* a,
                                         const unsigned* b, const float* c) {
    asm volatile("mma.sync.aligned.m16n8k16.row.col.f32.bf16.bf16.f32 "
        "{%0,%1,%2,%3}, {%4,%5,%6,%7}, {%8,%9}, {%10,%11,%12,%13};"
        : "=f"(d[0]),"=f"(d[1]),"=f"(d[2]),"=f"(d[3])
        : "r"(a[0]),"r"(a[1]),"r"(a[2]),"r"(a[3]),
          "r"(b[0]),"r"(b[1]),
          "f"(c[0]),"f"(c[1]),"f"(c[2]),"f"(c[3]));
}
__device__ __forceinline__ unsigned fbits(float f) { return __float_as_uint(f); }

// ---------------- tf32 tensor-core GEMM, BK=8, 2-stage, 2 blocks/SM ----------------
// TA=false: A [M,K] row-major. TA=true: A [K,M] row-major.
// TB=false: B [K,N] row-major. TB=true: B [N,K] row-major.
// BM=128 fixed. 256 threads, warps 2x4.
// EPI: 0=plain 2=qkv-scatter 3=xs(add g_xc + bias -> C)
template<int BM, int BN, bool TA, bool TB, int EPI>
__global__ __launch_bounds__(256, 2)
void gemm_tc(const float* __restrict__ A, const float* __restrict__ B,
             float* __restrict__ C, const float* __restrict__ bias,
             int M, int N, int K) {
    constexpr int BK = 8;
    constexpr int WM = BM/2, WN = BN/4;
    constexpr int MT = WM/16, NT = WN/8;
    constexpr int ASZ = TA ? BK*(BM+8) : BM*12;
    constexpr int BSZ = TB ? BN*12 : BK*(BN+8);

    __shared__ __align__(16) float As[2][ASZ];
    __shared__ __align__(16) float Bs[2][BSZ];

    const int bm = blockIdx.y*BM, bn = blockIdx.x*BN;
    const int tid = threadIdx.x;
    const int lane = tid & 31, wid = tid >> 5;
    const int wm = wid >> 2, wn = wid & 3;
    const int g = lane >> 2, tig = lane & 3;

    float acc[MT][NT][4];
    #pragma unroll
    for (int i = 0; i < MT; i++)
        #pragma unroll
        for (int j = 0; j < NT; j++)
            #pragma unroll
            for (int l = 0; l < 4; l++) acc[i][j][l] = 0.f;

    auto copy_tile = [&](int st, int k0) {
        // A: BM*BK/4 = 256 chunks
        {
            int ch = tid;
            if (!TA) {
                int row = ch >> 1, c4 = (ch & 1)*4;
                cp16(&As[st][row*12 + c4], &A[(size_t)(bm+row)*K + k0 + c4]);
            } else {
                int kr = ch >> 5, mc = (ch & 31)*4;
                cp16(&As[st][kr*(BM+8) + mc], &A[(size_t)(k0+kr)*M + bm + mc]);
            }
        }
        // B: BN*BK/4 chunks (256 or 128)
        {
            constexpr int CB = BN*BK/4;
            int ch = tid;
            if (CB == 256 || ch < CB) {
                if (!TB) {
                    constexpr int NC = BN/4;
                    int kr = ch / NC, nc = (ch % NC)*4;
                    cp16(&Bs[st][kr*(BN+8) + nc], &B[(size_t)(k0+kr)*N + bn + nc]);
                } else {
                    int row = ch >> 1, c4 = (ch & 1)*4;
                    cp16(&Bs[st][row*12 + c4], &B[(size_t)(bn+row)*K + k0 + c4]);
                }
            }
        }
    };

    copy_tile(0, 0);
    cp_commit();
    int stage = 0;
    for (int k0 = 0; k0 < K; k0 += BK) {
        cp_wait0();
        __syncthreads();
        if (k0 + BK < K) { copy_tile(stage^1, k0+BK); cp_commit(); }
        const float* as = As[stage];
        const float* bs = Bs[stage];
        int kk = tig;
        unsigned afr[MT][4];
        #pragma unroll
        for (int mt = 0; mt < MT; mt++) {
            int r0 = wm*WM + mt*16 + g;
            if (!TA) {
                afr[mt][0] = fbits(as[(r0  )*12 + kk  ]);
                afr[mt][1] = fbits(as[(r0+8)*12 + kk  ]);
                afr[mt][2] = fbits(as[(r0  )*12 + kk+4]);
                afr[mt][3] = fbits(as[(r0+8)*12 + kk+4]);
            } else {
                afr[mt][0] = fbits(as[(kk  )*(BM+8) + r0  ]);
                afr[mt][1] = fbits(as[(kk  )*(BM+8) + r0+8]);
                afr[mt][2] = fbits(as[(kk+4)*(BM+8) + r0  ]);
                afr[mt][3] = fbits(as[(kk+4)*(BM+8) + r0+8]);
            }
        }
        unsigned bfr[NT][2];
        #pragma unroll
        for (int nt = 0; nt < NT; nt++) {
            int c0 = wn*WN + nt*8 + g;
            if (!TB) {
                bfr[nt][0] = fbits(bs[(kk  )*(BN+8) + c0]);
                bfr[nt][1] = fbits(bs[(kk+4)*(BN+8) + c0]);
            } else {
                bfr[nt][0] = fbits(bs[c0*12 + kk  ]);
                bfr[nt][1] = fbits(bs[c0*12 + kk+4]);
            }
        }
        #pragma unroll
        for (int mt = 0; mt < MT; mt++)
            #pragma unroll
            for (int nt = 0; nt < NT; nt++)
                mma_tf32(acc[mt][nt], afr[mt], bfr[nt], acc[mt][nt]);
        stage ^= 1;
    }

    #pragma unroll
    for (int mt = 0; mt < MT; mt++) {
        int row0 = bm + wm*WM + mt*16 + g;
        #pragma unroll
        for (int nt = 0; nt < NT; nt++) {
            int col = bn + wn*WN + nt*8 + tig*2;
            #pragma unroll
            for (int half = 0; half < 2; half++) {
                int row = row0 + half*8;
                float v0 = acc[mt][nt][half*2], v1 = acc[mt][nt][half*2+1];
                if (EPI == 0) {
                    *(float2*)&C[(size_t)row*N + col] = make_float2(v0, v1);
                } else if (EPI == 2) {
                    int b = row / NN, n = row - b*NN;
                    int part = col >> 8, cc = col & 255;
                    int h = cc >> 5, d = cc & 31;
                    size_t dst = ((size_t)(b*NHEAD + h)*NN + n)*DH + d;
                    if (part == 0)
                        *(float2*)&g_q[dst] = make_float2(v0*QSCALE, v1*QSCALE);
                    else if (part == 1)
                        *(float2*)&g_k[dst] = make_float2(v0, v1);
                    else
                        *(float2*)&g_v[dst] = make_float2(v0, v1);
                } else { // EPI == 3
                    v0 += g_xc[(size_t)row*C_ + col]   + bias[col];
                    v1 += g_xc[(size_t)row*C_ + col+1] + bias[col+1];
                    *(float2*)&C[(size_t)row*N + col] = make_float2(v0, v1);
                }
            }
        }
    }
}

// ---------------- bf16 tensor-core GEMM (A [M,K] bf16, B [N,K] bf16), BK=16 ----------------
// smem stride 24 bf16 = 48 bytes (multiple of 16 for cp.async alignment).
// BM=128 fixed, 256 threads, warps 2x4.
// EPI: 1 = bias + gelu -> bf16 C.  4 = final: out = x2 + gamma2*(v + bias), NCHW f32.
template<int BM, int BN, int EPI>
__global__ __launch_bounds__(256, 2)
void gemm_bf(const __nv_bfloat16* __restrict__ A, const __nv_bfloat16* __restrict__ B,
             void* __restrict__ Cout, const float* __restrict__ bias,
             const float* __restrict__ aux, int M, int N, int K) {
    constexpr int BK = 16;
    constexpr int WM = BM/2, WN = BN/4;
    constexpr int MT = WM/16, NT = WN/8;
    constexpr int STR = 24;   // bf16 stride: 48 bytes, 16B-aligned rows

    __shared__ __align__(16) __nv_bfloat16 As[2][BM*STR];
    __shared__ __align__(16) __nv_bfloat16 Bs[2][BN*STR];

    const int bm = blockIdx.y*BM, bn = blockIdx.x*BN;
    const int tid = threadIdx.x;
    const int lane = tid & 31, wid = tid >> 5;
    const int wm = wid >> 2, wn = wid & 3;
    const int g = lane >> 2, tig = lane & 3;

    float acc[MT][NT][4];
    #pragma unroll
    for (int i = 0; i < MT; i++)
        #pragma unroll
        for (int j = 0; j < NT; j++)
            #pragma unroll
            for (int l = 0; l < 4; l++) acc[i][j][l] = 0.f;

    auto copy_tile = [&](int st, int k0) {
        {   // A: BM*2 = 256 chunks of 8 bf16
            int ch = tid;
            int row = ch >> 1, c8 = (ch & 1)*8;
            cp16(&As[st][row*STR + c8], &A[(size_t)(bm+row)*K + k0 + c8]);
        }
        {   // B: BN*2 chunks (256 or 128)
            constexpr int CB = BN*2;
            int ch = tid;
            if (CB == 256 || ch < CB) {
                int row = ch >> 1, c8 = (ch & 1)*8;
                cp16(&Bs[st][row*STR + c8], &B[(size_t)(bn+row)*K + k0 + c8]);
            }
        }
    };

    copy_tile(0, 0);
    cp_commit();
    int stage = 0;
    for (int k0 = 0; k0 < K; k0 += BK) {
        cp_wait0();
        __syncthreads();
        if (k0 + BK < K) { copy_tile(stage^1, k0+BK); cp_commit(); }
        const __nv_bfloat16* as = As[stage];
        const __nv_bfloat16* bs = Bs[stage];
        int kk = 2*tig;
        unsigned afr[MT][4];
        #pragma unroll
        for (int mt = 0; mt < MT; mt++) {
            int r0 = wm*WM + mt*16 + g;
            afr[mt][0] = *(const unsigned*)&as[(r0  )*STR + kk  ];
            afr[mt][1] = *(const unsigned*)&as[(r0+8)*STR + kk  ];
            afr[mt][2] = *(const unsigned*)&as[(r0  )*STR + kk+8];
            afr[mt][3] = *(const unsigned*)&as[(r0+8)*STR + kk+8];
        }
        unsigned bfr[NT][2];
        #pragma unroll
        for (int nt = 0; nt < NT; nt++) {
            int c0 = wn*WN + nt*8 + g;
            bfr[nt][0] = *(const unsigned*)&bs[c0*STR + kk  ];
            bfr[nt][1] = *(const unsigned*)&bs[c0*STR + kk+8];
        }
        #pragma unroll
        for (int mt = 0; mt < MT; mt++)
            #pragma unroll
            for (int nt = 0; nt < NT; nt++)
                mma_bf16(acc[mt][nt], afr[mt], bfr[nt], acc[mt][nt]);
        stage ^= 1;
    }

    #pragma unroll
    for (int mt = 0; mt < MT; mt++) {
        int row0 = bm + wm*WM + mt*16 + g;
        #pragma unroll
        for (int nt = 0; nt < NT; nt++) {
            int col = bn + wn*WN + nt*8 + tig*2;
            #pragma unroll
            for (int half = 0; half < 2; half++) {
                int row = row0 + half*8;
                float v0 = acc[mt][nt][half*2], v1 = acc[mt][nt][half*2+1];
                if (EPI == 1) {
                    v0 += bias[col]; v1 += bias[col+1];
                    v0 = 0.5f*v0*(1.0f + erff(v0*0.70710678118654752f));
                    v1 = 0.5f*v1*(1.0f + erff(v1*0.70710678118654752f));
                    __nv_bfloat162 p;
                    p.x = __float2bfloat16(v0); p.y = __float2bfloat16(v1);
                    *(__nv_bfloat162*)&((__nv_bfloat16*)Cout)[(size_t)row*N + col] = p;
                } else { // EPI == 4
                    int b = row / NN, n = row - b*NN;
                    float gm = aux[0];
                    float o0 = g_x2[(size_t)row*C_ + col]   + gm*(v0 + bias[col]);
                    float o1 = g_x2[(size_t)row*C_ + col+1] + gm*(v1 + bias[col+1]);
                    float* C = (float*)Cout;
                    C[(size_t)(b*C_ + col  )*NN + n] = o0;
                    C[(size_t)(b*C_ + col+1)*NN + n] = o1;
                }
            }
        }
    }
}

// ---------------- transpose + f32->bf16 convert: in [K][N] -> out [N][K] ----------------
__global__ __launch_bounds__(256) void tconv_k(const float* __restrict__ in,
                                               __nv_bfloat16* __restrict__ out,
                                               int K, int N) {
    __shared__ float tile[32][33];
    int nb = blockIdx.x*32, kb = blockIdx.y*32;
    int tx = threadIdx.x & 31, ty = threadIdx.x >> 5;
    #pragma unroll
    for (int i = 0; i < 32; i += 8)
        tile[ty+i][tx] = in[(size_t)(kb+ty+i)*N + nb+tx];
    __syncthreads();
    #pragma unroll
    for (int i = 0; i < 32; i += 8)
        out[(size_t)(nb+ty+i)*K + kb+tx] = __float2bfloat16(tile[tx][ty+i]);
}

// ---------------- LN1: NCHW -> normalized [B*N, C], tiled transpose ----------------
__global__ __launch_bounds__(256) void ln1_k(const float* __restrict__ x,
                                             const float* __restrict__ gg,
                                             const float* __restrict__ bb) {
    __shared__ float tile[C_*33];
    __shared__ float smu[32], sr[32];
    int blk = blockIdx.x;                  // B_*NN/32 = 144
    int b = blk / (NN/32);
    int n0 = (blk % (NN/32)) * 32;
    int tid = threadIdx.x;
    #pragma unroll
    for (int i = 0; i < 32; i++) {
        int idx = i*256 + tid;
        int c = idx >> 5, n = idx & 31;
        tile[c*33 + n] = x[(size_t)(b*C_ + c)*NN + n0 + n];
    }
    __syncthreads();
    int wid = tid >> 5, lane = tid & 31;
    #pragma unroll
    for (int j = 0; j < 4; j++) {
        int n = wid*4 + j;
        float s1 = 0, s2 = 0;
        #pragma unroll
        for (int i = 0; i < 8; i++) {
            float v = tile[(lane + i*32)*33 + n];
            s1 += v; s2 += v*v;
        }
        #pragma unroll
        for (int o = 16; o; o >>= 1) {
            s1 += __shfl_xor_sync(~0u, s1, o);
            s2 += __shfl_xor_sync(~0u, s2, o);
        }
        if (lane == 0) {
            float mu = s1*(1.0f/C_);
            float var = s2*(1.0f/C_) - mu*mu;
            smu[n] = mu; sr[n] = rsqrtf(var + 1e-6f);
        }
    }
    __syncthreads();
    #pragma unroll
    for (int i = 0; i < 32; i++) {
        int idx = i*256 + tid;
        int n = idx >> 8, c = idx & 255;
        float v = tile[c*33 + n];
        g_xa[(size_t)(b*NN + n0 + n)*C_ + c] = (v - smu[n])*sr[n]*gg[c] + bb[c];
    }
}

// ---------------- LN2: warp per row over g_x2 -> bf16 ----------------
__global__ void ln2_k(const float* __restrict__ gg, const float* __restrict__ bb) {
    int row = (blockIdx.x*256 + threadIdx.x) >> 5;
    int lane = threadIdx.x & 31;
    const float* p = &g_x2[(size_t)row*C_];
    float v[8]; float s1 = 0, s2 = 0;
    #pragma unroll
    for (int i = 0; i < 8; i++) { v[i] = p[lane + i*32]; s1 += v[i]; s2 += v[i]*v[i]; }
    #pragma unroll
    for (int o = 16; o; o >>= 1) {
        s1 += __shfl_xor_sync(~0u, s1, o);
        s2 += __shfl_xor_sync(~0u, s2, o);
    }
    float mu = s1*(1.0f/C_);
    float var = s2*(1.0f/C_) - mu*mu;
    float r = rsqrtf(var + 1e-6f);
    #pragma unroll
    for (int i = 0; i < 8; i++) {
        int c = lane + i*32;
        g_ln2b[(size_t)row*C_ + c] = __float2bfloat16((v[i]-mu)*r*gg[c] + bb[c]);
    }
}

// ---------------- per-(b,h) partial sums of q,k,v ----------------
__global__ void bh_sums1_k() {
    int bh = blockIdx.x, yy = blockIdx.y;     // 16 x 12
    int t = threadIdx.x;                      // 256
    int d = t & 31, part = t >> 5;            // 8 parts x 24 rows
    float sq = 0, sk = 0, sv = 0;
    int n0 = yy*192 + part*24;
    for (int j = 0; j < 24; j++) {
        int idx = (bh*NN + n0 + j)*DH + d;
        sq += g_q[idx]; sk += g_k[idx]; sv += g_v[idx];
    }
    __shared__ float sh[3][8][32];
    sh[0][part][d]=sq; sh[1][part][d]=sk; sh[2][part][d]=sv;
    __syncthreads();
    if (t < 96) {
        int which = t >> 5, dd = t & 31;
        float s = 0;
        #pragma unroll
        for (int p = 0; p < 8; p++) s += sh[which][p][dd];
        g_spart[((bh*12 + yy)*3 + which)*DH + dd] = s;
    }
}

// ---------------- reduce partials + row/col pruning scores (merged) ----------------
__global__ void scores_k() {
    int bh = blockIdx.x, yy = blockIdx.y;      // 16 x 9
    int t = threadIdx.x;                       // 256
    __shared__ float qs[DH], ks[DH];
    if (t < 96) {
        int which = t >> 5, d = t & 31;
        float s = 0;
        #pragma unroll
        for (int y = 0; y < 12; y++) s += g_spart[((bh*12 + y)*3 + which)*DH + d];
        if (which == 0) qs[d] = s;
        else if (which == 1) ks[d] = s;
        if (yy == 0) g_sums[(bh*3 + which)*DH + d] = s;
    }
    __syncthreads();
    int gid = bh*NN + yy*256 + t;
    float r = 0, c = 0;
    const float4* qp = (const float4*)&g_q[(size_t)gid*DH];
    const float4* kp = (const float4*)&g_k[(size_t)gid*DH];
    #pragma unroll
    for (int w = 0; w < 8; w++) {
        float4 qf = qp[w], kf = kp[w];
        r += qf.x*ks[4*w] + qf.y*ks[4*w+1] + qf.z*ks[4*w+2] + qf.w*ks[4*w+3];
        c += qs[4*w]*kf.x + qs[4*w+1]*kf.y + qs[4*w+2]*kf.z + qs[4*w+3]*kf.w;
    }
    g_rs[gid] = r; g_cs[gid] = c;
}

// ---------------- exact top-k selection (radix select, warp-scan version) ----------------
__device__ __forceinline__ unsigned f2key(float f) {
    unsigned u = __float_as_uint(f);
    return (u & 0x80000000u) ? ~u : (u | 0x80000000u);
}

// inclusive scan over 256 threads; wtot[8] shared scratch; after return wtot[7]=total
__device__ __forceinline__ int incl_scan256(int v, int t, int* wtot) {
    __syncthreads();                 // protect wtot reuse
    int lane = t & 31, wid = t >> 5;
    #pragma unroll
    for (int o = 1; o < 32; o <<= 1) {
        int u = __shfl_up_sync(~0u, v, o);
        if (lane >= o) v += u;
    }
    if (lane == 31) wtot[wid] = v;
    __syncthreads();
    if (wid == 0) {
        int s = (lane < 8) ? wtot[lane] : 0;
        #pragma unroll
        for (int o = 1; o < 8; o <<= 1) {
            int u = __shfl_up_sync(~0u, s, o);
            if (lane >= o) s += u;
        }
        if (lane < 8) wtot[lane] = s;
    }
    __syncthreads();
    return v + (wid > 0 ? wtot[wid-1] : 0);
}

__global__ void select_k() {
    int blk = blockIdx.x;          // 0..31
    int type = blk >> 4, bh = blk & 15;
    const float* s = (type == 0 ? g_rs : g_cs) + bh*NN;
    int* list = (type == 0 ? g_rowlist : g_collist) + bh*KTOP;
    __shared__ unsigned keys[NN];
    __shared__ int hist[256];
    __shared__ int wtot[8];
    __shared__ unsigned sh_T;
    __shared__ int sh_take;
    int t = threadIdx.x;           // 256
    for (int i = t; i < NN; i += 256) keys[i] = f2key(s[i]);
    __syncthreads();

    unsigned prefix = 0, pmask = 0;
    int kneed = KTOP;
    for (int pass = 0; pass < 4; pass++) {
        int shift = 24 - 8*pass;
        hist[t] = 0;
        __syncthreads();
        for (int i = t; i < NN; i += 256) {
            unsigned u = keys[i];
            if ((u & pmask) == prefix) atomicAdd(&hist[(u >> shift) & 255], 1);
        }
        __syncthreads();
        int h = hist[t];
        int pre = incl_scan256(h, t, wtot);       // sum_{j<=t}
        int total = wtot[7];
        int cum = total - pre;                    // sum_{j>t}
        if (cum < kneed && cum + h >= kneed) {    // unique bucket
            sh_T = prefix | ((unsigned)t << shift);
            sh_take = kneed - cum;
        }
        __syncthreads();
        prefix = sh_T;
        kneed = sh_take;
        pmask |= (0xffu << shift);
        __syncthreads();
    }
    unsigned T = prefix;
    int take = kneed;

    unsigned myk[9];
    int eqc = 0;
    #pragma unroll
    for (int j = 0; j < 9; j++) {
        myk[j] = keys[t*9 + j];
        eqc += (myk[j] == T);
    }
    int eqbase = incl_scan256(eqc, t, wtot) - eqc;

    bool kept[9];
    int keptc = 0, eqseen = 0;
    #pragma unroll
    for (int j = 0; j < 9; j++) {
        unsigned u = myk[j];
        bool gt = (u > T), eq = (u == T);
        bool kp = gt || (eq && (eqbase + eqseen) < take);
        if (eq) eqseen++;
        kept[j] = kp; keptc += kp;
    }
    int wbase = incl_scan256(keptc, t, wtot) - keptc;
    #pragma unroll
    for (int j = 0; j < 9; j++)
        if (kept[j]) list[wbase++] = t*9 + j;
}

// ---------------- v_unkept = vsum - sum over kept cols ----------------
__global__ void vunkept_k() {
    int bh = blockIdx.x;
    int t = threadIdx.x;
    int d = t & 31, part = t >> 5;
    float sv = 0;
    for (int jj = part; jj < KTOP; jj += 8) {
        int j = g_collist[bh*KTOP + jj];
        sv += g_v[(bh*NN + j)*DH + d];
    }
    __shared__ float sh[8][32];
    sh[part][d] = sv;
    __syncthreads();
    if (t < 32) {
        float s = 0;
        #pragma unroll
        for (int p = 0; p < 8; p++) s += sh[p][t];
        g_vunk[bh*DH + t] = g_sums[(bh*3+2)*DH + t] - s;
    }
}

// ---------------- pruned rows: uniform softmax -> mean(v) ----------------
__global__ void fill_o_k() {
    int gid = blockIdx.x*256 + threadIdx.x;
    if (gid >= BHN*NN*DH) return;
    int bh = gid / (NN*DH);
    int r = gid % (NN*DH);
    int n = r / DH, d = r & 31;
    int b = bh >> 3, h = bh & 7;
    g_o[(size_t)(b*NN + n)*C_ + h*DH + d] = g_sums[(bh*3+2)*DH + d] * (1.0f/NN);
}

// ---------------- kept-row attention partials over a column chunk ----------------
__global__ __launch_bounds__(64) void attn_part_k() {
    int bh = blockIdx.x;
    int t = threadIdx.x;                      // 64
    int slot = blockIdx.y*64 + t;             // 0..575
    int chunk = blockIdx.z;                   // 0..2
    int i = g_rowlist[bh*KTOP + slot];

    float qr[DH];
    const float4* qp = (const float4*)&g_q[(size_t)(bh*NN + i)*DH];
    #pragma unroll
    for (int w = 0; w < 8; w++) {
        float4 f = qp[w];
        qr[4*w]=f.x; qr[4*w+1]=f.y; qr[4*w+2]=f.z; qr[4*w+3]=f.w;
    }

    float m = -3.0e38f, Z = 0.f;
    float acc[DH];
    #pragma unroll
    for (int d = 0; d < DH; d++) acc[d] = 0.f;

    __shared__ int cj[96];
    __shared__ float Kc[96][DH];
    __shared__ float Vc[96][DH];

    for (int c0 = chunk*CHUNK; c0 < chunk*CHUNK + CHUNK; c0 += 96) {
        __syncthreads();
        for (int jj = t; jj < 96; jj += 64) cj[jj] = g_collist[bh*KTOP + c0 + jj];
        __syncthreads();
        for (int idx = t; idx < 96*DH; idx += 64) {
            int jj = idx >> 5, d = idx & 31;
            int base = (bh*NN + cj[jj])*DH + d;
            Kc[jj][d] = g_k[base];
            Vc[jj][d] = g_v[base];
        }
        __syncthreads();
        #pragma unroll 2
        for (int jj = 0; jj < 96; jj++) {
            float s0=0,s1=0,s2=0,s3=0;
            #pragma unroll
            for (int d = 0; d < DH; d += 4) {
                s0 += qr[d+0]*Kc[jj][d+0];
                s1 += qr[d+1]*Kc[jj][d+1];
                s2 += qr[d+2]*Kc[jj][d+2];
                s3 += qr[d+3]*Kc[jj][d+3];
            }
            float s = (s0+s1) + (s2+s3);
            if (s > m) {
                float cf = __expf(m - s);
                Z = Z*cf + 1.f;
                #pragma unroll
                for (int d = 0; d < DH; d++) acc[d] = acc[d]*cf + Vc[jj][d];
                m = s;
            } else {
                float e = __expf(s - m);
                Z += e;
                #pragma unroll
                for (int d = 0; d < DH; d++) acc[d] += e*Vc[jj][d];
            }
        }
    }
    int pidx = (bh*KTOP + slot)*NSPLIT + chunk;
    g_pm[pidx] = m;
    g_pz[pidx] = Z;
    float* pa = &g_pacc[(size_t)pidx*DH];
    #pragma unroll
    for (int d = 0; d < DH; d++) pa[d] = acc[d];
}

// ---------------- combine partials + zero-column correction ----------------
__global__ void attn_comb_k() {
    int gid = blockIdx.x*128 + threadIdx.x;
    if (gid >= BHN*KTOP) return;
    int bh = gid / KTOP, slot = gid % KTOP;
    int i = g_rowlist[bh*KTOP + slot];
    int p0 = gid*NSPLIT;
    float m0 = g_pm[p0], m1 = g_pm[p0+1], m2 = g_pm[p0+2];
    float mstar = fmaxf(0.f, fmaxf(m0, fmaxf(m1, m2)));
    float e0 = __expf(m0 - mstar), e1 = __expf(m1 - mstar), e2 = __expf(m2 - mstar);
    float ez = __expf(-mstar);
    float Z = g_pz[p0]*e0 + g_pz[p0+1]*e1 + g_pz[p0+2]*e2 + (float)(NN - KTOP)*ez;
    float invZ = 1.f / Z;
    const float* a0 = &g_pacc[(size_t)p0*DH];
    const float* a1 = &g_pacc[(size_t)(p0+1)*DH];
    const float* a2 = &g_pacc[(size_t)(p0+2)*DH];
    const float* vu = &g_vunk[bh*DH];
    int b = bh >> 3, h = bh & 7;
    float* op = &g_o[(size_t)(b*NN + i)*C_ + h*DH];
    #pragma unroll
    for (int d = 0; d < DH; d++)
        op[d] = (a0[d]*e0 + a1[d]*e1 + a2[d]*e2 + ez*vu[d]) * invZ;
}

// ---------------- depthwise 3x3 conv (writes [C][B*NN]) ----------------
__global__ void dw_k(const float* __restrict__ x,
                     const float* __restrict__ w,
                     const float* __restrict__ bias) {
    int gid = blockIdx.x*256 + threadIdx.x;
    if (gid >= B_*C_*NN) return;
    int n = gid % NN;
    int bc = gid / NN;
    int c = bc % C_, b = bc / C_;
    int y = n / WW, x0 = n % WW;
    float acc = bias[c];
    const float* xp = &x[(size_t)(b*C_ + c)*NN];
    const float* wp = &w[c*9];
    #pragma unroll
    for (int dy = 0; dy < 3; dy++) {
        int yy = y + dy - 1;
        if (yy < 0 || yy >= HH) continue;
        #pragma unroll
        for (int dx = 0; dx < 3; dx++) {
            int xx = x0 + dx - 1;
            if (xx < 0 || xx >= WW) continue;
            acc += xp[yy*WW + xx] * wp[dy*3 + dx];
        }
    }
    g_xdw[(size_t)c*(B_*NN) + b*NN + n] = acc;
}

// ---------------- spatial gate stage 1: 1x1 conv C->32 + silu ----------------
__global__ __launch_bounds__(256) void sg1_k(const float* __restrict__ w,
                                             const float* __restrict__ bias) {
    __shared__ float ws[C_*33];        // [ci][go] padded to 33 -> conflict-free
    __shared__ float rows[8][C_];
    int tid = threadIdx.x;
    for (int i = tid; i < GG*C_; i += 256) {
        int go = i >> 8, ci = i & 255;
        ws[ci*33 + go] = w[go*C_ + ci];
    }
    int bn0 = blockIdx.x * 8;          // 8 pixels per block
    for (int i = tid; i < 8*C_; i += 256)
        rows[i >> 8][i & 255] = g_xs[(size_t)(bn0 + (i >> 8))*C_ + (i & 255)];
    __syncthreads();
    int px = tid >> 5, go = tid & 31;
    float acc = bias[go];
    #pragma unroll 4
    for (int ci = 0; ci < C_; ci++)
        acc += rows[px][ci] * ws[ci*33 + go];
    g_t1[(bn0 + px)*GG + go] = acc / (1.f + expf(-acc));
}

// ---------------- spatial gate stage 2: 7x7 conv 32->1 + sigmoid (warp/pixel) ----------------
__global__ __launch_bounds__(256) void sg2_k(const float* __restrict__ w,
                                             const float* __restrict__ bias) {
    __shared__ float ws[GG*49];
    int tid = threadIdx.x;
    for (int i = tid; i < GG*49; i += 256) ws[i] = w[i];
    __syncthreads();
    int p = blockIdx.x*8 + (tid >> 5);     // pixel index
    int lane = tid & 31;
    int b = p / NN, n = p % NN;
    int y = n / WW, x0 = n % WW;
    float acc = 0.f;
    for (int ky = 0; ky < 7; ky++) {
        int yy = y + ky - 3;
        if (yy < 0 || yy >= HH) continue;
        #pragma unroll
        for (int kx = 0; kx < 7; kx++) {
            int xx = x0 + kx - 3;
            if (xx < 0 || xx >= WW) continue;
            acc += g_t1[(b*NN + yy*WW + xx)*GG + lane] * ws[lane*49 + ky*7 + kx];
        }
    }
    #pragma unroll
    for (int o = 16; o; o >>= 1) acc += __shfl_xor_sync(~0u, acc, o);
    if (lane == 0) g_sg[p] = 1.f / (1.f + expf(-(acc + bias[0])));
}

// ---------------- channel gate: pool partials ----------------
__global__ void cgpool_k() {
    int blk = blockIdx.x;            // b*16 + part
    int b = blk / 16, part = blk % 16;
    int c = threadIdx.x;             // 256
    float s = 0;
    int n0 = part*144;
    for (int n = n0; n < n0 + 144; n++) s += g_xs[(size_t)(b*NN + n)*C_ + c];
    g_cgpart[blk*C_ + c] = s;
}

// ---------------- channel gate: combine + silu + sigmoid ----------------
__global__ void cggate_k(const float* __restrict__ w1, const float* __restrict__ b1,
                         const float* __restrict__ w2, const float* __restrict__ b2) {
    int b = blockIdx.x;
    int c = threadIdx.x;
    __shared__ float cgm[C_];
    __shared__ float t2[GG];
    float s = 0;
    for (int p = 0; p < 16; p++) s += g_cgpart[(b*16 + p)*C_ + c];
    cgm[c] = s * (1.0f/NN);
    __syncthreads();
    if (c < GG) {
        float a = b1[c];
        const float* wp = &w1[c*C_];
        for (int ci = 0; ci < C_; ci++) a += cgm[ci]*wp[ci];
        t2[c] = a / (1.f + expf(-a));
    }
    __syncthreads();
    float a2 = b2[c];
    const float* wp2 = &w2[c*GG];
    #pragma unroll
    for (int g = 0; g < GG; g++) a2 += t2[g]*wp2[g];
    g_cg[b*C_ + c] = 1.f / (1.f + expf(-a2));
}

// ---------------- x2 = x + gamma1*xs*sg*cg, tiled transpose ----------------
__global__ __launch_bounds__(256) void x2_k(const float* __restrict__ x,
                                            const float* __restrict__ gamma1) {
    __shared__ float tile[C_*33];
    int blk = blockIdx.x;               // 144
    int b = blk / (NN/32);
    int n0 = (blk % (NN/32)) * 32;
    int tid = threadIdx.x;
    #pragma unroll
    for (int i = 0; i < 32; i++) {
        int idx = i*256 + tid;
        int c = idx >> 5, n = idx & 31;
        tile[c*33 + n] = x[(size_t)(b*C_ + c)*NN + n0 + n];
    }
    __syncthreads();
    float gm = gamma1[0];
    #pragma unroll
    for (int i = 0; i < 32; i++) {
        int idx = i*256 + tid;
        int n = idx >> 8, c = idx & 255;
        int row = b*NN + n0 + n;
        g_x2[(size_t)row*C_ + c] =
            tile[c*33 + n] + gm * g_xs[(size_t)row*C_ + c] * g_sg[row] * g_cg[b*C_ + c];
    }
}

// ---------------- host ----------------
#define GETSYM(p, s, T) do { void* _t; cudaGetSymbolAddress(&_t, s); p = (T*)_t; } while (0)

extern "C" void kernel_launch(void* const* d_in, const int* in_sizes, int n_in,
                              void* d_out, int out_size) {
    const float* x     = (const float*)d_in[0];
    const float* qkv_w = (const float*)d_in[1];
    const float* out_w = (const float*)d_in[2];
    const float* ln1_g = (const float*)d_in[3];
    const float* ln1_b = (const float*)d_in[4];
    const float* ln2_g = (const float*)d_in[5];
    const float* ln2_b = (const float*)d_in[6];
    const float* dw_w  = (const float*)d_in[7];
    const float* dw_b  = (const float*)d_in[8];
    const float* pw_w  = (const float*)d_in[9];
    const float* pw_b  = (const float*)d_in[10];
    const float* sg1_w = (const float*)d_in[11];
    const float* sg1_b = (const float*)d_in[12];
    const float* sg2_w = (const float*)d_in[13];
    const float* sg2_b = (const float*)d_in[14];
    const float* cg1_w = (const float*)d_in[15];
    const float* cg1_b = (const float*)d_in[16];
    const float* cg2_w = (const float*)d_in[17];
    const float* cg2_b = (const float*)d_in[18];
    const float* ff_w1 = (const float*)d_in[19];
    const float* ff_b1 = (const float*)d_in[20];
    const float* ff_w2 = (const float*)d_in[21];
    const float* ff_b2 = (const float*)d_in[22];
    const float* gamma1= (const float*)d_in[23];
    const float* gamma2= (const float*)d_in[24];
    float* out = (float*)d_out;
    (void)in_sizes; (void)n_in; (void)out_size;

    float *p_xa, *p_o, *p_xdw, *p_xc, *p_xs;
    __nv_bfloat16 *p_ln2b, *p_hb, *p_w1t, *p_w2t;
    GETSYM(p_xa, g_xa, float); GETSYM(p_o, g_o, float);
    GETSYM(p_xdw, g_xdw, float); GETSYM(p_xc, g_xc, float); GETSYM(p_xs, g_xs, float);
    GETSYM(p_ln2b, g_ln2b, __nv_bfloat16); GETSYM(p_hb, g_hb, __nv_bfloat16);
    GETSYM(p_w1t, g_w1t, __nv_bfloat16); GETSYM(p_w2t, g_w2t, __nv_bfloat16);

    const int M = B_*NN;   // 4608

    // 0-2: independent prep (conv branch first so QKV gemm lands at profiled idx 3)
    ln1_k<<<B_*NN/32, 256>>>(x, ln1_g, ln1_b);
    dw_k<<<(B_*C_*NN)/256, 256>>>(x, dw_w, dw_b);
    gemm_tc<128,64,true,true,0><<<dim3(C_/64, M/128), 256>>>(
        p_xdw, pw_w, p_xc, nullptr, M, C_, C_);
    // 3: QKV gemm  <-- ncu profiles this launch
    gemm_tc<128,128,false,false,2><<<dim3(768/128, M/128), 256>>>(
        p_xa, qkv_w, nullptr, nullptr, M, 3*C_, C_);
    // attention stats + selection
    bh_sums1_k<<<dim3(BHN, 12), 256>>>();
    scores_k<<<dim3(BHN, 9), 256>>>();
    select_k<<<32, 256>>>();
    vunkept_k<<<BHN, 256>>>();
    fill_o_k<<<(BHN*NN*DH)/256, 256>>>();
    attn_part_k<<<dim3(BHN, 9, NSPLIT), 64>>>();
    attn_comb_k<<<(BHN*KTOP + 127)/128, 128>>>();
    // out-proj epilogue: xs = o@out_w + xc + pw_b
    gemm_tc<128,64,false,false,3><<<dim3(C_/64, M/128), 256>>>(
        p_o, out_w, p_xs, pw_b, M, C_, C_);

    // gates
    sg1_k<<<B_*NN/8, 256>>>(sg1_w, sg1_b);
    sg2_k<<<B_*NN/8, 256>>>(sg2_w, sg2_b);
    cgpool_k<<<B_*16, 256>>>();
    cggate_k<<<B_, 256>>>(cg1_w, cg1_b, cg2_w, cg2_b);
    x2_k<<<B_*NN/32, 256>>>(x, gamma1);

    // FFN (bf16)
    ln2_k<<<M/8, 256>>>(ln2_g, ln2_b);
    tconv_k<<<dim3(HID/32, C_/32), 256>>>(ff_w1, p_w1t, C_, HID);   // [256][1024]->[1024][256]
    tconv_k<<<dim3(C_/32, HID/32), 256>>>(ff_w2, p_w2t, HID, C_);   // [1024][256]->[256][1024]
    gemm_bf<128,128,1><<<dim3(HID/128, M/128), 256>>>(
        p_ln2b, p_w1t, p_hb, ff_b1, nullptr, M, HID, C_);
    gemm_bf<128,64,4><<<dim3(C_/64, M/128), 256>>>(
        p_hb, p_w2t, out, ff_b2, gamma2, M, C_, HID);
}

// round 11
// speedup vs baseline: 3.5471x; 1.1169x over previous
#include <cuda_runtime.h>
#include <cuda_bf16.h>
#include <math.h>

#define B_ 2
#define C_ 256
#define HH 48
#define WW 48
#define NN 2304          // 48*48
#define NHEAD 8
#define DH 32
#define BHN 16           // B_*NHEAD
#define KTOP 576
#define HID 1024
#define GG 32            // C/8 gate channels
#define QSCALE 0.17677669529663687f   // 1/sqrt(32)
#define NSPLIT 3         // attention column-split
#define CHUNK 192        // KTOP / NSPLIT

// ---------------- scratch (static device arrays; no allocation) ----------------
__device__ __nv_bfloat16 g_xab[B_*NN*C_];      // ln1 out (bf16)
__device__ float g_q   [BHN*NN*DH];
__device__ float g_k   [BHN*NN*DH];
__device__ float g_v   [BHN*NN*DH];
__device__ float g_spart[BHN*12*3*DH];
__device__ float g_sums[BHN*3*DH];
__device__ float g_rs  [BHN*NN];
__device__ float g_cs  [BHN*NN];
__device__ int   g_rowlist[BHN*KTOP];
__device__ int   g_collist[BHN*KTOP];
__device__ float g_vunk[BHN*DH];
__device__ float g_pm  [BHN*KTOP*NSPLIT];
__device__ float g_pz  [BHN*KTOP*NSPLIT];
__device__ float g_pacc[BHN*KTOP*NSPLIT*DH];
__device__ __nv_bfloat16 g_ob [B_*NN*C_];      // attention out (bf16, gemm A)
__device__ float g_xdw [C_*B_*NN];             // dw out [c][b*NN+n]
__device__ __nv_bfloat16 g_xdwb[B_*NN*C_];     // dw out transposed [M][C] bf16
__device__ float g_xc  [B_*NN*C_];
__device__ float g_xs  [B_*NN*C_];
__device__ float g_t1  [B_*NN*GG];
__device__ float g_sg  [B_*NN];
__device__ float g_cgpart[B_*16*C_];
__device__ float g_cg  [B_*C_];
__device__ float g_x2  [B_*NN*C_];
__device__ __nv_bfloat16 g_ln2b[B_*NN*C_];
__device__ __nv_bfloat16 g_hb  [B_*NN*HID];
__device__ __nv_bfloat16 g_wqt [3*C_*C_];      // qkv_w^T [768][256]
__device__ __nv_bfloat16 g_wot [C_*C_];        // out_w^T [256][256]
__device__ __nv_bfloat16 g_wpwb[C_*C_];        // pw_w (already [N][K]) bf16
__device__ __nv_bfloat16 g_w1t [HID*C_];       // ff_w1^T [1024][256]
__device__ __nv_bfloat16 g_w2t [C_*HID];       // ff_w2^T [256][1024]

// ---------------- helpers ----------------
__device__ __forceinline__ void cp16(void* sptr, const void* gptr) {
    unsigned saddr = (unsigned)__cvta_generic_to_shared(sptr);
    asm volatile("cp.async.cg.shared.global [%0], [%1], 16;" :: "r"(saddr), "l"(gptr));
}
__device__ __forceinline__ void cp_commit() { asm volatile("cp.async.commit_group;"); }
__device__ __forceinline__ void cp_wait0()  { asm volatile("cp.async.wait_group 0;" ::: "memory"); }

__device__ __forceinline__ void mma_bf16(float* d, const unsigned* a,
                                         const unsigned* b, const float* c) {
    asm volatile("mma.sync.aligned.m16n8k16.row.col.f32.bf16.bf16.f32 "
        "{%0,%1,%2,%3}, {%4,%5,%6,%7}, {%8,%9}, {%10,%11,%12,%13};"
        : "=f"(d[0]),"=f"(d[1]),"=f"(d[2]),"=f"(d[3])
        : "r"(a[0]),"r"(a[1]),"r"(a[2]),"r"(a[3]),
          "r"(b[0]),"r"(b[1]),
          "f"(c[0]),"f"(c[1]),"f"(c[2]),"f"(c[3]));
}
__device__ __forceinline__ unsigned long long pack2(float lo, float hi) {
    unsigned long long r;
    asm("mov.b64 %0, {%1, %2};" : "=l"(r) : "f"(lo), "f"(hi));
    return r;
}
__device__ __forceinline__ void unpack2(unsigned long long v, float& lo, float& hi) {
    asm("mov.b64 {%0, %1}, %2;" : "=f"(lo), "=f"(hi) : "l"(v));
}
__device__ __forceinline__ unsigned long long fma2(unsigned long long a,
                                                   unsigned long long b,
                                                   unsigned long long c) {
    unsigned long long d;
    asm("fma.rn.f32x2 %0, %1, %2, %3;" : "=l"(d) : "l"(a), "l"(b), "l"(c));
    return d;
}
__device__ __forceinline__ unsigned long long mul2(unsigned long long a,
                                                   unsigned long long b) {
    unsigned long long d;
    asm("mul.rn.f32x2 %0, %1, %2;" : "=l"(d) : "l"(a), "l"(b));
    return d;
}

// ---------------- bf16 tensor-core GEMM (A [M,K] bf16, B [N,K] bf16), BK=16 ----------------
// smem stride 24 bf16 = 48 B (16B-aligned rows for cp.async).
// BM=128, 256 threads, warps 2x4.
// EPI: 0=plain f32 C   1=bias+gelu->bf16 C   2=qkv scatter (f32 q/k/v)
//      3=xs: C = v + g_xc + bias (f32)       4=final: out = x2 + gamma2*(v+bias), NCHW f32
template<int BM, int BN, int EPI>
__global__ __launch_bounds__(256, 2)
void gemm_bf(const __nv_bfloat16* __restrict__ A, const __nv_bfloat16* __restrict__ B,
             void* __restrict__ Cout, const float* __restrict__ bias,
             const float* __restrict__ aux, int M, int N, int K) {
    constexpr int BK = 16;
    constexpr int WM = BM/2, WN = BN/4;
    constexpr int MT = WM/16, NT = WN/8;
    constexpr int STR = 24;

    __shared__ __align__(16) __nv_bfloat16 As[2][BM*STR];
    __shared__ __align__(16) __nv_bfloat16 Bs[2][BN*STR];

    const int bm = blockIdx.y*BM, bn = blockIdx.x*BN;
    const int tid = threadIdx.x;
    const int lane = tid & 31, wid = tid >> 5;
    const int wm = wid >> 2, wn = wid & 3;
    const int g = lane >> 2, tig = lane & 3;

    float acc[MT][NT][4];
    #pragma unroll
    for (int i = 0; i < MT; i++)
        #pragma unroll
        for (int j = 0; j < NT; j++)
            #pragma unroll
            for (int l = 0; l < 4; l++) acc[i][j][l] = 0.f;

    auto copy_tile = [&](int st, int k0) {
        {
            int ch = tid;
            int row = ch >> 1, c8 = (ch & 1)*8;
            cp16(&As[st][row*STR + c8], &A[(size_t)(bm+row)*K + k0 + c8]);
        }
        {
            constexpr int CB = BN*2;
            int ch = tid;
            if (CB == 256 || ch < CB) {
                int row = ch >> 1, c8 = (ch & 1)*8;
                cp16(&Bs[st][row*STR + c8], &B[(size_t)(bn+row)*K + k0 + c8]);
            }
        }
    };

    copy_tile(0, 0);
    cp_commit();
    int stage = 0;
    for (int k0 = 0; k0 < K; k0 += BK) {
        cp_wait0();
        __syncthreads();
        if (k0 + BK < K) { copy_tile(stage^1, k0+BK); cp_commit(); }
        const __nv_bfloat16* as = As[stage];
        const __nv_bfloat16* bs = Bs[stage];
        int kk = 2*tig;
        unsigned afr[MT][4];
        #pragma unroll
        for (int mt = 0; mt < MT; mt++) {
            int r0 = wm*WM + mt*16 + g;
            afr[mt][0] = *(const unsigned*)&as[(r0  )*STR + kk  ];
            afr[mt][1] = *(const unsigned*)&as[(r0+8)*STR + kk  ];
            afr[mt][2] = *(const unsigned*)&as[(r0  )*STR + kk+8];
            afr[mt][3] = *(const unsigned*)&as[(r0+8)*STR + kk+8];
        }
        unsigned bfr[NT][2];
        #pragma unroll
        for (int nt = 0; nt < NT; nt++) {
            int c0 = wn*WN + nt*8 + g;
            bfr[nt][0] = *(const unsigned*)&bs[c0*STR + kk  ];
            bfr[nt][1] = *(const unsigned*)&bs[c0*STR + kk+8];
        }
        #pragma unroll
        for (int mt = 0; mt < MT; mt++)
            #pragma unroll
            for (int nt = 0; nt < NT; nt++)
                mma_bf16(acc[mt][nt], afr[mt], bfr[nt], acc[mt][nt]);
        stage ^= 1;
    }

    #pragma unroll
    for (int mt = 0; mt < MT; mt++) {
        int row0 = bm + wm*WM + mt*16 + g;
        #pragma unroll
        for (int nt = 0; nt < NT; nt++) {
            int col = bn + wn*WN + nt*8 + tig*2;
            #pragma unroll
            for (int half = 0; half < 2; half++) {
                int row = row0 + half*8;
                float v0 = acc[mt][nt][half*2], v1 = acc[mt][nt][half*2+1];
                if (EPI == 0) {
                    *(float2*)&((float*)Cout)[(size_t)row*N + col] = make_float2(v0, v1);
                } else if (EPI == 1) {
                    v0 += bias[col]; v1 += bias[col+1];
                    v0 = 0.5f*v0*(1.0f + erff(v0*0.70710678118654752f));
                    v1 = 0.5f*v1*(1.0f + erff(v1*0.70710678118654752f));
                    __nv_bfloat162 p;
                    p.x = __float2bfloat16(v0); p.y = __float2bfloat16(v1);
                    *(__nv_bfloat162*)&((__nv_bfloat16*)Cout)[(size_t)row*N + col] = p;
                } else if (EPI == 2) {
                    int b = row / NN, n = row - b*NN;
                    int part = col >> 8, cc = col & 255;
                    int h = cc >> 5, d = cc & 31;
                    size_t dst = ((size_t)(b*NHEAD + h)*NN + n)*DH + d;
                    if (part == 0)
                        *(float2*)&g_q[dst] = make_float2(v0*QSCALE, v1*QSCALE);
                    else if (part == 1)
                        *(float2*)&g_k[dst] = make_float2(v0, v1);
                    else
                        *(float2*)&g_v[dst] = make_float2(v0, v1);
                } else if (EPI == 3) {
                    v0 += g_xc[(size_t)row*C_ + col]   + bias[col];
                    v1 += g_xc[(size_t)row*C_ + col+1] + bias[col+1];
                    *(float2*)&((float*)Cout)[(size_t)row*N + col] = make_float2(v0, v1);
                } else { // EPI == 4
                    int b = row / NN, n = row - b*NN;
                    float gm = aux[0];
                    float o0 = g_x2[(size_t)row*C_ + col]   + gm*(v0 + bias[col]);
                    float o1 = g_x2[(size_t)row*C_ + col+1] + gm*(v1 + bias[col+1]);
                    float* C = (float*)Cout;
                    C[(size_t)(b*C_ + col  )*NN + n] = o0;
                    C[(size_t)(b*C_ + col+1)*NN + n] = o1;
                }
            }
        }
    }
}

// ---------------- transpose + f32->bf16 convert: in [K][N] -> out [N][K] ----------------
__global__ __launch_bounds__(256) void tconv_k(const float* __restrict__ in,
                                               __nv_bfloat16* __restrict__ out,
                                               int K, int N) {
    __shared__ float tile[32][33];
    int nb = blockIdx.x*32, kb = blockIdx.y*32;
    int tx = threadIdx.x & 31, ty = threadIdx.x >> 5;
    #pragma unroll
    for (int i = 0; i < 32; i += 8)
        tile[ty+i][tx] = in[(size_t)(kb+ty+i)*N + nb+tx];
    __syncthreads();
    #pragma unroll
    for (int i = 0; i < 32; i += 8)
        out[(size_t)(nb+ty+i)*K + kb+tx] = __float2bfloat16(tile[tx][ty+i]);
}

// ---------------- straight f32->bf16 convert ----------------
__global__ void cvt_k(const float* __restrict__ in, __nv_bfloat16* __restrict__ out, int n) {
    int i = blockIdx.x*256 + threadIdx.x;
    if (i < n) out[i] = __float2bfloat16(in[i]);
}

// ---------------- LN1: NCHW -> normalized [B*N, C] bf16, tiled transpose ----------------
__global__ __launch_bounds__(256) void ln1_k(const float* __restrict__ x,
                                             const float* __restrict__ gg,
                                             const float* __restrict__ bb) {
    __shared__ float tile[C_*33];
    __shared__ float smu[32], sr[32];
    int blk = blockIdx.x;                  // 144
    int b = blk / (NN/32);
    int n0 = (blk % (NN/32)) * 32;
    int tid = threadIdx.x;
    #pragma unroll
    for (int i = 0; i < 32; i++) {
        int idx = i*256 + tid;
        int c = idx >> 5, n = idx & 31;
        tile[c*33 + n] = x[(size_t)(b*C_ + c)*NN + n0 + n];
    }
    __syncthreads();
    int wid = tid >> 5, lane = tid & 31;
    #pragma unroll
    for (int j = 0; j < 4; j++) {
        int n = wid*4 + j;
        float s1 = 0, s2 = 0;
        #pragma unroll
        for (int i = 0; i < 8; i++) {
            float v = tile[(lane + i*32)*33 + n];
            s1 += v; s2 += v*v;
        }
        #pragma unroll
        for (int o = 16; o; o >>= 1) {
            s1 += __shfl_xor_sync(~0u, s1, o);
            s2 += __shfl_xor_sync(~0u, s2, o);
        }
        if (lane == 0) {
            float mu = s1*(1.0f/C_);
            float var = s2*(1.0f/C_) - mu*mu;
            smu[n] = mu; sr[n] = rsqrtf(var + 1e-6f);
        }
    }
    __syncthreads();
    #pragma unroll
    for (int i = 0; i < 32; i++) {
        int idx = i*256 + tid;
        int n = idx >> 8, c = idx & 255;
        float v = tile[c*33 + n];
        g_xab[(size_t)(b*NN + n0 + n)*C_ + c] =
            __float2bfloat16((v - smu[n])*sr[n]*gg[c] + bb[c]);
    }
}

// ---------------- LN2: warp per row over g_x2 -> bf16 ----------------
__global__ void ln2_k(const float* __restrict__ gg, const float* __restrict__ bb) {
    int row = (blockIdx.x*256 + threadIdx.x) >> 5;
    int lane = threadIdx.x & 31;
    const float* p = &g_x2[(size_t)row*C_];
    float v[8]; float s1 = 0, s2 = 0;
    #pragma unroll
    for (int i = 0; i < 8; i++) { v[i] = p[lane + i*32]; s1 += v[i]; s2 += v[i]*v[i]; }
    #pragma unroll
    for (int o = 16; o; o >>= 1) {
        s1 += __shfl_xor_sync(~0u, s1, o);
        s2 += __shfl_xor_sync(~0u, s2, o);
    }
    float mu = s1*(1.0f/C_);
    float var = s2*(1.0f/C_) - mu*mu;
    float r = rsqrtf(var + 1e-6f);
    #pragma unroll
    for (int i = 0; i < 8; i++) {
        int c = lane + i*32;
        g_ln2b[(size_t)row*C_ + c] = __float2bfloat16((v[i]-mu)*r*gg[c] + bb[c]);
    }
}

// ---------------- per-(b,h) partial sums of q,k,v ----------------
__global__ void bh_sums1_k() {
    int bh = blockIdx.x, yy = blockIdx.y;     // 16 x 12
    int t = threadIdx.x;
    int d = t & 31, part = t >> 5;
    float sq = 0, sk = 0, sv = 0;
    int n0 = yy*192 + part*24;
    for (int j = 0; j < 24; j++) {
        int idx = (bh*NN + n0 + j)*DH + d;
        sq += g_q[idx]; sk += g_k[idx]; sv += g_v[idx];
    }
    __shared__ float sh[3][8][32];
    sh[0][part][d]=sq; sh[1][part][d]=sk; sh[2][part][d]=sv;
    __syncthreads();
    if (t < 96) {
        int which = t >> 5, dd = t & 31;
        float s = 0;
        #pragma unroll
        for (int p = 0; p < 8; p++) s += sh[which][p][dd];
        g_spart[((bh*12 + yy)*3 + which)*DH + dd] = s;
    }
}

// ---------------- reduce partials + row/col pruning scores ----------------
__global__ void scores_k() {
    int bh = blockIdx.x, yy = blockIdx.y;      // 16 x 9
    int t = threadIdx.x;
    __shared__ float qs[DH], ks[DH];
    if (t < 96) {
        int which = t >> 5, d = t & 31;
        float s = 0;
        #pragma unroll
        for (int y = 0; y < 12; y++) s += g_spart[((bh*12 + y)*3 + which)*DH + d];
        if (which == 0) qs[d] = s;
        else if (which == 1) ks[d] = s;
        if (yy == 0) g_sums[(bh*3 + which)*DH + d] = s;
    }
    __syncthreads();
    int gid = bh*NN + yy*256 + t;
    float r = 0, c = 0;
    const float4* qp = (const float4*)&g_q[(size_t)gid*DH];
    const float4* kp = (const float4*)&g_k[(size_t)gid*DH];
    #pragma unroll
    for (int w = 0; w < 8; w++) {
        float4 qf = qp[w], kf = kp[w];
        r += qf.x*ks[4*w] + qf.y*ks[4*w+1] + qf.z*ks[4*w+2] + qf.w*ks[4*w+3];
        c += qs[4*w]*kf.x + qs[4*w+1]*kf.y + qs[4*w+2]*kf.z + qs[4*w+3]*kf.w;
    }
    g_rs[gid] = r; g_cs[gid] = c;
}

// ---------------- exact top-k selection ----------------
__device__ __forceinline__ unsigned f2key(float f) {
    unsigned u = __float_as_uint(f);
    return (u & 0x80000000u) ? ~u : (u | 0x80000000u);
}

__device__ __forceinline__ int incl_scan256(int v, int t, int* wtot) {
    __syncthreads();
    int lane = t & 31, wid = t >> 5;
    #pragma unroll
    for (int o = 1; o < 32; o <<= 1) {
        int u = __shfl_up_sync(~0u, v, o);
        if (lane >= o) v += u;
    }
    if (lane == 31) wtot[wid] = v;
    __syncthreads();
    if (wid == 0) {
        int s = (lane < 8) ? wtot[lane] : 0;
        #pragma unroll
        for (int o = 1; o < 8; o <<= 1) {
            int u = __shfl_up_sync(~0u, s, o);
            if (lane >= o) s += u;
        }
        if (lane < 8) wtot[lane] = s;
    }
    __syncthreads();
    return v + (wid > 0 ? wtot[wid-1] : 0);
}

__global__ void select_k() {
    int blk = blockIdx.x;
    int type = blk >> 4, bh = blk & 15;
    const float* s = (type == 0 ? g_rs : g_cs) + bh*NN;
    int* list = (type == 0 ? g_rowlist : g_collist) + bh*KTOP;
    __shared__ unsigned keys[NN];
    __shared__ int hist[256];
    __shared__ int wtot[8];
    __shared__ unsigned sh_T;
    __shared__ int sh_take;
    int t = threadIdx.x;
    for (int i = t; i < NN; i += 256) keys[i] = f2key(s[i]);
    __syncthreads();

    unsigned prefix = 0, pmask = 0;
    int kneed = KTOP;
    for (int pass = 0; pass < 4; pass++) {
        int shift = 24 - 8*pass;
        hist[t] = 0;
        __syncthreads();
        for (int i = t; i < NN; i += 256) {
            unsigned u = keys[i];
            if ((u & pmask) == prefix) atomicAdd(&hist[(u >> shift) & 255], 1);
        }
        __syncthreads();
        int h = hist[t];
        int pre = incl_scan256(h, t, wtot);
        int total = wtot[7];
        int cum = total - pre;
        if (cum < kneed && cum + h >= kneed) {
            sh_T = prefix | ((unsigned)t << shift);
            sh_take = kneed - cum;
        }
        __syncthreads();
        prefix = sh_T;
        kneed = sh_take;
        pmask |= (0xffu << shift);
        __syncthreads();
    }
    unsigned T = prefix;
    int take = kneed;

    unsigned myk[9];
    int eqc = 0;
    #pragma unroll
    for (int j = 0; j < 9; j++) {
        myk[j] = keys[t*9 + j];
        eqc += (myk[j] == T);
    }
    int eqbase = incl_scan256(eqc, t, wtot) - eqc;

    bool kept[9];
    int keptc = 0, eqseen = 0;
    #pragma unroll
    for (int j = 0; j < 9; j++) {
        unsigned u = myk[j];
        bool gt = (u > T), eq = (u == T);
        bool kp = gt || (eq && (eqbase + eqseen) < take);
        if (eq) eqseen++;
        kept[j] = kp; keptc += kp;
    }
    int wbase = incl_scan256(keptc, t, wtot) - keptc;
    #pragma unroll
    for (int j = 0; j < 9; j++)
        if (kept[j]) list[wbase++] = t*9 + j;
}

// ---------------- v_unkept ----------------
__global__ void vunkept_k() {
    int bh = blockIdx.x;
    int t = threadIdx.x;
    int d = t & 31, part = t >> 5;
    float sv = 0;
    for (int jj = part; jj < KTOP; jj += 8) {
        int j = g_collist[bh*KTOP + jj];
        sv += g_v[(bh*NN + j)*DH + d];
    }
    __shared__ float sh[8][32];
    sh[part][d] = sv;
    __syncthreads();
    if (t < 32) {
        float s = 0;
        #pragma unroll
        for (int p = 0; p < 8; p++) s += sh[p][t];
        g_vunk[bh*DH + t] = g_sums[(bh*3+2)*DH + t] - s;
    }
}

// ---------------- pruned rows: mean(v) -> bf16 ----------------
__global__ void fill_o_k() {
    int gid = blockIdx.x*256 + threadIdx.x;
    if (gid >= BHN*NN*DH) return;
    int bh = gid / (NN*DH);
    int r = gid % (NN*DH);
    int n = r / DH, d = r & 31;
    int b = bh >> 3, h = bh & 7;
    g_ob[(size_t)(b*NN + n)*C_ + h*DH + d] =
        __float2bfloat16(g_sums[(bh*3+2)*DH + d] * (1.0f/NN));
}

// ---------------- kept-row attention partials (packed f32x2) ----------------
__global__ __launch_bounds__(64) void attn_part_k() {
    int bh = blockIdx.x;
    int t = threadIdx.x;                      // 64
    int slot = blockIdx.y*64 + t;
    int chunk = blockIdx.z;
    int i = g_rowlist[bh*KTOP + slot];

    unsigned long long qp2[16];
    {
        const float4* qp = (const float4*)&g_q[(size_t)(bh*NN + i)*DH];
        #pragma unroll
        for (int w = 0; w < 8; w++) {
            float4 f = qp[w];
            qp2[2*w  ] = pack2(f.x, f.y);
            qp2[2*w+1] = pack2(f.z, f.w);
        }
    }

    float m = -3.0e38f, Z = 0.f;
    unsigned long long acc2[16];
    #pragma unroll
    for (int idx = 0; idx < 16; idx++) acc2[idx] = 0ull;   // (0.0f, 0.0f)

    __shared__ int cj[96];
    __shared__ __align__(16) float Kc[96][DH];
    __shared__ __align__(16) float Vc[96][DH];

    for (int c0 = chunk*CHUNK; c0 < chunk*CHUNK + CHUNK; c0 += 96) {
        __syncthreads();
        for (int jj = t; jj < 96; jj += 64) cj[jj] = g_collist[bh*KTOP + c0 + jj];
        __syncthreads();
        for (int idx = t; idx < 96*DH; idx += 64) {
            int jj = idx >> 5, d = idx & 31;
            int base = (bh*NN + cj[jj])*DH + d;
            Kc[jj][d] = g_k[base];
            Vc[jj][d] = g_v[base];
        }
        __syncthreads();
        #pragma unroll 2
        for (int jj = 0; jj < 96; jj++) {
            const unsigned long long* kp = (const unsigned long long*)Kc[jj];
            unsigned long long p0 = 0ull, p1 = 0ull;
            #pragma unroll
            for (int w = 0; w < 16; w += 2) {
                p0 = fma2(qp2[w  ], kp[w  ], p0);
                p1 = fma2(qp2[w+1], kp[w+1], p1);
            }
            float a, b2, c2, d2;
            unpack2(p0, a, b2); unpack2(p1, c2, d2);
            float s = (a + b2) + (c2 + d2);
            float e;
            if (s > m) {
                float cf = __expf(m - s);
                unsigned long long cf2 = pack2(cf, cf);
                Z = Z*cf;
                #pragma unroll
                for (int w = 0; w < 16; w++) acc2[w] = mul2(acc2[w], cf2);
                m = s;
                e = 1.f;
            } else {
                e = __expf(s - m);
            }
            Z += e;
            unsigned long long ee = pack2(e, e);
            const unsigned long long* vp = (const unsigned long long*)Vc[jj];
            #pragma unroll
            for (int w = 0; w < 16; w++) acc2[w] = fma2(ee, vp[w], acc2[w]);
        }
    }
    int pidx = (bh*KTOP + slot)*NSPLIT + chunk;
    g_pm[pidx] = m;
    g_pz[pidx] = Z;
    float* pa = &g_pacc[(size_t)pidx*DH];
    #pragma unroll
    for (int w = 0; w < 16; w++) {
        float lo, hi;
        unpack2(acc2[w], lo, hi);
        pa[2*w] = lo; pa[2*w+1] = hi;
    }
}

// ---------------- combine partials + zero-column correction -> bf16 ----------------
__global__ void attn_comb_k() {
    int gid = blockIdx.x*128 + threadIdx.x;
    if (gid >= BHN*KTOP) return;
    int bh = gid / KTOP, slot = gid % KTOP;
    int i = g_rowlist[bh*KTOP + slot];
    int p0 = gid*NSPLIT;
    float m0 = g_pm[p0], m1 = g_pm[p0+1], m2 = g_pm[p0+2];
    float mstar = fmaxf(0.f, fmaxf(m0, fmaxf(m1, m2)));
    float e0 = __expf(m0 - mstar), e1 = __expf(m1 - mstar), e2 = __expf(m2 - mstar);
    float ez = __expf(-mstar);
    float Z = g_pz[p0]*e0 + g_pz[p0+1]*e1 + g_pz[p0+2]*e2 + (float)(NN - KTOP)*ez;
    float invZ = 1.f / Z;
    const float* a0 = &g_pacc[(size_t)p0*DH];
    const float* a1 = &g_pacc[(size_t)(p0+1)*DH];
    const float* a2 = &g_pacc[(size_t)(p0+2)*DH];
    const float* vu = &g_vunk[bh*DH];
    int b = bh >> 3, h = bh & 7;
    __nv_bfloat16* op = &g_ob[(size_t)(b*NN + i)*C_ + h*DH];
    #pragma unroll
    for (int d = 0; d < DH; d++)
        op[d] = __float2bfloat16((a0[d]*e0 + a1[d]*e1 + a2[d]*e2 + ez*vu[d]) * invZ);
}

// ---------------- depthwise 3x3 conv (writes [C][B*NN] f32) ----------------
__global__ void dw_k(const float* __restrict__ x,
                     const float* __restrict__ w,
                     const float* __restrict__ bias) {
    int gid = blockIdx.x*256 + threadIdx.x;
    if (gid >= B_*C_*NN) return;
    int n = gid % NN;
    int bc = gid / NN;
    int c = bc % C_, b = bc / C_;
    int y = n / WW, x0 = n % WW;
    float acc = bias[c];
    const float* xp = &x[(size_t)(b*C_ + c)*NN];
    const float* wp = &w[c*9];
    #pragma unroll
    for (int dy = 0; dy < 3; dy++) {
        int yy = y + dy - 1;
        if (yy < 0 || yy >= HH) continue;
        #pragma unroll
        for (int dx = 0; dx < 3; dx++) {
            int xx = x0 + dx - 1;
            if (xx < 0 || xx >= WW) continue;
            acc += xp[yy*WW + xx] * wp[dy*3 + dx];
        }
    }
    g_xdw[(size_t)c*(B_*NN) + b*NN + n] = acc;
}

// ---------------- spatial gate stage 1 ----------------
__global__ __launch_bounds__(256) void sg1_k(const float* __restrict__ w,
                                             const float* __restrict__ bias) {
    __shared__ float ws[C_*33];
    __shared__ float rows[8][C_];
    int tid = threadIdx.x;
    for (int i = tid; i < GG*C_; i += 256) {
        int go = i >> 8, ci = i & 255;
        ws[ci*33 + go] = w[go*C_ + ci];
    }
    int bn0 = blockIdx.x * 8;
    for (int i = tid; i < 8*C_; i += 256)
        rows[i >> 8][i & 255] = g_xs[(size_t)(bn0 + (i >> 8))*C_ + (i & 255)];
    __syncthreads();
    int px = tid >> 5, go = tid & 31;
    float acc = bias[go];
    #pragma unroll 4
    for (int ci = 0; ci < C_; ci++)
        acc += rows[px][ci] * ws[ci*33 + go];
    g_t1[(bn0 + px)*GG + go] = acc / (1.f + expf(-acc));
}

// ---------------- spatial gate stage 2 ----------------
__global__ __launch_bounds__(256) void sg2_k(const float* __restrict__ w,
                                             const float* __restrict__ bias) {
    __shared__ float ws[GG*49];
    int tid = threadIdx.x;
    for (int i = tid; i < GG*49; i += 256) ws[i] = w[i];
    __syncthreads();
    int p = blockIdx.x*8 + (tid >> 5);
    int lane = tid & 31;
    int b = p / NN, n = p % NN;
    int y = n / WW, x0 = n % WW;
    float acc = 0.f;
    for (int ky = 0; ky < 7; ky++) {
        int yy = y + ky - 3;
        if (yy < 0 || yy >= HH) continue;
        #pragma unroll
        for (int kx = 0; kx < 7; kx++) {
            int xx = x0 + kx - 3;
            if (xx < 0 || xx >= WW) continue;
            acc += g_t1[(b*NN + yy*WW + xx)*GG + lane] * ws[lane*49 + ky*7 + kx];
        }
    }
    #pragma unroll
    for (int o = 16; o; o >>= 1) acc += __shfl_xor_sync(~0u, acc, o);
    if (lane == 0) g_sg[p] = 1.f / (1.f + expf(-(acc + bias[0])));
}

// ---------------- channel gate: pool partials ----------------
__global__ void cgpool_k() {
    int blk = blockIdx.x;
    int b = blk / 16, part = blk % 16;
    int c = threadIdx.x;
    float s = 0;
    int n0 = part*144;
    for (int n = n0; n < n0 + 144; n++) s += g_xs[(size_t)(b*NN + n)*C_ + c];
    g_cgpart[blk*C_ + c] = s;
}

// ---------------- channel gate: combine ----------------
__global__ void cggate_k(const float* __restrict__ w1, const float* __restrict__ b1,
                         const float* __restrict__ w2, const float* __restrict__ b2) {
    int b = blockIdx.x;
    int c = threadIdx.x;
    __shared__ float cgm[C_];
    __shared__ float t2[GG];
    float s = 0;
    for (int p = 0; p < 16; p++) s += g_cgpart[(b*16 + p)*C_ + c];
    cgm[c] = s * (1.0f/NN);
    __syncthreads();
    if (c < GG) {
        float a = b1[c];
        const float* wp = &w1[c*C_];
        for (int ci = 0; ci < C_; ci++) a += cgm[ci]*wp[ci];
        t2[c] = a / (1.f + expf(-a));
    }
    __syncthreads();
    float a2 = b2[c];
    const float* wp2 = &w2[c*GG];
    #pragma unroll
    for (int g = 0; g < GG; g++) a2 += t2[g]*wp2[g];
    g_cg[b*C_ + c] = 1.f / (1.f + expf(-a2));
}

// ---------------- x2 = x + gamma1*xs*sg*cg ----------------
__global__ __launch_bounds__(256) void x2_k(const float* __restrict__ x,
                                            const float* __restrict__ gamma1) {
    __shared__ float tile[C_*33];
    int blk = blockIdx.x;
    int b = blk / (NN/32);
    int n0 = (blk % (NN/32)) * 32;
    int tid = threadIdx.x;
    #pragma unroll
    for (int i = 0; i < 32; i++) {
        int idx = i*256 + tid;
        int c = idx >> 5, n = idx & 31;
        tile[c*33 + n] = x[(size_t)(b*C_ + c)*NN + n0 + n];
    }
    __syncthreads();
    float gm = gamma1[0];
    #pragma unroll
    for (int i = 0; i < 32; i++) {
        int idx = i*256 + tid;
        int n = idx >> 8, c = idx & 255;
        int row = b*NN + n0 + n;
        g_x2[(size_t)row*C_ + c] =
            tile[c*33 + n] + gm * g_xs[(size_t)row*C_ + c] * g_sg[row] * g_cg[b*C_ + c];
    }
}

// ---------------- host ----------------
#define GETSYM(p, s, T) do { void* _t; cudaGetSymbolAddress(&_t, s); p = (T*)_t; } while (0)

extern "C" void kernel_launch(void* const* d_in, const int* in_sizes, int n_in,
                              void* d_out, int out_size) {
    const float* x     = (const float*)d_in[0];
    const float* qkv_w = (const float*)d_in[1];
    const float* out_w = (const float*)d_in[2];
    const float* ln1_g = (const float*)d_in[3];
    const float* ln1_b = (const float*)d_in[4];
    const float* ln2_g = (const float*)d_in[5];
    const float* ln2_b = (const float*)d_in[6];
    const float* dw_w  = (const float*)d_in[7];
    const float* dw_b  = (const float*)d_in[8];
    const float* pw_w  = (const float*)d_in[9];
    const float* pw_b  = (const float*)d_in[10];
    const float* sg1_w = (const float*)d_in[11];
    const float* sg1_b = (const float*)d_in[12];
    const float* sg2_w = (const float*)d_in[13];
    const float* sg2_b = (const float*)d_in[14];
    const float* cg1_w = (const float*)d_in[15];
    const float* cg1_b = (const float*)d_in[16];
    const float* cg2_w = (const float*)d_in[17];
    const float* cg2_b = (const float*)d_in[18];
    const float* ff_w1 = (const float*)d_in[19];
    const float* ff_b1 = (const float*)d_in[20];
    const float* ff_w2 = (const float*)d_in[21];
    const float* ff_b2 = (const float*)d_in[22];
    const float* gamma1= (const float*)d_in[23];
    const float* gamma2= (const float*)d_in[24];
    float* out = (float*)d_out;
    (void)in_sizes; (void)n_in; (void)out_size;

    float *p_xdw, *p_xc, *p_xs;
    __nv_bfloat16 *p_xab, *p_ob, *p_xdwb, *p_ln2b, *p_hb;
    __nv_bfloat16 *p_wqt, *p_wot, *p_wpwb, *p_w1t, *p_w2t;
    GETSYM(p_xdw, g_xdw, float); GETSYM(p_xc, g_xc, float); GETSYM(p_xs, g_xs, float);
    GETSYM(p_xab, g_xab, __nv_bfloat16); GETSYM(p_ob, g_ob, __nv_bfloat16);
    GETSYM(p_xdwb, g_xdwb, __nv_bfloat16);
    GETSYM(p_ln2b, g_ln2b, __nv_bfloat16); GETSYM(p_hb, g_hb, __nv_bfloat16);
    GETSYM(p_wqt, g_wqt, __nv_bfloat16); GETSYM(p_wot, g_wot, __nv_bfloat16);
    GETSYM(p_wpwb, g_wpwb, __nv_bfloat16);
    GETSYM(p_w1t, g_w1t, __nv_bfloat16); GETSYM(p_w2t, g_w2t, __nv_bfloat16);

    const int M = B_*NN;   // 4608

    // prep (QKV gemm at profiled launch idx 3)
    ln1_k<<<B_*NN/32, 256>>>(x, ln1_g, ln1_b);
    tconv_k<<<dim3(768/32, C_/32), 256>>>(qkv_w, p_wqt, C_, 768);
    dw_k<<<(B_*C_*NN)/256, 256>>>(x, dw_w, dw_b);
    gemm_bf<128,128,2><<<dim3(768/128, M/128), 256>>>(
        p_xab, p_wqt, nullptr, nullptr, nullptr, M, 3*C_, C_);
    tconv_k<<<dim3(C_/32, C_/32), 256>>>(out_w, p_wot, C_, C_);
    cvt_k<<<(C_*C_)/256, 256>>>(pw_w, p_wpwb, C_*C_);
    tconv_k<<<dim3(M/32, C_/32), 256>>>(p_xdw, p_xdwb, C_, M);
    gemm_bf<128,64,0><<<dim3(C_/64, M/128), 256>>>(
        p_xdwb, p_wpwb, p_xc, nullptr, nullptr, M, C_, C_);
    // attention stats + selection
    bh_sums1_k<<<dim3(BHN, 12), 256>>>();
    scores_k<<<dim3(BHN, 9), 256>>>();
    select_k<<<32, 256>>>();
    vunkept_k<<<BHN, 256>>>();
    fill_o_k<<<(BHN*NN*DH)/256, 256>>>();
    attn_part_k<<<dim3(BHN, 9, NSPLIT), 64>>>();
    attn_comb_k<<<(BHN*KTOP + 127)/128, 128>>>();
    // out-proj epilogue: xs = o@out_w + xc + pw_b
    gemm_bf<128,64,3><<<dim3(C_/64, M/128), 256>>>(
        p_ob, p_wot, p_xs, pw_b, nullptr, M, C_, C_);

    // gates
    sg1_k<<<B_*NN/8, 256>>>(sg1_w, sg1_b);
    sg2_k<<<B_*NN/8, 256>>>(sg2_w, sg2_b);
    cgpool_k<<<B_*16, 256>>>();
    cggate_k<<<B_, 256>>>(cg1_w, cg1_b, cg2_w, cg2_b);
    x2_k<<<B_*NN/32, 256>>>(x, gamma1);

    // FFN (bf16)
    ln2_k<<<M/8, 256>>>(ln2_g, ln2_b);
    tconv_k<<<dim3(HID/32, C_/32), 256>>>(ff_w1, p_w1t, C_, HID);
    tconv_k<<<dim3(C_/32, HID/32), 256>>>(ff_w2, p_w2t, HID, C_);
    gemm_bf<128,128,1><<<dim3(HID/128, M/128), 256>>>(
        p_ln2b, p_w1t, p_hb, ff_b1, nullptr, M, HID, C_);
    gemm_bf<128,64,4><<<dim3(C_/64, M/128), 256>>>(
        p_hb, p_w2t, out, ff_b2, gamma2, M, C_, HID);
}

// round 12
// speedup vs baseline: 3.7523x; 1.0579x over previous
#include <cuda_runtime.h>
#include <cuda_bf16.h>
#include <math.h>

#define B_ 2
#define C_ 256
#define HH 48
#define WW 48
#define NN 2304          // 48*48
#define NHEAD 8
#define DH 32
#define BHN 16           // B_*NHEAD
#define KTOP 576
#define HID 1024
#define GG 32            // C/8 gate channels
#define QSCALE 0.17677669529663687f   // 1/sqrt(32)
#define NSPLIT 3         // attention column-split
#define CHUNK 192        // KTOP / NSPLIT

// ---------------- scratch (static device arrays; no allocation) ----------------
__device__ __nv_bfloat16 g_xab[B_*NN*C_];      // ln1 out (bf16)
__device__ __nv_bfloat16 g_qb [BHN*NN*DH];
__device__ __nv_bfloat16 g_kb [BHN*NN*DH];
__device__ __nv_bfloat16 g_vb [BHN*NN*DH];
__device__ float g_spart[BHN*12*3*DH];
__device__ float g_sums[BHN*3*DH];
__device__ float g_rs  [BHN*NN];
__device__ float g_cs  [BHN*NN];
__device__ int   g_rowlist[BHN*KTOP];
__device__ int   g_collist[BHN*KTOP];
__device__ float g_vunk[BHN*DH];
__device__ float g_pm  [BHN*KTOP*NSPLIT];
__device__ float g_pz  [BHN*KTOP*NSPLIT];
__device__ float g_pacc[BHN*KTOP*NSPLIT*DH];
__device__ __nv_bfloat16 g_ob [B_*NN*C_];      // attention out (bf16, gemm A)
__device__ float g_xdw [C_*B_*NN];             // dw out [c][b*NN+n]
__device__ __nv_bfloat16 g_xdwb[B_*NN*C_];     // dw out transposed [M][C] bf16
__device__ float g_xc  [B_*NN*C_];
__device__ float g_xs  [B_*NN*C_];
__device__ __nv_bfloat16 g_xsb[B_*NN*C_];      // xs bf16 (sg1 gemm A)
__device__ float g_t1  [B_*NN*GG];
__device__ float g_sg  [B_*NN];
__device__ float g_cgpart[B_*16*C_];
__device__ float g_cg  [B_*C_];
__device__ float g_x2  [B_*NN*C_];
__device__ __nv_bfloat16 g_ln2b[B_*NN*C_];
__device__ __nv_bfloat16 g_hb  [B_*NN*HID];
__device__ __nv_bfloat16 g_wqt [3*C_*C_];      // qkv_w^T [768][256]
__device__ __nv_bfloat16 g_wot [C_*C_];        // out_w^T [256][256]
__device__ __nv_bfloat16 g_wpwb[C_*C_];        // pw_w ([N][K]) bf16
__device__ __nv_bfloat16 g_wsg1[GG*C_];        // sg1_w ([N][K]) bf16
__device__ __nv_bfloat16 g_w1t [HID*C_];       // ff_w1^T [1024][256]
__device__ __nv_bfloat16 g_w2t [C_*HID];       // ff_w2^T [256][1024]

// ---------------- helpers ----------------
__device__ __forceinline__ void cp16(void* sptr, const void* gptr) {
    unsigned saddr = (unsigned)__cvta_generic_to_shared(sptr);
    asm volatile("cp.async.cg.shared.global [%0], [%1], 16;" :: "r"(saddr), "l"(gptr));
}
__device__ __forceinline__ void cp_commit() { asm volatile("cp.async.commit_group;"); }
__device__ __forceinline__ void cp_wait0()  { asm volatile("cp.async.wait_group 0;" ::: "memory"); }

__device__ __forceinline__ void mma_bf16(float* d, const unsigned* a,
                                         const unsigned* b, const float* c) {
    asm volatile("mma.sync.aligned.m16n8k16.row.col.f32.bf16.bf16.f32 "
        "{%0,%1,%2,%3}, {%4,%5,%6,%7}, {%8,%9}, {%10,%11,%12,%13};"
        : "=f"(d[0]),"=f"(d[1]),"=f"(d[2]),"=f"(d[3])
        : "r"(a[0]),"r"(a[1]),"r"(a[2]),"r"(a[3]),
          "r"(b[0]),"r"(b[1]),
          "f"(c[0]),"f"(c[1]),"f"(c[2]),"f"(c[3]));
}
__device__ __forceinline__ unsigned long long pack2(float lo, float hi) {
    unsigned long long r;
    asm("mov.b64 %0, {%1, %2};" : "=l"(r) : "f"(lo), "f"(hi));
    return r;
}
__device__ __forceinline__ void unpack2(unsigned long long v, float& lo, float& hi) {
    asm("mov.b64 {%0, %1}, %2;" : "=f"(lo), "=f"(hi) : "l"(v));
}
__device__ __forceinline__ unsigned long long fma2(unsigned long long a,
                                                   unsigned long long b,
                                                   unsigned long long c) {
    unsigned long long d;
    asm("fma.rn.f32x2 %0, %1, %2, %3;" : "=l"(d) : "l"(a), "l"(b), "l"(c));
    return d;
}
__device__ __forceinline__ unsigned long long mul2(unsigned long long a,
                                                   unsigned long long b) {
    unsigned long long d;
    asm("mul.rn.f32x2 %0, %1, %2;" : "=l"(d) : "l"(a), "l"(b));
    return d;
}
__device__ __forceinline__ float2 bf2f(unsigned u) {
    __nv_bfloat162 h = *reinterpret_cast<__nv_bfloat162*>(&u);
    return __bfloat1622float2(h);
}

// ---------------- bf16 tensor-core GEMM (A [M,K] bf16, B [N,K] bf16), BK=16 ----------------
// EPI: 0=plain f32   1=bias+gelu->bf16   2=qkv scatter (bf16 q/k/v)
//      3=xs: f32 g_xs + bf16 g_xsb = v + g_xc + bias
//      4=final: out = x2 + gamma2*(v+bias), NCHW f32
//      5=sg1: silu(v+bias) -> f32 g_t1 (N=32)
template<int BM, int BN, int EPI>
__global__ __launch_bounds__(256, 2)
void gemm_bf(const __nv_bfloat16* __restrict__ A, const __nv_bfloat16* __restrict__ B,
             void* __restrict__ Cout, const float* __restrict__ bias,
             const float* __restrict__ aux, int M, int N, int K) {
    constexpr int BK = 16;
    constexpr int WM = BM/2, WN = BN/4;
    constexpr int MT = WM/16, NT = WN/8;
    constexpr int STR = 24;

    __shared__ __align__(16) __nv_bfloat16 As[2][BM*STR];
    __shared__ __align__(16) __nv_bfloat16 Bs[2][BN*STR];

    const int bm = blockIdx.y*BM, bn = blockIdx.x*BN;
    const int tid = threadIdx.x;
    const int lane = tid & 31, wid = tid >> 5;
    const int wm = wid >> 2, wn = wid & 3;
    const int g = lane >> 2, tig = lane & 3;

    float acc[MT][NT][4];
    #pragma unroll
    for (int i = 0; i < MT; i++)
        #pragma unroll
        for (int j = 0; j < NT; j++)
            #pragma unroll
            for (int l = 0; l < 4; l++) acc[i][j][l] = 0.f;

    auto copy_tile = [&](int st, int k0) {
        {
            int ch = tid;
            int row = ch >> 1, c8 = (ch & 1)*8;
            cp16(&As[st][row*STR + c8], &A[(size_t)(bm+row)*K + k0 + c8]);
        }
        {
            constexpr int CB = BN*2;
            int ch = tid;
            if (CB == 256 || ch < CB) {
                int row = ch >> 1, c8 = (ch & 1)*8;
                cp16(&Bs[st][row*STR + c8], &B[(size_t)(bn+row)*K + k0 + c8]);
            }
        }
    };

    copy_tile(0, 0);
    cp_commit();
    int stage = 0;
    for (int k0 = 0; k0 < K; k0 += BK) {
        cp_wait0();
        __syncthreads();
        if (k0 + BK < K) { copy_tile(stage^1, k0+BK); cp_commit(); }
        const __nv_bfloat16* as = As[stage];
        const __nv_bfloat16* bs = Bs[stage];
        int kk = 2*tig;
        unsigned afr[MT][4];
        #pragma unroll
        for (int mt = 0; mt < MT; mt++) {
            int r0 = wm*WM + mt*16 + g;
            afr[mt][0] = *(const unsigned*)&as[(r0  )*STR + kk  ];
            afr[mt][1] = *(const unsigned*)&as[(r0+8)*STR + kk  ];
            afr[mt][2] = *(const unsigned*)&as[(r0  )*STR + kk+8];
            afr[mt][3] = *(const unsigned*)&as[(r0+8)*STR + kk+8];
        }
        unsigned bfr[NT][2];
        #pragma unroll
        for (int nt = 0; nt < NT; nt++) {
            int c0 = wn*WN + nt*8 + g;
            bfr[nt][0] = *(const unsigned*)&bs[c0*STR + kk  ];
            bfr[nt][1] = *(const unsigned*)&bs[c0*STR + kk+8];
        }
        #pragma unroll
        for (int mt = 0; mt < MT; mt++)
            #pragma unroll
            for (int nt = 0; nt < NT; nt++)
                mma_bf16(acc[mt][nt], afr[mt], bfr[nt], acc[mt][nt]);
        stage ^= 1;
    }

    #pragma unroll
    for (int mt = 0; mt < MT; mt++) {
        int row0 = bm + wm*WM + mt*16 + g;
        #pragma unroll
        for (int nt = 0; nt < NT; nt++) {
            int col = bn + wn*WN + nt*8 + tig*2;
            #pragma unroll
            for (int half = 0; half < 2; half++) {
                int row = row0 + half*8;
                float v0 = acc[mt][nt][half*2], v1 = acc[mt][nt][half*2+1];
                if (EPI == 0) {
                    *(float2*)&((float*)Cout)[(size_t)row*N + col] = make_float2(v0, v1);
                } else if (EPI == 1) {
                    v0 += bias[col]; v1 += bias[col+1];
                    v0 = 0.5f*v0*(1.0f + erff(v0*0.70710678118654752f));
                    v1 = 0.5f*v1*(1.0f + erff(v1*0.70710678118654752f));
                    __nv_bfloat162 p;
                    p.x = __float2bfloat16(v0); p.y = __float2bfloat16(v1);
                    *(__nv_bfloat162*)&((__nv_bfloat16*)Cout)[(size_t)row*N + col] = p;
                } else if (EPI == 2) {
                    int b = row / NN, n = row - b*NN;
                    int part = col >> 8, cc = col & 255;
                    int h = cc >> 5, d = cc & 31;
                    size_t dst = ((size_t)(b*NHEAD + h)*NN + n)*DH + d;
                    __nv_bfloat162 p;
                    if (part == 0) {
                        p.x = __float2bfloat16(v0*QSCALE);
                        p.y = __float2bfloat16(v1*QSCALE);
                        *(__nv_bfloat162*)&g_qb[dst] = p;
                    } else if (part == 1) {
                        p.x = __float2bfloat16(v0); p.y = __float2bfloat16(v1);
                        *(__nv_bfloat162*)&g_kb[dst] = p;
                    } else {
                        p.x = __float2bfloat16(v0); p.y = __float2bfloat16(v1);
                        *(__nv_bfloat162*)&g_vb[dst] = p;
                    }
                } else if (EPI == 3) {
                    v0 += g_xc[(size_t)row*C_ + col]   + bias[col];
                    v1 += g_xc[(size_t)row*C_ + col+1] + bias[col+1];
                    *(float2*)&((float*)Cout)[(size_t)row*N + col] = make_float2(v0, v1);
                    __nv_bfloat162 p;
                    p.x = __float2bfloat16(v0); p.y = __float2bfloat16(v1);
                    *(__nv_bfloat162*)&g_xsb[(size_t)row*C_ + col] = p;
                } else if (EPI == 4) {
                    int b = row / NN, n = row - b*NN;
                    float gm = aux[0];
                    float o0 = g_x2[(size_t)row*C_ + col]   + gm*(v0 + bias[col]);
                    float o1 = g_x2[(size_t)row*C_ + col+1] + gm*(v1 + bias[col+1]);
                    float* C = (float*)Cout;
                    C[(size_t)(b*C_ + col  )*NN + n] = o0;
                    C[(size_t)(b*C_ + col+1)*NN + n] = o1;
                } else { // EPI == 5
                    v0 += bias[col]; v1 += bias[col+1];
                    v0 = v0 / (1.f + expf(-v0));
                    v1 = v1 / (1.f + expf(-v1));
                    *(float2*)&((float*)Cout)[(size_t)row*N + col] = make_float2(v0, v1);
                }
            }
        }
    }
}

// ---------------- merged weight prep: transposes + converts ----------------
__global__ __launch_bounds__(256) void wprep_k(const float* __restrict__ qkv_w,
                                               const float* __restrict__ out_w,
                                               const float* __restrict__ ff_w1,
                                               const float* __restrict__ ff_w2,
                                               const float* __restrict__ pw_w,
                                               const float* __restrict__ sg1_w) {
    __shared__ float tile[32][33];
    int bb = blockIdx.x;
    if (bb < 768) {
        const float* in; __nv_bfloat16* outp; int K, N, t0;
        if (bb < 192)      { in = qkv_w; outp = g_wqt; K = 256; N = 768;  t0 = bb; }
        else if (bb < 256) { in = out_w; outp = g_wot; K = 256; N = 256;  t0 = bb-192; }
        else if (bb < 512) { in = ff_w1; outp = g_w1t; K = 256; N = 1024; t0 = bb-256; }
        else               { in = ff_w2; outp = g_w2t; K = 1024; N = 256; t0 = bb-512; }
        int ntile = N/32;
        int nb = (t0 % ntile)*32, kb = (t0 / ntile)*32;
        int tx = threadIdx.x & 31, ty = threadIdx.x >> 5;
        #pragma unroll
        for (int i = 0; i < 32; i += 8)
            tile[ty+i][tx] = in[(size_t)(kb+ty+i)*N + nb+tx];
        __syncthreads();
        #pragma unroll
        for (int i = 0; i < 32; i += 8)
            outp[(size_t)(nb+ty+i)*K + kb+tx] = __float2bfloat16(tile[tx][ty+i]);
    } else if (bb < 832) {
        int base = (bb-768)*1024 + threadIdx.x;
        #pragma unroll
        for (int r = 0; r < 4; r++)
            g_wpwb[base + r*256] = __float2bfloat16(pw_w[base + r*256]);
    } else {
        for (int i = threadIdx.x; i < GG*C_; i += 256)
            g_wsg1[i] = __float2bfloat16(sg1_w[i]);
    }
}

// ---------------- transpose + f32->bf16 convert (for dw output) ----------------
__global__ __launch_bounds__(256) void tconv_k(const float* __restrict__ in,
                                               __nv_bfloat16* __restrict__ out,
                                               int K, int N) {
    __shared__ float tile[32][33];
    int nb = blockIdx.x*32, kb = blockIdx.y*32;
    int tx = threadIdx.x & 31, ty = threadIdx.x >> 5;
    #pragma unroll
    for (int i = 0; i < 32; i += 8)
        tile[ty+i][tx] = in[(size_t)(kb+ty+i)*N + nb+tx];
    __syncthreads();
    #pragma unroll
    for (int i = 0; i < 32; i += 8)
        out[(size_t)(nb+ty+i)*K + kb+tx] = __float2bfloat16(tile[tx][ty+i]);
}

// ---------------- LN1: NCHW -> normalized [B*N, C] bf16 ----------------
__global__ __launch_bounds__(256) void ln1_k(const float* __restrict__ x,
                                             const float* __restrict__ gg,
                                             const float* __restrict__ bb) {
    __shared__ float tile[C_*33];
    __shared__ float smu[32], sr[32];
    int blk = blockIdx.x;
    int b = blk / (NN/32);
    int n0 = (blk % (NN/32)) * 32;
    int tid = threadIdx.x;
    #pragma unroll
    for (int i = 0; i < 32; i++) {
        int idx = i*256 + tid;
        int c = idx >> 5, n = idx & 31;
        tile[c*33 + n] = x[(size_t)(b*C_ + c)*NN + n0 + n];
    }
    __syncthreads();
    int wid = tid >> 5, lane = tid & 31;
    #pragma unroll
    for (int j = 0; j < 4; j++) {
        int n = wid*4 + j;
        float s1 = 0, s2 = 0;
        #pragma unroll
        for (int i = 0; i < 8; i++) {
            float v = tile[(lane + i*32)*33 + n];
            s1 += v; s2 += v*v;
        }
        #pragma unroll
        for (int o = 16; o; o >>= 1) {
            s1 += __shfl_xor_sync(~0u, s1, o);
            s2 += __shfl_xor_sync(~0u, s2, o);
        }
        if (lane == 0) {
            float mu = s1*(1.0f/C_);
            float var = s2*(1.0f/C_) - mu*mu;
            smu[n] = mu; sr[n] = rsqrtf(var + 1e-6f);
        }
    }
    __syncthreads();
    #pragma unroll
    for (int i = 0; i < 32; i++) {
        int idx = i*256 + tid;
        int n = idx >> 8, c = idx & 255;
        float v = tile[c*33 + n];
        g_xab[(size_t)(b*NN + n0 + n)*C_ + c] =
            __float2bfloat16((v - smu[n])*sr[n]*gg[c] + bb[c]);
    }
}

// ---------------- per-(b,h) partial sums of q,k,v (bf16 in) ----------------
__global__ void bh_sums1_k() {
    int bh = blockIdx.x, yy = blockIdx.y;     // 16 x 12
    int t = threadIdx.x;
    int d = t & 31, part = t >> 5;
    float sq = 0, sk = 0, sv = 0;
    int n0 = yy*192 + part*24;
    for (int j = 0; j < 24; j++) {
        int idx = (bh*NN + n0 + j)*DH + d;
        sq += __bfloat162float(g_qb[idx]);
        sk += __bfloat162float(g_kb[idx]);
        sv += __bfloat162float(g_vb[idx]);
    }
    __shared__ float sh[3][8][32];
    sh[0][part][d]=sq; sh[1][part][d]=sk; sh[2][part][d]=sv;
    __syncthreads();
    if (t < 96) {
        int which = t >> 5, dd = t & 31;
        float s = 0;
        #pragma unroll
        for (int p = 0; p < 8; p++) s += sh[which][p][dd];
        g_spart[((bh*12 + yy)*3 + which)*DH + dd] = s;
    }
}

// ---------------- reduce partials + row/col pruning scores ----------------
__global__ void scores_k() {
    int bh = blockIdx.x, yy = blockIdx.y;      // 16 x 9
    int t = threadIdx.x;
    __shared__ float qs[DH], ks[DH];
    if (t < 96) {
        int which = t >> 5, d = t & 31;
        float s = 0;
        #pragma unroll
        for (int y = 0; y < 12; y++) s += g_spart[((bh*12 + y)*3 + which)*DH + d];
        if (which == 0) qs[d] = s;
        else if (which == 1) ks[d] = s;
        if (yy == 0) g_sums[(bh*3 + which)*DH + d] = s;
    }
    __syncthreads();
    int gid = bh*NN + yy*256 + t;
    unsigned uq[16], uk[16];
    {
        const uint4* qp4 = (const uint4*)&g_qb[(size_t)gid*DH];
        const uint4* kp4 = (const uint4*)&g_kb[(size_t)gid*DH];
        #pragma unroll
        for (int w = 0; w < 4; w++) {
            *(uint4*)&uq[w*4] = qp4[w];
            *(uint4*)&uk[w*4] = kp4[w];
        }
    }
    float r = 0, c = 0;
    #pragma unroll
    for (int w = 0; w < 16; w++) {
        float2 fq = bf2f(uq[w]), fk = bf2f(uk[w]);
        r += fq.x*ks[2*w] + fq.y*ks[2*w+1];
        c += qs[2*w]*fk.x + qs[2*w+1]*fk.y;
    }
    g_rs[gid] = r; g_cs[gid] = c;
}

// ---------------- exact top-k selection ----------------
__device__ __forceinline__ unsigned f2key(float f) {
    unsigned u = __float_as_uint(f);
    return (u & 0x80000000u) ? ~u : (u | 0x80000000u);
}

__device__ __forceinline__ int incl_scan256(int v, int t, int* wtot) {
    __syncthreads();
    int lane = t & 31, wid = t >> 5;
    #pragma unroll
    for (int o = 1; o < 32; o <<= 1) {
        int u = __shfl_up_sync(~0u, v, o);
        if (lane >= o) v += u;
    }
    if (lane == 31) wtot[wid] = v;
    __syncthreads();
    if (wid == 0) {
        int s = (lane < 8) ? wtot[lane] : 0;
        #pragma unroll
        for (int o = 1; o < 8; o <<= 1) {
            int u = __shfl_up_sync(~0u, s, o);
            if (lane >= o) s += u;
        }
        if (lane < 8) wtot[lane] = s;
    }
    __syncthreads();
    return v + (wid > 0 ? wtot[wid-1] : 0);
}

__global__ void select_k() {
    int blk = blockIdx.x;
    int type = blk >> 4, bh = blk & 15;
    const float* s = (type == 0 ? g_rs : g_cs) + bh*NN;
    int* list = (type == 0 ? g_rowlist : g_collist) + bh*KTOP;
    __shared__ unsigned keys[NN];
    __shared__ int hist[256];
    __shared__ int wtot[8];
    __shared__ unsigned sh_T;
    __shared__ int sh_take;
    int t = threadIdx.x;
    for (int i = t; i < NN; i += 256) keys[i] = f2key(s[i]);
    __syncthreads();

    unsigned prefix = 0, pmask = 0;
    int kneed = KTOP;
    for (int pass = 0; pass < 4; pass++) {
        int shift = 24 - 8*pass;
        hist[t] = 0;
        __syncthreads();
        for (int i = t; i < NN; i += 256) {
            unsigned u = keys[i];
            if ((u & pmask) == prefix) atomicAdd(&hist[(u >> shift) & 255], 1);
        }
        __syncthreads();
        int h = hist[t];
        int pre = incl_scan256(h, t, wtot);
        int total = wtot[7];
        int cum = total - pre;
        if (cum < kneed && cum + h >= kneed) {
            sh_T = prefix | ((unsigned)t << shift);
            sh_take = kneed - cum;
        }
        __syncthreads();
        prefix = sh_T;
        kneed = sh_take;
        pmask |= (0xffu << shift);
        __syncthreads();
    }
    unsigned T = prefix;
    int take = kneed;

    unsigned myk[9];
    int eqc = 0;
    #pragma unroll
    for (int j = 0; j < 9; j++) {
        myk[j] = keys[t*9 + j];
        eqc += (myk[j] == T);
    }
    int eqbase = incl_scan256(eqc, t, wtot) - eqc;

    bool kept[9];
    int keptc = 0, eqseen = 0;
    #pragma unroll
    for (int j = 0; j < 9; j++) {
        unsigned u = myk[j];
        bool gt = (u > T), eq = (u == T);
        bool kp = gt || (eq && (eqbase + eqseen) < take);
        if (eq) eqseen++;
        kept[j] = kp; keptc += kp;
    }
    int wbase = incl_scan256(keptc, t, wtot) - keptc;
    #pragma unroll
    for (int j = 0; j < 9; j++)
        if (kept[j]) list[wbase++] = t*9 + j;
}

// ---------------- v_unkept ----------------
__global__ void vunkept_k() {
    int bh = blockIdx.x;
    int t = threadIdx.x;
    int d = t & 31, part = t >> 5;
    float sv = 0;
    for (int jj = part; jj < KTOP; jj += 8) {
        int j = g_collist[bh*KTOP + jj];
        sv += __bfloat162float(g_vb[(bh*NN + j)*DH + d]);
    }
    __shared__ float sh[8][32];
    sh[part][d] = sv;
    __syncthreads();
    if (t < 32) {
        float s = 0;
        #pragma unroll
        for (int p = 0; p < 8; p++) s += sh[p][t];
        g_vunk[bh*DH + t] = g_sums[(bh*3+2)*DH + t] - s;
    }
}

// ---------------- pruned rows: mean(v) -> bf16 ----------------
__global__ void fill_o_k() {
    int gid = blockIdx.x*256 + threadIdx.x;
    if (gid >= BHN*NN*DH) return;
    int bh = gid / (NN*DH);
    int r = gid % (NN*DH);
    int n = r / DH, d = r & 31;
    int b = bh >> 3, h = bh & 7;
    g_ob[(size_t)(b*NN + n)*C_ + h*DH + d] =
        __float2bfloat16(g_sums[(bh*3+2)*DH + d] * (1.0f/NN));
}

// ---------------- kept-row attention partials (bf16 in, packed f32x2 math) ----------------
__global__ __launch_bounds__(64) void attn_part_k() {
    int bh = blockIdx.x;
    int t = threadIdx.x;                      // 64
    int slot = blockIdx.y*64 + t;
    int chunk = blockIdx.z;
    int i = g_rowlist[bh*KTOP + slot];

    unsigned long long qp2[16];
    {
        unsigned uq[16];
        const uint4* qp4 = (const uint4*)&g_qb[(size_t)(bh*NN + i)*DH];
        #pragma unroll
        for (int w = 0; w < 4; w++) *(uint4*)&uq[w*4] = qp4[w];
        #pragma unroll
        for (int w = 0; w < 16; w++) {
            float2 f = bf2f(uq[w]);
            qp2[w] = pack2(f.x, f.y);
        }
    }

    float m = -3.0e38f, Z = 0.f;
    unsigned long long acc2[16];
    #pragma unroll
    for (int idx = 0; idx < 16; idx++) acc2[idx] = 0ull;

    __shared__ int cj[96];
    __shared__ __align__(16) float Kc[96][DH];
    __shared__ __align__(16) float Vc[96][DH];

    for (int c0 = chunk*CHUNK; c0 < chunk*CHUNK + CHUNK; c0 += 96) {
        __syncthreads();
        for (int jj = t; jj < 96; jj += 64) cj[jj] = g_collist[bh*KTOP + c0 + jj];
        __syncthreads();
        for (int idx = t; idx < 96*DH; idx += 64) {
            int jj = idx >> 5, d = idx & 31;
            int base = (bh*NN + cj[jj])*DH + d;
            Kc[jj][d] = __bfloat162float(g_kb[base]);
            Vc[jj][d] = __bfloat162float(g_vb[base]);
        }
        __syncthreads();
        #pragma unroll 2
        for (int jj = 0; jj < 96; jj++) {
            const unsigned long long* kp = (const unsigned long long*)Kc[jj];
            unsigned long long p0 = 0ull, p1 = 0ull;
            #pragma unroll
            for (int w = 0; w < 16; w += 2) {
                p0 = fma2(qp2[w  ], kp[w  ], p0);
                p1 = fma2(qp2[w+1], kp[w+1], p1);
            }
            float a, b2, c2, d2;
            unpack2(p0, a, b2); unpack2(p1, c2, d2);
            float s = (a + b2) + (c2 + d2);
            float e;
            if (s > m) {
                float cf = __expf(m - s);
                unsigned long long cf2 = pack2(cf, cf);
                Z = Z*cf;
                #pragma unroll
                for (int w = 0; w < 16; w++) acc2[w] = mul2(acc2[w], cf2);
                m = s;
                e = 1.f;
            } else {
                e = __expf(s - m);
            }
            Z += e;
            unsigned long long ee = pack2(e, e);
            const unsigned long long* vp = (const unsigned long long*)Vc[jj];
            #pragma unroll
            for (int w = 0; w < 16; w++) acc2[w] = fma2(ee, vp[w], acc2[w]);
        }
    }
    int pidx = (bh*KTOP + slot)*NSPLIT + chunk;
    g_pm[pidx] = m;
    g_pz[pidx] = Z;
    float* pa = &g_pacc[(size_t)pidx*DH];
    #pragma unroll
    for (int w = 0; w < 16; w++) {
        float lo, hi;
        unpack2(acc2[w], lo, hi);
        pa[2*w] = lo; pa[2*w+1] = hi;
    }
}

// ---------------- combine partials + zero-column correction -> bf16 ----------------
__global__ void attn_comb_k() {
    int gid = blockIdx.x*128 + threadIdx.x;
    if (gid >= BHN*KTOP) return;
    int bh = gid / KTOP, slot = gid % KTOP;
    int i = g_rowlist[bh*KTOP + slot];
    int p0 = gid*NSPLIT;
    float m0 = g_pm[p0], m1 = g_pm[p0+1], m2 = g_pm[p0+2];
    float mstar = fmaxf(0.f, fmaxf(m0, fmaxf(m1, m2)));
    float e0 = __expf(m0 - mstar), e1 = __expf(m1 - mstar), e2 = __expf(m2 - mstar);
    float ez = __expf(-mstar);
    float Z = g_pz[p0]*e0 + g_pz[p0+1]*e1 + g_pz[p0+2]*e2 + (float)(NN - KTOP)*ez;
    float invZ = 1.f / Z;
    const float* a0 = &g_pacc[(size_t)p0*DH];
    const float* a1 = &g_pacc[(size_t)(p0+1)*DH];
    const float* a2 = &g_pacc[(size_t)(p0+2)*DH];
    const float* vu = &g_vunk[bh*DH];
    int b = bh >> 3, h = bh & 7;
    __nv_bfloat16* op = &g_ob[(size_t)(b*NN + i)*C_ + h*DH];
    #pragma unroll
    for (int d = 0; d < DH; d++)
        op[d] = __float2bfloat16((a0[d]*e0 + a1[d]*e1 + a2[d]*e2 + ez*vu[d]) * invZ);
}

// ---------------- depthwise 3x3 conv (writes [C][B*NN] f32) ----------------
__global__ void dw_k(const float* __restrict__ x,
                     const float* __restrict__ w,
                     const float* __restrict__ bias) {
    int gid = blockIdx.x*256 + threadIdx.x;
    if (gid >= B_*C_*NN) return;
    int n = gid % NN;
    int bc = gid / NN;
    int c = bc % C_, b = bc / C_;
    int y = n / WW, x0 = n % WW;
    float acc = bias[c];
    const float* xp = &x[(size_t)(b*C_ + c)*NN];
    const float* wp = &w[c*9];
    #pragma unroll
    for (int dy = 0; dy < 3; dy++) {
        int yy = y + dy - 1;
        if (yy < 0 || yy >= HH) continue;
        #pragma unroll
        for (int dx = 0; dx < 3; dx++) {
            int xx = x0 + dx - 1;
            if (xx < 0 || xx >= WW) continue;
            acc += xp[yy*WW + xx] * wp[dy*3 + dx];
        }
    }
    g_xdw[(size_t)c*(B_*NN) + b*NN + n] = acc;
}

// ---------------- spatial gate stage 2 ----------------
__global__ __launch_bounds__(256) void sg2_k(const float* __restrict__ w,
                                             const float* __restrict__ bias) {
    __shared__ float ws[GG*49];
    int tid = threadIdx.x;
    for (int i = tid; i < GG*49; i += 256) ws[i] = w[i];
    __syncthreads();
    int p = blockIdx.x*8 + (tid >> 5);
    int lane = tid & 31;
    int b = p / NN, n = p % NN;
    int y = n / WW, x0 = n % WW;
    float acc = 0.f;
    for (int ky = 0; ky < 7; ky++) {
        int yy = y + ky - 3;
        if (yy < 0 || yy >= HH) continue;
        #pragma unroll
        for (int kx = 0; kx < 7; kx++) {
            int xx = x0 + kx - 3;
            if (xx < 0 || xx >= WW) continue;
            acc += g_t1[(b*NN + yy*WW + xx)*GG + lane] * ws[lane*49 + ky*7 + kx];
        }
    }
    #pragma unroll
    for (int o = 16; o; o >>= 1) acc += __shfl_xor_sync(~0u, acc, o);
    if (lane == 0) g_sg[p] = 1.f / (1.f + expf(-(acc + bias[0])));
}

// ---------------- channel gate: pool partials ----------------
__global__ void cgpool_k() {
    int blk = blockIdx.x;
    int b = blk / 16, part = blk % 16;
    int c = threadIdx.x;
    float s = 0;
    int n0 = part*144;
    for (int n = n0; n < n0 + 144; n++) s += g_xs[(size_t)(b*NN + n)*C_ + c];
    g_cgpart[blk*C_ + c] = s;
}

// ---------------- channel gate: combine ----------------
__global__ void cggate_k(const float* __restrict__ w1, const float* __restrict__ b1,
                         const float* __restrict__ w2, const float* __restrict__ b2) {
    int b = blockIdx.x;
    int c = threadIdx.x;
    __shared__ float cgm[C_];
    __shared__ float t2[GG];
    float s = 0;
    for (int p = 0; p < 16; p++) s += g_cgpart[(b*16 + p)*C_ + c];
    cgm[c] = s * (1.0f/NN);
    __syncthreads();
    if (c < GG) {
        float a = b1[c];
        const float* wp = &w1[c*C_];
        for (int ci = 0; ci < C_; ci++) a += cgm[ci]*wp[ci];
        t2[c] = a / (1.f + expf(-a));
    }
    __syncthreads();
    float a2 = b2[c];
    const float* wp2 = &w2[c*GG];
    #pragma unroll
    for (int g = 0; g < GG; g++) a2 += t2[g]*wp2[g];
    g_cg[b*C_ + c] = 1.f / (1.f + expf(-a2));
}

// ---------------- x2 = x + gamma1*xs*sg*cg, fused LN2 -> g_x2 f32 + g_ln2b bf16 ----------------
__global__ __launch_bounds__(256) void x2ln2_k(const float* __restrict__ x,
                                               const float* __restrict__ gamma1,
                                               const float* __restrict__ gg2,
                                               const float* __restrict__ bb2) {
    __shared__ float tile[C_*33];
    __shared__ float smu[32], sr[32];
    int blk = blockIdx.x;
    int b = blk / (NN/32);
    int n0 = (blk % (NN/32)) * 32;
    int tid = threadIdx.x;
    #pragma unroll
    for (int i = 0; i < 32; i++) {
        int idx = i*256 + tid;
        int c = idx >> 5, n = idx & 31;
        tile[c*33 + n] = x[(size_t)(b*C_ + c)*NN + n0 + n];
    }
    __syncthreads();
    float gm = gamma1[0];
    // phase 2: iteration i handles row n=i, c=tid. Read x from tile[c*33+i],
    // compute x2, write to g_x2, and stash x2 back to the SAME slot (no future
    // iteration reads it: reads at iter i' touch only column i').
    #pragma unroll
    for (int i = 0; i < 32; i++) {
        int row = b*NN + n0 + i;
        int c = tid;
        float v = tile[c*33 + i] + gm * g_xs[(size_t)row*C_ + c] * g_sg[row] * g_cg[b*C_ + c];
        g_x2[(size_t)row*C_ + c] = v;
        tile[c*33 + i] = v;
    }
    __syncthreads();
    // phase 3: LN stats per row (same pattern as ln1)
    int wid = tid >> 5, lane = tid & 31;
    #pragma unroll
    for (int j = 0; j < 4; j++) {
        int n = wid*4 + j;
        float s1 = 0, s2 = 0;
        #pragma unroll
        for (int i = 0; i < 8; i++) {
            float v = tile[(lane + i*32)*33 + n];
            s1 += v; s2 += v*v;
        }
        #pragma unroll
        for (int o = 16; o; o >>= 1) {
            s1 += __shfl_xor_sync(~0u, s1, o);
            s2 += __shfl_xor_sync(~0u, s2, o);
        }
        if (lane == 0) {
            float mu = s1*(1.0f/C_);
            float var = s2*(1.0f/C_) - mu*mu;
            smu[n] = mu; sr[n] = rsqrtf(var + 1e-6f);
        }
    }
    __syncthreads();
    #pragma unroll
    for (int i = 0; i < 32; i++) {
        int idx = i*256 + tid;
        int n = idx >> 8, c = idx & 255;
        float v = tile[c*33 + n];
        g_ln2b[(size_t)(b*NN + n0 + n)*C_ + c] =
            __float2bfloat16((v - smu[n])*sr[n]*gg2[c] + bb2[c]);
    }
}

// ---------------- host ----------------
#define GETSYM(p, s, T) do { void* _t; cudaGetSymbolAddress(&_t, s); p = (T*)_t; } while (0)

extern "C" void kernel_launch(void* const* d_in, const int* in_sizes, int n_in,
                              void* d_out, int out_size) {
    const float* x     = (const float*)d_in[0];
    const float* qkv_w = (const float*)d_in[1];
    const float* out_w = (const float*)d_in[2];
    const float* ln1_g = (const float*)d_in[3];
    const float* ln1_b = (const float*)d_in[4];
    const float* ln2_g = (const float*)d_in[5];
    const float* ln2_b = (const float*)d_in[6];
    const float* dw_w  = (const float*)d_in[7];
    const float* dw_b  = (const float*)d_in[8];
    const float* pw_w  = (const float*)d_in[9];
    const float* pw_b  = (const float*)d_in[10];
    const float* sg1_w = (const float*)d_in[11];
    const float* sg1_b = (const float*)d_in[12];
    const float* sg2_w = (const float*)d_in[13];
    const float* sg2_b = (const float*)d_in[14];
    const float* cg1_w = (const float*)d_in[15];
    const float* cg1_b = (const float*)d_in[16];
    const float* cg2_w = (const float*)d_in[17];
    const float* cg2_b = (const float*)d_in[18];
    const float* ff_w1 = (const float*)d_in[19];
    const float* ff_b1 = (const float*)d_in[20];
    const float* ff_w2 = (const float*)d_in[21];
    const float* ff_b2 = (const float*)d_in[22];
    const float* gamma1= (const float*)d_in[23];
    const float* gamma2= (const float*)d_in[24];
    float* out = (float*)d_out;
    (void)in_sizes; (void)n_in; (void)out_size;

    float *p_xdw, *p_xc, *p_xs, *p_t1;
    __nv_bfloat16 *p_xab, *p_ob, *p_xdwb, *p_xsb, *p_ln2b, *p_hb;
    __nv_bfloat16 *p_wqt, *p_wot, *p_wpwb, *p_wsg1, *p_w1t, *p_w2t;
    GETSYM(p_xdw, g_xdw, float); GETSYM(p_xc, g_xc, float); GETSYM(p_xs, g_xs, float);
    GETSYM(p_t1, g_t1, float);
    GETSYM(p_xab, g_xab, __nv_bfloat16); GETSYM(p_ob, g_ob, __nv_bfloat16);
    GETSYM(p_xdwb, g_xdwb, __nv_bfloat16); GETSYM(p_xsb, g_xsb, __nv_bfloat16);
    GETSYM(p_ln2b, g_ln2b, __nv_bfloat16); GETSYM(p_hb, g_hb, __nv_bfloat16);
    GETSYM(p_wqt, g_wqt, __nv_bfloat16); GETSYM(p_wot, g_wot, __nv_bfloat16);
    GETSYM(p_wpwb, g_wpwb, __nv_bfloat16); GETSYM(p_wsg1, g_wsg1, __nv_bfloat16);
    GETSYM(p_w1t, g_w1t, __nv_bfloat16); GETSYM(p_w2t, g_w2t, __nv_bfloat16);

    const int M = B_*NN;   // 4608

    // prep (QKV gemm stays at profiled launch idx 3)
    wprep_k<<<833, 256>>>(qkv_w, out_w, ff_w1, ff_w2, pw_w, sg1_w);
    ln1_k<<<B_*NN/32, 256>>>(x, ln1_g, ln1_b);
    dw_k<<<(B_*C_*NN)/256, 256>>>(x, dw_w, dw_b);
    gemm_bf<128,128,2><<<dim3(768/128, M/128), 256>>>(
        p_xab, p_wqt, nullptr, nullptr, nullptr, M, 3*C_, C_);
    tconv_k<<<dim3(M/32, C_/32), 256>>>(p_xdw, p_xdwb, C_, M);
    gemm_bf<128,64,0><<<dim3(C_/64, M/128), 256>>>(
        p_xdwb, p_wpwb, p_xc, nullptr, nullptr, M, C_, C_);
    // attention stats + selection
    bh_sums1_k<<<dim3(BHN, 12), 256>>>();
    scores_k<<<dim3(BHN, 9), 256>>>();
    select_k<<<32, 256>>>();
    vunkept_k<<<BHN, 256>>>();
    fill_o_k<<<(BHN*NN*DH)/256, 256>>>();
    attn_part_k<<<dim3(BHN, 9, NSPLIT), 64>>>();
    attn_comb_k<<<(BHN*KTOP + 127)/128, 128>>>();
    // out-proj epilogue: xs = o@out_w + xc + pw_b (f32 + bf16 copies)
    gemm_bf<128,64,3><<<dim3(C_/64, M/128), 256>>>(
        p_ob, p_wot, p_xs, pw_b, nullptr, M, C_, C_);

    // gates
    gemm_bf<128,32,5><<<dim3(1, M/128), 256>>>(
        p_xsb, p_wsg1, p_t1, sg1_b, nullptr, M, GG, C_);
    sg2_k<<<B_*NN/8, 256>>>(sg2_w, sg2_b);
    cgpool_k<<<B_*16, 256>>>();
    cggate_k<<<B_, 256>>>(cg1_w, cg1_b, cg2_w, cg2_b);
    x2ln2_k<<<B_*NN/32, 256>>>(x, gamma1, ln2_g, ln2_b);

    // FFN (bf16)
    gemm_bf<128,128,1><<<dim3(HID/128, M/128), 256>>>(
        p_ln2b, p_w1t, p_hb, ff_b1, nullptr, M, HID, C_);
    gemm_bf<128,64,4><<<dim3(C_/64, M/128), 256>>>(
        p_hb, p_w2t, out, ff_b2, gamma2, M, C_, HID);
}

// round 14
// speedup vs baseline: 4.0051x; 1.0673x over previous
#include <cuda_runtime.h>
#include <cuda_bf16.h>
#include <math.h>

#define B_ 2
#define C_ 256
#define HH 48
#define WW 48
#define NN 2304          // 48*48
#define NHEAD 8
#define DH 32
#define BHN 16           // B_*NHEAD
#define KTOP 576
#define HID 1024
#define GG 32            // C/8 gate channels
#define QSCALE 0.17677669529663687f   // 1/sqrt(32)
#define NSPLIT 6         // attention column-split
#define CHUNK 96         // KTOP / NSPLIT

// ---------------- scratch (static device arrays; no allocation) ----------------
__device__ __nv_bfloat16 g_xab[B_*NN*C_];      // ln1 out (bf16)
__device__ __nv_bfloat16 g_qb [BHN*NN*DH];
__device__ __nv_bfloat16 g_kb [BHN*NN*DH];
__device__ __nv_bfloat16 g_vb [BHN*NN*DH];
__device__ float g_spart[BHN*12*3*DH];
__device__ float g_sums[BHN*3*DH];
__device__ float g_rs  [BHN*NN];
__device__ float g_cs  [BHN*NN];
__device__ int   g_rowlist[BHN*KTOP];
__device__ int   g_collist[BHN*KTOP];
__device__ float g_vunk[BHN*DH];
__device__ float g_pm  [BHN*KTOP*NSPLIT];
__device__ float g_pz  [BHN*KTOP*NSPLIT];
__device__ float g_pacc[BHN*KTOP*NSPLIT*DH];
__device__ __nv_bfloat16 g_ob [B_*NN*C_];      // attention out (bf16, gemm A)
__device__ float g_xdw [C_*B_*NN];             // dw out [c][b*NN+n]
__device__ __nv_bfloat16 g_xdwb[B_*NN*C_];     // dw out transposed [M][C] bf16
__device__ float g_xc  [B_*NN*C_];
__device__ float g_xs  [B_*NN*C_];
__device__ __nv_bfloat16 g_xsb[B_*NN*C_];      // xs bf16 (sg1 gemm A)
__device__ float g_t1  [B_*NN*GG];
__device__ float g_sg  [B_*NN];
__device__ float g_cgpart[B_*16*C_];
__device__ float g_cg  [B_*C_];
__device__ float g_x2  [B_*NN*C_];
__device__ __nv_bfloat16 g_ln2b[B_*NN*C_];
__device__ __nv_bfloat16 g_hb  [B_*NN*HID];
__device__ __nv_bfloat16 g_wqt [3*C_*C_];      // qkv_w^T [768][256]
__device__ __nv_bfloat16 g_wot [C_*C_];        // out_w^T [256][256]
__device__ __nv_bfloat16 g_wpwb[C_*C_];        // pw_w ([N][K]) bf16
__device__ __nv_bfloat16 g_wsg1[GG*C_];        // sg1_w ([N][K]) bf16
__device__ __nv_bfloat16 g_w1t [HID*C_];       // ff_w1^T [1024][256]
__device__ __nv_bfloat16 g_w2t [C_*HID];       // ff_w2^T [256][1024]

// ---------------- helpers ----------------
__device__ __forceinline__ void cp16(void* sptr, const void* gptr) {
    unsigned saddr = (unsigned)__cvta_generic_to_shared(sptr);
    asm volatile("cp.async.cg.shared.global [%0], [%1], 16;" :: "r"(saddr), "l"(gptr));
}
__device__ __forceinline__ void cp_commit() { asm volatile("cp.async.commit_group;"); }
__device__ __forceinline__ void cp_wait0()  { asm volatile("cp.async.wait_group 0;" ::: "memory"); }

__device__ __forceinline__ void mma_bf16(float* d, const unsigned* a,
                                         const unsigned* b, const float* c) {
    asm volatile("mma.sync.aligned.m16n8k16.row.col.f32.bf16.bf16.f32 "
        "{%0,%1,%2,%3}, {%4,%5,%6,%7}, {%8,%9}, {%10,%11,%12,%13};"
        : "=f"(d[0]),"=f"(d[1]),"=f"(d[2]),"=f"(d[3])
        : "r"(a[0]),"r"(a[1]),"r"(a[2]),"r"(a[3]),
          "r"(b[0]),"r"(b[1]),
          "f"(c[0]),"f"(c[1]),"f"(c[2]),"f"(c[3]));
}
__device__ __forceinline__ unsigned long long pack2(float lo, float hi) {
    unsigned long long r;
    asm("mov.b64 %0, {%1, %2};" : "=l"(r) : "f"(lo), "f"(hi));
    return r;
}
__device__ __forceinline__ void unpack2(unsigned long long v, float& lo, float& hi) {
    asm("mov.b64 {%0, %1}, %2;" : "=f"(lo), "=f"(hi) : "l"(v));
}
__device__ __forceinline__ unsigned long long fma2(unsigned long long a,
                                                   unsigned long long b,
                                                   unsigned long long c) {
    unsigned long long d;
    asm("fma.rn.f32x2 %0, %1, %2, %3;" : "=l"(d) : "l"(a), "l"(b), "l"(c));
    return d;
}
__device__ __forceinline__ unsigned long long mul2(unsigned long long a,
                                                   unsigned long long b) {
    unsigned long long d;
    asm("mul.rn.f32x2 %0, %1, %2;" : "=l"(d) : "l"(a), "l"(b));
    return d;
}
__device__ __forceinline__ float2 bf2f(unsigned u) {
    __nv_bfloat162 h = *reinterpret_cast<__nv_bfloat162*>(&u);
    return __bfloat1622float2(h);
}

// ---------------- bf16 tensor-core GEMM (A [M,K] bf16, B [N,K] bf16), BK=16, BM=64 ----------------
// EPI: 0=plain f32   1=bias+gelu->bf16   2=qkv scatter (bf16 q/k/v)
//      3=xs: f32 g_xs + bf16 g_xsb = v + g_xc + bias
//      4=final: out = x2 + gamma2*(v+bias), NCHW f32
//      5=sg1: silu(v+bias) -> f32 g_t1
template<int BM, int BN, int EPI>
__global__ __launch_bounds__(256, 3)
void gemm_bf(const __nv_bfloat16* __restrict__ A, const __nv_bfloat16* __restrict__ B,
             void* __restrict__ Cout, const float* __restrict__ bias,
             const float* __restrict__ aux, int M, int N, int K) {
    constexpr int BK = 16;
    constexpr int WM = BM/2, WN = BN/4;
    constexpr int MT = WM/16, NT = WN/8;
    constexpr int STR = 24;

    __shared__ __align__(16) __nv_bfloat16 As[2][BM*STR];
    __shared__ __align__(16) __nv_bfloat16 Bs[2][BN*STR];

    const int bm = blockIdx.y*BM, bn = blockIdx.x*BN;
    const int tid = threadIdx.x;
    const int lane = tid & 31, wid = tid >> 5;
    const int wm = wid >> 2, wn = wid & 3;
    const int g = lane >> 2, tig = lane & 3;

    float acc[MT][NT][4];
    #pragma unroll
    for (int i = 0; i < MT; i++)
        #pragma unroll
        for (int j = 0; j < NT; j++)
            #pragma unroll
            for (int l = 0; l < 4; l++) acc[i][j][l] = 0.f;

    auto copy_tile = [&](int st, int k0) {
        {
            constexpr int CA = BM*2;
            int ch = tid;
            if (CA == 256 || ch < CA) {
                int row = ch >> 1, c8 = (ch & 1)*8;
                cp16(&As[st][row*STR + c8], &A[(size_t)(bm+row)*K + k0 + c8]);
            }
        }
        {
            constexpr int CB = BN*2;
            int ch = tid;
            if (CB == 256 || ch < CB) {
                int row = ch >> 1, c8 = (ch & 1)*8;
                cp16(&Bs[st][row*STR + c8], &B[(size_t)(bn+row)*K + k0 + c8]);
            }
        }
    };

    copy_tile(0, 0);
    cp_commit();
    int stage = 0;
    for (int k0 = 0; k0 < K; k0 += BK) {
        cp_wait0();
        __syncthreads();
        if (k0 + BK < K) { copy_tile(stage^1, k0+BK); cp_commit(); }
        const __nv_bfloat16* as = As[stage];
        const __nv_bfloat16* bs = Bs[stage];
        int kk = 2*tig;
        unsigned afr[MT][4];
        #pragma unroll
        for (int mt = 0; mt < MT; mt++) {
            int r0 = wm*WM + mt*16 + g;
            afr[mt][0] = *(const unsigned*)&as[(r0  )*STR + kk  ];
            afr[mt][1] = *(const unsigned*)&as[(r0+8)*STR + kk  ];
            afr[mt][2] = *(const unsigned*)&as[(r0  )*STR + kk+8];
            afr[mt][3] = *(const unsigned*)&as[(r0+8)*STR + kk+8];
        }
        unsigned bfr[NT][2];
        #pragma unroll
        for (int nt = 0; nt < NT; nt++) {
            int c0 = wn*WN + nt*8 + g;
            bfr[nt][0] = *(const unsigned*)&bs[c0*STR + kk  ];
            bfr[nt][1] = *(const unsigned*)&bs[c0*STR + kk+8];
        }
        #pragma unroll
        for (int mt = 0; mt < MT; mt++)
            #pragma unroll
            for (int nt = 0; nt < NT; nt++)
                mma_bf16(acc[mt][nt], afr[mt], bfr[nt], acc[mt][nt]);
        stage ^= 1;
    }

    #pragma unroll
    for (int mt = 0; mt < MT; mt++) {
        int row0 = bm + wm*WM + mt*16 + g;
        #pragma unroll
        for (int nt = 0; nt < NT; nt++) {
            int col = bn + wn*WN + nt*8 + tig*2;
            #pragma unroll
            for (int half = 0; half < 2; half++) {
                int row = row0 + half*8;
                float v0 = acc[mt][nt][half*2], v1 = acc[mt][nt][half*2+1];
                if (EPI == 0) {
                    *(float2*)&((float*)Cout)[(size_t)row*N + col] = make_float2(v0, v1);
                } else if (EPI == 1) {
                    v0 += bias[col]; v1 += bias[col+1];
                    v0 = 0.5f*v0*(1.0f + erff(v0*0.70710678118654752f));
                    v1 = 0.5f*v1*(1.0f + erff(v1*0.70710678118654752f));
                    __nv_bfloat162 p;
                    p.x = __float2bfloat16(v0); p.y = __float2bfloat16(v1);
                    *(__nv_bfloat162*)&((__nv_bfloat16*)Cout)[(size_t)row*N + col] = p;
                } else if (EPI == 2) {
                    int b = row / NN, n = row - b*NN;
                    int part = col >> 8, cc = col & 255;
                    int h = cc >> 5, d = cc & 31;
                    size_t dst = ((size_t)(b*NHEAD + h)*NN + n)*DH + d;
                    __nv_bfloat162 p;
                    if (part == 0) {
                        p.x = __float2bfloat16(v0*QSCALE);
                        p.y = __float2bfloat16(v1*QSCALE);
                        *(__nv_bfloat162*)&g_qb[dst] = p;
                    } else if (part == 1) {
                        p.x = __float2bfloat16(v0); p.y = __float2bfloat16(v1);
                        *(__nv_bfloat162*)&g_kb[dst] = p;
                    } else {
                        p.x = __float2bfloat16(v0); p.y = __float2bfloat16(v1);
                        *(__nv_bfloat162*)&g_vb[dst] = p;
                    }
                } else if (EPI == 3) {
                    v0 += g_xc[(size_t)row*C_ + col]   + bias[col];
                    v1 += g_xc[(size_t)row*C_ + col+1] + bias[col+1];
                    *(float2*)&((float*)Cout)[(size_t)row*N + col] = make_float2(v0, v1);
                    __nv_bfloat162 p;
                    p.x = __float2bfloat16(v0); p.y = __float2bfloat16(v1);
                    *(__nv_bfloat162*)&g_xsb[(size_t)row*C_ + col] = p;
                } else if (EPI == 4) {
                    int b = row / NN, n = row - b*NN;
                    float gm = aux[0];
                    float o0 = g_x2[(size_t)row*C_ + col]   + gm*(v0 + bias[col]);
                    float o1 = g_x2[(size_t)row*C_ + col+1] + gm*(v1 + bias[col+1]);
                    float* C = (float*)Cout;
                    C[(size_t)(b*C_ + col  )*NN + n] = o0;
                    C[(size_t)(b*C_ + col+1)*NN + n] = o1;
                } else { // EPI == 5
                    v0 += bias[col]; v1 += bias[col+1];
                    v0 = v0 / (1.f + expf(-v0));
                    v1 = v1 / (1.f + expf(-v1));
                    *(float2*)&((float*)Cout)[(size_t)row*N + col] = make_float2(v0, v1);
                }
            }
        }
    }
}

// ---------------- merged weight prep ----------------
__global__ __launch_bounds__(256) void wprep_k(const float* __restrict__ qkv_w,
                                               const float* __restrict__ out_w,
                                               const float* __restrict__ ff_w1,
                                               const float* __restrict__ ff_w2,
                                               const float* __restrict__ pw_w,
                                               const float* __restrict__ sg1_w) {
    __shared__ float tile[32][33];
    int bb = blockIdx.x;
    if (bb < 768) {
        const float* in; __nv_bfloat16* outp; int K, N, t0;
        if (bb < 192)      { in = qkv_w; outp = g_wqt; K = 256; N = 768;  t0 = bb; }
        else if (bb < 256) { in = out_w; outp = g_wot; K = 256; N = 256;  t0 = bb-192; }
        else if (bb < 512) { in = ff_w1; outp = g_w1t; K = 256; N = 1024; t0 = bb-256; }
        else               { in = ff_w2; outp = g_w2t; K = 1024; N = 256; t0 = bb-512; }
        int ntile = N/32;
        int nb = (t0 % ntile)*32, kb = (t0 / ntile)*32;
        int tx = threadIdx.x & 31, ty = threadIdx.x >> 5;
        #pragma unroll
        for (int i = 0; i < 32; i += 8)
            tile[ty+i][tx] = in[(size_t)(kb+ty+i)*N + nb+tx];
        __syncthreads();
        #pragma unroll
        for (int i = 0; i < 32; i += 8)
            outp[(size_t)(nb+ty+i)*K + kb+tx] = __float2bfloat16(tile[tx][ty+i]);
    } else if (bb < 832) {
        int base = (bb-768)*1024 + threadIdx.x;
        #pragma unroll
        for (int r = 0; r < 4; r++)
            g_wpwb[base + r*256] = __float2bfloat16(pw_w[base + r*256]);
    } else {
        for (int i = threadIdx.x; i < GG*C_; i += 256)
            g_wsg1[i] = __float2bfloat16(sg1_w[i]);
    }
}

// ---------------- transpose + f32->bf16 convert (dw output) ----------------
__global__ __launch_bounds__(256) void tconv_k(const float* __restrict__ in,
                                               __nv_bfloat16* __restrict__ out,
                                               int K, int N) {
    __shared__ float tile[32][33];
    int nb = blockIdx.x*32, kb = blockIdx.y*32;
    int tx = threadIdx.x & 31, ty = threadIdx.x >> 5;
    #pragma unroll
    for (int i = 0; i < 32; i += 8)
        tile[ty+i][tx] = in[(size_t)(kb+ty+i)*N + nb+tx];
    __syncthreads();
    #pragma unroll
    for (int i = 0; i < 32; i += 8)
        out[(size_t)(nb+ty+i)*K + kb+tx] = __float2bfloat16(tile[tx][ty+i]);
}

// ---------------- LN1 ----------------
__global__ __launch_bounds__(256) void ln1_k(const float* __restrict__ x,
                                             const float* __restrict__ gg,
                                             const float* __restrict__ bb) {
    __shared__ float tile[C_*33];
    __shared__ float smu[32], sr[32];
    int blk = blockIdx.x;
    int b = blk / (NN/32);
    int n0 = (blk % (NN/32)) * 32;
    int tid = threadIdx.x;
    #pragma unroll
    for (int i = 0; i < 32; i++) {
        int idx = i*256 + tid;
        int c = idx >> 5, n = idx & 31;
        tile[c*33 + n] = x[(size_t)(b*C_ + c)*NN + n0 + n];
    }
    __syncthreads();
    int wid = tid >> 5, lane = tid & 31;
    #pragma unroll
    for (int j = 0; j < 4; j++) {
        int n = wid*4 + j;
        float s1 = 0, s2 = 0;
        #pragma unroll
        for (int i = 0; i < 8; i++) {
            float v = tile[(lane + i*32)*33 + n];
            s1 += v; s2 += v*v;
        }
        #pragma unroll
        for (int o = 16; o; o >>= 1) {
            s1 += __shfl_xor_sync(~0u, s1, o);
            s2 += __shfl_xor_sync(~0u, s2, o);
        }
        if (lane == 0) {
            float mu = s1*(1.0f/C_);
            float var = s2*(1.0f/C_) - mu*mu;
            smu[n] = mu; sr[n] = rsqrtf(var + 1e-6f);
        }
    }
    __syncthreads();
    #pragma unroll
    for (int i = 0; i < 32; i++) {
        int idx = i*256 + tid;
        int n = idx >> 8, c = idx & 255;
        float v = tile[c*33 + n];
        g_xab[(size_t)(b*NN + n0 + n)*C_ + c] =
            __float2bfloat16((v - smu[n])*sr[n]*gg[c] + bb[c]);
    }
}

// ---------------- per-(b,h) partial sums ----------------
__global__ void bh_sums1_k() {
    int bh = blockIdx.x, yy = blockIdx.y;
    int t = threadIdx.x;
    int d = t & 31, part = t >> 5;
    float sq = 0, sk = 0, sv = 0;
    int n0 = yy*192 + part*24;
    for (int j = 0; j < 24; j++) {
        int idx = (bh*NN + n0 + j)*DH + d;
        sq += __bfloat162float(g_qb[idx]);
        sk += __bfloat162float(g_kb[idx]);
        sv += __bfloat162float(g_vb[idx]);
    }
    __shared__ float sh[3][8][32];
    sh[0][part][d]=sq; sh[1][part][d]=sk; sh[2][part][d]=sv;
    __syncthreads();
    if (t < 96) {
        int which = t >> 5, dd = t & 31;
        float s = 0;
        #pragma unroll
        for (int p = 0; p < 8; p++) s += sh[which][p][dd];
        g_spart[((bh*12 + yy)*3 + which)*DH + dd] = s;
    }
}

// ---------------- reduce partials + scores ----------------
__global__ void scores_k() {
    int bh = blockIdx.x, yy = blockIdx.y;
    int t = threadIdx.x;
    __shared__ float qs[DH], ks[DH];
    if (t < 96) {
        int which = t >> 5, d = t & 31;
        float s = 0;
        #pragma unroll
        for (int y = 0; y < 12; y++) s += g_spart[((bh*12 + y)*3 + which)*DH + d];
        if (which == 0) qs[d] = s;
        else if (which == 1) ks[d] = s;
        if (yy == 0) g_sums[(bh*3 + which)*DH + d] = s;
    }
    __syncthreads();
    int gid = bh*NN + yy*256 + t;
    unsigned uq[16], uk[16];
    {
        const uint4* qp4 = (const uint4*)&g_qb[(size_t)gid*DH];
        const uint4* kp4 = (const uint4*)&g_kb[(size_t)gid*DH];
        #pragma unroll
        for (int w = 0; w < 4; w++) {
            *(uint4*)&uq[w*4] = qp4[w];
            *(uint4*)&uk[w*4] = kp4[w];
        }
    }
    float r = 0, c = 0;
    #pragma unroll
    for (int w = 0; w < 16; w++) {
        float2 fq = bf2f(uq[w]), fk = bf2f(uk[w]);
        r += fq.x*ks[2*w] + fq.y*ks[2*w+1];
        c += qs[2*w]*fk.x + qs[2*w+1]*fk.y;
    }
    g_rs[gid] = r; g_cs[gid] = c;
}

// ---------------- exact top-k selection ----------------
__device__ __forceinline__ unsigned f2key(float f) {
    unsigned u = __float_as_uint(f);
    return (u & 0x80000000u) ? ~u : (u | 0x80000000u);
}

__device__ __forceinline__ int incl_scan256(int v, int t, int* wtot) {
    __syncthreads();
    int lane = t & 31, wid = t >> 5;
    #pragma unroll
    for (int o = 1; o < 32; o <<= 1) {
        int u = __shfl_up_sync(~0u, v, o);
        if (lane >= o) v += u;
    }
    if (lane == 31) wtot[wid] = v;
    __syncthreads();
    if (wid == 0) {
        int s = (lane < 8) ? wtot[lane] : 0;
        #pragma unroll
        for (int o = 1; o < 8; o <<= 1) {
            int u = __shfl_up_sync(~0u, s, o);
            if (lane >= o) s += u;
        }
        if (lane < 8) wtot[lane] = s;
    }
    __syncthreads();
    return v + (wid > 0 ? wtot[wid-1] : 0);
}

__global__ void select_k() {
    int blk = blockIdx.x;
    int type = blk >> 4, bh = blk & 15;
    const float* s = (type == 0 ? g_rs : g_cs) + bh*NN;
    int* list = (type == 0 ? g_rowlist : g_collist) + bh*KTOP;
    __shared__ unsigned keys[NN];
    __shared__ int hist[256];
    __shared__ int wtot[8];
    __shared__ unsigned sh_T;
    __shared__ int sh_take;
    int t = threadIdx.x;
    for (int i = t; i < NN; i += 256) keys[i] = f2key(s[i]);
    __syncthreads();

    unsigned prefix = 0, pmask = 0;
    int kneed = KTOP;
    for (int pass = 0; pass < 4; pass++) {
        int shift = 24 - 8*pass;
        hist[t] = 0;
        __syncthreads();
        for (int i = t; i < NN; i += 256) {
            unsigned u = keys[i];
            if ((u & pmask) == prefix) atomicAdd(&hist[(u >> shift) & 255], 1);
        }
        __syncthreads();
        int h = hist[t];
        int pre = incl_scan256(h, t, wtot);
        int total = wtot[7];
        int cum = total - pre;
        if (cum < kneed && cum + h >= kneed) {
            sh_T = prefix | ((unsigned)t << shift);
            sh_take = kneed - cum;
        }
        __syncthreads();
        prefix = sh_T;
        kneed = sh_take;
        pmask |= (0xffu << shift);
        __syncthreads();
    }
    unsigned T = prefix;
    int take = kneed;

    unsigned myk[9];
    int eqc = 0;
    #pragma unroll
    for (int j = 0; j < 9; j++) {
        myk[j] = keys[t*9 + j];
        eqc += (myk[j] == T);
    }
    int eqbase = incl_scan256(eqc, t, wtot) - eqc;

    bool kept[9];
    int keptc = 0, eqseen = 0;
    #pragma unroll
    for (int j = 0; j < 9; j++) {
        unsigned u = myk[j];
        bool gt = (u > T), eq = (u == T);
        bool kp = gt || (eq && (eqbase + eqseen) < take);
        if (eq) eqseen++;
        kept[j] = kp; keptc += kp;
    }
    int wbase = incl_scan256(keptc, t, wtot) - keptc;
    #pragma unroll
    for (int j = 0; j < 9; j++)
        if (kept[j]) list[wbase++] = t*9 + j;
}

// ---------------- merged: vunkept (blocks 0..15) + fill_o (rest) ----------------
__global__ void vunk_fillo_k() {
    int bb = blockIdx.x;
    if (bb < BHN) {
        int bh = bb;
        int t = threadIdx.x;
        int d = t & 31, part = t >> 5;
        float sv = 0;
        for (int jj = part; jj < KTOP; jj += 8) {
            int j = g_collist[bh*KTOP + jj];
            sv += __bfloat162float(g_vb[(bh*NN + j)*DH + d]);
        }
        __shared__ float sh[8][32];
        sh[part][d] = sv;
        __syncthreads();
        if (t < 32) {
            float s = 0;
            #pragma unroll
            for (int p = 0; p < 8; p++) s += sh[p][t];
            g_vunk[bh*DH + t] = g_sums[(bh*3+2)*DH + t] - s;
        }
    } else {
        int gid = (bb - BHN)*256 + threadIdx.x;
        if (gid >= BHN*NN*DH) return;
        int bh = gid / (NN*DH);
        int r = gid % (NN*DH);
        int n = r / DH, d = r & 31;
        int b = bh >> 3, h = bh & 7;
        g_ob[(size_t)(b*NN + n)*C_ + h*DH + d] =
            __float2bfloat16(g_sums[(bh*3+2)*DH + d] * (1.0f/NN));
    }
}

// ---------------- kept-row attention partials ----------------
__global__ __launch_bounds__(64) void attn_part_k() {
    int bh = blockIdx.x;
    int t = threadIdx.x;
    int slot = blockIdx.y*64 + t;
    int chunk = blockIdx.z;
    int i = g_rowlist[bh*KTOP + slot];

    unsigned long long qp2[16];
    {
        unsigned uq[16];
        const uint4* qp4 = (const uint4*)&g_qb[(size_t)(bh*NN + i)*DH];
        #pragma unroll
        for (int w = 0; w < 4; w++) *(uint4*)&uq[w*4] = qp4[w];
        #pragma unroll
        for (int w = 0; w < 16; w++) {
            float2 f = bf2f(uq[w]);
            qp2[w] = pack2(f.x, f.y);
        }
    }

    float m = -3.0e38f, Z = 0.f;
    unsigned long long acc2[16];
    #pragma unroll
    for (int idx = 0; idx < 16; idx++) acc2[idx] = 0ull;

    __shared__ int cj[CHUNK];
    __shared__ __align__(16) float Kc[CHUNK][DH];
    __shared__ __align__(16) float Vc[CHUNK][DH];

    {
        int c0 = chunk*CHUNK;
        for (int jj = t; jj < CHUNK; jj += 64) cj[jj] = g_collist[bh*KTOP + c0 + jj];
        __syncthreads();
        for (int idx = t; idx < CHUNK*DH; idx += 64) {
            int jj = idx >> 5, d = idx & 31;
            int base = (bh*NN + cj[jj])*DH + d;
            Kc[jj][d] = __bfloat162float(g_kb[base]);
            Vc[jj][d] = __bfloat162float(g_vb[base]);
        }
        __syncthreads();
        #pragma unroll 2
        for (int jj = 0; jj < CHUNK; jj++) {
            const unsigned long long* kp = (const unsigned long long*)Kc[jj];
            unsigned long long p0 = 0ull, p1 = 0ull;
            #pragma unroll
            for (int w = 0; w < 16; w += 2) {
                p0 = fma2(qp2[w  ], kp[w  ], p0);
                p1 = fma2(qp2[w+1], kp[w+1], p1);
            }
            float a, b2, c2, d2;
            unpack2(p0, a, b2); unpack2(p1, c2, d2);
            float s = (a + b2) + (c2 + d2);
            float e;
            if (s > m) {
                float cf = __expf(m - s);
                unsigned long long cf2 = pack2(cf, cf);
                Z = Z*cf;
                #pragma unroll
                for (int w = 0; w < 16; w++) acc2[w] = mul2(acc2[w], cf2);
                m = s;
                e = 1.f;
            } else {
                e = __expf(s - m);
            }
            Z += e;
            unsigned long long ee = pack2(e, e);
            const unsigned long long* vp = (const unsigned long long*)Vc[jj];
            #pragma unroll
            for (int w = 0; w < 16; w++) acc2[w] = fma2(ee, vp[w], acc2[w]);
        }
    }
    int pidx = (bh*KTOP + slot)*NSPLIT + chunk;
    g_pm[pidx] = m;
    g_pz[pidx] = Z;
    float* pa = &g_pacc[(size_t)pidx*DH];
    #pragma unroll
    for (int w = 0; w < 16; w++) {
        float lo, hi;
        unpack2(acc2[w], lo, hi);
        pa[2*w] = lo; pa[2*w+1] = hi;
    }
}

// ---------------- combine partials + zero-column correction -> bf16 ----------------
__global__ void attn_comb_k() {
    int gid = blockIdx.x*128 + threadIdx.x;
    if (gid >= BHN*KTOP) return;
    int bh = gid / KTOP, slot = gid % KTOP;
    int i = g_rowlist[bh*KTOP + slot];
    int p0 = gid*NSPLIT;
    float mm[NSPLIT];
    float mstar = 0.f;
    #pragma unroll
    for (int s = 0; s < NSPLIT; s++) { mm[s] = g_pm[p0+s]; mstar = fmaxf(mstar, mm[s]); }
    float ee[NSPLIT];
    float ez = __expf(-mstar);
    float Z = (float)(NN - KTOP) * ez;
    #pragma unroll
    for (int s = 0; s < NSPLIT; s++) { ee[s] = __expf(mm[s] - mstar); Z += g_pz[p0+s]*ee[s]; }
    float invZ = 1.f / Z;
    const float* vu = &g_vunk[bh*DH];
    int b = bh >> 3, h = bh & 7;
    __nv_bfloat16* op = &g_ob[(size_t)(b*NN + i)*C_ + h*DH];
    #pragma unroll
    for (int d = 0; d < DH; d++) {
        float acc = ez*vu[d];
        #pragma unroll
        for (int s = 0; s < NSPLIT; s++)
            acc += g_pacc[(size_t)(p0+s)*DH + d]*ee[s];
        op[d] = __float2bfloat16(acc * invZ);
    }
}

// ---------------- depthwise 3x3 conv ----------------
__global__ void dw_k(const float* __restrict__ x,
                     const float* __restrict__ w,
                     const float* __restrict__ bias) {
    int gid = blockIdx.x*256 + threadIdx.x;
    if (gid >= B_*C_*NN) return;
    int n = gid % NN;
    int bc = gid / NN;
    int c = bc % C_, b = bc / C_;
    int y = n / WW, x0 = n % WW;
    float acc = bias[c];
    const float* xp = &x[(size_t)(b*C_ + c)*NN];
    const float* wp = &w[c*9];
    #pragma unroll
    for (int dy = 0; dy < 3; dy++) {
        int yy = y + dy - 1;
        if (yy < 0 || yy >= HH) continue;
        #pragma unroll
        for (int dx = 0; dx < 3; dx++) {
            int xx = x0 + dx - 1;
            if (xx < 0 || xx >= WW) continue;
            acc += xp[yy*WW + xx] * wp[dy*3 + dx];
        }
    }
    g_xdw[(size_t)c*(B_*NN) + b*NN + n] = acc;
}

// ---------------- merged: sg2 (blocks 0..575) + cgpool (576..607) ----------------
__global__ __launch_bounds__(256) void sg2_cgpool_k(const float* __restrict__ w,
                                                    const float* __restrict__ bias) {
    int bb = blockIdx.x;
    if (bb < B_*NN/8) {
        __shared__ float ws[GG*49];
        int tid = threadIdx.x;
        for (int i = tid; i < GG*49; i += 256) ws[i] = w[i];
        __syncthreads();
        int p = bb*8 + (tid >> 5);
        int lane = tid & 31;
        int b = p / NN, n = p % NN;
        int y = n / WW, x0 = n % WW;
        float acc = 0.f;
        for (int ky = 0; ky < 7; ky++) {
            int yy = y + ky - 3;
            if (yy < 0 || yy >= HH) continue;
            #pragma unroll
            for (int kx = 0; kx < 7; kx++) {
                int xx = x0 + kx - 3;
                if (xx < 0 || xx >= WW) continue;
                acc += g_t1[(b*NN + yy*WW + xx)*GG + lane] * ws[lane*49 + ky*7 + kx];
            }
        }
        #pragma unroll
        for (int o = 16; o; o >>= 1) acc += __shfl_xor_sync(~0u, acc, o);
        if (lane == 0) g_sg[p] = 1.f / (1.f + expf(-(acc + bias[0])));
    } else {
        int blk = bb - B_*NN/8;          // 0..31
        int b = blk / 16, part = blk % 16;
        int c = threadIdx.x;
        float s = 0;
        int n0 = part*144;
        for (int n = n0; n < n0 + 144; n++) s += g_xs[(size_t)(b*NN + n)*C_ + c];
        g_cgpart[blk*C_ + c] = s;
    }
}

// ---------------- channel gate: combine ----------------
__global__ void cggate_k(const float* __restrict__ w1, const float* __restrict__ b1,
                         const float* __restrict__ w2, const float* __restrict__ b2) {
    int b = blockIdx.x;
    int c = threadIdx.x;
    __shared__ float cgm[C_];
    __shared__ float t2[GG];
    float s = 0;
    for (int p = 0; p < 16; p++) s += g_cgpart[(b*16 + p)*C_ + c];
    cgm[c] = s * (1.0f/NN);
    __syncthreads();
    if (c < GG) {
        float a = b1[c];
        const float* wp = &w1[c*C_];
        for (int ci = 0; ci < C_; ci++) a += cgm[ci]*wp[ci];
        t2[c] = a / (1.f + expf(-a));
    }
    __syncthreads();
    float a2 = b2[c];
    const float* wp2 = &w2[c*GG];
    #pragma unroll
    for (int g = 0; g < GG; g++) a2 += t2[g]*wp2[g];
    g_cg[b*C_ + c] = 1.f / (1.f + expf(-a2));
}

// ---------------- x2 = x + gamma1*xs*sg*cg, fused LN2 ----------------
__global__ __launch_bounds__(256) void x2ln2_k(const float* __restrict__ x,
                                               const float* __restrict__ gamma1,
                                               const float* __restrict__ gg2,
                                               const float* __restrict__ bb2) {
    __shared__ float tile[C_*33];
    __shared__ float smu[32], sr[32];
    int blk = blockIdx.x;
    int b = blk / (NN/32);
    int n0 = (blk % (NN/32)) * 32;
    int tid = threadIdx.x;
    #pragma unroll
    for (int i = 0; i < 32; i++) {
        int idx = i*256 + tid;
        int c = idx >> 5, n = idx & 31;
        tile[c*33 + n] = x[(size_t)(b*C_ + c)*NN + n0 + n];
    }
    __syncthreads();
    float gm = gamma1[0];
    #pragma unroll
    for (int i = 0; i < 32; i++) {
        int row = b*NN + n0 + i;
        int c = tid;
        float v = tile[c*33 + i] + gm * g_xs[(size_t)row*C_ + c] * g_sg[row] * g_cg[b*C_ + c];
        g_x2[(size_t)row*C_ + c] = v;
        tile[c*33 + i] = v;
    }
    __syncthreads();
    int wid = tid >> 5, lane = tid & 31;
    #pragma unroll
    for (int j = 0; j < 4; j++) {
        int n = wid*4 + j;
        float s1 = 0, s2 = 0;
        #pragma unroll
        for (int i = 0; i < 8; i++) {
            float v = tile[(lane + i*32)*33 + n];
            s1 += v; s2 += v*v;
        }
        #pragma unroll
        for (int o = 16; o; o >>= 1) {
            s1 += __shfl_xor_sync(~0u, s1, o);
            s2 += __shfl_xor_sync(~0u, s2, o);
        }
        if (lane == 0) {
            float mu = s1*(1.0f/C_);
            float var = s2*(1.0f/C_) - mu*mu;
            smu[n] = mu; sr[n] = rsqrtf(var + 1e-6f);
        }
    }
    __syncthreads();
    #pragma unroll
    for (int i = 0; i < 32; i++) {
        int idx = i*256 + tid;
        int n = idx >> 8, c = idx & 255;
        float v = tile[c*33 + n];
        g_ln2b[(size_t)(b*NN + n0 + n)*C_ + c] =
            __float2bfloat16((v - smu[n])*sr[n]*gg2[c] + bb2[c]);
    }
}

// ---------------- host ----------------
#define GETSYM(p, s, T) do { void* _t; cudaGetSymbolAddress(&_t, s); p = (T*)_t; } while (0)

extern "C" void kernel_launch(void* const* d_in, const int* in_sizes, int n_in,
                              void* d_out, int out_size) {
    const float* x     = (const float*)d_in[0];
    const float* qkv_w = (const float*)d_in[1];
    const float* out_w = (const float*)d_in[2];
    const float* ln1_g = (const float*)d_in[3];
    const float* ln1_b = (const float*)d_in[4];
    const float* ln2_g = (const float*)d_in[5];
    const float* ln2_b = (const float*)d_in[6];
    const float* dw_w  = (const float*)d_in[7];
    const float* dw_b  = (const float*)d_in[8];
    const float* pw_w  = (const float*)d_in[9];
    const float* pw_b  = (const float*)d_in[10];
    const float* sg1_w = (const float*)d_in[11];
    const float* sg1_b = (const float*)d_in[12];
    const float* sg2_w = (const float*)d_in[13];
    const float* sg2_b = (const float*)d_in[14];
    const float* cg1_w = (const float*)d_in[15];
    const float* cg1_b = (const float*)d_in[16];
    const float* cg2_w = (const float*)d_in[17];
    const float* cg2_b = (const float*)d_in[18];
    const float* ff_w1 = (const float*)d_in[19];
    const float* ff_b1 = (const float*)d_in[20];
    const float* ff_w2 = (const float*)d_in[21];
    const float* ff_b2 = (const float*)d_in[22];
    const float* gamma1= (const float*)d_in[23];
    const float* gamma2= (const float*)d_in[24];
    float* out = (float*)d_out;
    (void)in_sizes; (void)n_in; (void)out_size;

    float *p_xdw, *p_xc, *p_xs, *p_t1;
    __nv_bfloat16 *p_xab, *p_ob, *p_xdwb, *p_xsb, *p_ln2b, *p_hb;
    __nv_bfloat16 *p_wqt, *p_wot, *p_wpwb, *p_wsg1, *p_w1t, *p_w2t;
    GETSYM(p_xdw, g_xdw, float); GETSYM(p_xc, g_xc, float); GETSYM(p_xs, g_xs, float);
    GETSYM(p_t1, g_t1, float);
    GETSYM(p_xab, g_xab, __nv_bfloat16); GETSYM(p_ob, g_ob, __nv_bfloat16);
    GETSYM(p_xdwb, g_xdwb, __nv_bfloat16); GETSYM(p_xsb, g_xsb, __nv_bfloat16);
    GETSYM(p_ln2b, g_ln2b, __nv_bfloat16); GETSYM(p_hb, g_hb, __nv_bfloat16);
    GETSYM(p_wqt, g_wqt, __nv_bfloat16); GETSYM(p_wot, g_wot, __nv_bfloat16);
    GETSYM(p_wpwb, g_wpwb, __nv_bfloat16); GETSYM(p_wsg1, g_wsg1, __nv_bfloat16);
    GETSYM(p_w1t, g_w1t, __nv_bfloat16); GETSYM(p_w2t, g_w2t, __nv_bfloat16);

    const int M = B_*NN;   // 4608

    // prep (QKV gemm stays at profiled launch idx 3)
    wprep_k<<<833, 256>>>(qkv_w, out_w, ff_w1, ff_w2, pw_w, sg1_w);
    ln1_k<<<B_*NN/32, 256>>>(x, ln1_g, ln1_b);
    dw_k<<<(B_*C_*NN)/256, 256>>>(x, dw_w, dw_b);
    gemm_bf<64,128,2><<<dim3(768/128, M/64), 256>>>(
        p_xab, p_wqt, nullptr, nullptr, nullptr, M, 3*C_, C_);
    tconv_k<<<dim3(M/32, C_/32), 256>>>(p_xdw, p_xdwb, C_, M);
    gemm_bf<64,64,0><<<dim3(C_/64, M/64), 256>>>(
        p_xdwb, p_wpwb, p_xc, nullptr, nullptr, M, C_, C_);
    // attention stats + selection
    bh_sums1_k<<<dim3(BHN, 12), 256>>>();
    scores_k<<<dim3(BHN, 9), 256>>>();
    select_k<<<32, 256>>>();
    vunk_fillo_k<<<BHN + (BHN*NN*DH)/256, 256>>>();
    attn_part_k<<<dim3(BHN, 9, NSPLIT), 64>>>();
    attn_comb_k<<<(BHN*KTOP + 127)/128, 128>>>();
    // out-proj epilogue: xs = o@out_w + xc + pw_b
    gemm_bf<64,64,3><<<dim3(C_/64, M/64), 256>>>(
        p_ob, p_wot, p_xs, pw_b, nullptr, M, C_, C_);

    // gates
    gemm_bf<64,32,5><<<dim3(1, M/64), 256>>>(
        p_xsb, p_wsg1, p_t1, sg1_b, nullptr, M, GG, C_);
    sg2_cgpool_k<<<B_*NN/8 + B_*16, 256>>>(sg2_w, sg2_b);
    cggate_k<<<B_, 256>>>(cg1_w, cg1_b, cg2_w, cg2_b);
    x2ln2_k<<<B_*NN/32, 256>>>(x, gamma1, ln2_g, ln2_b);

    // FFN (bf16)
    gemm_bf<64,128,1><<<dim3(HID/128, M/64), 256>>>(
        p_ln2b, p_w1t, p_hb, ff_b1, nullptr, M, HID, C_);
    gemm_bf<64,64,4><<<dim3(C_/64, M/64), 256>>>(
        p_hb, p_w2t, out, ff_b2, gamma2, M, C_, HID);
}

// round 15
// speedup vs baseline: 4.0454x; 1.0101x over previous
#include <cuda_runtime.h>
#include <cuda_bf16.h>
#include <math.h>

#define B_ 2
#define C_ 256
#define HH 48
#define WW 48
#define NN 2304          // 48*48
#define NHEAD 8
#define DH 32
#define BHN 16           // B_*NHEAD
#define KTOP 576
#define HID 1024
#define GG 32            // C/8 gate channels
#define QSCALE 0.17677669529663687f   // 1/sqrt(32)
#define NSPLIT 6         // attention column-split
#define CHUNK 96         // KTOP / NSPLIT

// ---------------- scratch (static device arrays; no allocation) ----------------
__device__ __nv_bfloat16 g_xab[B_*NN*C_];      // ln1 out (bf16)
__device__ __nv_bfloat16 g_qb [BHN*NN*DH];
__device__ __nv_bfloat16 g_kb [BHN*NN*DH];
__device__ __nv_bfloat16 g_vb [BHN*NN*DH];
__device__ float g_spart[BHN*12*3*DH];
__device__ float g_sums[BHN*3*DH];
__device__ float g_rs  [BHN*NN];
__device__ float g_cs  [BHN*NN];
__device__ int   g_rowlist[BHN*KTOP];
__device__ int   g_collist[BHN*KTOP];
__device__ float g_vunk[BHN*DH];
__device__ float g_pm  [BHN*KTOP*NSPLIT];
__device__ float g_pz  [BHN*KTOP*NSPLIT];
__device__ float g_pacc[BHN*KTOP*NSPLIT*DH];
__device__ __nv_bfloat16 g_ob [B_*NN*C_];      // attention out (bf16, gemm A)
__device__ __nv_bfloat16 g_xdwb[B_*NN*C_];     // dw out [M][C] bf16 (direct)
__device__ float g_xc  [B_*NN*C_];
__device__ float g_xs  [B_*NN*C_];
__device__ __nv_bfloat16 g_xsb[B_*NN*C_];      // xs bf16 (sg1 gemm A)
__device__ float g_t1  [B_*NN*GG];
__device__ float g_sg  [B_*NN];
__device__ float g_cgpart[B_*16*C_];
__device__ float g_x2  [B_*NN*C_];
__device__ __nv_bfloat16 g_ln2b[B_*NN*C_];
__device__ __nv_bfloat16 g_hb  [B_*NN*HID];
__device__ __nv_bfloat16 g_wqt [3*C_*C_];      // qkv_w^T [768][256]
__device__ __nv_bfloat16 g_wot [C_*C_];        // out_w^T [256][256]
__device__ __nv_bfloat16 g_wpwb[C_*C_];        // pw_w ([N][K]) bf16
__device__ __nv_bfloat16 g_wsg1[GG*C_];        // sg1_w ([N][K]) bf16
__device__ __nv_bfloat16 g_w1t [HID*C_];       // ff_w1^T [1024][256]
__device__ __nv_bfloat16 g_w2t [C_*HID];       // ff_w2^T [256][1024]

// ---------------- helpers ----------------
__device__ __forceinline__ void cp16(void* sptr, const void* gptr) {
    unsigned saddr = (unsigned)__cvta_generic_to_shared(sptr);
    asm volatile("cp.async.cg.shared.global [%0], [%1], 16;" :: "r"(saddr), "l"(gptr));
}
__device__ __forceinline__ void cp_commit() { asm volatile("cp.async.commit_group;"); }
__device__ __forceinline__ void cp_wait0()  { asm volatile("cp.async.wait_group 0;" ::: "memory"); }

__device__ __forceinline__ void mma_bf16(float* d, const unsigned* a,
                                         const unsigned* b, const float* c) {
    asm volatile("mma.sync.aligned.m16n8k16.row.col.f32.bf16.bf16.f32 "
        "{%0,%1,%2,%3}, {%4,%5,%6,%7}, {%8,%9}, {%10,%11,%12,%13};"
        : "=f"(d[0]),"=f"(d[1]),"=f"(d[2]),"=f"(d[3])
        : "r"(a[0]),"r"(a[1]),"r"(a[2]),"r"(a[3]),
          "r"(b[0]),"r"(b[1]),
          "f"(c[0]),"f"(c[1]),"f"(c[2]),"f"(c[3]));
}
__device__ __forceinline__ unsigned long long pack2(float lo, float hi) {
    unsigned long long r;
    asm("mov.b64 %0, {%1, %2};" : "=l"(r) : "f"(lo), "f"(hi));
    return r;
}
__device__ __forceinline__ void unpack2(unsigned long long v, float& lo, float& hi) {
    asm("mov.b64 {%0, %1}, %2;" : "=f"(lo), "=f"(hi) : "l"(v));
}
__device__ __forceinline__ unsigned long long fma2(unsigned long long a,
                                                   unsigned long long b,
                                                   unsigned long long c) {
    unsigned long long d;
    asm("fma.rn.f32x2 %0, %1, %2, %3;" : "=l"(d) : "l"(a), "l"(b), "l"(c));
    return d;
}
__device__ __forceinline__ unsigned long long mul2(unsigned long long a,
                                                   unsigned long long b) {
    unsigned long long d;
    asm("mul.rn.f32x2 %0, %1, %2;" : "=l"(d) : "l"(a), "l"(b));
    return d;
}
__device__ __forceinline__ float2 bf2f(unsigned u) {
    __nv_bfloat162 h = *reinterpret_cast<__nv_bfloat162*>(&u);
    return __bfloat1622float2(h);
}

// ---------------- bf16 tensor-core GEMM (A [M,K] bf16, B [N,K] bf16), BK=16, BM=64 ----------------
// EPI: 0=plain f32   1=bias+gelu->bf16   2=qkv scatter (bf16 q/k/v)
//      3=xs: f32 g_xs + bf16 g_xsb = v + g_xc + bias
//      4=final: out = x2 + gamma2*(v+bias), NCHW f32
//      5=sg1: silu(v+bias) -> f32 g_t1
template<int BM, int BN, int EPI>
__global__ __launch_bounds__(256, 3)
void gemm_bf(const __nv_bfloat16* __restrict__ A, const __nv_bfloat16* __restrict__ B,
             void* __restrict__ Cout, const float* __restrict__ bias,
             const float* __restrict__ aux, int M, int N, int K) {
    constexpr int BK = 16;
    constexpr int WM = BM/2, WN = BN/4;
    constexpr int MT = WM/16, NT = WN/8;
    constexpr int STR = 24;

    __shared__ __align__(16) __nv_bfloat16 As[2][BM*STR];
    __shared__ __align__(16) __nv_bfloat16 Bs[2][BN*STR];

    const int bm = blockIdx.y*BM, bn = blockIdx.x*BN;
    const int tid = threadIdx.x;
    const int lane = tid & 31, wid = tid >> 5;
    const int wm = wid >> 2, wn = wid & 3;
    const int g = lane >> 2, tig = lane & 3;

    float acc[MT][NT][4];
    #pragma unroll
    for (int i = 0; i < MT; i++)
        #pragma unroll
        for (int j = 0; j < NT; j++)
            #pragma unroll
            for (int l = 0; l < 4; l++) acc[i][j][l] = 0.f;

    auto copy_tile = [&](int st, int k0) {
        {
            constexpr int CA = BM*2;
            int ch = tid;
            if (CA == 256 || ch < CA) {
                int row = ch >> 1, c8 = (ch & 1)*8;
                cp16(&As[st][row*STR + c8], &A[(size_t)(bm+row)*K + k0 + c8]);
            }
        }
        {
            constexpr int CB = BN*2;
            int ch = tid;
            if (CB == 256 || ch < CB) {
                int row = ch >> 1, c8 = (ch & 1)*8;
                cp16(&Bs[st][row*STR + c8], &B[(size_t)(bn+row)*K + k0 + c8]);
            }
        }
    };

    copy_tile(0, 0);
    cp_commit();
    int stage = 0;
    for (int k0 = 0; k0 < K; k0 += BK) {
        cp_wait0();
        __syncthreads();
        if (k0 + BK < K) { copy_tile(stage^1, k0+BK); cp_commit(); }
        const __nv_bfloat16* as = As[stage];
        const __nv_bfloat16* bs = Bs[stage];
        int kk = 2*tig;
        unsigned afr[MT][4];
        #pragma unroll
        for (int mt = 0; mt < MT; mt++) {
            int r0 = wm*WM + mt*16 + g;
            afr[mt][0] = *(const unsigned*)&as[(r0  )*STR + kk  ];
            afr[mt][1] = *(const unsigned*)&as[(r0+8)*STR + kk  ];
            afr[mt][2] = *(const unsigned*)&as[(r0  )*STR + kk+8];
            afr[mt][3] = *(const unsigned*)&as[(r0+8)*STR + kk+8];
        }
        unsigned bfr[NT][2];
        #pragma unroll
        for (int nt = 0; nt < NT; nt++) {
            int c0 = wn*WN + nt*8 + g;
            bfr[nt][0] = *(const unsigned*)&bs[c0*STR + kk  ];
            bfr[nt][1] = *(const unsigned*)&bs[c0*STR + kk+8];
        }
        #pragma unroll
        for (int mt = 0; mt < MT; mt++)
            #pragma unroll
            for (int nt = 0; nt < NT; nt++)
                mma_bf16(acc[mt][nt], afr[mt], bfr[nt], acc[mt][nt]);
        stage ^= 1;
    }

    #pragma unroll
    for (int mt = 0; mt < MT; mt++) {
        int row0 = bm + wm*WM + mt*16 + g;
        #pragma unroll
        for (int nt = 0; nt < NT; nt++) {
            int col = bn + wn*WN + nt*8 + tig*2;
            #pragma unroll
            for (int half = 0; half < 2; half++) {
                int row = row0 + half*8;
                float v0 = acc[mt][nt][half*2], v1 = acc[mt][nt][half*2+1];
                if (EPI == 0) {
                    *(float2*)&((float*)Cout)[(size_t)row*N + col] = make_float2(v0, v1);
                } else if (EPI == 1) {
                    v0 += bias[col]; v1 += bias[col+1];
                    v0 = 0.5f*v0*(1.0f + erff(v0*0.70710678118654752f));
                    v1 = 0.5f*v1*(1.0f + erff(v1*0.70710678118654752f));
                    __nv_bfloat162 p;
                    p.x = __float2bfloat16(v0); p.y = __float2bfloat16(v1);
                    *(__nv_bfloat162*)&((__nv_bfloat16*)Cout)[(size_t)row*N + col] = p;
                } else if (EPI == 2) {
                    int b = row / NN, n = row - b*NN;
                    int part = col >> 8, cc = col & 255;
                    int h = cc >> 5, d = cc & 31;
                    size_t dst = ((size_t)(b*NHEAD + h)*NN + n)*DH + d;
                    __nv_bfloat162 p;
                    if (part == 0) {
                        p.x = __float2bfloat16(v0*QSCALE);
                        p.y = __float2bfloat16(v1*QSCALE);
                        *(__nv_bfloat162*)&g_qb[dst] = p;
                    } else if (part == 1) {
                        p.x = __float2bfloat16(v0); p.y = __float2bfloat16(v1);
                        *(__nv_bfloat162*)&g_kb[dst] = p;
                    } else {
                        p.x = __float2bfloat16(v0); p.y = __float2bfloat16(v1);
                        *(__nv_bfloat162*)&g_vb[dst] = p;
                    }
                } else if (EPI == 3) {
                    v0 += g_xc[(size_t)row*C_ + col]   + bias[col];
                    v1 += g_xc[(size_t)row*C_ + col+1] + bias[col+1];
                    *(float2*)&((float*)Cout)[(size_t)row*N + col] = make_float2(v0, v1);
                    __nv_bfloat162 p;
                    p.x = __float2bfloat16(v0); p.y = __float2bfloat16(v1);
                    *(__nv_bfloat162*)&g_xsb[(size_t)row*C_ + col] = p;
                } else if (EPI == 4) {
                    int b = row / NN, n = row - b*NN;
                    float gm = aux[0];
                    float o0 = g_x2[(size_t)row*C_ + col]   + gm*(v0 + bias[col]);
                    float o1 = g_x2[(size_t)row*C_ + col+1] + gm*(v1 + bias[col+1]);
                    float* C = (float*)Cout;
                    C[(size_t)(b*C_ + col  )*NN + n] = o0;
                    C[(size_t)(b*C_ + col+1)*NN + n] = o1;
                } else { // EPI == 5
                    v0 += bias[col]; v1 += bias[col+1];
                    v0 = v0 / (1.f + expf(-v0));
                    v1 = v1 / (1.f + expf(-v1));
                    *(float2*)&((float*)Cout)[(size_t)row*N + col] = make_float2(v0, v1);
                }
            }
        }
    }
}

// ---------------- prep mega-kernel: wprep (0..832) + ln1 (833..976) + dw (977..1744) ----------------
__global__ __launch_bounds__(256) void prep_k(const float* __restrict__ x,
                                              const float* __restrict__ dw_w,
                                              const float* __restrict__ dw_b,
                                              const float* __restrict__ ln1_g,
                                              const float* __restrict__ ln1_b,
                                              const float* __restrict__ qkv_w,
                                              const float* __restrict__ out_w,
                                              const float* __restrict__ ff_w1,
                                              const float* __restrict__ ff_w2,
                                              const float* __restrict__ pw_w,
                                              const float* __restrict__ sg1_w) {
    __shared__ float sm[C_*33];              // 33.8 KB union
    __shared__ float smu[32], sr[32];
    int bb = blockIdx.x;
    int tid = threadIdx.x;
    if (bb < 832) {
        if (bb < 768) {
            const float* in; __nv_bfloat16* outp; int K, N, t0;
            if (bb < 192)      { in = qkv_w; outp = g_wqt; K = 256; N = 768;  t0 = bb; }
            else if (bb < 256) { in = out_w; outp = g_wot; K = 256; N = 256;  t0 = bb-192; }
            else if (bb < 512) { in = ff_w1; outp = g_w1t; K = 256; N = 1024; t0 = bb-256; }
            else               { in = ff_w2; outp = g_w2t; K = 1024; N = 256; t0 = bb-512; }
            int ntile = N/32;
            int nb = (t0 % ntile)*32, kb = (t0 / ntile)*32;
            int tx = tid & 31, ty = tid >> 5;
            float (*tile)[33] = (float(*)[33])sm;
            #pragma unroll
            for (int i = 0; i < 32; i += 8)
                tile[ty+i][tx] = in[(size_t)(kb+ty+i)*N + nb+tx];
            __syncthreads();
            #pragma unroll
            for (int i = 0; i < 32; i += 8)
                outp[(size_t)(nb+ty+i)*K + kb+tx] = __float2bfloat16(tile[tx][ty+i]);
        } else {
            int base = (bb-768)*1024 + tid;
            #pragma unroll
            for (int r = 0; r < 4; r++)
                g_wpwb[base + r*256] = __float2bfloat16(pw_w[base + r*256]);
        }
    } else if (bb == 832) {
        for (int i = tid; i < GG*C_; i += 256)
            g_wsg1[i] = __float2bfloat16(sg1_w[i]);
    } else if (bb < 833 + 144) {
        // ---- ln1 ----
        int blk = bb - 833;
        int b = blk / (NN/32);
        int n0 = (blk % (NN/32)) * 32;
        #pragma unroll
        for (int i = 0; i < 32; i++) {
            int idx = i*256 + tid;
            int c = idx >> 5, n = idx & 31;
            sm[c*33 + n] = x[(size_t)(b*C_ + c)*NN + n0 + n];
        }
        __syncthreads();
        int wid = tid >> 5, lane = tid & 31;
        #pragma unroll
        for (int j = 0; j < 4; j++) {
            int n = wid*4 + j;
            float s1 = 0, s2 = 0;
            #pragma unroll
            for (int i = 0; i < 8; i++) {
                float v = sm[(lane + i*32)*33 + n];
                s1 += v; s2 += v*v;
            }
            #pragma unroll
            for (int o = 16; o; o >>= 1) {
                s1 += __shfl_xor_sync(~0u, s1, o);
                s2 += __shfl_xor_sync(~0u, s2, o);
            }
            if (lane == 0) {
                float mu = s1*(1.0f/C_);
                float var = s2*(1.0f/C_) - mu*mu;
                smu[n] = mu; sr[n] = rsqrtf(var + 1e-6f);
            }
        }
        __syncthreads();
        #pragma unroll
        for (int i = 0; i < 32; i++) {
            int idx = i*256 + tid;
            int n = idx >> 8, c = idx & 255;
            float v = sm[c*33 + n];
            g_xab[(size_t)(b*NN + n0 + n)*C_ + c] =
                __float2bfloat16((v - smu[n])*sr[n]*ln1_g[c] + ln1_b[c]);
        }
    } else {
        // ---- depthwise 3x3 conv, tile = (b, y-row, 32 channels), zero-pad rows ----
        int blk = bb - 977;                 // 0..767
        int b = blk / (HH*8);
        int rem = blk % (HH*8);
        int y = rem / 8;
        int c0 = (rem % 8) * 32;
        // sm layout: sm[c*147 + r*49 + xx]  (c stride 147: gcd(147,32)=1 -> conflict-free)
        for (int idx = tid; idx < 32*3*WW; idx += 256) {
            int c = idx / (3*WW);
            int rr = (idx / WW) % 3;
            int xx = idx % WW;
            int yy = y + rr - 1;
            float v = (yy >= 0 && yy < HH)
                ? x[(size_t)(b*C_ + c0 + c)*NN + yy*WW + xx] : 0.f;
            sm[c*147 + rr*49 + xx] = v;
        }
        __syncthreads();
        int c = tid & 31, xg = tid >> 5;
        float wreg[9];
        #pragma unroll
        for (int j = 0; j < 9; j++) wreg[j] = dw_w[(c0 + c)*9 + j];
        float bz = dw_b[c0 + c];
        #pragma unroll
        for (int xp = 0; xp < 6; xp++) {
            int xx = xp*8 + xg;
            float acc = bz;
            #pragma unroll
            for (int dy = 0; dy < 3; dy++) {
                #pragma unroll
                for (int dx = 0; dx < 3; dx++) {
                    int xn = xx + dx - 1;
                    if (xn < 0 || xn >= WW) continue;
                    acc += sm[c*147 + dy*49 + xn] * wreg[dy*3 + dx];
                }
            }
            g_xdwb[(size_t)(b*NN + y*WW + xx)*C_ + c0 + c] = __float2bfloat16(acc);
        }
    }
}

// ---------------- per-(b,h) partial sums ----------------
__global__ void bh_sums1_k() {
    int bh = blockIdx.x, yy = blockIdx.y;
    int t = threadIdx.x;
    int d = t & 31, part = t >> 5;
    float sq = 0, sk = 0, sv = 0;
    int n0 = yy*192 + part*24;
    for (int j = 0; j < 24; j++) {
        int idx = (bh*NN + n0 + j)*DH + d;
        sq += __bfloat162float(g_qb[idx]);
        sk += __bfloat162float(g_kb[idx]);
        sv += __bfloat162float(g_vb[idx]);
    }
    __shared__ float sh[3][8][32];
    sh[0][part][d]=sq; sh[1][part][d]=sk; sh[2][part][d]=sv;
    __syncthreads();
    if (t < 96) {
        int which = t >> 5, dd = t & 31;
        float s = 0;
        #pragma unroll
        for (int p = 0; p < 8; p++) s += sh[which][p][dd];
        g_spart[((bh*12 + yy)*3 + which)*DH + dd] = s;
    }
}

// ---------------- reduce partials + scores ----------------
__global__ void scores_k() {
    int bh = blockIdx.x, yy = blockIdx.y;
    int t = threadIdx.x;
    __shared__ float qs[DH], ks[DH];
    if (t < 96) {
        int which = t >> 5, d = t & 31;
        float s = 0;
        #pragma unroll
        for (int y = 0; y < 12; y++) s += g_spart[((bh*12 + y)*3 + which)*DH + d];
        if (which == 0) qs[d] = s;
        else if (which == 1) ks[d] = s;
        if (yy == 0) g_sums[(bh*3 + which)*DH + d] = s;
    }
    __syncthreads();
    int gid = bh*NN + yy*256 + t;
    unsigned uq[16], uk[16];
    {
        const uint4* qp4 = (const uint4*)&g_qb[(size_t)gid*DH];
        const uint4* kp4 = (const uint4*)&g_kb[(size_t)gid*DH];
        #pragma unroll
        for (int w = 0; w < 4; w++) {
            *(uint4*)&uq[w*4] = qp4[w];
            *(uint4*)&uk[w*4] = kp4[w];
        }
    }
    float r = 0, c = 0;
    #pragma unroll
    for (int w = 0; w < 16; w++) {
        float2 fq = bf2f(uq[w]), fk = bf2f(uk[w]);
        r += fq.x*ks[2*w] + fq.y*ks[2*w+1];
        c += qs[2*w]*fk.x + qs[2*w+1]*fk.y;
    }
    g_rs[gid] = r; g_cs[gid] = c;
}

// ---------------- exact top-k selection ----------------
__device__ __forceinline__ unsigned f2key(float f) {
    unsigned u = __float_as_uint(f);
    return (u & 0x80000000u) ? ~u : (u | 0x80000000u);
}

__device__ __forceinline__ int incl_scan256(int v, int t, int* wtot) {
    __syncthreads();
    int lane = t & 31, wid = t >> 5;
    #pragma unroll
    for (int o = 1; o < 32; o <<= 1) {
        int u = __shfl_up_sync(~0u, v, o);
        if (lane >= o) v += u;
    }
    if (lane == 31) wtot[wid] = v;
    __syncthreads();
    if (wid == 0) {
        int s = (lane < 8) ? wtot[lane] : 0;
        #pragma unroll
        for (int o = 1; o < 8; o <<= 1) {
            int u = __shfl_up_sync(~0u, s, o);
            if (lane >= o) s += u;
        }
        if (lane < 8) wtot[lane] = s;
    }
    __syncthreads();
    return v + (wid > 0 ? wtot[wid-1] : 0);
}

__global__ void select_k() {
    int blk = blockIdx.x;
    int type = blk >> 4, bh = blk & 15;
    const float* s = (type == 0 ? g_rs : g_cs) + bh*NN;
    int* list = (type == 0 ? g_rowlist : g_collist) + bh*KTOP;
    __shared__ unsigned keys[NN];
    __shared__ int hist[256];
    __shared__ int wtot[8];
    __shared__ unsigned sh_T;
    __shared__ int sh_take;
    int t = threadIdx.x;
    for (int i = t; i < NN; i += 256) keys[i] = f2key(s[i]);
    __syncthreads();

    unsigned prefix = 0, pmask = 0;
    int kneed = KTOP;
    for (int pass = 0; pass < 4; pass++) {
        int shift = 24 - 8*pass;
        hist[t] = 0;
        __syncthreads();
        for (int i = t; i < NN; i += 256) {
            unsigned u = keys[i];
            if ((u & pmask) == prefix) atomicAdd(&hist[(u >> shift) & 255], 1);
        }
        __syncthreads();
        int h = hist[t];
        int pre = incl_scan256(h, t, wtot);
        int total = wtot[7];
        int cum = total - pre;
        if (cum < kneed && cum + h >= kneed) {
            sh_T = prefix | ((unsigned)t << shift);
            sh_take = kneed - cum;
        }
        __syncthreads();
        prefix = sh_T;
        kneed = sh_take;
        pmask |= (0xffu << shift);
        __syncthreads();
    }
    unsigned T = prefix;
    int take = kneed;

    unsigned myk[9];
    int eqc = 0;
    #pragma unroll
    for (int j = 0; j < 9; j++) {
        myk[j] = keys[t*9 + j];
        eqc += (myk[j] == T);
    }
    int eqbase = incl_scan256(eqc, t, wtot) - eqc;

    bool kept[9];
    int keptc = 0, eqseen = 0;
    #pragma unroll
    for (int j = 0; j < 9; j++) {
        unsigned u = myk[j];
        bool gt = (u > T), eq = (u == T);
        bool kp = gt || (eq && (eqbase + eqseen) < take);
        if (eq) eqseen++;
        kept[j] = kp; keptc += kp;
    }
    int wbase = incl_scan256(keptc, t, wtot) - keptc;
    #pragma unroll
    for (int j = 0; j < 9; j++)
        if (kept[j]) list[wbase++] = t*9 + j;
}

// ---------------- merged: vunkept (blocks 0..15) + fill_o (rest) ----------------
__global__ void vunk_fillo_k() {
    int bb = blockIdx.x;
    if (bb < BHN) {
        int bh = bb;
        int t = threadIdx.x;
        int d = t & 31, part = t >> 5;
        float sv = 0;
        for (int jj = part; jj < KTOP; jj += 8) {
            int j = g_collist[bh*KTOP + jj];
            sv += __bfloat162float(g_vb[(bh*NN + j)*DH + d]);
        }
        __shared__ float sh[8][32];
        sh[part][d] = sv;
        __syncthreads();
        if (t < 32) {
            float s = 0;
            #pragma unroll
            for (int p = 0; p < 8; p++) s += sh[p][t];
            g_vunk[bh*DH + t] = g_sums[(bh*3+2)*DH + t] - s;
        }
    } else {
        int gid = (bb - BHN)*256 + threadIdx.x;
        if (gid >= BHN*NN*DH) return;
        int bh = gid / (NN*DH);
        int r = gid % (NN*DH);
        int n = r / DH, d = r & 31;
        int b = bh >> 3, h = bh & 7;
        g_ob[(size_t)(b*NN + n)*C_ + h*DH + d] =
            __float2bfloat16(g_sums[(bh*3+2)*DH + d] * (1.0f/NN));
    }
}

// ---------------- kept-row attention partials ----------------
__global__ __launch_bounds__(64) void attn_part_k() {
    int bh = blockIdx.x;
    int t = threadIdx.x;
    int slot = blockIdx.y*64 + t;
    int chunk = blockIdx.z;
    int i = g_rowlist[bh*KTOP + slot];

    unsigned long long qp2[16];
    {
        unsigned uq[16];
        const uint4* qp4 = (const uint4*)&g_qb[(size_t)(bh*NN + i)*DH];
        #pragma unroll
        for (int w = 0; w < 4; w++) *(uint4*)&uq[w*4] = qp4[w];
        #pragma unroll
        for (int w = 0; w < 16; w++) {
            float2 f = bf2f(uq[w]);
            qp2[w] = pack2(f.x, f.y);
        }
    }

    float m = -3.0e38f, Z = 0.f;
    unsigned long long acc2[16];
    #pragma unroll
    for (int idx = 0; idx < 16; idx++) acc2[idx] = 0ull;

    __shared__ int cj[CHUNK];
    __shared__ __align__(16) float Kc[CHUNK][DH];
    __shared__ __align__(16) float Vc[CHUNK][DH];

    {
        int c0 = chunk*CHUNK;
        for (int jj = t; jj < CHUNK; jj += 64) cj[jj] = g_collist[bh*KTOP + c0 + jj];
        __syncthreads();
        for (int idx = t; idx < CHUNK*DH; idx += 64) {
            int jj = idx >> 5, d = idx & 31;
            int base = (bh*NN + cj[jj])*DH + d;
            Kc[jj][d] = __bfloat162float(g_kb[base]);
            Vc[jj][d] = __bfloat162float(g_vb[base]);
        }
        __syncthreads();
        #pragma unroll 2
        for (int jj = 0; jj < CHUNK; jj++) {
            const unsigned long long* kp = (const unsigned long long*)Kc[jj];
            unsigned long long p0 = 0ull, p1 = 0ull;
            #pragma unroll
            for (int w = 0; w < 16; w += 2) {
                p0 = fma2(qp2[w  ], kp[w  ], p0);
                p1 = fma2(qp2[w+1], kp[w+1], p1);
            }
            float a, b2, c2, d2;
            unpack2(p0, a, b2); unpack2(p1, c2, d2);
            float s = (a + b2) + (c2 + d2);
            float e;
            if (s > m) {
                float cf = __expf(m - s);
                unsigned long long cf2 = pack2(cf, cf);
                Z = Z*cf;
                #pragma unroll
                for (int w = 0; w < 16; w++) acc2[w] = mul2(acc2[w], cf2);
                m = s;
                e = 1.f;
            } else {
                e = __expf(s - m);
            }
            Z += e;
            unsigned long long ee = pack2(e, e);
            const unsigned long long* vp = (const unsigned long long*)Vc[jj];
            #pragma unroll
            for (int w = 0; w < 16; w++) acc2[w] = fma2(ee, vp[w], acc2[w]);
        }
    }
    int pidx = (bh*KTOP + slot)*NSPLIT + chunk;
    g_pm[pidx] = m;
    g_pz[pidx] = Z;
    float* pa = &g_pacc[(size_t)pidx*DH];
    #pragma unroll
    for (int w = 0; w < 16; w++) {
        float lo, hi;
        unpack2(acc2[w], lo, hi);
        pa[2*w] = lo; pa[2*w+1] = hi;
    }
}

// ---------------- combine partials + zero-column correction -> bf16 ----------------
__global__ void attn_comb_k() {
    int gid = blockIdx.x*128 + threadIdx.x;
    if (gid >= BHN*KTOP) return;
    int bh = gid / KTOP, slot = gid % KTOP;
    int i = g_rowlist[bh*KTOP + slot];
    int p0 = gid*NSPLIT;
    float mm[NSPLIT];
    float mstar = 0.f;
    #pragma unroll
    for (int s = 0; s < NSPLIT; s++) { mm[s] = g_pm[p0+s]; mstar = fmaxf(mstar, mm[s]); }
    float ee[NSPLIT];
    float ez = __expf(-mstar);
    float Z = (float)(NN - KTOP) * ez;
    #pragma unroll
    for (int s = 0; s < NSPLIT; s++) { ee[s] = __expf(mm[s] - mstar); Z += g_pz[p0+s]*ee[s]; }
    float invZ = 1.f / Z;
    const float* vu = &g_vunk[bh*DH];
    int b = bh >> 3, h = bh & 7;
    __nv_bfloat16* op = &g_ob[(size_t)(b*NN + i)*C_ + h*DH];
    #pragma unroll
    for (int d = 0; d < DH; d++) {
        float acc = ez*vu[d];
        #pragma unroll
        for (int s = 0; s < NSPLIT; s++)
            acc += g_pacc[(size_t)(p0+s)*DH + d]*ee[s];
        op[d] = __float2bfloat16(acc * invZ);
    }
}

// ---------------- merged: sg2 (blocks 0..575) + cgpool (576..607) ----------------
__global__ __launch_bounds__(256) void sg2_cgpool_k(const float* __restrict__ w,
                                                    const float* __restrict__ bias) {
    int bb = blockIdx.x;
    if (bb < B_*NN/8) {
        __shared__ float ws[GG*49];
        int tid = threadIdx.x;
        for (int i = tid; i < GG*49; i += 256) ws[i] = w[i];
        __syncthreads();
        int p = bb*8 + (tid >> 5);
        int lane = tid & 31;
        int b = p / NN, n = p % NN;
        int y = n / WW, x0 = n % WW;
        float acc = 0.f;
        for (int ky = 0; ky < 7; ky++) {
            int yy = y + ky - 3;
            if (yy < 0 || yy >= HH) continue;
            #pragma unroll
            for (int kx = 0; kx < 7; kx++) {
                int xx = x0 + kx - 3;
                if (xx < 0 || xx >= WW) continue;
                acc += g_t1[(b*NN + yy*WW + xx)*GG + lane] * ws[lane*49 + ky*7 + kx];
            }
        }
        #pragma unroll
        for (int o = 16; o; o >>= 1) acc += __shfl_xor_sync(~0u, acc, o);
        if (lane == 0) g_sg[p] = 1.f / (1.f + expf(-(acc + bias[0])));
    } else {
        int blk = bb - B_*NN/8;          // 0..31
        int b = blk / 16, part = blk % 16;
        int c = threadIdx.x;
        float s = 0;
        int n0 = part*144;
        for (int n = n0; n < n0 + 144; n++) s += g_xs[(size_t)(b*NN + n)*C_ + c];
        g_cgpart[blk*C_ + c] = s;
    }
}

// ---------------- x2 = x + gamma1*xs*sg*cg, fused channel-gate + LN2 ----------------
__global__ __launch_bounds__(256) void x2ln2_k(const float* __restrict__ x,
                                               const float* __restrict__ gamma1,
                                               const float* __restrict__ gg2,
                                               const float* __restrict__ bb2,
                                               const float* __restrict__ cg1w,
                                               const float* __restrict__ cg1b,
                                               const float* __restrict__ cg2w,
                                               const float* __restrict__ cg2b) {
    __shared__ float tile[C_*33];
    __shared__ float smu[32], sr[32];
    __shared__ float cgm[C_];
    __shared__ float t2s[GG];
    int blk = blockIdx.x;
    int b = blk / (NN/32);
    int n0 = (blk % (NN/32)) * 32;
    int tid = threadIdx.x;
    // channel gate (redundant per block; tiny)
    {
        float s = 0;
        #pragma unroll
        for (int p = 0; p < 16; p++) s += g_cgpart[(b*16 + p)*C_ + tid];
        cgm[tid] = s * (1.0f/NN);
    }
    #pragma unroll
    for (int i = 0; i < 32; i++) {
        int idx = i*256 + tid;
        int c = idx >> 5, n = idx & 31;
        tile[c*33 + n] = x[(size_t)(b*C_ + c)*NN + n0 + n];
    }
    __syncthreads();
    if (tid < GG) {
        float a = cg1b[tid];
        const float* wp = &cg1w[tid*C_];
        for (int ci = 0; ci < C_; ci++) a += cgm[ci]*wp[ci];
        t2s[tid] = a / (1.f + expf(-a));
    }
    __syncthreads();
    float cgv;
    {
        float a2 = cg2b[tid];
        const float* wp2 = &cg2w[tid*GG];
        #pragma unroll
        for (int g = 0; g < GG; g++) a2 += t2s[g]*wp2[g];
        cgv = 1.f / (1.f + expf(-a2));
    }
    float gm = gamma1[0];
    #pragma unroll
    for (int i = 0; i < 32; i++) {
        int row = b*NN + n0 + i;
        int c = tid;
        float v = tile[c*33 + i] + gm * g_xs[(size_t)row*C_ + c] * g_sg[row] * cgv;
        g_x2[(size_t)row*C_ + c] = v;
        tile[c*33 + i] = v;
    }
    __syncthreads();
    int wid = tid >> 5, lane = tid & 31;
    #pragma unroll
    for (int j = 0; j < 4; j++) {
        int n = wid*4 + j;
        float s1 = 0, s2 = 0;
        #pragma unroll
        for (int i = 0; i < 8; i++) {
            float v = tile[(lane + i*32)*33 + n];
            s1 += v; s2 += v*v;
        }
        #pragma unroll
        for (int o = 16; o; o >>= 1) {
            s1 += __shfl_xor_sync(~0u, s1, o);
            s2 += __shfl_xor_sync(~0u, s2, o);
        }
        if (lane == 0) {
            float mu = s1*(1.0f/C_);
            float var = s2*(1.0f/C_) - mu*mu;
            smu[n] = mu; sr[n] = rsqrtf(var + 1e-6f);
        }
    }
    __syncthreads();
    #pragma unroll
    for (int i = 0; i < 32; i++) {
        int idx = i*256 + tid;
        int n = idx >> 8, c = idx & 255;
        float v = tile[c*33 + n];
        g_ln2b[(size_t)(b*NN + n0 + n)*C_ + c] =
            __float2bfloat16((v - smu[n])*sr[n]*gg2[c] + bb2[c]);
    }
}

// ---------------- host ----------------
#define GETSYM(p, s, T) do { void* _t; cudaGetSymbolAddress(&_t, s); p = (T*)_t; } while (0)

extern "C" void kernel_launch(void* const* d_in, const int* in_sizes, int n_in,
                              void* d_out, int out_size) {
    const float* x     = (const float*)d_in[0];
    const float* qkv_w = (const float*)d_in[1];
    const float* out_w = (const float*)d_in[2];
    const float* ln1_g = (const float*)d_in[3];
    const float* ln1_b = (const float*)d_in[4];
    const float* ln2_g = (const float*)d_in[5];
    const float* ln2_b = (const float*)d_in[6];
    const float* dw_w  = (const float*)d_in[7];
    const float* dw_b  = (const float*)d_in[8];
    const float* pw_w  = (const float*)d_in[9];
    const float* pw_b  = (const float*)d_in[10];
    const float* sg1_w = (const float*)d_in[11];
    const float* sg1_b = (const float*)d_in[12];
    const float* sg2_w = (const float*)d_in[13];
    const float* sg2_b = (const float*)d_in[14];
    const float* cg1_w = (const float*)d_in[15];
    const float* cg1_b = (const float*)d_in[16];
    const float* cg2_w = (const float*)d_in[17];
    const float* cg2_b = (const float*)d_in[18];
    const float* ff_w1 = (const float*)d_in[19];
    const float* ff_b1 = (const float*)d_in[20];
    const float* ff_w2 = (const float*)d_in[21];
    const float* ff_b2 = (const float*)d_in[22];
    const float* gamma1= (const float*)d_in[23];
    const float* gamma2= (const float*)d_in[24];
    float* out = (float*)d_out;
    (void)in_sizes; (void)n_in; (void)out_size;

    float *p_xc, *p_xs, *p_t1;
    __nv_bfloat16 *p_xab, *p_ob, *p_xdwb, *p_xsb, *p_ln2b, *p_hb;
    __nv_bfloat16 *p_wqt, *p_wot, *p_wpwb, *p_wsg1, *p_w1t, *p_w2t;
    GETSYM(p_xc, g_xc, float); GETSYM(p_xs, g_xs, float);
    GETSYM(p_t1, g_t1, float);
    GETSYM(p_xab, g_xab, __nv_bfloat16); GETSYM(p_ob, g_ob, __nv_bfloat16);
    GETSYM(p_xdwb, g_xdwb, __nv_bfloat16); GETSYM(p_xsb, g_xsb, __nv_bfloat16);
    GETSYM(p_ln2b, g_ln2b, __nv_bfloat16); GETSYM(p_hb, g_hb, __nv_bfloat16);
    GETSYM(p_wqt, g_wqt, __nv_bfloat16); GETSYM(p_wot, g_wot, __nv_bfloat16);
    GETSYM(p_wpwb, g_wpwb, __nv_bfloat16); GETSYM(p_wsg1, g_wsg1, __nv_bfloat16);
    GETSYM(p_w1t, g_w1t, __nv_bfloat16); GETSYM(p_w2t, g_w2t, __nv_bfloat16);

    const int M = B_*NN;   // 4608

    // 0: all prep (weights + ln1 + depthwise conv)
    prep_k<<<1745, 256>>>(x, dw_w, dw_b, ln1_g, ln1_b,
                          qkv_w, out_w, ff_w1, ff_w2, pw_w, sg1_w);
    // 1: pw gemm (xc = xdw @ pw_w)
    gemm_bf<64,64,0><<<dim3(C_/64, M/64), 256>>>(
        p_xdwb, p_wpwb, p_xc, nullptr, nullptr, M, C_, C_);
    // 2: QKV gemm
    gemm_bf<64,128,2><<<dim3(768/128, M/64), 256>>>(
        p_xab, p_wqt, nullptr, nullptr, nullptr, M, 3*C_, C_);
    // attention stats + selection
    bh_sums1_k<<<dim3(BHN, 12), 256>>>();
    scores_k<<<dim3(BHN, 9), 256>>>();
    select_k<<<32, 256>>>();
    vunk_fillo_k<<<BHN + (BHN*NN*DH)/256, 256>>>();
    attn_part_k<<<dim3(BHN, 9, NSPLIT), 64>>>();
    attn_comb_k<<<(BHN*KTOP + 127)/128, 128>>>();
    // out-proj epilogue: xs = o@out_w + xc + pw_b
    gemm_bf<64,64,3><<<dim3(C_/64, M/64), 256>>>(
        p_ob, p_wot, p_xs, pw_b, nullptr, M, C_, C_);

    // gates
    gemm_bf<64,32,5><<<dim3(1, M/64), 256>>>(
        p_xsb, p_wsg1, p_t1, sg1_b, nullptr, M, GG, C_);
    sg2_cgpool_k<<<B_*NN/8 + B_*16, 256>>>(sg2_w, sg2_b);
    x2ln2_k<<<B_*NN/32, 256>>>(x, gamma1, ln2_g, ln2_b,
                               cg1_w, cg1_b, cg2_w, cg2_b);

    // FFN (bf16)
    gemm_bf<64,128,1><<<dim3(HID/128, M/64), 256>>>(
        p_ln2b, p_w1t, p_hb, ff_b1, nullptr, M, HID, C_);
    gemm_bf<64,64,4><<<dim3(C_/64, M/64), 256>>>(
        p_hb, p_w2t, out, ff_b2, gamma2, M, C_, HID);
}

// round 16
// speedup vs baseline: 4.1703x; 1.0309x over previous
#include <cuda_runtime.h>
#include <cuda_bf16.h>
#include <math.h>

#define B_ 2
#define C_ 256
#define HH 48
#define WW 48
#define NN 2304          // 48*48
#define NHEAD 8
#define DH 32
#define BHN 16           // B_*NHEAD
#define KTOP 576
#define HID 1024
#define GG 32            // C/8 gate channels
#define QSCALE 0.17677669529663687f   // 1/sqrt(32)
#define NSPLIT 6         // attention column-split
#define CHUNK 96         // KTOP / NSPLIT

// ---------------- scratch (static device arrays; no allocation) ----------------
__device__ __nv_bfloat16 g_xab[B_*NN*C_];      // ln1 out (bf16)
__device__ __nv_bfloat16 g_qb [BHN*NN*DH];
__device__ __nv_bfloat16 g_kb [BHN*NN*DH];
__device__ __nv_bfloat16 g_vb [BHN*NN*DH];
__device__ float g_spart[BHN*12*3*DH];
__device__ float g_sums[BHN*3*DH];
__device__ float g_rs  [BHN*NN];
__device__ float g_cs  [BHN*NN];
__device__ int   g_rowlist[BHN*KTOP];
__device__ int   g_collist[BHN*KTOP];
__device__ float g_vunk[BHN*DH];
__device__ float g_pm  [BHN*KTOP*NSPLIT];
__device__ float g_pz  [BHN*KTOP*NSPLIT];
__device__ float g_pacc[BHN*KTOP*NSPLIT*DH];
__device__ __nv_bfloat16 g_ob [B_*NN*C_];      // attention out (bf16, gemm A)
__device__ __nv_bfloat16 g_xdwb[B_*NN*C_];     // dw out [M][C] bf16 (direct)
__device__ float g_xc  [B_*NN*C_];
__device__ float g_xs  [B_*NN*C_];
__device__ __nv_bfloat16 g_xsb[B_*NN*C_];      // xs bf16 (sg1 gemm A)
__device__ float g_t1  [B_*NN*GG];
__device__ float g_sg  [B_*NN];
__device__ float g_cgpart[B_*16*C_];
__device__ float g_x2  [B_*NN*C_];
__device__ __nv_bfloat16 g_ln2b[B_*NN*C_];
__device__ __nv_bfloat16 g_hb  [B_*NN*HID];
__device__ __nv_bfloat16 g_wqt [3*C_*C_];      // qkv_w^T [768][256]
__device__ __nv_bfloat16 g_wot [C_*C_];        // out_w^T [256][256]
__device__ __nv_bfloat16 g_wpwb[C_*C_];        // pw_w ([N][K]) bf16
__device__ __nv_bfloat16 g_wsg1[GG*C_];        // sg1_w ([N][K]) bf16
__device__ __nv_bfloat16 g_w1t [HID*C_];       // ff_w1^T [1024][256]
__device__ __nv_bfloat16 g_w2t [C_*HID];       // ff_w2^T [256][1024]

// ---------------- helpers ----------------
__device__ __forceinline__ void cp16(void* sptr, const void* gptr) {
    unsigned saddr = (unsigned)__cvta_generic_to_shared(sptr);
    asm volatile("cp.async.cg.shared.global [%0], [%1], 16;" :: "r"(saddr), "l"(gptr));
}
__device__ __forceinline__ void cp_commit() { asm volatile("cp.async.commit_group;"); }
__device__ __forceinline__ void cp_wait0()  { asm volatile("cp.async.wait_group 0;" ::: "memory"); }

__device__ __forceinline__ void mma_bf16(float* d, const unsigned* a,
                                         const unsigned* b, const float* c) {
    asm volatile("mma.sync.aligned.m16n8k16.row.col.f32.bf16.bf16.f32 "
        "{%0,%1,%2,%3}, {%4,%5,%6,%7}, {%8,%9}, {%10,%11,%12,%13};"
        : "=f"(d[0]),"=f"(d[1]),"=f"(d[2]),"=f"(d[3])
        : "r"(a[0]),"r"(a[1]),"r"(a[2]),"r"(a[3]),
          "r"(b[0]),"r"(b[1]),
          "f"(c[0]),"f"(c[1]),"f"(c[2]),"f"(c[3]));
}
__device__ __forceinline__ unsigned long long pack2(float lo, float hi) {
    unsigned long long r;
    asm("mov.b64 %0, {%1, %2};" : "=l"(r) : "f"(lo), "f"(hi));
    return r;
}
__device__ __forceinline__ void unpack2(unsigned long long v, float& lo, float& hi) {
    asm("mov.b64 {%0, %1}, %2;" : "=f"(lo), "=f"(hi) : "l"(v));
}
__device__ __forceinline__ unsigned long long fma2(unsigned long long a,
                                                   unsigned long long b,
                                                   unsigned long long c) {
    unsigned long long d;
    asm("fma.rn.f32x2 %0, %1, %2, %3;" : "=l"(d) : "l"(a), "l"(b), "l"(c));
    return d;
}
__device__ __forceinline__ unsigned long long mul2(unsigned long long a,
                                                   unsigned long long b) {
    unsigned long long d;
    asm("mul.rn.f32x2 %0, %1, %2;" : "=l"(d) : "l"(a), "l"(b));
    return d;
}
__device__ __forceinline__ float2 bf2f(unsigned u) {
    __nv_bfloat162 h = *reinterpret_cast<__nv_bfloat162*>(&u);
    return __bfloat1622float2(h);
}

// ---------------- bf16 tensor-core GEMM body (A [M,K], B [N,K]), BK=16 ----------------
// EPI: 0=plain f32   1=bias+gelu->bf16   2=qkv scatter (bf16 q/k/v)
//      3=xs: f32 g_xs + bf16 g_xsb = v + g_xc + bias
//      4=final: out = x2 + gamma2*(v+bias), NCHW f32
//      5=sg1: silu(v+bias) -> f32 g_t1
template<int BM, int BN, int EPI>
__device__ __forceinline__ void gemm_body(
    __nv_bfloat16* As, __nv_bfloat16* Bs,   // [2*BM*24], [2*BN*24]
    const __nv_bfloat16* __restrict__ A, const __nv_bfloat16* __restrict__ B,
    void* __restrict__ Cout, const float* __restrict__ bias,
    const float* __restrict__ aux, int M, int N, int K, int bxi, int byi) {
    constexpr int BK = 16;
    constexpr int WM = BM/2, WN = BN/4;
    constexpr int MT = WM/16, NT = WN/8;
    constexpr int STR = 24;

    const int bm = byi*BM, bn = bxi*BN;
    const int tid = threadIdx.x;
    const int lane = tid & 31, wid = tid >> 5;
    const int wm = wid >> 2, wn = wid & 3;
    const int g = lane >> 2, tig = lane & 3;

    float acc[MT][NT][4];
    #pragma unroll
    for (int i = 0; i < MT; i++)
        #pragma unroll
        for (int j = 0; j < NT; j++)
            #pragma unroll
            for (int l = 0; l < 4; l++) acc[i][j][l] = 0.f;

    auto copy_tile = [&](int st, int k0) {
        {
            constexpr int CA = BM*2;
            int ch = tid;
            if (CA == 256 || ch < CA) {
                int row = ch >> 1, c8 = (ch & 1)*8;
                cp16(&As[st*BM*STR + row*STR + c8], &A[(size_t)(bm+row)*K + k0 + c8]);
            }
        }
        {
            constexpr int CB = BN*2;
            int ch = tid;
            if (CB == 256 || ch < CB) {
                int row = ch >> 1, c8 = (ch & 1)*8;
                cp16(&Bs[st*BN*STR + row*STR + c8], &B[(size_t)(bn+row)*K + k0 + c8]);
            }
        }
    };

    copy_tile(0, 0);
    cp_commit();
    int stage = 0;
    for (int k0 = 0; k0 < K; k0 += BK) {
        cp_wait0();
        __syncthreads();
        if (k0 + BK < K) { copy_tile(stage^1, k0+BK); cp_commit(); }
        const __nv_bfloat16* as = As + stage*BM*STR;
        const __nv_bfloat16* bs = Bs + stage*BN*STR;
        int kk = 2*tig;
        unsigned afr[MT][4];
        #pragma unroll
        for (int mt = 0; mt < MT; mt++) {
            int r0 = wm*WM + mt*16 + g;
            afr[mt][0] = *(const unsigned*)&as[(r0  )*STR + kk  ];
            afr[mt][1] = *(const unsigned*)&as[(r0+8)*STR + kk  ];
            afr[mt][2] = *(const unsigned*)&as[(r0  )*STR + kk+8];
            afr[mt][3] = *(const unsigned*)&as[(r0+8)*STR + kk+8];
        }
        unsigned bfr[NT][2];
        #pragma unroll
        for (int nt = 0; nt < NT; nt++) {
            int c0 = wn*WN + nt*8 + g;
            bfr[nt][0] = *(const unsigned*)&bs[c0*STR + kk  ];
            bfr[nt][1] = *(const unsigned*)&bs[c0*STR + kk+8];
        }
        #pragma unroll
        for (int mt = 0; mt < MT; mt++)
            #pragma unroll
            for (int nt = 0; nt < NT; nt++)
                mma_bf16(acc[mt][nt], afr[mt], bfr[nt], acc[mt][nt]);
        stage ^= 1;
    }

    #pragma unroll
    for (int mt = 0; mt < MT; mt++) {
        int row0 = bm + wm*WM + mt*16 + g;
        #pragma unroll
        for (int nt = 0; nt < NT; nt++) {
            int col = bn + wn*WN + nt*8 + tig*2;
            #pragma unroll
            for (int half = 0; half < 2; half++) {
                int row = row0 + half*8;
                float v0 = acc[mt][nt][half*2], v1 = acc[mt][nt][half*2+1];
                if (EPI == 0) {
                    *(float2*)&((float*)Cout)[(size_t)row*N + col] = make_float2(v0, v1);
                } else if (EPI == 1) {
                    v0 += bias[col]; v1 += bias[col+1];
                    v0 = 0.5f*v0*(1.0f + erff(v0*0.70710678118654752f));
                    v1 = 0.5f*v1*(1.0f + erff(v1*0.70710678118654752f));
                    __nv_bfloat162 p;
                    p.x = __float2bfloat16(v0); p.y = __float2bfloat16(v1);
                    *(__nv_bfloat162*)&((__nv_bfloat16*)Cout)[(size_t)row*N + col] = p;
                } else if (EPI == 2) {
                    int b = row / NN, n = row - b*NN;
                    int part = col >> 8, cc = col & 255;
                    int h = cc >> 5, d = cc & 31;
                    size_t dst = ((size_t)(b*NHEAD + h)*NN + n)*DH + d;
                    __nv_bfloat162 p;
                    if (part == 0) {
                        p.x = __float2bfloat16(v0*QSCALE);
                        p.y = __float2bfloat16(v1*QSCALE);
                        *(__nv_bfloat162*)&g_qb[dst] = p;
                    } else if (part == 1) {
                        p.x = __float2bfloat16(v0); p.y = __float2bfloat16(v1);
                        *(__nv_bfloat162*)&g_kb[dst] = p;
                    } else {
                        p.x = __float2bfloat16(v0); p.y = __float2bfloat16(v1);
                        *(__nv_bfloat162*)&g_vb[dst] = p;
                    }
                } else if (EPI == 3) {
                    v0 += g_xc[(size_t)row*C_ + col]   + bias[col];
                    v1 += g_xc[(size_t)row*C_ + col+1] + bias[col+1];
                    *(float2*)&((float*)Cout)[(size_t)row*N + col] = make_float2(v0, v1);
                    __nv_bfloat162 p;
                    p.x = __float2bfloat16(v0); p.y = __float2bfloat16(v1);
                    *(__nv_bfloat162*)&g_xsb[(size_t)row*C_ + col] = p;
                } else if (EPI == 4) {
                    int b = row / NN, n = row - b*NN;
                    float gm = aux[0];
                    float o0 = g_x2[(size_t)row*C_ + col]   + gm*(v0 + bias[col]);
                    float o1 = g_x2[(size_t)row*C_ + col+1] + gm*(v1 + bias[col+1]);
                    float* C = (float*)Cout;
                    C[(size_t)(b*C_ + col  )*NN + n] = o0;
                    C[(size_t)(b*C_ + col+1)*NN + n] = o1;
                } else { // EPI == 5
                    v0 += bias[col]; v1 += bias[col+1];
                    v0 = v0 / (1.f + expf(-v0));
                    v1 = v1 / (1.f + expf(-v1));
                    *(float2*)&((float*)Cout)[(size_t)row*N + col] = make_float2(v0, v1);
                }
            }
        }
    }
}

template<int BM, int BN, int EPI>
__global__ __launch_bounds__(256, 3)
void gemm_bf(const __nv_bfloat16* __restrict__ A, const __nv_bfloat16* __restrict__ B,
             void* __restrict__ Cout, const float* __restrict__ bias,
             const float* __restrict__ aux, int M, int N, int K) {
    __shared__ __align__(16) __nv_bfloat16 As[2*BM*24];
    __shared__ __align__(16) __nv_bfloat16 Bs[2*BN*24];
    gemm_body<BM,BN,EPI>(As, Bs, A, B, Cout, bias, aux, M, N, K,
                         blockIdx.x, blockIdx.y);
}

// merged pw (blocks 0..287: 4x72) + QKV (blocks 288..719: 6x72)
__global__ __launch_bounds__(256, 3)
void gemm_pw_qkv_k(const __nv_bfloat16* __restrict__ xdwb,
                   const __nv_bfloat16* __restrict__ wpwb,
                   float* __restrict__ xc,
                   const __nv_bfloat16* __restrict__ xab,
                   const __nv_bfloat16* __restrict__ wqt) {
    __shared__ __align__(16) __nv_bfloat16 As[2*64*24];
    __shared__ __align__(16) __nv_bfloat16 Bs[2*128*24];
    int bb = blockIdx.x;
    if (bb < 288) {
        gemm_body<64,64,0>(As, Bs, xdwb, wpwb, xc, nullptr, nullptr,
                           B_*NN, C_, C_, bb % 4, bb / 4);
    } else {
        bb -= 288;
        gemm_body<64,128,2>(As, Bs, xab, wqt, nullptr, nullptr, nullptr,
                            B_*NN, 3*C_, C_, bb % 6, bb / 6);
    }
}

// ---------------- prep mega-kernel: wprep (0..832) + ln1 (833..976) + dw (977..1744) ----------------
__global__ __launch_bounds__(256) void prep_k(const float* __restrict__ x,
                                              const float* __restrict__ dw_w,
                                              const float* __restrict__ dw_b,
                                              const float* __restrict__ ln1_g,
                                              const float* __restrict__ ln1_b,
                                              const float* __restrict__ qkv_w,
                                              const float* __restrict__ out_w,
                                              const float* __restrict__ ff_w1,
                                              const float* __restrict__ ff_w2,
                                              const float* __restrict__ pw_w,
                                              const float* __restrict__ sg1_w) {
    __shared__ float sm[C_*33];
    __shared__ float smu[32], sr[32];
    int bb = blockIdx.x;
    int tid = threadIdx.x;
    if (bb < 832) {
        if (bb < 768) {
            const float* in; __nv_bfloat16* outp; int K, N, t0;
            if (bb < 192)      { in = qkv_w; outp = g_wqt; K = 256; N = 768;  t0 = bb; }
            else if (bb < 256) { in = out_w; outp = g_wot; K = 256; N = 256;  t0 = bb-192; }
            else if (bb < 512) { in = ff_w1; outp = g_w1t; K = 256; N = 1024; t0 = bb-256; }
            else               { in = ff_w2; outp = g_w2t; K = 1024; N = 256; t0 = bb-512; }
            int ntile = N/32;
            int nb = (t0 % ntile)*32, kb = (t0 / ntile)*32;
            int tx = tid & 31, ty = tid >> 5;
            float (*tile)[33] = (float(*)[33])sm;
            #pragma unroll
            for (int i = 0; i < 32; i += 8)
                tile[ty+i][tx] = in[(size_t)(kb+ty+i)*N + nb+tx];
            __syncthreads();
            #pragma unroll
            for (int i = 0; i < 32; i += 8)
                outp[(size_t)(nb+ty+i)*K + kb+tx] = __float2bfloat16(tile[tx][ty+i]);
        } else {
            int base = (bb-768)*1024 + tid;
            #pragma unroll
            for (int r = 0; r < 4; r++)
                g_wpwb[base + r*256] = __float2bfloat16(pw_w[base + r*256]);
        }
    } else if (bb == 832) {
        for (int i = tid; i < GG*C_; i += 256)
            g_wsg1[i] = __float2bfloat16(sg1_w[i]);
    } else if (bb < 833 + 144) {
        int blk = bb - 833;
        int b = blk / (NN/32);
        int n0 = (blk % (NN/32)) * 32;
        #pragma unroll
        for (int i = 0; i < 32; i++) {
            int idx = i*256 + tid;
            int c = idx >> 5, n = idx & 31;
            sm[c*33 + n] = x[(size_t)(b*C_ + c)*NN + n0 + n];
        }
        __syncthreads();
        int wid = tid >> 5, lane = tid & 31;
        #pragma unroll
        for (int j = 0; j < 4; j++) {
            int n = wid*4 + j;
            float s1 = 0, s2 = 0;
            #pragma unroll
            for (int i = 0; i < 8; i++) {
                float v = sm[(lane + i*32)*33 + n];
                s1 += v; s2 += v*v;
            }
            #pragma unroll
            for (int o = 16; o; o >>= 1) {
                s1 += __shfl_xor_sync(~0u, s1, o);
                s2 += __shfl_xor_sync(~0u, s2, o);
            }
            if (lane == 0) {
                float mu = s1*(1.0f/C_);
                float var = s2*(1.0f/C_) - mu*mu;
                smu[n] = mu; sr[n] = rsqrtf(var + 1e-6f);
            }
        }
        __syncthreads();
        #pragma unroll
        for (int i = 0; i < 32; i++) {
            int idx = i*256 + tid;
            int n = idx >> 8, c = idx & 255;
            float v = sm[c*33 + n];
            g_xab[(size_t)(b*NN + n0 + n)*C_ + c] =
                __float2bfloat16((v - smu[n])*sr[n]*ln1_g[c] + ln1_b[c]);
        }
    } else {
        int blk = bb - 977;                 // 0..767
        int b = blk / (HH*8);
        int rem = blk % (HH*8);
        int y = rem / 8;
        int c0 = (rem % 8) * 32;
        for (int idx = tid; idx < 32*3*WW; idx += 256) {
            int c = idx / (3*WW);
            int rr = (idx / WW) % 3;
            int xx = idx % WW;
            int yy = y + rr - 1;
            float v = (yy >= 0 && yy < HH)
                ? x[(size_t)(b*C_ + c0 + c)*NN + yy*WW + xx] : 0.f;
            sm[c*147 + rr*49 + xx] = v;
        }
        __syncthreads();
        int c = tid & 31, xg = tid >> 5;
        float wreg[9];
        #pragma unroll
        for (int j = 0; j < 9; j++) wreg[j] = dw_w[(c0 + c)*9 + j];
        float bz = dw_b[c0 + c];
        #pragma unroll
        for (int xp = 0; xp < 6; xp++) {
            int xx = xp*8 + xg;
            float acc = bz;
            #pragma unroll
            for (int dy = 0; dy < 3; dy++) {
                #pragma unroll
                for (int dx = 0; dx < 3; dx++) {
                    int xn = xx + dx - 1;
                    if (xn < 0 || xn >= WW) continue;
                    acc += sm[c*147 + dy*49 + xn] * wreg[dy*3 + dx];
                }
            }
            g_xdwb[(size_t)(b*NN + y*WW + xx)*C_ + c0 + c] = __float2bfloat16(acc);
        }
    }
}

// ---------------- per-(b,h) partial sums (uint4 + shuffle reduction) ----------------
__global__ void bh_sums1_k() {
    int bh = blockIdx.x, yy = blockIdx.y;     // 16 x 12
    int t = threadIdx.x;                      // 256
    size_t base = ((size_t)bh*NN + yy*192)*DH;    // 6144 elems = 768 uint4
    const uint4* q4 = (const uint4*)(g_qb + base);
    const uint4* k4 = (const uint4*)(g_kb + base);
    const uint4* v4 = (const uint4*)(g_vb + base);
    float pq[8], pk[8], pv[8];
    #pragma unroll
    for (int i = 0; i < 8; i++) { pq[i]=0; pk[i]=0; pv[i]=0; }
    #pragma unroll
    for (int j = 0; j < 3; j++) {
        int u = t + j*256;
        uint4 aq = q4[u], ak = k4[u], av = v4[u];
        const unsigned* wq = (const unsigned*)&aq;
        const unsigned* wk = (const unsigned*)&ak;
        const unsigned* wv = (const unsigned*)&av;
        #pragma unroll
        for (int w = 0; w < 4; w++) {
            float2 fq = bf2f(wq[w]), fk = bf2f(wk[w]), fv = bf2f(wv[w]);
            pq[2*w] += fq.x; pq[2*w+1] += fq.y;
            pk[2*w] += fk.x; pk[2*w+1] += fk.y;
            pv[2*w] += fv.x; pv[2*w+1] += fv.y;
        }
    }
    // uint4 index u has d-range d0 = (u&3)*8 = (t&3)*8 (stride 256 preserves &3).
    // fold lanes sharing lane&3 (8 lanes per group): xor strides 4,8,16
    #pragma unroll
    for (int o = 4; o <= 16; o <<= 1) {
        #pragma unroll
        for (int i = 0; i < 8; i++) {
            pq[i] += __shfl_xor_sync(~0u, pq[i], o);
            pk[i] += __shfl_xor_sync(~0u, pk[i], o);
            pv[i] += __shfl_xor_sync(~0u, pv[i], o);
        }
    }
    __shared__ float sh[3][8][32];
    int lane = t & 31, wid = t >> 5;
    if (lane < 4) {
        #pragma unroll
        for (int i = 0; i < 8; i++) {
            sh[0][wid][lane*8 + i] = pq[i];
            sh[1][wid][lane*8 + i] = pk[i];
            sh[2][wid][lane*8 + i] = pv[i];
        }
    }
    __syncthreads();
    if (t < 96) {
        int which = t >> 5, dd = t & 31;
        float s = 0;
        #pragma unroll
        for (int p = 0; p < 8; p++) s += sh[which][p][dd];
        g_spart[((bh*12 + yy)*3 + which)*DH + dd] = s;
    }
}

// ---------------- reduce partials + scores ----------------
__global__ void scores_k() {
    int bh = blockIdx.x, yy = blockIdx.y;
    int t = threadIdx.x;
    __shared__ float qs[DH], ks[DH];
    if (t < 96) {
        int which = t >> 5, d = t & 31;
        float s = 0;
        #pragma unroll
        for (int y = 0; y < 12; y++) s += g_spart[((bh*12 + y)*3 + which)*DH + d];
        if (which == 0) qs[d] = s;
        else if (which == 1) ks[d] = s;
        if (yy == 0) g_sums[(bh*3 + which)*DH + d] = s;
    }
    __syncthreads();
    int gid = bh*NN + yy*256 + t;
    unsigned uq[16], uk[16];
    {
        const uint4* qp4 = (const uint4*)&g_qb[(size_t)gid*DH];
        const uint4* kp4 = (const uint4*)&g_kb[(size_t)gid*DH];
        #pragma unroll
        for (int w = 0; w < 4; w++) {
            *(uint4*)&uq[w*4] = qp4[w];
            *(uint4*)&uk[w*4] = kp4[w];
        }
    }
    float r = 0, c = 0;
    #pragma unroll
    for (int w = 0; w < 16; w++) {
        float2 fq = bf2f(uq[w]), fk = bf2f(uk[w]);
        r += fq.x*ks[2*w] + fq.y*ks[2*w+1];
        c += qs[2*w]*fk.x + qs[2*w+1]*fk.y;
    }
    g_rs[gid] = r; g_cs[gid] = c;
}

// ---------------- exact top-k selection ----------------
__device__ __forceinline__ unsigned f2key(float f) {
    unsigned u = __float_as_uint(f);
    return (u & 0x80000000u) ? ~u : (u | 0x80000000u);
}

__device__ __forceinline__ int incl_scan256(int v, int t, int* wtot) {
    __syncthreads();
    int lane = t & 31, wid = t >> 5;
    #pragma unroll
    for (int o = 1; o < 32; o <<= 1) {
        int u = __shfl_up_sync(~0u, v, o);
        if (lane >= o) v += u;
    }
    if (lane == 31) wtot[wid] = v;
    __syncthreads();
    if (wid == 0) {
        int s = (lane < 8) ? wtot[lane] : 0;
        #pragma unroll
        for (int o = 1; o < 8; o <<= 1) {
            int u = __shfl_up_sync(~0u, s, o);
            if (lane >= o) s += u;
        }
        if (lane < 8) wtot[lane] = s;
    }
    __syncthreads();
    return v + (wid > 0 ? wtot[wid-1] : 0);
}

__global__ void select_k() {
    int blk = blockIdx.x;
    int type = blk >> 4, bh = blk & 15;
    const float* s = (type == 0 ? g_rs : g_cs) + bh*NN;
    int* list = (type == 0 ? g_rowlist : g_collist) + bh*KTOP;
    __shared__ unsigned keys[NN];
    __shared__ int hist[256];
    __shared__ int wtot[8];
    __shared__ unsigned sh_T;
    __shared__ int sh_take;
    int t = threadIdx.x;
    for (int i = t; i < NN; i += 256) keys[i] = f2key(s[i]);
    __syncthreads();

    unsigned prefix = 0, pmask = 0;
    int kneed = KTOP;
    for (int pass = 0; pass < 4; pass++) {
        int shift = 24 - 8*pass;
        hist[t] = 0;
        __syncthreads();
        for (int i = t; i < NN; i += 256) {
            unsigned u = keys[i];
            if ((u & pmask) == prefix) atomicAdd(&hist[(u >> shift) & 255], 1);
        }
        __syncthreads();
        int h = hist[t];
        int pre = incl_scan256(h, t, wtot);
        int total = wtot[7];
        int cum = total - pre;
        if (cum < kneed && cum + h >= kneed) {
            sh_T = prefix | ((unsigned)t << shift);
            sh_take = kneed - cum;
        }
        __syncthreads();
        prefix = sh_T;
        kneed = sh_take;
        pmask |= (0xffu << shift);
        __syncthreads();
    }
    unsigned T = prefix;
    int take = kneed;

    unsigned myk[9];
    int eqc = 0;
    #pragma unroll
    for (int j = 0; j < 9; j++) {
        myk[j] = keys[t*9 + j];
        eqc += (myk[j] == T);
    }
    int eqbase = incl_scan256(eqc, t, wtot) - eqc;

    bool kept[9];
    int keptc = 0, eqseen = 0;
    #pragma unroll
    for (int j = 0; j < 9; j++) {
        unsigned u = myk[j];
        bool gt = (u > T), eq = (u == T);
        bool kp = gt || (eq && (eqbase + eqseen) < take);
        if (eq) eqseen++;
        kept[j] = kp; keptc += kp;
    }
    int wbase = incl_scan256(keptc, t, wtot) - keptc;
    #pragma unroll
    for (int j = 0; j < 9; j++)
        if (kept[j]) list[wbase++] = t*9 + j;
}

// ---------------- merged: vunkept (blocks 0..15) + fill_o (rest) ----------------
__global__ void vunk_fillo_k() {
    int bb = blockIdx.x;
    if (bb < BHN) {
        int bh = bb;
        int t = threadIdx.x;
        int d = t & 31, part = t >> 5;
        float sv = 0;
        for (int jj = part; jj < KTOP; jj += 8) {
            int j = g_collist[bh*KTOP + jj];
            sv += __bfloat162float(g_vb[(bh*NN + j)*DH + d]);
        }
        __shared__ float sh[8][32];
        sh[part][d] = sv;
        __syncthreads();
        if (t < 32) {
            float s = 0;
            #pragma unroll
            for (int p = 0; p < 8; p++) s += sh[p][t];
            g_vunk[bh*DH + t] = g_sums[(bh*3+2)*DH + t] - s;
        }
    } else {
        int gid = (bb - BHN)*256 + threadIdx.x;
        if (gid >= BHN*NN*DH) return;
        int bh = gid / (NN*DH);
        int r = gid % (NN*DH);
        int n = r / DH, d = r & 31;
        int b = bh >> 3, h = bh & 7;
        g_ob[(size_t)(b*NN + n)*C_ + h*DH + d] =
            __float2bfloat16(g_sums[(bh*3+2)*DH + d] * (1.0f/NN));
    }
}

// ---------------- kept-row attention partials ----------------
__global__ __launch_bounds__(64) void attn_part_k() {
    int bh = blockIdx.x;
    int t = threadIdx.x;
    int slot = blockIdx.y*64 + t;
    int chunk = blockIdx.z;
    int i = g_rowlist[bh*KTOP + slot];

    unsigned long long qp2[16];
    {
        unsigned uq[16];
        const uint4* qp4 = (const uint4*)&g_qb[(size_t)(bh*NN + i)*DH];
        #pragma unroll
        for (int w = 0; w < 4; w++) *(uint4*)&uq[w*4] = qp4[w];
        #pragma unroll
        for (int w = 0; w < 16; w++) {
            float2 f = bf2f(uq[w]);
            qp2[w] = pack2(f.x, f.y);
        }
    }

    float m = -3.0e38f, Z = 0.f;
    unsigned long long acc2[16];
    #pragma unroll
    for (int idx = 0; idx < 16; idx++) acc2[idx] = 0ull;

    __shared__ int cj[CHUNK];
    __shared__ __align__(16) float Kc[CHUNK][DH];
    __shared__ __align__(16) float Vc[CHUNK][DH];

    {
        int c0 = chunk*CHUNK;
        for (int jj = t; jj < CHUNK; jj += 64) cj[jj] = g_collist[bh*KTOP + c0 + jj];
        __syncthreads();
        for (int idx = t; idx < CHUNK*DH; idx += 64) {
            int jj = idx >> 5, d = idx & 31;
            int base = (bh*NN + cj[jj])*DH + d;
            Kc[jj][d] = __bfloat162float(g_kb[base]);
            Vc[jj][d] = __bfloat162float(g_vb[base]);
        }
        __syncthreads();
        #pragma unroll 2
        for (int jj = 0; jj < CHUNK; jj++) {
            const unsigned long long* kp = (const unsigned long long*)Kc[jj];
            unsigned long long p0 = 0ull, p1 = 0ull;
            #pragma unroll
            for (int w = 0; w < 16; w += 2) {
                p0 = fma2(qp2[w  ], kp[w  ], p0);
                p1 = fma2(qp2[w+1], kp[w+1], p1);
            }
            float a, b2, c2, d2;
            unpack2(p0, a, b2); unpack2(p1, c2, d2);
            float s = (a + b2) + (c2 + d2);
            float e;
            if (s > m) {
                float cf = __expf(m - s);
                unsigned long long cf2 = pack2(cf, cf);
                Z = Z*cf;
                #pragma unroll
                for (int w = 0; w < 16; w++) acc2[w] = mul2(acc2[w], cf2);
                m = s;
                e = 1.f;
            } else {
                e = __expf(s - m);
            }
            Z += e;
            unsigned long long ee = pack2(e, e);
            const unsigned long long* vp = (const unsigned long long*)Vc[jj];
            #pragma unroll
            for (int w = 0; w < 16; w++) acc2[w] = fma2(ee, vp[w], acc2[w]);
        }
    }
    int pidx = (bh*KTOP + slot)*NSPLIT + chunk;
    g_pm[pidx] = m;
    g_pz[pidx] = Z;
    float* pa = &g_pacc[(size_t)pidx*DH];
    #pragma unroll
    for (int w = 0; w < 16; w++) {
        float lo, hi;
        unpack2(acc2[w], lo, hi);
        pa[2*w] = lo; pa[2*w+1] = hi;
    }
}

// ---------------- combine partials + zero-column correction -> bf16 ----------------
__global__ void attn_comb_k() {
    int gid = blockIdx.x*128 + threadIdx.x;
    if (gid >= BHN*KTOP) return;
    int bh = gid / KTOP, slot = gid % KTOP;
    int i = g_rowlist[bh*KTOP + slot];
    int p0 = gid*NSPLIT;
    float mm[NSPLIT];
    float mstar = 0.f;
    #pragma unroll
    for (int s = 0; s < NSPLIT; s++) { mm[s] = g_pm[p0+s]; mstar = fmaxf(mstar, mm[s]); }
    float ee[NSPLIT];
    float ez = __expf(-mstar);
    float Z = (float)(NN - KTOP) * ez;
    #pragma unroll
    for (int s = 0; s < NSPLIT; s++) { ee[s] = __expf(mm[s] - mstar); Z += g_pz[p0+s]*ee[s]; }
    float invZ = 1.f / Z;
    const float* vu = &g_vunk[bh*DH];
    int b = bh >> 3, h = bh & 7;
    __nv_bfloat16* op = &g_ob[(size_t)(b*NN + i)*C_ + h*DH];
    #pragma unroll
    for (int d = 0; d < DH; d++) {
        float acc = ez*vu[d];
        #pragma unroll
        for (int s = 0; s < NSPLIT; s++)
            acc += g_pacc[(size_t)(p0+s)*DH + d]*ee[s];
        op[d] = __float2bfloat16(acc * invZ);
    }
}

// ---------------- merged: sg2 (blocks 0..575) + cgpool (576..607) ----------------
__global__ __launch_bounds__(256) void sg2_cgpool_k(const float* __restrict__ w,
                                                    const float* __restrict__ bias) {
    int bb = blockIdx.x;
    if (bb < B_*NN/8) {
        __shared__ float ws[GG*49];
        int tid = threadIdx.x;
        for (int i = tid; i < GG*49; i += 256) ws[i] = w[i];
        __syncthreads();
        int p = bb*8 + (tid >> 5);
        int lane = tid & 31;
        int b = p / NN, n = p % NN;
        int y = n / WW, x0 = n % WW;
        float acc = 0.f;
        for (int ky = 0; ky < 7; ky++) {
            int yy = y + ky - 3;
            if (yy < 0 || yy >= HH) continue;
            #pragma unroll
            for (int kx = 0; kx < 7; kx++) {
                int xx = x0 + kx - 3;
                if (xx < 0 || xx >= WW) continue;
                acc += g_t1[(b*NN + yy*WW + xx)*GG + lane] * ws[lane*49 + ky*7 + kx];
            }
        }
        #pragma unroll
        for (int o = 16; o; o >>= 1) acc += __shfl_xor_sync(~0u, acc, o);
        if (lane == 0) g_sg[p] = 1.f / (1.f + expf(-(acc + bias[0])));
    } else {
        int blk = bb - B_*NN/8;          // 0..31
        int b = blk / 16, part = blk % 16;
        int c = threadIdx.x;
        float s = 0;
        int n0 = part*144;
        for (int n = n0; n < n0 + 144; n++) s += g_xs[(size_t)(b*NN + n)*C_ + c];
        g_cgpart[blk*C_ + c] = s;
    }
}

// ---------------- x2 = x + gamma1*xs*sg*cg, fused channel-gate + LN2 ----------------
__global__ __launch_bounds__(256) void x2ln2_k(const float* __restrict__ x,
                                               const float* __restrict__ gamma1,
                                               const float* __restrict__ gg2,
                                               const float* __restrict__ bb2,
                                               const float* __restrict__ cg1w,
                                               const float* __restrict__ cg1b,
                                               const float* __restrict__ cg2w,
                                               const float* __restrict__ cg2b) {
    __shared__ float tile[C_*33];
    __shared__ float smu[32], sr[32];
    __shared__ float cgm[C_];
    __shared__ float t2s[GG];
    int blk = blockIdx.x;
    int b = blk / (NN/32);
    int n0 = (blk % (NN/32)) * 32;
    int tid = threadIdx.x;
    {
        float s = 0;
        #pragma unroll
        for (int p = 0; p < 16; p++) s += g_cgpart[(b*16 + p)*C_ + tid];
        cgm[tid] = s * (1.0f/NN);
    }
    #pragma unroll
    for (int i = 0; i < 32; i++) {
        int idx = i*256 + tid;
        int c = idx >> 5, n = idx & 31;
        tile[c*33 + n] = x[(size_t)(b*C_ + c)*NN + n0 + n];
    }
    __syncthreads();
    if (tid < GG) {
        float a = cg1b[tid];
        const float* wp = &cg1w[tid*C_];
        for (int ci = 0; ci < C_; ci++) a += cgm[ci]*wp[ci];
        t2s[tid] = a / (1.f + expf(-a));
    }
    __syncthreads();
    float cgv;
    {
        float a2 = cg2b[tid];
        const float* wp2 = &cg2w[tid*GG];
        #pragma unroll
        for (int g = 0; g < GG; g++) a2 += t2s[g]*wp2[g];
        cgv = 1.f / (1.f + expf(-a2));
    }
    float gm = gamma1[0];
    #pragma unroll
    for (int i = 0; i < 32; i++) {
        int row = b*NN + n0 + i;
        int c = tid;
        float v = tile[c*33 + i] + gm * g_xs[(size_t)row*C_ + c] * g_sg[row] * cgv;
        g_x2[(size_t)row*C_ + c] = v;
        tile[c*33 + i] = v;
    }
    __syncthreads();
    int wid = tid >> 5, lane = tid & 31;
    #pragma unroll
    for (int j = 0; j < 4; j++) {
        int n = wid*4 + j;
        float s1 = 0, s2 = 0;
        #pragma unroll
        for (int i = 0; i < 8; i++) {
            float v = tile[(lane + i*32)*33 + n];
            s1 += v; s2 += v*v;
        }
        #pragma unroll
        for (int o = 16; o; o >>= 1) {
            s1 += __shfl_xor_sync(~0u, s1, o);
            s2 += __shfl_xor_sync(~0u, s2, o);
        }
        if (lane == 0) {
            float mu = s1*(1.0f/C_);
            float var = s2*(1.0f/C_) - mu*mu;
            smu[n] = mu; sr[n] = rsqrtf(var + 1e-6f);
        }
    }
    __syncthreads();
    #pragma unroll
    for (int i = 0; i < 32; i++) {
        int idx = i*256 + tid;
        int n = idx >> 8, c = idx & 255;
        float v = tile[c*33 + n];
        g_ln2b[(size_t)(b*NN + n0 + n)*C_ + c] =
            __float2bfloat16((v - smu[n])*sr[n]*gg2[c] + bb2[c]);
    }
}

// ---------------- host ----------------
#define GETSYM(p, s, T) do { void* _t; cudaGetSymbolAddress(&_t, s); p = (T*)_t; } while (0)

extern "C" void kernel_launch(void* const* d_in, const int* in_sizes, int n_in,
                              void* d_out, int out_size) {
    const float* x     = (const float*)d_in[0];
    const float* qkv_w = (const float*)d_in[1];
    const float* out_w = (const float*)d_in[2];
    const float* ln1_g = (const float*)d_in[3];
    const float* ln1_b = (const float*)d_in[4];
    const float* ln2_g = (const float*)d_in[5];
    const float* ln2_b = (const float*)d_in[6];
    const float* dw_w  = (const float*)d_in[7];
    const float* dw_b  = (const float*)d_in[8];
    const float* pw_w  = (const float*)d_in[9];
    const float* pw_b  = (const float*)d_in[10];
    const float* sg1_w = (const float*)d_in[11];
    const float* sg1_b = (const float*)d_in[12];
    const float* sg2_w = (const float*)d_in[13];
    const float* sg2_b = (const float*)d_in[14];
    const float* cg1_w = (const float*)d_in[15];
    const float* cg1_b = (const float*)d_in[16];
    const float* cg2_w = (const float*)d_in[17];
    const float* cg2_b = (const float*)d_in[18];
    const float* ff_w1 = (const float*)d_in[19];
    const float* ff_b1 = (const float*)d_in[20];
    const float* ff_w2 = (const float*)d_in[21];
    const float* ff_b2 = (const float*)d_in[22];
    const float* gamma1= (const float*)d_in[23];
    const float* gamma2= (const float*)d_in[24];
    float* out = (float*)d_out;
    (void)in_sizes; (void)n_in; (void)out_size;

    float *p_xc, *p_xs, *p_t1;
    __nv_bfloat16 *p_xab, *p_ob, *p_xdwb, *p_xsb, *p_ln2b, *p_hb;
    __nv_bfloat16 *p_wqt, *p_wot, *p_wpwb, *p_wsg1, *p_w1t, *p_w2t;
    GETSYM(p_xc, g_xc, float); GETSYM(p_xs, g_xs, float);
    GETSYM(p_t1, g_t1, float);
    GETSYM(p_xab, g_xab, __nv_bfloat16); GETSYM(p_ob, g_ob, __nv_bfloat16);
    GETSYM(p_xdwb, g_xdwb, __nv_bfloat16); GETSYM(p_xsb, g_xsb, __nv_bfloat16);
    GETSYM(p_ln2b, g_ln2b, __nv_bfloat16); GETSYM(p_hb, g_hb, __nv_bfloat16);
    GETSYM(p_wqt, g_wqt, __nv_bfloat16); GETSYM(p_wot, g_wot, __nv_bfloat16);
    GETSYM(p_wpwb, g_wpwb, __nv_bfloat16); GETSYM(p_wsg1, g_wsg1, __nv_bfloat16);
    GETSYM(p_w1t, g_w1t, __nv_bfloat16); GETSYM(p_w2t, g_w2t, __nv_bfloat16);

    const int M = B_*NN;   // 4608

    // 0: all prep (weights + ln1 + depthwise conv)
    prep_k<<<1745, 256>>>(x, dw_w, dw_b, ln1_g, ln1_b,
                          qkv_w, out_w, ff_w1, ff_w2, pw_w, sg1_w);
    // 1: merged pw + QKV gemms
    gemm_pw_qkv_k<<<720, 256>>>(p_xdwb, p_wpwb, p_xc, p_xab, p_wqt);
    // attention stats + selection
    bh_sums1_k<<<dim3(BHN, 12), 256>>>();
    scores_k<<<dim3(BHN, 9), 256>>>();
    select_k<<<32, 256>>>();
    vunk_fillo_k<<<BHN + (BHN*NN*DH)/256, 256>>>();
    attn_part_k<<<dim3(BHN, 9, NSPLIT), 64>>>();
    attn_comb_k<<<(BHN*KTOP + 127)/128, 128>>>();
    // out-proj epilogue: xs = o@out_w + xc + pw_b
    gemm_bf<64,64,3><<<dim3(C_/64, M/64), 256>>>(
        p_ob, p_wot, p_xs, pw_b, nullptr, M, C_, C_);

    // gates
    gemm_bf<64,32,5><<<dim3(1, M/64), 256>>>(
        p_xsb, p_wsg1, p_t1, sg1_b, nullptr, M, GG, C_);
    sg2_cgpool_k<<<B_*NN/8 + B_*16, 256>>>(sg2_w, sg2_b);
    x2ln2_k<<<B_*NN/32, 256>>>(x, gamma1, ln2_g, ln2_b,
                               cg1_w, cg1_b, cg2_w, cg2_b);

    // FFN (bf16)
    gemm_bf<64,128,1><<<dim3(HID/128, M/64), 256>>>(
        p_ln2b, p_w1t, p_hb, ff_b1, nullptr, M, HID, C_);
    gemm_bf<64,64,4><<<dim3(C_/64, M/64), 256>>>(
        p_hb, p_w2t, out, ff_b2, gamma2, M, C_, HID);
}

// round 17
// speedup vs baseline: 4.2378x; 1.0162x over previous
#include <cuda_runtime.h>
#include <cuda_bf16.h>
#include <math.h>

#define B_ 2
#define C_ 256
#define HH 48
#define WW 48
#define NN 2304          // 48*48
#define NHEAD 8
#define DH 32
#define BHN 16           // B_*NHEAD
#define KTOP 576
#define HID 1024
#define GG 32            // C/8 gate channels
#define QSCALE 0.17677669529663687f   // 1/sqrt(32)
#define NSPLIT 6         // attention column-split
#define CHUNK 96         // KTOP / NSPLIT

// ---------------- scratch (static device arrays; no allocation) ----------------
__device__ __nv_bfloat16 g_xab[B_*NN*C_];      // ln1 out (bf16)
__device__ __nv_bfloat16 g_qb [BHN*NN*DH];
__device__ __nv_bfloat16 g_kb [BHN*NN*DH];
__device__ __nv_bfloat16 g_vb [BHN*NN*DH];
__device__ float g_spart[BHN*12*3*DH];
__device__ float g_sums[BHN*3*DH];
__device__ float g_rs  [BHN*NN];
__device__ float g_cs  [BHN*NN];
__device__ int   g_rowlist[BHN*KTOP];
__device__ int   g_collist[BHN*KTOP];
__device__ float g_vunk[BHN*DH];
__device__ float g_pm  [BHN*KTOP*NSPLIT];
__device__ float g_pz  [BHN*KTOP*NSPLIT];
__device__ float g_pacc[BHN*KTOP*NSPLIT*DH];
__device__ __nv_bfloat16 g_ob [B_*NN*C_];      // attention out (bf16, gemm A)
__device__ __nv_bfloat16 g_xdwb[B_*NN*C_];     // dw out [M][C] bf16 (direct)
__device__ float g_xc  [B_*NN*C_];
__device__ float g_xs  [B_*NN*C_];
__device__ __nv_bfloat16 g_xsb[B_*NN*C_];      // xs bf16 (sg1 gemm A)
__device__ float g_t1  [B_*NN*GG];
__device__ float g_sg  [B_*NN];
__device__ float g_cgpart[B_*16*C_];
__device__ float g_x2  [B_*NN*C_];
__device__ __nv_bfloat16 g_ln2b[B_*NN*C_];
__device__ __nv_bfloat16 g_hb  [B_*NN*HID];
__device__ __nv_bfloat16 g_wqt [3*C_*C_];      // qkv_w^T [768][256]
__device__ __nv_bfloat16 g_wot [C_*C_];        // out_w^T [256][256]
__device__ __nv_bfloat16 g_wpwb[C_*C_];        // pw_w ([N][K]) bf16
__device__ __nv_bfloat16 g_wsg1[GG*C_];        // sg1_w ([N][K]) bf16
__device__ __nv_bfloat16 g_w1t [HID*C_];       // ff_w1^T [1024][256]
__device__ __nv_bfloat16 g_w2t [C_*HID];       // ff_w2^T [256][1024]

// ---------------- helpers ----------------
__device__ __forceinline__ void cp16(void* sptr, const void* gptr) {
    unsigned saddr = (unsigned)__cvta_generic_to_shared(sptr);
    asm volatile("cp.async.cg.shared.global [%0], [%1], 16;" :: "r"(saddr), "l"(gptr));
}
__device__ __forceinline__ void cp_commit() { asm volatile("cp.async.commit_group;"); }
__device__ __forceinline__ void cp_wait0()  { asm volatile("cp.async.wait_group 0;" ::: "memory"); }

__device__ __forceinline__ void mma_bf16(float* d, const unsigned* a,
                                         const unsigned* b, const float* c) {
    asm volatile("mma.sync.aligned.m16n8k16.row.col.f32.bf16.bf16.f32 "
        "{%0,%1,%2,%3}, {%4,%5,%6,%7}, {%8,%9}, {%10,%11,%12,%13};"
        : "=f"(d[0]),"=f"(d[1]),"=f"(d[2]),"=f"(d[3])
        : "r"(a[0]),"r"(a[1]),"r"(a[2]),"r"(a[3]),
          "r"(b[0]),"r"(b[1]),
          "f"(c[0]),"f"(c[1]),"f"(c[2]),"f"(c[3]));
}
__device__ __forceinline__ unsigned long long pack2(float lo, float hi) {
    unsigned long long r;
    asm("mov.b64 %0, {%1, %2};" : "=l"(r) : "f"(lo), "f"(hi));
    return r;
}
__device__ __forceinline__ void unpack2(unsigned long long v, float& lo, float& hi) {
    asm("mov.b64 {%0, %1}, %2;" : "=f"(lo), "=f"(hi) : "l"(v));
}
__device__ __forceinline__ unsigned long long fma2(unsigned long long a,
                                                   unsigned long long b,
                                                   unsigned long long c) {
    unsigned long long d;
    asm("fma.rn.f32x2 %0, %1, %2, %3;" : "=l"(d) : "l"(a), "l"(b), "l"(c));
    return d;
}
__device__ __forceinline__ unsigned long long mul2(unsigned long long a,
                                                   unsigned long long b) {
    unsigned long long d;
    asm("mul.rn.f32x2 %0, %1, %2;" : "=l"(d) : "l"(a), "l"(b));
    return d;
}
__device__ __forceinline__ float2 bf2f(unsigned u) {
    __nv_bfloat162 h = *reinterpret_cast<__nv_bfloat162*>(&u);
    return __bfloat1622float2(h);
}

// ---------------- bf16 tensor-core GEMM body (A [M,K], B [N,K]), BK=16 ----------------
template<int BM, int BN, int EPI>
__device__ __forceinline__ void gemm_body(
    __nv_bfloat16* As, __nv_bfloat16* Bs,
    const __nv_bfloat16* __restrict__ A, const __nv_bfloat16* __restrict__ B,
    void* __restrict__ Cout, const float* __restrict__ bias,
    const float* __restrict__ aux, int M, int N, int K, int bxi, int byi) {
    constexpr int BK = 16;
    constexpr int WM = BM/2, WN = BN/4;
    constexpr int MT = WM/16, NT = WN/8;
    constexpr int STR = 24;

    const int bm = byi*BM, bn = bxi*BN;
    const int tid = threadIdx.x;
    const int lane = tid & 31, wid = tid >> 5;
    const int wm = wid >> 2, wn = wid & 3;
    const int g = lane >> 2, tig = lane & 3;

    float acc[MT][NT][4];
    #pragma unroll
    for (int i = 0; i < MT; i++)
        #pragma unroll
        for (int j = 0; j < NT; j++)
            #pragma unroll
            for (int l = 0; l < 4; l++) acc[i][j][l] = 0.f;

    auto copy_tile = [&](int st, int k0) {
        {
            constexpr int CA = BM*2;
            int ch = tid;
            if (CA == 256 || ch < CA) {
                int row = ch >> 1, c8 = (ch & 1)*8;
                cp16(&As[st*BM*STR + row*STR + c8], &A[(size_t)(bm+row)*K + k0 + c8]);
            }
        }
        {
            constexpr int CB = BN*2;
            int ch = tid;
            if (CB == 256 || ch < CB) {
                int row = ch >> 1, c8 = (ch & 1)*8;
                cp16(&Bs[st*BN*STR + row*STR + c8], &B[(size_t)(bn+row)*K + k0 + c8]);
            }
        }
    };

    copy_tile(0, 0);
    cp_commit();
    int stage = 0;
    for (int k0 = 0; k0 < K; k0 += BK) {
        cp_wait0();
        __syncthreads();
        if (k0 + BK < K) { copy_tile(stage^1, k0+BK); cp_commit(); }
        const __nv_bfloat16* as = As + stage*BM*STR;
        const __nv_bfloat16* bs = Bs + stage*BN*STR;
        int kk = 2*tig;
        unsigned afr[MT][4];
        #pragma unroll
        for (int mt = 0; mt < MT; mt++) {
            int r0 = wm*WM + mt*16 + g;
            afr[mt][0] = *(const unsigned*)&as[(r0  )*STR + kk  ];
            afr[mt][1] = *(const unsigned*)&as[(r0+8)*STR + kk  ];
            afr[mt][2] = *(const unsigned*)&as[(r0  )*STR + kk+8];
            afr[mt][3] = *(const unsigned*)&as[(r0+8)*STR + kk+8];
        }
        unsigned bfr[NT][2];
        #pragma unroll
        for (int nt = 0; nt < NT; nt++) {
            int c0 = wn*WN + nt*8 + g;
            bfr[nt][0] = *(const unsigned*)&bs[c0*STR + kk  ];
            bfr[nt][1] = *(const unsigned*)&bs[c0*STR + kk+8];
        }
        #pragma unroll
        for (int mt = 0; mt < MT; mt++)
            #pragma unroll
            for (int nt = 0; nt < NT; nt++)
                mma_bf16(acc[mt][nt], afr[mt], bfr[nt], acc[mt][nt]);
        stage ^= 1;
    }

    #pragma unroll
    for (int mt = 0; mt < MT; mt++) {
        int row0 = bm + wm*WM + mt*16 + g;
        #pragma unroll
        for (int nt = 0; nt < NT; nt++) {
            int col = bn + wn*WN + nt*8 + tig*2;
            #pragma unroll
            for (int half = 0; half < 2; half++) {
                int row = row0 + half*8;
                float v0 = acc[mt][nt][half*2], v1 = acc[mt][nt][half*2+1];
                if (EPI == 0) {
                    *(float2*)&((float*)Cout)[(size_t)row*N + col] = make_float2(v0, v1);
                } else if (EPI == 1) {
                    v0 += bias[col]; v1 += bias[col+1];
                    v0 = 0.5f*v0*(1.0f + erff(v0*0.70710678118654752f));
                    v1 = 0.5f*v1*(1.0f + erff(v1*0.70710678118654752f));
                    __nv_bfloat162 p;
                    p.x = __float2bfloat16(v0); p.y = __float2bfloat16(v1);
                    *(__nv_bfloat162*)&((__nv_bfloat16*)Cout)[(size_t)row*N + col] = p;
                } else if (EPI == 2) {
                    int b = row / NN, n = row - b*NN;
                    int part = col >> 8, cc = col & 255;
                    int h = cc >> 5, d = cc & 31;
                    size_t dst = ((size_t)(b*NHEAD + h)*NN + n)*DH + d;
                    __nv_bfloat162 p;
                    if (part == 0) {
                        p.x = __float2bfloat16(v0*QSCALE);
                        p.y = __float2bfloat16(v1*QSCALE);
                        *(__nv_bfloat162*)&g_qb[dst] = p;
                    } else if (part == 1) {
                        p.x = __float2bfloat16(v0); p.y = __float2bfloat16(v1);
                        *(__nv_bfloat162*)&g_kb[dst] = p;
                    } else {
                        p.x = __float2bfloat16(v0); p.y = __float2bfloat16(v1);
                        *(__nv_bfloat162*)&g_vb[dst] = p;
                    }
                } else if (EPI == 3) {
                    v0 += g_xc[(size_t)row*C_ + col]   + bias[col];
                    v1 += g_xc[(size_t)row*C_ + col+1] + bias[col+1];
                    *(float2*)&((float*)Cout)[(size_t)row*N + col] = make_float2(v0, v1);
                    __nv_bfloat162 p;
                    p.x = __float2bfloat16(v0); p.y = __float2bfloat16(v1);
                    *(__nv_bfloat162*)&g_xsb[(size_t)row*C_ + col] = p;
                } else if (EPI == 4) {
                    int b = row / NN, n = row - b*NN;
                    float gm = aux[0];
                    float o0 = g_x2[(size_t)row*C_ + col]   + gm*(v0 + bias[col]);
                    float o1 = g_x2[(size_t)row*C_ + col+1] + gm*(v1 + bias[col+1]);
                    float* C = (float*)Cout;
                    C[(size_t)(b*C_ + col  )*NN + n] = o0;
                    C[(size_t)(b*C_ + col+1)*NN + n] = o1;
                } else { // EPI == 5
                    v0 += bias[col]; v1 += bias[col+1];
                    v0 = v0 / (1.f + expf(-v0));
                    v1 = v1 / (1.f + expf(-v1));
                    *(float2*)&((float*)Cout)[(size_t)row*N + col] = make_float2(v0, v1);
                }
            }
        }
    }
}

template<int BM, int BN, int EPI>
__global__ __launch_bounds__(256, 3)
void gemm_bf(const __nv_bfloat16* __restrict__ A, const __nv_bfloat16* __restrict__ B,
             void* __restrict__ Cout, const float* __restrict__ bias,
             const float* __restrict__ aux, int M, int N, int K) {
    cudaGridDependencySynchronize();
    __shared__ __align__(16) __nv_bfloat16 As[2*BM*24];
    __shared__ __align__(16) __nv_bfloat16 Bs[2*BN*24];
    gemm_body<BM,BN,EPI>(As, Bs, A, B, Cout, bias, aux, M, N, K,
                         blockIdx.x, blockIdx.y);
}

// merged pw (blocks 0..287: 4x72) + QKV (blocks 288..719: 6x72)
__global__ __launch_bounds__(256, 3)
void gemm_pw_qkv_k(const __nv_bfloat16* __restrict__ xdwb,
                   const __nv_bfloat16* __restrict__ wpwb,
                   float* __restrict__ xc,
                   const __nv_bfloat16* __restrict__ xab,
                   const __nv_bfloat16* __restrict__ wqt) {
    cudaGridDependencySynchronize();
    __shared__ __align__(16) __nv_bfloat16 As[2*64*24];
    __shared__ __align__(16) __nv_bfloat16 Bs[2*128*24];
    int bb = blockIdx.x;
    if (bb < 288) {
        gemm_body<64,64,0>(As, Bs, xdwb, wpwb, xc, nullptr, nullptr,
                           B_*NN, C_, C_, bb % 4, bb / 4);
    } else {
        bb -= 288;
        gemm_body<64,128,2>(As, Bs, xab, wqt, nullptr, nullptr, nullptr,
                            B_*NN, 3*C_, C_, bb % 6, bb / 6);
    }
}

// ---------------- prep mega-kernel: wprep (0..832) + ln1 (833..976) + dw (977..1744) ----------------
__global__ __launch_bounds__(256) void prep_k(const float* __restrict__ x,
                                              const float* __restrict__ dw_w,
                                              const float* __restrict__ dw_b,
                                              const float* __restrict__ ln1_g,
                                              const float* __restrict__ ln1_b,
                                              const float* __restrict__ qkv_w,
                                              const float* __restrict__ out_w,
                                              const float* __restrict__ ff_w1,
                                              const float* __restrict__ ff_w2,
                                              const float* __restrict__ pw_w,
                                              const float* __restrict__ sg1_w) {
    cudaGridDependencySynchronize();
    __shared__ float sm[C_*33];
    __shared__ float smu[32], sr[32];
    int bb = blockIdx.x;
    int tid = threadIdx.x;
    if (bb < 832) {
        if (bb < 768) {
            const float* in; __nv_bfloat16* outp; int K, N, t0;
            if (bb < 192)      { in = qkv_w; outp = g_wqt; K = 256; N = 768;  t0 = bb; }
            else if (bb < 256) { in = out_w; outp = g_wot; K = 256; N = 256;  t0 = bb-192; }
            else if (bb < 512) { in = ff_w1; outp = g_w1t; K = 256; N = 1024; t0 = bb-256; }
            else               { in = ff_w2; outp = g_w2t; K = 1024; N = 256; t0 = bb-512; }
            int ntile = N/32;
            int nb = (t0 % ntile)*32, kb = (t0 / ntile)*32;
            int tx = tid & 31, ty = tid >> 5;
            float (*tile)[33] = (float(*)[33])sm;
            #pragma unroll
            for (int i = 0; i < 32; i += 8)
                tile[ty+i][tx] = in[(size_t)(kb+ty+i)*N + nb+tx];
            __syncthreads();
            #pragma unroll
            for (int i = 0; i < 32; i += 8)
                outp[(size_t)(nb+ty+i)*K + kb+tx] = __float2bfloat16(tile[tx][ty+i]);
        } else {
            int base = (bb-768)*1024 + tid;
            #pragma unroll
            for (int r = 0; r < 4; r++)
                g_wpwb[base + r*256] = __float2bfloat16(pw_w[base + r*256]);
        }
    } else if (bb == 832) {
        for (int i = tid; i < GG*C_; i += 256)
            g_wsg1[i] = __float2bfloat16(sg1_w[i]);
    } else if (bb < 833 + 144) {
        int blk = bb - 833;
        int b = blk / (NN/32);
        int n0 = (blk % (NN/32)) * 32;
        #pragma unroll
        for (int i = 0; i < 32; i++) {
            int idx = i*256 + tid;
            int c = idx >> 5, n = idx & 31;
            sm[c*33 + n] = x[(size_t)(b*C_ + c)*NN + n0 + n];
        }
        __syncthreads();
        int wid = tid >> 5, lane = tid & 31;
        #pragma unroll
        for (int j = 0; j < 4; j++) {
            int n = wid*4 + j;
            float s1 = 0, s2 = 0;
            #pragma unroll
            for (int i = 0; i < 8; i++) {
                float v = sm[(lane + i*32)*33 + n];
                s1 += v; s2 += v*v;
            }
            #pragma unroll
            for (int o = 16; o; o >>= 1) {
                s1 += __shfl_xor_sync(~0u, s1, o);
                s2 += __shfl_xor_sync(~0u, s2, o);
            }
            if (lane == 0) {
                float mu = s1*(1.0f/C_);
                float var = s2*(1.0f/C_) - mu*mu;
                smu[n] = mu; sr[n] = rsqrtf(var + 1e-6f);
            }
        }
        __syncthreads();
        #pragma unroll
        for (int i = 0; i < 32; i++) {
            int idx = i*256 + tid;
            int n = idx >> 8, c = idx & 255;
            float v = sm[c*33 + n];
            g_xab[(size_t)(b*NN + n0 + n)*C_ + c] =
                __float2bfloat16((v - smu[n])*sr[n]*ln1_g[c] + ln1_b[c]);
        }
    } else {
        int blk = bb - 977;                 // 0..767
        int b = blk / (HH*8);
        int rem = blk % (HH*8);
        int y = rem / 8;
        int c0 = (rem % 8) * 32;
        for (int idx = tid; idx < 32*3*WW; idx += 256) {
            int c = idx / (3*WW);
            int rr = (idx / WW) % 3;
            int xx = idx % WW;
            int yy = y + rr - 1;
            float v = (yy >= 0 && yy < HH)
                ? x[(size_t)(b*C_ + c0 + c)*NN + yy*WW + xx] : 0.f;
            sm[c*147 + rr*49 + xx] = v;
        }
        __syncthreads();
        int c = tid & 31, xg = tid >> 5;
        float wreg[9];
        #pragma unroll
        for (int j = 0; j < 9; j++) wreg[j] = dw_w[(c0 + c)*9 + j];
        float bz = dw_b[c0 + c];
        #pragma unroll
        for (int xp = 0; xp < 6; xp++) {
            int xx = xp*8 + xg;
            float acc = bz;
            #pragma unroll
            for (int dy = 0; dy < 3; dy++) {
                #pragma unroll
                for (int dx = 0; dx < 3; dx++) {
                    int xn = xx + dx - 1;
                    if (xn < 0 || xn >= WW) continue;
                    acc += sm[c*147 + dy*49 + xn] * wreg[dy*3 + dx];
                }
            }
            g_xdwb[(size_t)(b*NN + y*WW + xx)*C_ + c0 + c] = __float2bfloat16(acc);
        }
    }
}

// ---------------- per-(b,h) partial sums (uint4 + shuffle reduction) ----------------
__global__ void bh_sums1_k() {
    cudaGridDependencySynchronize();
    int bh = blockIdx.x, yy = blockIdx.y;     // 16 x 12
    int t = threadIdx.x;                      // 256
    size_t base = ((size_t)bh*NN + yy*192)*DH;
    const uint4* q4 = (const uint4*)(g_qb + base);
    const uint4* k4 = (const uint4*)(g_kb + base);
    const uint4* v4 = (const uint4*)(g_vb + base);
    float pq[8], pk[8], pv[8];
    #pragma unroll
    for (int i = 0; i < 8; i++) { pq[i]=0; pk[i]=0; pv[i]=0; }
    #pragma unroll
    for (int j = 0; j < 3; j++) {
        int u = t + j*256;
        uint4 aq = q4[u], ak = k4[u], av = v4[u];
        const unsigned* wq = (const unsigned*)&aq;
        const unsigned* wk = (const unsigned*)&ak;
        const unsigned* wv = (const unsigned*)&av;
        #pragma unroll
        for (int w = 0; w < 4; w++) {
            float2 fq = bf2f(wq[w]), fk = bf2f(wk[w]), fv = bf2f(wv[w]);
            pq[2*w] += fq.x; pq[2*w+1] += fq.y;
            pk[2*w] += fk.x; pk[2*w+1] += fk.y;
            pv[2*w] += fv.x; pv[2*w+1] += fv.y;
        }
    }
    #pragma unroll
    for (int o = 4; o <= 16; o <<= 1) {
        #pragma unroll
        for (int i = 0; i < 8; i++) {
            pq[i] += __shfl_xor_sync(~0u, pq[i], o);
            pk[i] += __shfl_xor_sync(~0u, pk[i], o);
            pv[i] += __shfl_xor_sync(~0u, pv[i], o);
        }
    }
    __shared__ float sh[3][8][32];
    int lane = t & 31, wid = t >> 5;
    if (lane < 4) {
        #pragma unroll
        for (int i = 0; i < 8; i++) {
            sh[0][wid][lane*8 + i] = pq[i];
            sh[1][wid][lane*8 + i] = pk[i];
            sh[2][wid][lane*8 + i] = pv[i];
        }
    }
    __syncthreads();
    if (t < 96) {
        int which = t >> 5, dd = t & 31;
        float s = 0;
        #pragma unroll
        for (int p = 0; p < 8; p++) s += sh[which][p][dd];
        g_spart[((bh*12 + yy)*3 + which)*DH + dd] = s;
    }
}

// ---------------- reduce partials + scores (128 threads, 18 y-blocks) ----------------
__global__ void scores_k() {
    cudaGridDependencySynchronize();
    int bh = blockIdx.x, yy = blockIdx.y;      // 16 x 18
    int t = threadIdx.x;                       // 128
    __shared__ float qs[DH], ks[DH];
    if (t < 96) {
        int which = t >> 5, d = t & 31;
        float s = 0;
        #pragma unroll
        for (int y = 0; y < 12; y++) s += g_spart[((bh*12 + y)*3 + which)*DH + d];
        if (which == 0) qs[d] = s;
        else if (which == 1) ks[d] = s;
        if (yy == 0) g_sums[(bh*3 + which)*DH + d] = s;
    }
    __syncthreads();
    int gid = bh*NN + yy*128 + t;
    unsigned uq[16], uk[16];
    {
        const uint4* qp4 = (const uint4*)&g_qb[(size_t)gid*DH];
        const uint4* kp4 = (const uint4*)&g_kb[(size_t)gid*DH];
        #pragma unroll
        for (int w = 0; w < 4; w++) {
            *(uint4*)&uq[w*4] = qp4[w];
            *(uint4*)&uk[w*4] = kp4[w];
        }
    }
    float r = 0, c = 0;
    #pragma unroll
    for (int w = 0; w < 16; w++) {
        float2 fq = bf2f(uq[w]), fk = bf2f(uk[w]);
        r += fq.x*ks[2*w] + fq.y*ks[2*w+1];
        c += qs[2*w]*fk.x + qs[2*w+1]*fk.y;
    }
    g_rs[gid] = r; g_cs[gid] = c;
}

// ---------------- exact top-k selection ----------------
__device__ __forceinline__ unsigned f2key(float f) {
    unsigned u = __float_as_uint(f);
    return (u & 0x80000000u) ? ~u : (u | 0x80000000u);
}

__device__ __forceinline__ int incl_scan256(int v, int t, int* wtot) {
    __syncthreads();
    int lane = t & 31, wid = t >> 5;
    #pragma unroll
    for (int o = 1; o < 32; o <<= 1) {
        int u = __shfl_up_sync(~0u, v, o);
        if (lane >= o) v += u;
    }
    if (lane == 31) wtot[wid] = v;
    __syncthreads();
    if (wid == 0) {
        int s = (lane < 8) ? wtot[lane] : 0;
        #pragma unroll
        for (int o = 1; o < 8; o <<= 1) {
            int u = __shfl_up_sync(~0u, s, o);
            if (lane >= o) s += u;
        }
        if (lane < 8) wtot[lane] = s;
    }
    __syncthreads();
    return v + (wid > 0 ? wtot[wid-1] : 0);
}

__global__ void select_k() {
    cudaGridDependencySynchronize();
    int blk = blockIdx.x;
    int type = blk >> 4, bh = blk & 15;
    const float* s = (type == 0 ? g_rs : g_cs) + bh*NN;
    int* list = (type == 0 ? g_rowlist : g_collist) + bh*KTOP;
    __shared__ unsigned keys[NN];
    __shared__ int hist[256];
    __shared__ int wtot[8];
    __shared__ unsigned sh_T;
    __shared__ int sh_take;
    int t = threadIdx.x;
    for (int i = t; i < NN; i += 256) keys[i] = f2key(s[i]);
    __syncthreads();

    unsigned prefix = 0, pmask = 0;
    int kneed = KTOP;
    for (int pass = 0; pass < 4; pass++) {
        int shift = 24 - 8*pass;
        hist[t] = 0;
        __syncthreads();
        for (int i = t; i < NN; i += 256) {
            unsigned u = keys[i];
            if ((u & pmask) == prefix) atomicAdd(&hist[(u >> shift) & 255], 1);
        }
        __syncthreads();
        int h = hist[t];
        int pre = incl_scan256(h, t, wtot);
        int total = wtot[7];
        int cum = total - pre;
        if (cum < kneed && cum + h >= kneed) {
            sh_T = prefix | ((unsigned)t << shift);
            sh_take = kneed - cum;
        }
        __syncthreads();
        prefix = sh_T;
        kneed = sh_take;
        pmask |= (0xffu << shift);
        __syncthreads();
    }
    unsigned T = prefix;
    int take = kneed;

    unsigned myk[9];
    int eqc = 0;
    #pragma unroll
    for (int j = 0; j < 9; j++) {
        myk[j] = keys[t*9 + j];
        eqc += (myk[j] == T);
    }
    int eqbase = incl_scan256(eqc, t, wtot) - eqc;

    bool kept[9];
    int keptc = 0, eqseen = 0;
    #pragma unroll
    for (int j = 0; j < 9; j++) {
        unsigned u = myk[j];
        bool gt = (u > T), eq = (u == T);
        bool kp = gt || (eq && (eqbase + eqseen) < take);
        if (eq) eqseen++;
        kept[j] = kp; keptc += kp;
    }
    int wbase = incl_scan256(keptc, t, wtot) - keptc;
    #pragma unroll
    for (int j = 0; j < 9; j++)
        if (kept[j]) list[wbase++] = t*9 + j;
}

// ---------------- merged: vunkept (blocks 0..15) + fill_o (rest) ----------------
__global__ void vunk_fillo_k() {
    cudaGridDependencySynchronize();
    int bb = blockIdx.x;
    if (bb < BHN) {
        int bh = bb;
        int t = threadIdx.x;
        int d = t & 31, part = t >> 5;
        float sv = 0;
        for (int jj = part; jj < KTOP; jj += 8) {
            int j = g_collist[bh*KTOP + jj];
            sv += __bfloat162float(g_vb[(bh*NN + j)*DH + d]);
        }
        __shared__ float sh[8][32];
        sh[part][d] = sv;
        __syncthreads();
        if (t < 32) {
            float s = 0;
            #pragma unroll
            for (int p = 0; p < 8; p++) s += sh[p][t];
            g_vunk[bh*DH + t] = g_sums[(bh*3+2)*DH + t] - s;
        }
    } else {
        int gid = (bb - BHN)*256 + threadIdx.x;
        if (gid >= BHN*NN*DH) return;
        int bh = gid / (NN*DH);
        int r = gid % (NN*DH);
        int n = r / DH, d = r & 31;
        int b = bh >> 3, h = bh & 7;
        g_ob[(size_t)(b*NN + n)*C_ + h*DH + d] =
            __float2bfloat16(g_sums[(bh*3+2)*DH + d] * (1.0f/NN));
    }
}

// ---------------- kept-row attention partials ----------------
__global__ __launch_bounds__(64) void attn_part_k() {
    cudaGridDependencySynchronize();
    int bh = blockIdx.x;
    int t = threadIdx.x;
    int slot = blockIdx.y*64 + t;
    int chunk = blockIdx.z;
    int i = g_rowlist[bh*KTOP + slot];

    unsigned long long qp2[16];
    {
        unsigned uq[16];
        const uint4* qp4 = (const uint4*)&g_qb[(size_t)(bh*NN + i)*DH];
        #pragma unroll
        for (int w = 0; w < 4; w++) *(uint4*)&uq[w*4] = qp4[w];
        #pragma unroll
        for (int w = 0; w < 16; w++) {
            float2 f = bf2f(uq[w]);
            qp2[w] = pack2(f.x, f.y);
        }
    }

    float m = -3.0e38f, Z = 0.f;
    unsigned long long acc2[16];
    #pragma unroll
    for (int idx = 0; idx < 16; idx++) acc2[idx] = 0ull;

    __shared__ int cj[CHUNK];
    __shared__ __align__(16) float Kc[CHUNK][DH];
    __shared__ __align__(16) float Vc[CHUNK][DH];

    {
        int c0 = chunk*CHUNK;
        for (int jj = t; jj < CHUNK; jj += 64) cj[jj] = g_collist[bh*KTOP + c0 + jj];
        __syncthreads();
        for (int idx = t; idx < CHUNK*DH; idx += 64) {
            int jj = idx >> 5, d = idx & 31;
            int base = (bh*NN + cj[jj])*DH + d;
            Kc[jj][d] = __bfloat162float(g_kb[base]);
            Vc[jj][d] = __bfloat162float(g_vb[base]);
        }
        __syncthreads();
        #pragma unroll 2
        for (int jj = 0; jj < CHUNK; jj++) {
            const unsigned long long* kp = (const unsigned long long*)Kc[jj];
            unsigned long long p0 = 0ull, p1 = 0ull;
            #pragma unroll
            for (int w = 0; w < 16; w += 2) {
                p0 = fma2(qp2[w  ], kp[w  ], p0);
                p1 = fma2(qp2[w+1], kp[w+1], p1);
            }
            float a, b2, c2, d2;
            unpack2(p0, a, b2); unpack2(p1, c2, d2);
            float s = (a + b2) + (c2 + d2);
            float e;
            if (s > m) {
                float cf = __expf(m - s);
                unsigned long long cf2 = pack2(cf, cf);
                Z = Z*cf;
                #pragma unroll
                for (int w = 0; w < 16; w++) acc2[w] = mul2(acc2[w], cf2);
                m = s;
                e = 1.f;
            } else {
                e = __expf(s - m);
            }
            Z += e;
            unsigned long long ee = pack2(e, e);
            const unsigned long long* vp = (const unsigned long long*)Vc[jj];
            #pragma unroll
            for (int w = 0; w < 16; w++) acc2[w] = fma2(ee, vp[w], acc2[w]);
        }
    }
    int pidx = (bh*KTOP + slot)*NSPLIT + chunk;
    g_pm[pidx] = m;
    g_pz[pidx] = Z;
    float* pa = &g_pacc[(size_t)pidx*DH];
    #pragma unroll
    for (int w = 0; w < 16; w++) {
        float lo, hi;
        unpack2(acc2[w], lo, hi);
        pa[2*w] = lo; pa[2*w+1] = hi;
    }
}

// ---------------- combine partials + zero-column correction -> bf16 ----------------
__global__ void attn_comb_k() {
    cudaGridDependencySynchronize();
    int gid = blockIdx.x*128 + threadIdx.x;
    if (gid >= BHN*KTOP) return;
    int bh = gid / KTOP, slot = gid % KTOP;
    int i = g_rowlist[bh*KTOP + slot];
    int p0 = gid*NSPLIT;
    float mm[NSPLIT];
    float mstar = 0.f;
    #pragma unroll
    for (int s = 0; s < NSPLIT; s++) { mm[s] = g_pm[p0+s]; mstar = fmaxf(mstar, mm[s]); }
    float ee[NSPLIT];
    float ez = __expf(-mstar);
    float Z = (float)(NN - KTOP) * ez;
    #pragma unroll
    for (int s = 0; s < NSPLIT; s++) { ee[s] = __expf(mm[s] - mstar); Z += g_pz[p0+s]*ee[s]; }
    float invZ = 1.f / Z;
    const float* vu = &g_vunk[bh*DH];
    int b = bh >> 3, h = bh & 7;
    __nv_bfloat16* op = &g_ob[(size_t)(b*NN + i)*C_ + h*DH];
    #pragma unroll
    for (int d = 0; d < DH; d++) {
        float acc = ez*vu[d];
        #pragma unroll
        for (int s = 0; s < NSPLIT; s++)
            acc += g_pacc[(size_t)(p0+s)*DH + d]*ee[s];
        op[d] = __float2bfloat16(acc * invZ);
    }
}

// ---------------- merged: sg2 (blocks 0..575) + cgpool (576..607) ----------------
__global__ __launch_bounds__(256) void sg2_cgpool_k(const float* __restrict__ w,
                                                    const float* __restrict__ bias) {
    cudaGridDependencySynchronize();
    int bb = blockIdx.x;
    if (bb < B_*NN/8) {
        __shared__ float ws[GG*49];
        int tid = threadIdx.x;
        for (int i = tid; i < GG*49; i += 256) ws[i] = w[i];
        __syncthreads();
        int p = bb*8 + (tid >> 5);
        int lane = tid & 31;
        int b = p / NN, n = p % NN;
        int y = n / WW, x0 = n % WW;
        float acc = 0.f;
        for (int ky = 0; ky < 7; ky++) {
            int yy = y + ky - 3;
            if (yy < 0 || yy >= HH) continue;
            #pragma unroll
            for (int kx = 0; kx < 7; kx++) {
                int xx = x0 + kx - 3;
                if (xx < 0 || xx >= WW) continue;
                acc += g_t1[(b*NN + yy*WW + xx)*GG + lane] * ws[lane*49 + ky*7 + kx];
            }
        }
        #pragma unroll
        for (int o = 16; o; o >>= 1) acc += __shfl_xor_sync(~0u, acc, o);
        if (lane == 0) g_sg[p] = 1.f / (1.f + expf(-(acc + bias[0])));
    } else {
        int blk = bb - B_*NN/8;          // 0..31
        int b = blk / 16, part = blk % 16;
        int c = threadIdx.x;
        float s = 0;
        int n0 = part*144;
        for (int n = n0; n < n0 + 144; n++) s += g_xs[(size_t)(b*NN + n)*C_ + c];
        g_cgpart[blk*C_ + c] = s;
    }
}

// ---------------- x2 = x + gamma1*xs*sg*cg, fused channel-gate + LN2 ----------------
__global__ __launch_bounds__(256) void x2ln2_k(const float* __restrict__ x,
                                               const float* __restrict__ gamma1,
                                               const float* __restrict__ gg2,
                                               const float* __restrict__ bb2,
                                               const float* __restrict__ cg1w,
                                               const float* __restrict__ cg1b,
                                               const float* __restrict__ cg2w,
                                               const float* __restrict__ cg2b) {
    cudaGridDependencySynchronize();
    __shared__ float tile[C_*33];
    __shared__ float smu[32], sr[32];
    __shared__ float cgm[C_];
    __shared__ float t2s[GG];
    int blk = blockIdx.x;
    int b = blk / (NN/32);
    int n0 = (blk % (NN/32)) * 32;
    int tid = threadIdx.x;
    {
        float s = 0;
        #pragma unroll
        for (int p = 0; p < 16; p++) s += g_cgpart[(b*16 + p)*C_ + tid];
        cgm[tid] = s * (1.0f/NN);
    }
    #pragma unroll
    for (int i = 0; i < 32; i++) {
        int idx = i*256 + tid;
        int c = idx >> 5, n = idx & 31;
        tile[c*33 + n] = x[(size_t)(b*C_ + c)*NN + n0 + n];
    }
    __syncthreads();
    if (tid < GG) {
        float a = cg1b[tid];
        const float* wp = &cg1w[tid*C_];
        for (int ci = 0; ci < C_; ci++) a += cgm[ci]*wp[ci];
        t2s[tid] = a / (1.f + expf(-a));
    }
    __syncthreads();
    float cgv;
    {
        float a2 = cg2b[tid];
        const float* wp2 = &cg2w[tid*GG];
        #pragma unroll
        for (int g = 0; g < GG; g++) a2 += t2s[g]*wp2[g];
        cgv = 1.f / (1.f + expf(-a2));
    }
    float gm = gamma1[0];
    #pragma unroll
    for (int i = 0; i < 32; i++) {
        int row = b*NN + n0 + i;
        int c = tid;
        float v = tile[c*33 + i] + gm * g_xs[(size_t)row*C_ + c] * g_sg[row] * cgv;
        g_x2[(size_t)row*C_ + c] = v;
        tile[c*33 + i] = v;
    }
    __syncthreads();
    int wid = tid >> 5, lane = tid & 31;
    #pragma unroll
    for (int j = 0; j < 4; j++) {
        int n = wid*4 + j;
        float s1 = 0, s2 = 0;
        #pragma unroll
        for (int i = 0; i < 8; i++) {
            float v = tile[(lane + i*32)*33 + n];
            s1 += v; s2 += v*v;
        }
        #pragma unroll
        for (int o = 16; o; o >>= 1) {
            s1 += __shfl_xor_sync(~0u, s1, o);
            s2 += __shfl_xor_sync(~0u, s2, o);
        }
        if (lane == 0) {
            float mu = s1*(1.0f/C_);
            float var = s2*(1.0f/C_) - mu*mu;
            smu[n] = mu; sr[n] = rsqrtf(var + 1e-6f);
        }
    }
    __syncthreads();
    #pragma unroll
    for (int i = 0; i < 32; i++) {
        int idx = i*256 + tid;
        int n = idx >> 8, c = idx & 255;
        float v = tile[c*33 + n];
        g_ln2b[(size_t)(b*NN + n0 + n)*C_ + c] =
            __float2bfloat16((v - smu[n])*sr[n]*gg2[c] + bb2[c]);
    }
}

// ---------------- host ----------------
#define GETSYM(p, s, T) do { void* _t; cudaGetSymbolAddress(&_t, s); p = (T*)_t; } while (0)

template<typename... A>
static void pdl_launch(dim3 g, dim3 b, void(*k)(A...), A... args) {
    cudaLaunchConfig_t cfg = {};
    cfg.gridDim = g; cfg.blockDim = b;
    cfg.dynamicSmemBytes = 0; cfg.stream = 0;
    cudaLaunchAttribute at[1];
    at[0].id = cudaLaunchAttributeProgrammaticStreamSerialization;
    at[0].val.programmaticStreamSerializationAllowed = 1;
    cfg.attrs = at; cfg.numAttrs = 1;
    cudaLaunchKernelEx(&cfg, k, args...);
}

extern "C" void kernel_launch(void* const* d_in, const int* in_sizes, int n_in,
                              void* d_out, int out_size) {
    const float* x     = (const float*)d_in[0];
    const float* qkv_w = (const float*)d_in[1];
    const float* out_w = (const float*)d_in[2];
    const float* ln1_g = (const float*)d_in[3];
    const float* ln1_b = (const float*)d_in[4];
    const float* ln2_g = (const float*)d_in[5];
    const float* ln2_b = (const float*)d_in[6];
    const float* dw_w  = (const float*)d_in[7];
    const float* dw_b  = (const float*)d_in[8];
    const float* pw_w  = (const float*)d_in[9];
    const float* pw_b  = (const float*)d_in[10];
    const float* sg1_w = (const float*)d_in[11];
    const float* sg1_b = (const float*)d_in[12];
    const float* sg2_w = (const float*)d_in[13];
    const float* sg2_b = (const float*)d_in[14];
    const float* cg1_w = (const float*)d_in[15];
    const float* cg1_b = (const float*)d_in[16];
    const float* cg2_w = (const float*)d_in[17];
    const float* cg2_b = (const float*)d_in[18];
    const float* ff_w1 = (const float*)d_in[19];
    const float* ff_b1 = (const float*)d_in[20];
    const float* ff_w2 = (const float*)d_in[21];
    const float* ff_b2 = (const float*)d_in[22];
    const float* gamma1= (const float*)d_in[23];
    const float* gamma2= (const float*)d_in[24];
    float* out = (float*)d_out;
    (void)in_sizes; (void)n_in; (void)out_size;

    float *p_xc, *p_xs, *p_t1;
    __nv_bfloat16 *p_xab, *p_ob, *p_xdwb, *p_xsb, *p_ln2b, *p_hb;
    __nv_bfloat16 *p_wqt, *p_wot, *p_wpwb, *p_wsg1, *p_w1t, *p_w2t;
    GETSYM(p_xc, g_xc, float); GETSYM(p_xs, g_xs, float);
    GETSYM(p_t1, g_t1, float);
    GETSYM(p_xab, g_xab, __nv_bfloat16); GETSYM(p_ob, g_ob, __nv_bfloat16);
    GETSYM(p_xdwb, g_xdwb, __nv_bfloat16); GETSYM(p_xsb, g_xsb, __nv_bfloat16);
    GETSYM(p_ln2b, g_ln2b, __nv_bfloat16); GETSYM(p_hb, g_hb, __nv_bfloat16);
    GETSYM(p_wqt, g_wqt, __nv_bfloat16); GETSYM(p_wot, g_wot, __nv_bfloat16);
    GETSYM(p_wpwb, g_wpwb, __nv_bfloat16); GETSYM(p_wsg1, g_wsg1, __nv_bfloat16);
    GETSYM(p_w1t, g_w1t, __nv_bfloat16); GETSYM(p_w2t, g_w2t, __nv_bfloat16);

    const int M = B_*NN;   // 4608

    pdl_launch(dim3(1745), dim3(256), prep_k,
               x, dw_w, dw_b, ln1_g, ln1_b, qkv_w, out_w, ff_w1, ff_w2, pw_w, sg1_w);
    pdl_launch(dim3(720), dim3(256), gemm_pw_qkv_k,
               (const __nv_bfloat16*)p_xdwb, (const __nv_bfloat16*)p_wpwb, p_xc,
               (const __nv_bfloat16*)p_xab, (const __nv_bfloat16*)p_wqt);
    pdl_launch(dim3(BHN, 12), dim3(256), bh_sums1_k);
    pdl_launch(dim3(BHN, 18), dim3(128), scores_k);
    pdl_launch(dim3(32), dim3(256), select_k);
    pdl_launch(dim3(BHN + (BHN*NN*DH)/256), dim3(256), vunk_fillo_k);
    pdl_launch(dim3(BHN, 9, NSPLIT), dim3(64), attn_part_k);
    pdl_launch(dim3((BHN*KTOP + 127)/128), dim3(128), attn_comb_k);
    pdl_launch(dim3(C_/64, M/64), dim3(256), gemm_bf<64,64,3>,
               (const __nv_bfloat16*)p_ob, (const __nv_bfloat16*)p_wot,
               (void*)p_xs, (const float*)pw_b, (const float*)nullptr, M, C_, C_);

    pdl_launch(dim3(1, M/64), dim3(256), gemm_bf<64,32,5>,
               (const __nv_bfloat16*)p_xsb, (const __nv_bfloat16*)p_wsg1,
               (void*)p_t1, (const float*)sg1_b, (const float*)nullptr, M, GG, C_);
    pdl_launch(dim3(B_*NN/8 + B_*16), dim3(256), sg2_cgpool_k, sg2_w, sg2_b);
    pdl_launch(dim3(B_*NN/32), dim3(256), x2ln2_k,
               x, gamma1, ln2_g, ln2_b, cg1_w, cg1_b, cg2_w, cg2_b);

    pdl_launch(dim3(HID/128, M/64), dim3(256), gemm_bf<64,128,1>,
               (const __nv_bfloat16*)p_ln2b, (const __nv_bfloat16*)p_w1t,
               (void*)p_hb, (const float*)ff_b1, (const float*)nullptr, M, HID, C_);
    pdl_launch(dim3(C_/64, M/64), dim3(256), gemm_bf<64,64,4>,
               (const __nv_bfloat16*)p_hb, (const __nv_bfloat16*)p_w2t,
               (void*)out, (const float*)ff_b2, (const float*)gamma2, M, C_, HID);
}